// round 4
// baseline (speedup 1.0000x reference)
#include <cuda_runtime.h>
#include <math.h>
#include <stdint.h>

// ---------------- problem constants ----------------
constexpr int B_  = 8;
constexpr int NN  = 2000;
constexpr int E_  = 512;
constexpr int HEN = 1024;
constexpr int D_  = 128;   // 2*IB
constexpr int HD  = 512;
constexpr int KF  = 4096;  // P*HD
constexpr int IB_ = 64;
constexpr long long MR = (long long)B_ * NN; // 16000 rows

// ---------------- scratch layout ----------------
constexpr long long SZ_AG   = MR * E_;
constexpr long long SZ_HENC = MR * HEN;
constexpr long long SZ_H    = MR * D_;
constexpr long long SZ_GLW  = (long long)D_ * KF;
constexpr long long SZ_F    = MR * KF;
constexpr long long SZ_ATT  = (long long)B_ * NN * NN;
constexpr long long SZ_DINV = MR;
constexpr long long SZ_T    = MR * HD;
constexpr long long SZ_O    = MR * HD;
constexpr long long SZ_O3   = MR * D_;
constexpr long long SZ_Z    = (long long)B_ * IB_;

constexpr long long OFF_AG   = 0;
constexpr long long OFF_HENC = OFF_AG + SZ_AG;
constexpr long long OFF_H1   = OFF_HENC + SZ_HENC;
constexpr long long OFF_H2   = OFF_H1 + SZ_H;
constexpr long long OFF_GLW  = OFF_H2 + SZ_H;
constexpr long long OFF_F    = OFF_GLW + SZ_GLW;
constexpr long long OFF_ATT  = OFF_F + SZ_F;
constexpr long long OFF_DINV = OFF_ATT + SZ_ATT;
constexpr long long OFF_T    = OFF_DINV + SZ_DINV;
constexpr long long OFF_O1   = OFF_T + SZ_T;
constexpr long long OFF_O2   = OFF_O1 + SZ_O;
constexpr long long OFF_O3   = OFF_O2 + SZ_O;
constexpr long long OFF_Z    = OFF_O3 + SZ_O3;
constexpr long long SCRATCH_TOTAL = OFF_Z + SZ_Z;

__device__ float g_scratch[SCRATCH_TOTAL];

// ---------------- tf32 helpers ----------------
__device__ __forceinline__ uint32_t f2tf32(float v) {
    uint32_t r;
    asm("cvt.rna.tf32.f32 %0, %1;" : "=r"(r) : "f"(v));
    return r;
}

__device__ __forceinline__ void mma_tf32(float* c, const uint32_t* a, uint32_t b0, uint32_t b1) {
    asm volatile(
        "mma.sync.aligned.m16n8k8.row.col.f32.tf32.tf32.f32 "
        "{%0,%1,%2,%3}, {%4,%5,%6,%7}, {%8,%9}, {%0,%1,%2,%3};"
        : "+f"(c[0]), "+f"(c[1]), "+f"(c[2]), "+f"(c[3])
        : "r"(a[0]), "r"(a[1]), "r"(a[2]), "r"(a[3]), "r"(b0), "r"(b1));
}

// ---------------- tf32 tensor GEMM: 128x256 CTA tile, 64x64 warp tile ----------------
// C[M,N] = act( epi( alpha * op(A) @ op(B) ) + bias )
// TA=0: A[m,k]. TA=1: A[k,m] -> A^T @ B.  TB=0: B[k,n]. TB=1: B[n,k] -> A @ B^T.
// ACT: 0 none, 1 relu, 2 gelu(exact)
// EPI: 0 none, 1: v=dinv[m]*v, 2: v=dinv[m]*(v+Tm[m,n])+bias (GCN aggregate)
// SYM: symmetric output (M==N): skip tiles fully below diagonal; mirror-write
//      elements whose transpose-tile is inactive (exactly-once coverage).
constexpr int GPAD = 20;        // u32 row stride (16 + 4) -> conflict-free frag LDS
constexpr int GTM = 128, GTN = 256;
constexpr int SMEM_U32 = 2 * GTM * GPAD + 2 * GTN * GPAD;   // 15360
constexpr int SMEM_BYTES = SMEM_U32 * 4;                    // 61440

template<int TA, int TB, int ACT, int EPI, int SYM>
__global__ void __launch_bounds__(256) tgemm_k(
    int M, int N, int K, float alpha,
    const float* __restrict__ A, int lda, long long sA,
    const float* __restrict__ B, int ldb, long long sB,
    float* __restrict__ C, int ldc, long long sC,
    const float* __restrict__ bias,
    const float* __restrict__ dinv, long long sD,
    const float* __restrict__ Tm, int ldt, long long sT)
{
    extern __shared__ uint32_t sh[];
    uint32_t* Asb[2] = { sh,                sh + GTM * GPAD };
    uint32_t* Bsb[2] = { sh + 2*GTM*GPAD,   sh + 2*GTM*GPAD + GTN*GPAD };

    const int bz = blockIdx.z;
    A += bz * sA; B += bz * sB; C += bz * sC;
    if (EPI)      dinv += bz * sD;
    if (EPI == 2) Tm   += bz * sT;

    const int bn = blockIdx.x, bm = blockIdx.y;
    const int m0 = bm * GTM, n0 = bn * GTN;
    if (SYM && m0 >= n0 + GTN) return;     // fully below diagonal

    const int tid  = threadIdx.x;
    const int lane = tid & 31, warp = tid >> 5;
    const int g = lane >> 2, th = lane & 3;
    const int wm = (warp >> 2) * 64;       // 2 warp rows
    const int wn = (warp & 3) * 64;        // 4 warp cols

    float acc[4][8][4];
#pragma unroll
    for (int i = 0; i < 4; i++)
#pragma unroll
        for (int j = 0; j < 8; j++)
#pragma unroll
            for (int l = 0; l < 4; l++) acc[i][j][l] = 0.f;

    float ra[8], rb[16];
    const int KT = K >> 4;

    auto loadA = [&](int kt) {
#pragma unroll
        for (int it = 0; it < 2; it++) {
            int c = tid * 2 + it;
            if (TA == 0) {
                int row = c >> 2, kc = (c & 3) * 4;
                int gm = m0 + row;
                float4 v = make_float4(0.f, 0.f, 0.f, 0.f);
                if (gm < M) v = *reinterpret_cast<const float4*>(A + (long long)gm * lda + kt * 16 + kc);
                ra[it*4+0]=v.x; ra[it*4+1]=v.y; ra[it*4+2]=v.z; ra[it*4+3]=v.w;
            } else {
                int kr = c >> 5, mc = (c & 31) * 4;
                int gm = m0 + mc;
                float4 v = make_float4(0.f, 0.f, 0.f, 0.f);
                const float* src = A + (long long)(kt * 16 + kr) * lda + gm;
                if (gm + 3 < M) v = *reinterpret_cast<const float4*>(src);
                else { float t[4]={0,0,0,0}; for (int j=0;j<4;j++) if (gm+j<M) t[j]=src[j]; v=make_float4(t[0],t[1],t[2],t[3]); }
                ra[it*4+0]=v.x; ra[it*4+1]=v.y; ra[it*4+2]=v.z; ra[it*4+3]=v.w;
            }
        }
    };
    auto loadB = [&](int kt) {
#pragma unroll
        for (int it = 0; it < 4; it++) {
            if (TB == 1) {
                int row = tid, kc = it * 4;            // c = tid*4+it -> row=tid
                int gn = n0 + row;
                float4 v = make_float4(0.f, 0.f, 0.f, 0.f);
                if (gn < N) v = *reinterpret_cast<const float4*>(B + (long long)gn * ldb + kt * 16 + kc);
                rb[it*4+0]=v.x; rb[it*4+1]=v.y; rb[it*4+2]=v.z; rb[it*4+3]=v.w;
            } else {
                int kr = tid >> 4, nc = ((tid & 15) * 4 + it) * 4;
                int gn = n0 + nc;
                float4 v = make_float4(0.f, 0.f, 0.f, 0.f);
                const float* src = B + (long long)(kt * 16 + kr) * ldb + gn;
                if (gn + 3 < N) v = *reinterpret_cast<const float4*>(src);
                else { float t[4]={0,0,0,0}; for (int j=0;j<4;j++) if (gn+j<N) t[j]=src[j]; v=make_float4(t[0],t[1],t[2],t[3]); }
                rb[it*4+0]=v.x; rb[it*4+1]=v.y; rb[it*4+2]=v.z; rb[it*4+3]=v.w;
            }
        }
    };
    auto stsA = [&](int buf) {
        uint32_t* dst = Asb[buf];
#pragma unroll
        for (int it = 0; it < 2; it++) {
            int c = tid * 2 + it;
            if (TA == 0) {
                int row = c >> 2, kc = (c & 3) * 4;
                uint4 p = make_uint4(f2tf32(ra[it*4+0]), f2tf32(ra[it*4+1]),
                                     f2tf32(ra[it*4+2]), f2tf32(ra[it*4+3]));
                *reinterpret_cast<uint4*>(&dst[row * GPAD + kc]) = p;   // STS.128
            } else {
                int kr = c >> 5, mc = (c & 31) * 4;
#pragma unroll
                for (int j = 0; j < 4; j++) dst[(mc + j) * GPAD + kr] = f2tf32(ra[it*4+j]);
            }
        }
    };
    auto stsB = [&](int buf) {
        uint32_t* dst = Bsb[buf];
#pragma unroll
        for (int it = 0; it < 4; it++) {
            if (TB == 1) {
                uint4 p = make_uint4(f2tf32(rb[it*4+0]), f2tf32(rb[it*4+1]),
                                     f2tf32(rb[it*4+2]), f2tf32(rb[it*4+3]));
                *reinterpret_cast<uint4*>(&dst[tid * GPAD + it * 4]) = p;  // STS.128
            } else {
                int kr = tid >> 4, nc = ((tid & 15) * 4 + it) * 4;
#pragma unroll
                for (int j = 0; j < 4; j++) dst[(nc + j) * GPAD + kr] = f2tf32(rb[it*4+j]);
            }
        }
    };
    auto mmaTile = [&](int buf) {
        const uint32_t* Ab = Asb[buf];
        const uint32_t* Bb = Bsb[buf];
#pragma unroll
        for (int s = 0; s < 2; s++) {
            const int k0 = s * 8;
            uint32_t a[4][4];
#pragma unroll
            for (int mt = 0; mt < 4; mt++) {
                int mrow = wm + mt * 16 + g;
                a[mt][0] = Ab[mrow * GPAD + k0 + th];
                a[mt][1] = Ab[(mrow + 8) * GPAD + k0 + th];
                a[mt][2] = Ab[mrow * GPAD + k0 + th + 4];
                a[mt][3] = Ab[(mrow + 8) * GPAD + k0 + th + 4];
            }
#pragma unroll
            for (int nt = 0; nt < 8; nt++) {
                int nrow = wn + nt * 8 + g;
                uint32_t b0 = Bb[nrow * GPAD + k0 + th];
                uint32_t b1 = Bb[nrow * GPAD + k0 + th + 4];
#pragma unroll
                for (int mt = 0; mt < 4; mt++)
                    mma_tf32(acc[mt][nt], a[mt], b0, b1);
            }
        }
    };

    // ---- pipelined mainloop ----
    loadA(0); loadB(0);
    stsA(0);  stsB(0);
    if (KT > 1) { loadA(1); loadB(1); }
    __syncthreads();
    for (int kt = 0; kt < KT; kt++) {
        int cur = kt & 1, nxt = cur ^ 1;
        if (kt + 1 < KT) { stsA(nxt); stsB(nxt); }
        if (kt + 2 < KT) { loadA(kt + 2); loadB(kt + 2); }
        mmaTile(cur);
        __syncthreads();
    }

    // ---- epilogue ----
#pragma unroll
    for (int mt = 0; mt < 4; mt++) {
#pragma unroll
        for (int nt = 0; nt < 8; nt++) {
#pragma unroll
            for (int e = 0; e < 4; e++) {
                int gm = m0 + wm + mt * 16 + g + (e >= 2 ? 8 : 0);
                int gn = n0 + wn + nt * 8 + 2 * th + (e & 1);
                if (gm >= M || gn >= N) continue;
                float v = alpha * acc[mt][nt][e];
                if (EPI == 1) v = dinv[gm] * v;
                if (EPI == 2) v = dinv[gm] * (v + Tm[(long long)gm * ldt + gn]);
                if (bias)     v += bias[gn];
                if (ACT == 1) v = fmaxf(v, 0.f);
                if (ACT == 2) v = 0.5f * v * (1.f + erff(v * 0.70710678118654752f));
                C[(long long)gm * ldc + gn] = v;
                if (SYM) {
                    // mirror (gn,gm) only if its owning tile is inactive
                    int mp0 = (gn >> 7) << 7;       // tile row start of mirror
                    int np0 = (gm >> 8) << 8;       // tile col start of mirror
                    if (mp0 >= np0 + GTN) C[(long long)gn * ldc + gm] = v;
                }
            }
        }
    }
}

// ---------------- A-matrix builder ----------------
__global__ void build_ag_k(const float* __restrict__ x, const float* __restrict__ emb,
                           const float* __restrict__ gw, const float* __restrict__ gb,
                           float* __restrict__ Ag)
{
    long long idx = (long long)blockIdx.x * blockDim.x + threadIdx.x;
    if (idx >= MR * E_) return;
    int e = (int)(idx & (E_ - 1));
    long long rn = idx >> 9;
    int n = (int)(rn % NN);
    float t = fmaf(x[rn], gw[e], gb[e]);
    float sgm = 1.0f / (1.0f + expf(-t));
    Ag[idx] = sgm * emb[(long long)n * E_ + e];
}

// ---------------- concat gl_w [P,D,HD] -> GLW [D, P*HD] ----------------
__global__ void build_glw_k(const float* __restrict__ glw, float* __restrict__ GLW)
{
    int idx = blockIdx.x * blockDim.x + threadIdx.x;
    if (idx >= D_ * KF) return;
    int k = idx / KF, c = idx % KF;
    int p = c >> 9, hh = c & 511;
    GLW[idx] = glw[((long long)p * D_ + k) * HD + hh];
}

// ---------------- top-k(50): byte-histogram radix select + masked softmax ----------------
__global__ void __launch_bounds__(256) topk_softmax_k(float* __restrict__ att)
{
    __shared__ float s[2000];
    __shared__ int   hist[256];
    __shared__ float wredf[8];
    __shared__ float s_bcast;
    __shared__ int   s_selb, s_selk;

    long long row = blockIdx.x;
    float* r = att + row * 2000;
    int tid = threadIdx.x;
    int lane = tid & 31, wid = tid >> 5;

    for (int i = tid; i < 2000; i += 256) s[i] = r[i];
    __syncthreads();

    float mx = 0.f;
    for (int i = tid; i < 2000; i += 256) mx = fmaxf(mx, s[i]);
#pragma unroll
    for (int o = 16; o; o >>= 1) mx = fmaxf(mx, __shfl_xor_sync(0xffffffffu, mx, o));
    if (lane == 0) wredf[wid] = mx;
    __syncthreads();
    if (tid == 0) { float m = wredf[0]; for (int w = 1; w < 8; w++) m = fmaxf(m, wredf[w]); s_bcast = m; }
    __syncthreads();
    mx = s_bcast;

    unsigned prefix = 0u;
    int k = 50;
#pragma unroll
    for (int pass = 0; pass < 4; pass++) {
        const int shift = 24 - 8 * pass;
        const unsigned hmask = (pass == 0) ? 0u : (0xFFFFFFFFu << (shift + 8));
        if (tid < 256) hist[tid] = 0;
        __syncthreads();
        for (int i = tid; i < 2000; i += 256) {
            unsigned u = __float_as_uint(s[i]);
            if ((u & hmask) == prefix)
                atomicAdd(&hist[(u >> shift) & 255], 1);
        }
        __syncthreads();
        if (tid == 0) {
            int acc = 0, b = 255;
            for (; b > 0; b--) { acc += hist[b]; if (acc >= k) break; }
            if (acc < k) acc += hist[0];
            s_selb = b;
            s_selk = k - (acc - hist[b]);
        }
        __syncthreads();
        prefix |= ((unsigned)s_selb) << shift;
        k = s_selk;
        __syncthreads();
    }
    float thr = __uint_as_float(prefix);

    float sum = 0.f;
    for (int i = tid; i < 2000; i += 256) {
        float v = s[i];
        float e = (v >= thr) ? expf(v - mx) : 0.f;
        s[i] = e; sum += e;
    }
#pragma unroll
    for (int o = 16; o; o >>= 1) sum += __shfl_xor_sync(0xffffffffu, sum, o);
    if (lane == 0) wredf[wid] = sum;
    __syncthreads();
    if (tid == 0) { float t = 0.f; for (int w = 0; w < 8; w++) t += wredf[w]; s_bcast = t; }
    __syncthreads();
    float inv = 1.0f / s_bcast;
    for (int i = tid; i < 2000; i += 256) r[i] = s[i] * inv;
}

// ---------------- dinv[b,i] = 1/sqrt(1 + sum_j adj[b,j,i]) ----------------
__global__ void colsum_k(const float* __restrict__ adj, float* __restrict__ dinv)
{
    int b = blockIdx.y;
    int i = blockIdx.x * blockDim.x + threadIdx.x;
    if (i >= 2000) return;
    const float* p = adj + (long long)b * 2000 * 2000 + i;
    float s0 = 0.f, s1 = 0.f, s2 = 0.f, s3 = 0.f;
    for (int j = 0; j < 2000; j += 4) {
        s0 += p[(long long)j * 2000];
        s1 += p[(long long)(j + 1) * 2000];
        s2 += p[(long long)(j + 2) * 2000];
        s3 += p[(long long)(j + 3) * 2000];
    }
    float d = 1.0f + ((s0 + s1) + (s2 + s3));
    dinv[b * 2000 + i] = 1.0f / sqrtf(d);
}

// ---------------- mean over nodes; mu/std/z ----------------
__global__ void meanz_k(const float* __restrict__ O3, const float* __restrict__ eps,
                        float* __restrict__ mu, float* __restrict__ stdv, float* __restrict__ z)
{
    int b = blockIdx.x, d = threadIdx.x;
    const float* p = O3 + ((long long)b * 2000) * 128 + d;
    float s0 = 0.f, s1 = 0.f, s2 = 0.f, s3 = 0.f;
    for (int i = 0; i < 2000; i += 4) {
        s0 += p[(long long)i * 128];
        s1 += p[(long long)(i + 1) * 128];
        s2 += p[(long long)(i + 2) * 128];
        s3 += p[(long long)(i + 3) * 128];
    }
    __shared__ float sg[128];
    sg[d] = ((s0 + s1) + (s2 + s3)) / 2000.0f;
    __syncthreads();
    if (d < 64) {
        float m = sg[d];
        float sp = log1pf(expf(sg[64 + d] - 64.0f));
        mu[b * 64 + d] = m;
        stdv[b * 64 + d] = sp;
        z[b * 64 + d] = fmaf(eps[b * 64 + d], sp, m);
    }
}

// ---------------- decoder (grid: b x col-chunks of 250) ----------------
__global__ void __launch_bounds__(256) decode_k(
    const float* __restrict__ z, const float* __restrict__ w1, const float* __restrict__ b1,
    const float* __restrict__ gamma, const float* __restrict__ beta,
    const float* __restrict__ w2, const float* __restrict__ b2,
    float* __restrict__ xrec)
{
    __shared__ float h[1024];
    __shared__ float zs[64];
    int b = blockIdx.x, tid = threadIdx.x;
    if (tid < 64) zs[tid] = z[b * 64 + tid];
    __syncthreads();
    const float invc = 1.0f / sqrtf(1.0f + 1e-5f);
    for (int c = tid; c < 1024; c += 256) {
        float a = b1[c];
#pragma unroll 8
        for (int k = 0; k < 64; k++) a = fmaf(zs[k], w1[k * 1024 + c], a);
        a = a * (gamma[c] * invc) + beta[c];
        h[c] = fmaxf(a, 0.f);
    }
    __syncthreads();
    int c0 = blockIdx.y * 250;
    int c1 = min(c0 + 250, 2000);
    for (int c = c0 + tid; c < c1; c += 256) {
        float a = b2[c];
        for (int k = 0; k < 1024; k++) a = fmaf(h[k], w2[k * 2000 + c], a);
        xrec[b * 2000 + c] = fmaxf(a, 0.f);
    }
}

// ---------------- host orchestration ----------------
extern "C" void kernel_launch(void* const* d_in, const int* in_sizes, int n_in,
                              void* d_out, int out_size)
{
    const float* x1     = (const float*)d_in[0];
    const float* x2     = (const float*)d_in[1];
    const float* emb1   = (const float*)d_in[2];
    const float* gate_w = (const float*)d_in[3];
    const float* gate_b = (const float*)d_in[4];
    const float* enc_w1 = (const float*)d_in[5];
    const float* enc_b1 = (const float*)d_in[6];
    const float* enc_w2 = (const float*)d_in[7];
    const float* enc_b2 = (const float*)d_in[8];
    const float* gl_w   = (const float*)d_in[9];
    const float* g_w1   = (const float*)d_in[10];
    const float* g_b1   = (const float*)d_in[11];
    const float* g_w2   = (const float*)d_in[12];
    const float* g_b2   = (const float*)d_in[13];
    const float* g_w3   = (const float*)d_in[14];
    const float* g_b3   = (const float*)d_in[15];
    const float* dW1[2] = {(const float*)d_in[16], (const float*)d_in[22]};
    const float* dB1[2] = {(const float*)d_in[17], (const float*)d_in[23]};
    const float* dG [2] = {(const float*)d_in[18], (const float*)d_in[24]};
    const float* dBe[2] = {(const float*)d_in[19], (const float*)d_in[25]};
    const float* dW2[2] = {(const float*)d_in[20], (const float*)d_in[26]};
    const float* dB2[2] = {(const float*)d_in[21], (const float*)d_in[27]};
    const float* epsA[2]= {(const float*)d_in[28], (const float*)d_in[29]};

    // opt-in to 60KB dynamic smem (idempotent; not a stream op -> capture-safe)
    static bool attr_done = false;
    if (!attr_done) {
        cudaFuncSetAttribute(tgemm_k<0,0,2,0,0>, cudaFuncAttributeMaxDynamicSharedMemorySize, SMEM_BYTES);
        cudaFuncSetAttribute(tgemm_k<0,0,0,0,0>, cudaFuncAttributeMaxDynamicSharedMemorySize, SMEM_BYTES);
        cudaFuncSetAttribute(tgemm_k<0,0,1,0,0>, cudaFuncAttributeMaxDynamicSharedMemorySize, SMEM_BYTES);
        cudaFuncSetAttribute(tgemm_k<0,1,0,0,1>, cudaFuncAttributeMaxDynamicSharedMemorySize, SMEM_BYTES);
        cudaFuncSetAttribute(tgemm_k<0,0,0,1,0>, cudaFuncAttributeMaxDynamicSharedMemorySize, SMEM_BYTES);
        cudaFuncSetAttribute(tgemm_k<1,0,1,2,0>, cudaFuncAttributeMaxDynamicSharedMemorySize, SMEM_BYTES);
        cudaFuncSetAttribute(tgemm_k<1,0,0,2,0>, cudaFuncAttributeMaxDynamicSharedMemorySize, SMEM_BYTES);
        attr_done = true;
    }

    float* sc = nullptr;
    cudaGetSymbolAddress((void**)&sc, g_scratch);
    float* Ag   = sc + OFF_AG;
    float* Henc = sc + OFF_HENC;
    float* Hbuf[2] = {sc + OFF_H1, sc + OFF_H2};
    float* GLW  = sc + OFF_GLW;
    float* F    = sc + OFF_F;
    float* att  = sc + OFF_ATT;
    float* dinv = sc + OFF_DINV;
    float* T    = sc + OFF_T;
    float* O1   = sc + OFF_O1;
    float* O2   = sc + OFF_O2;
    float* O3   = sc + OFF_O3;
    float* zb   = sc + OFF_Z;

    float* out = (float*)d_out;
    float* xrec[2] = {out,          out + 16000};
    float* muo [2] = {out + 32000,  out + 33024};
    float* stdo[2] = {out + 32512,  out + 33536};

    build_glw_k<<<(D_ * KF + 255) / 256, 256>>>(gl_w, GLW);

    // ---- encoders ----
    for (int xi = 0; xi < 2; xi++) {
        const float* x = xi ? x2 : x1;
        long long tot = MR * E_;
        build_ag_k<<<(unsigned)((tot + 255) / 256), 256>>>(x, emb1, gate_w, gate_b, Ag);
        tgemm_k<0,0,2,0,0><<<dim3(HEN / 256, 125, 1), 256, SMEM_BYTES>>>(
            16000, HEN, E_, 1.f, Ag, E_, 0, enc_w1, HEN, 0, Henc, HEN, 0,
            enc_b1, nullptr, 0, nullptr, 0, 0);
        tgemm_k<0,0,0,0,0><<<dim3(1, 125, 1), 256, SMEM_BYTES>>>(
            16000, D_, HEN, 1.f, Henc, HEN, 0, enc_w2, D_, 0, Hbuf[xi], D_, 0,
            enc_b2, nullptr, 0, nullptr, 0, 0);
    }

    // ---- per-view ----
    for (int xi = 0; xi < 2; xi++) {
        float* H = Hbuf[xi];
        // F = relu(H @ GLW)
        tgemm_k<0,0,1,0,0><<<dim3(KF / 256, 125, 1), 256, SMEM_BYTES>>>(
            16000, KF, D_, 1.f, H, D_, 0, GLW, KF, 0, F, KF, 0,
            nullptr, nullptr, 0, nullptr, 0, 0);
        // att[b] = F_b @ F_b^T / 8 (symmetric)
        tgemm_k<0,1,0,0,1><<<dim3(8, 16, 8), 256, SMEM_BYTES>>>(
            2000, 2000, KF, 0.125f,
            F, KF, (long long)2000 * KF,
            F, KF, (long long)2000 * KF,
            att, 2000, (long long)2000 * 2000,
            nullptr, nullptr, 0, nullptr, 0, 0);
        topk_softmax_k<<<16000, 256>>>(att);
        colsum_k<<<dim3(8, 8), 256>>>(att, dinv);

        // GCN layer 1
        tgemm_k<0,0,0,1,0><<<dim3(HD / 256, 125, 1), 256, SMEM_BYTES>>>(
            16000, HD, D_, 1.f, H, D_, 0, g_w1, HD, 0, T, HD, 0,
            nullptr, dinv, 0, nullptr, 0, 0);
        tgemm_k<1,0,1,2,0><<<dim3(HD / 256, 16, 8), 256, SMEM_BYTES>>>(
            2000, HD, 2000, 1.f,
            att, 2000, (long long)2000 * 2000,
            T, HD, (long long)2000 * HD,
            O1, HD, (long long)2000 * HD,
            g_b1, dinv, 2000, T, HD, (long long)2000 * HD);
        // layer 2
        tgemm_k<0,0,0,1,0><<<dim3(HD / 256, 125, 1), 256, SMEM_BYTES>>>(
            16000, HD, HD, 1.f, O1, HD, 0, g_w2, HD, 0, T, HD, 0,
            nullptr, dinv, 0, nullptr, 0, 0);
        tgemm_k<1,0,1,2,0><<<dim3(HD / 256, 16, 8), 256, SMEM_BYTES>>>(
            2000, HD, 2000, 1.f,
            att, 2000, (long long)2000 * 2000,
            T, HD, (long long)2000 * HD,
            O2, HD, (long long)2000 * HD,
            g_b2, dinv, 2000, T, HD, (long long)2000 * HD);
        // layer 3 (no relu)
        tgemm_k<0,0,0,1,0><<<dim3(1, 125, 1), 256, SMEM_BYTES>>>(
            16000, D_, HD, 1.f, O2, HD, 0, g_w3, D_, 0, T, D_, 0,
            nullptr, dinv, 0, nullptr, 0, 0);
        tgemm_k<1,0,0,2,0><<<dim3(1, 16, 8), 256, SMEM_BYTES>>>(
            2000, D_, 2000, 1.f,
            att, 2000, (long long)2000 * 2000,
            T, D_, (long long)2000 * D_,
            O3, D_, (long long)2000 * D_,
            g_b3, dinv, 2000, T, D_, (long long)2000 * D_);

        meanz_k<<<8, 128>>>(O3, epsA[xi], muo[xi], stdo[xi], zb);
        decode_k<<<dim3(8, 8), 256>>>(zb, dW1[xi], dB1[xi], dG[xi], dBe[xi], dW2[xi], dB2[xi], xrec[xi]);
    }
}

// round 5
// speedup vs baseline: 2.0078x; 2.0078x over previous
#include <cuda_runtime.h>
#include <math.h>
#include <stdint.h>

// ---------------- problem constants ----------------
constexpr int B_  = 8;
constexpr int NN  = 2000;
constexpr int E_  = 512;
constexpr int HEN = 1024;
constexpr int D_  = 128;   // 2*IB
constexpr int HD  = 512;
constexpr int KF  = 4096;  // P*HD
constexpr int IB_ = 64;
constexpr long long MR = (long long)B_ * NN; // 16000 rows

// ---------------- scratch layout ----------------
constexpr long long SZ_AG   = MR * E_;
constexpr long long SZ_HENC = MR * HEN;
constexpr long long SZ_H    = MR * D_;
constexpr long long SZ_GLW  = (long long)D_ * KF;
constexpr long long SZ_F    = MR * KF;
constexpr long long SZ_ATT  = (long long)B_ * NN * NN;
constexpr long long SZ_DINV = MR;
constexpr long long SZ_T    = MR * HD;
constexpr long long SZ_O    = MR * HD;
constexpr long long SZ_O3   = MR * D_;
constexpr long long SZ_Z    = (long long)B_ * IB_;
constexpr long long SZ_W1   = (long long)E_ * HEN;    // enc_w1
constexpr long long SZ_W2   = (long long)HEN * D_;    // enc_w2
constexpr long long SZ_GW1  = (long long)D_ * HD;
constexpr long long SZ_GW2  = (long long)HD * HD;
constexpr long long SZ_GW3  = (long long)HD * D_;

constexpr long long OFF_AG   = 0;
constexpr long long OFF_HENC = OFF_AG + SZ_AG;
constexpr long long OFF_H1   = OFF_HENC + SZ_HENC;
constexpr long long OFF_H2   = OFF_H1 + SZ_H;
constexpr long long OFF_GLW  = OFF_H2 + SZ_H;
constexpr long long OFF_F    = OFF_GLW + SZ_GLW;
constexpr long long OFF_ATT  = OFF_F + SZ_F;
constexpr long long OFF_DINV = OFF_ATT + SZ_ATT;
constexpr long long OFF_T    = OFF_DINV + SZ_DINV;
constexpr long long OFF_O1   = OFF_T + SZ_T;
constexpr long long OFF_O2   = OFF_O1 + SZ_O;
constexpr long long OFF_O3   = OFF_O2 + SZ_O;
constexpr long long OFF_Z    = OFF_O3 + SZ_O3;
constexpr long long OFF_W1   = OFF_Z + SZ_Z;
constexpr long long OFF_W2   = OFF_W1 + SZ_W1;
constexpr long long OFF_GW1  = OFF_W2 + SZ_W2;
constexpr long long OFF_GW2  = OFF_GW1 + SZ_GW1;
constexpr long long OFF_GW3  = OFF_GW2 + SZ_GW2;
constexpr long long SCRATCH_TOTAL = OFF_GW3 + SZ_GW3;

__device__ float g_scratch[SCRATCH_TOTAL];

// ---------------- tf32 helpers ----------------
__device__ __forceinline__ float rtf32(float v) {
    uint32_t r;
    asm("cvt.rna.tf32.f32 %0, %1;" : "=r"(r) : "f"(v));
    return __uint_as_float(r);
}

__device__ __forceinline__ void mma_tf32(float* c, const uint32_t* a, uint32_t b0, uint32_t b1) {
    asm volatile(
        "mma.sync.aligned.m16n8k8.row.col.f32.tf32.tf32.f32 "
        "{%0,%1,%2,%3}, {%4,%5,%6,%7}, {%8,%9}, {%0,%1,%2,%3};"
        : "+f"(c[0]), "+f"(c[1]), "+f"(c[2]), "+f"(c[3])
        : "r"(a[0]), "r"(a[1]), "r"(a[2]), "r"(a[3]), "r"(b0), "r"(b1));
}

__device__ __forceinline__ void cpa16(uint32_t dst, const float* src, bool pred) {
    int sz = pred ? 16 : 0;
    asm volatile("cp.async.cg.shared.global [%0], [%1], 16, %2;\n"
                 :: "r"(dst), "l"(src), "r"(sz));
}
__device__ __forceinline__ void cpa_commit() { asm volatile("cp.async.commit_group;\n"); }
__device__ __forceinline__ void cpa_wait1()  { asm volatile("cp.async.wait_group 1;\n"); }

// ---------------- tf32 tensor GEMM: 128x128 tile, cp.async 3-stage ----------------
// Inputs MUST already be tf32-rounded fp32 (producers round via rtf32).
// TA=0: A[m,k]. TA=1: A[k,m] -> A^T @ B.  TB=0: B[k,n]. TB=1: B[n,k] -> A @ B^T.
// ACT: 0 none, 1 relu, 2 gelu(exact). EPI: 0 none, 1 dinv scale, 2 GCN aggregate.
// SYM: symmetric output, square tiles: skip bm>bn, mirror-write when bm<bn.
// RND: round C store to tf32 (for tensors feeding later GEMMs).
constexpr int PK = 20;    // [row][k] row stride in u32 (80B, 16B-aligned, conflict-free)
constexpr int PM = 136;   // [k][row] row stride in u32 (544B, 16B-aligned, conflict-free)
constexpr int ASTG = 2560;            // max(128*PK, 16*PM) = 2560
constexpr int BSTG = 2560;
constexpr int SMEM_BYTES = (3 * ASTG + 3 * BSTG) * 4;   // 61440

template<int TA, int TB, int ACT, int EPI, int SYM, int RND>
__global__ void __launch_bounds__(256, 2) tgemm_k(
    int M, int N, int K, float alpha,
    const float* __restrict__ A, int lda, long long sA,
    const float* __restrict__ B, int ldb, long long sB,
    float* __restrict__ C, int ldc, long long sC,
    const float* __restrict__ bias,
    const float* __restrict__ dinv, long long sD,
    const float* __restrict__ Tm, int ldt, long long sT)
{
    extern __shared__ uint32_t sh[];

    const int bz = blockIdx.z;
    A += bz * sA; B += bz * sB; C += bz * sC;
    if (EPI)      dinv += bz * sD;
    if (EPI == 2) Tm   += bz * sT;

    const int bn = blockIdx.x, bm = blockIdx.y;
    if (SYM && bm > bn) return;
    const int m0 = bm * 128, n0 = bn * 128;

    const int tid  = threadIdx.x;
    const int lane = tid & 31, warp = tid >> 5;
    const int g = lane >> 2, th = lane & 3;
    const int wm = (warp >> 1) * 32;
    const int wn = (warp & 1) * 64;

    uint32_t sbase;
    asm("{ .reg .u64 t; cvta.to.shared.u64 t, %1; cvt.u32.u64 %0, t; }"
        : "=r"(sbase) : "l"(sh));

    float acc[2][8][4];
#pragma unroll
    for (int i = 0; i < 2; i++)
#pragma unroll
        for (int j = 0; j < 8; j++)
#pragma unroll
            for (int l = 0; l < 4; l++) acc[i][j][l] = 0.f;

    const int KT = K >> 4;

    auto issue = [&](int kt, int stg) {
        uint32_t abase = sbase + (uint32_t)(stg * ASTG) * 4u;
#pragma unroll
        for (int it = 0; it < 2; it++) {
            int c = tid * 2 + it;
            if (TA == 0) {
                int row = c >> 2, kc = (c & 3) * 4;
                const float* src = A + (long long)(m0 + row) * lda + kt * 16 + kc;
                cpa16(abase + (uint32_t)(row * PK + kc) * 4u, src, (m0 + row) < M);
            } else {
                int kr = c >> 5, mc = (c & 31) * 4;
                const float* src = A + (long long)(kt * 16 + kr) * lda + m0 + mc;
                cpa16(abase + (uint32_t)(kr * PM + mc) * 4u, src, (m0 + mc) < M);
            }
        }
        uint32_t bbase = sbase + (uint32_t)(3 * ASTG + stg * BSTG) * 4u;
#pragma unroll
        for (int it = 0; it < 2; it++) {
            int c = tid * 2 + it;
            if (TB == 1) {
                int row = c >> 2, kc = (c & 3) * 4;
                const float* src = B + (long long)(n0 + row) * ldb + kt * 16 + kc;
                cpa16(bbase + (uint32_t)(row * PK + kc) * 4u, src, (n0 + row) < N);
            } else {
                int kr = c >> 5, nc = (c & 31) * 4;
                const float* src = B + (long long)(kt * 16 + kr) * ldb + n0 + nc;
                cpa16(bbase + (uint32_t)(kr * PM + nc) * 4u, src, (n0 + nc) < N);
            }
        }
    };

    auto mmaTile = [&](int stg) {
        const uint32_t* Ab = sh + stg * ASTG;
        const uint32_t* Bb = sh + 3 * ASTG + stg * BSTG;
#pragma unroll
        for (int s = 0; s < 2; s++) {
            const int k0 = s * 8;
            uint32_t a[2][4];
#pragma unroll
            for (int mt = 0; mt < 2; mt++) {
                int mrow = wm + mt * 16 + g;
                if (TA == 0) {
                    a[mt][0] = Ab[mrow * PK + k0 + th];
                    a[mt][1] = Ab[(mrow + 8) * PK + k0 + th];
                    a[mt][2] = Ab[mrow * PK + k0 + th + 4];
                    a[mt][3] = Ab[(mrow + 8) * PK + k0 + th + 4];
                } else {
                    a[mt][0] = Ab[(k0 + th) * PM + mrow];
                    a[mt][1] = Ab[(k0 + th) * PM + mrow + 8];
                    a[mt][2] = Ab[(k0 + th + 4) * PM + mrow];
                    a[mt][3] = Ab[(k0 + th + 4) * PM + mrow + 8];
                }
            }
#pragma unroll
            for (int nt = 0; nt < 8; nt++) {
                int nrow = wn + nt * 8 + g;
                uint32_t b0, b1;
                if (TB == 1) {
                    b0 = Bb[nrow * PK + k0 + th];
                    b1 = Bb[nrow * PK + k0 + th + 4];
                } else {
                    b0 = Bb[(k0 + th) * PM + nrow];
                    b1 = Bb[(k0 + th + 4) * PM + nrow];
                }
                mma_tf32(acc[0][nt], a[0], b0, b1);
                mma_tf32(acc[1][nt], a[1], b0, b1);
            }
        }
    };

    // ---- 3-stage pipeline ----
    issue(0, 0); cpa_commit();
    if (KT > 1) issue(1, 1);
    cpa_commit();
    cpa_wait1();
    __syncthreads();

    for (int kt = 0; kt < KT; kt++) {
        int stg = kt % 3;
        if (kt + 2 < KT) issue(kt + 2, (kt + 2) % 3);
        cpa_commit();
        mmaTile(stg);
        cpa_wait1();
        __syncthreads();
    }

    // ---- epilogue ----
#pragma unroll
    for (int mt = 0; mt < 2; mt++) {
#pragma unroll
        for (int nt = 0; nt < 8; nt++) {
#pragma unroll
            for (int e = 0; e < 4; e++) {
                int gm = m0 + wm + mt * 16 + g + (e >= 2 ? 8 : 0);
                int gn = n0 + wn + nt * 8 + 2 * th + (e & 1);
                if (gm >= M || gn >= N) continue;
                float v = alpha * acc[mt][nt][e];
                if (EPI == 1) v = dinv[gm] * v;
                if (EPI == 2) v = dinv[gm] * (v + Tm[(long long)gm * ldt + gn]);
                if (bias)     v += bias[gn];
                if (ACT == 1) v = fmaxf(v, 0.f);
                if (ACT == 2) v = 0.5f * v * (1.f + erff(v * 0.70710678118654752f));
                if (RND)      v = rtf32(v);
                C[(long long)gm * ldc + gn] = v;
                if (SYM && bm < bn) C[(long long)gn * ldc + gm] = v;
            }
        }
    }
}

// ---------------- tf32 round-copy (weights) ----------------
__global__ void round_copy_k(const float* __restrict__ src, float* __restrict__ dst, int n)
{
    int i = blockIdx.x * blockDim.x + threadIdx.x;
    if (i < n) dst[i] = rtf32(src[i]);
}

// ---------------- A-matrix builder (tf32-rounded) ----------------
__global__ void build_ag_k(const float* __restrict__ x, const float* __restrict__ emb,
                           const float* __restrict__ gw, const float* __restrict__ gb,
                           float* __restrict__ Ag)
{
    long long idx = (long long)blockIdx.x * blockDim.x + threadIdx.x;
    if (idx >= MR * E_) return;
    int e = (int)(idx & (E_ - 1));
    long long rn = idx >> 9;
    int n = (int)(rn % NN);
    float t = fmaf(x[rn], gw[e], gb[e]);
    float sgm = 1.0f / (1.0f + expf(-t));
    Ag[idx] = rtf32(sgm * emb[(long long)n * E_ + e]);
}

// ---------------- concat gl_w [P,D,HD] -> GLW [D, P*HD] (tf32-rounded) ----------------
__global__ void build_glw_k(const float* __restrict__ glw, float* __restrict__ GLW)
{
    int idx = blockIdx.x * blockDim.x + threadIdx.x;
    if (idx >= D_ * KF) return;
    int k = idx / KF, c = idx % KF;
    int p = c >> 9, hh = c & 511;
    GLW[idx] = rtf32(glw[((long long)p * D_ + k) * HD + hh]);
}

// ---------------- top-k(50): byte-histogram radix select + masked softmax ----------------
__global__ void __launch_bounds__(256) topk_softmax_k(float* __restrict__ att)
{
    __shared__ float s[2000];
    __shared__ int   hist[256];
    __shared__ float wredf[8];
    __shared__ float s_bcast;
    __shared__ int   s_selb, s_selk;

    long long row = blockIdx.x;
    float* r = att + row * 2000;
    int tid = threadIdx.x;
    int lane = tid & 31, wid = tid >> 5;

    for (int i = tid; i < 2000; i += 256) s[i] = r[i];
    __syncthreads();

    float mx = 0.f;
    for (int i = tid; i < 2000; i += 256) mx = fmaxf(mx, s[i]);
#pragma unroll
    for (int o = 16; o; o >>= 1) mx = fmaxf(mx, __shfl_xor_sync(0xffffffffu, mx, o));
    if (lane == 0) wredf[wid] = mx;
    __syncthreads();
    if (tid == 0) { float m = wredf[0]; for (int w = 1; w < 8; w++) m = fmaxf(m, wredf[w]); s_bcast = m; }
    __syncthreads();
    mx = s_bcast;

    unsigned prefix = 0u;
    int k = 50;
#pragma unroll
    for (int pass = 0; pass < 4; pass++) {
        const int shift = 24 - 8 * pass;
        const unsigned hmask = (pass == 0) ? 0u : (0xFFFFFFFFu << (shift + 8));
        if (tid < 256) hist[tid] = 0;
        __syncthreads();
        for (int i = tid; i < 2000; i += 256) {
            unsigned u = __float_as_uint(s[i]);
            if ((u & hmask) == prefix)
                atomicAdd(&hist[(u >> shift) & 255], 1);
        }
        __syncthreads();
        if (tid == 0) {
            int acc = 0, b = 255;
            for (; b > 0; b--) { acc += hist[b]; if (acc >= k) break; }
            if (acc < k) acc += hist[0];
            s_selb = b;
            s_selk = k - (acc - hist[b]);
        }
        __syncthreads();
        prefix |= ((unsigned)s_selb) << shift;
        k = s_selk;
        __syncthreads();
    }
    float thr = __uint_as_float(prefix);

    float sum = 0.f;
    for (int i = tid; i < 2000; i += 256) {
        float v = s[i];
        float e = (v >= thr) ? expf(v - mx) : 0.f;
        s[i] = e; sum += e;
    }
#pragma unroll
    for (int o = 16; o; o >>= 1) sum += __shfl_xor_sync(0xffffffffu, sum, o);
    if (lane == 0) wredf[wid] = sum;
    __syncthreads();
    if (tid == 0) { float t = 0.f; for (int w = 0; w < 8; w++) t += wredf[w]; s_bcast = t; }
    __syncthreads();
    float inv = 1.0f / s_bcast;
    for (int i = tid; i < 2000; i += 256) r[i] = rtf32(s[i] * inv);
}

// ---------------- dinv[b,i] = 1/sqrt(1 + sum_j adj[b,j,i]) ----------------
__global__ void colsum_k(const float* __restrict__ adj, float* __restrict__ dinv)
{
    int b = blockIdx.y;
    int i = blockIdx.x * blockDim.x + threadIdx.x;
    if (i >= 2000) return;
    const float* p = adj + (long long)b * 2000 * 2000 + i;
    float s0 = 0.f, s1 = 0.f, s2 = 0.f, s3 = 0.f;
    for (int j = 0; j < 2000; j += 4) {
        s0 += p[(long long)j * 2000];
        s1 += p[(long long)(j + 1) * 2000];
        s2 += p[(long long)(j + 2) * 2000];
        s3 += p[(long long)(j + 3) * 2000];
    }
    float d = 1.0f + ((s0 + s1) + (s2 + s3));
    dinv[b * 2000 + i] = 1.0f / sqrtf(d);
}

// ---------------- mean over nodes; mu/std/z ----------------
__global__ void meanz_k(const float* __restrict__ O3, const float* __restrict__ eps,
                        float* __restrict__ mu, float* __restrict__ stdv, float* __restrict__ z)
{
    int b = blockIdx.x, d = threadIdx.x;
    const float* p = O3 + ((long long)b * 2000) * 128 + d;
    float s0 = 0.f, s1 = 0.f, s2 = 0.f, s3 = 0.f;
    for (int i = 0; i < 2000; i += 4) {
        s0 += p[(long long)i * 128];
        s1 += p[(long long)(i + 1) * 128];
        s2 += p[(long long)(i + 2) * 128];
        s3 += p[(long long)(i + 3) * 128];
    }
    __shared__ float sg[128];
    sg[d] = ((s0 + s1) + (s2 + s3)) / 2000.0f;
    __syncthreads();
    if (d < 64) {
        float m = sg[d];
        float sp = log1pf(expf(sg[64 + d] - 64.0f));
        mu[b * 64 + d] = m;
        stdv[b * 64 + d] = sp;
        z[b * 64 + d] = fmaf(eps[b * 64 + d], sp, m);
    }
}

// ---------------- decoder (grid: b x col-chunks of 250) ----------------
__global__ void __launch_bounds__(256) decode_k(
    const float* __restrict__ z, const float* __restrict__ w1, const float* __restrict__ b1,
    const float* __restrict__ gamma, const float* __restrict__ beta,
    const float* __restrict__ w2, const float* __restrict__ b2,
    float* __restrict__ xrec)
{
    __shared__ float h[1024];
    __shared__ float zs[64];
    int b = blockIdx.x, tid = threadIdx.x;
    if (tid < 64) zs[tid] = z[b * 64 + tid];
    __syncthreads();
    const float invc = 1.0f / sqrtf(1.0f + 1e-5f);
    for (int c = tid; c < 1024; c += 256) {
        float a = b1[c];
#pragma unroll 8
        for (int k = 0; k < 64; k++) a = fmaf(zs[k], w1[k * 1024 + c], a);
        a = a * (gamma[c] * invc) + beta[c];
        h[c] = fmaxf(a, 0.f);
    }
    __syncthreads();
    int c0 = blockIdx.y * 250;
    int c1 = min(c0 + 250, 2000);
    for (int c = c0 + tid; c < c1; c += 256) {
        float a = b2[c];
        for (int k = 0; k < 1024; k++) a = fmaf(h[k], w2[k * 2000 + c], a);
        xrec[b * 2000 + c] = fmaxf(a, 0.f);
    }
}

// ---------------- host orchestration ----------------
extern "C" void kernel_launch(void* const* d_in, const int* in_sizes, int n_in,
                              void* d_out, int out_size)
{
    const float* x1     = (const float*)d_in[0];
    const float* x2     = (const float*)d_in[1];
    const float* emb1   = (const float*)d_in[2];
    const float* gate_w = (const float*)d_in[3];
    const float* gate_b = (const float*)d_in[4];
    const float* enc_w1 = (const float*)d_in[5];
    const float* enc_b1 = (const float*)d_in[6];
    const float* enc_w2 = (const float*)d_in[7];
    const float* enc_b2 = (const float*)d_in[8];
    const float* gl_w   = (const float*)d_in[9];
    const float* g_w1   = (const float*)d_in[10];
    const float* g_b1   = (const float*)d_in[11];
    const float* g_w2   = (const float*)d_in[12];
    const float* g_b2   = (const float*)d_in[13];
    const float* g_w3   = (const float*)d_in[14];
    const float* g_b3   = (const float*)d_in[15];
    const float* dW1[2] = {(const float*)d_in[16], (const float*)d_in[22]};
    const float* dB1[2] = {(const float*)d_in[17], (const float*)d_in[23]};
    const float* dG [2] = {(const float*)d_in[18], (const float*)d_in[24]};
    const float* dBe[2] = {(const float*)d_in[19], (const float*)d_in[25]};
    const float* dW2[2] = {(const float*)d_in[20], (const float*)d_in[26]};
    const float* dB2[2] = {(const float*)d_in[21], (const float*)d_in[27]};
    const float* epsA[2]= {(const float*)d_in[28], (const float*)d_in[29]};

    static bool attr_done = false;
    if (!attr_done) {
        cudaFuncSetAttribute(tgemm_k<0,0,2,0,0,1>, cudaFuncAttributeMaxDynamicSharedMemorySize, SMEM_BYTES);
        cudaFuncSetAttribute(tgemm_k<0,0,0,0,0,1>, cudaFuncAttributeMaxDynamicSharedMemorySize, SMEM_BYTES);
        cudaFuncSetAttribute(tgemm_k<0,0,1,0,0,1>, cudaFuncAttributeMaxDynamicSharedMemorySize, SMEM_BYTES);
        cudaFuncSetAttribute(tgemm_k<0,1,0,0,1,0>, cudaFuncAttributeMaxDynamicSharedMemorySize, SMEM_BYTES);
        cudaFuncSetAttribute(tgemm_k<0,0,0,1,0,1>, cudaFuncAttributeMaxDynamicSharedMemorySize, SMEM_BYTES);
        cudaFuncSetAttribute(tgemm_k<1,0,1,2,0,1>, cudaFuncAttributeMaxDynamicSharedMemorySize, SMEM_BYTES);
        cudaFuncSetAttribute(tgemm_k<1,0,0,2,0,0>, cudaFuncAttributeMaxDynamicSharedMemorySize, SMEM_BYTES);
        attr_done = true;
    }

    float* sc = nullptr;
    cudaGetSymbolAddress((void**)&sc, g_scratch);
    float* Ag   = sc + OFF_AG;
    float* Henc = sc + OFF_HENC;
    float* Hbuf[2] = {sc + OFF_H1, sc + OFF_H2};
    float* GLW  = sc + OFF_GLW;
    float* F    = sc + OFF_F;
    float* att  = sc + OFF_ATT;
    float* dinv = sc + OFF_DINV;
    float* T    = sc + OFF_T;
    float* O1   = sc + OFF_O1;
    float* O2   = sc + OFF_O2;
    float* O3   = sc + OFF_O3;
    float* zb   = sc + OFF_Z;
    float* W1r  = sc + OFF_W1;
    float* W2r  = sc + OFF_W2;
    float* GW1r = sc + OFF_GW1;
    float* GW2r = sc + OFF_GW2;
    float* GW3r = sc + OFF_GW3;

    float* out = (float*)d_out;
    float* xrec[2] = {out,          out + 16000};
    float* muo [2] = {out + 32000,  out + 33024};
    float* stdo[2] = {out + 32512,  out + 33536};

    // weight rounding (tf32 RNA) + GLW build
    round_copy_k<<<(int)((SZ_W1  + 255) / 256), 256>>>(enc_w1, W1r,  (int)SZ_W1);
    round_copy_k<<<(int)((SZ_W2  + 255) / 256), 256>>>(enc_w2, W2r,  (int)SZ_W2);
    round_copy_k<<<(int)((SZ_GW1 + 255) / 256), 256>>>(g_w1,   GW1r, (int)SZ_GW1);
    round_copy_k<<<(int)((SZ_GW2 + 255) / 256), 256>>>(g_w2,   GW2r, (int)SZ_GW2);
    round_copy_k<<<(int)((SZ_GW3 + 255) / 256), 256>>>(g_w3,   GW3r, (int)SZ_GW3);
    build_glw_k<<<(D_ * KF + 255) / 256, 256>>>(gl_w, GLW);

    // ---- encoders ----
    for (int xi = 0; xi < 2; xi++) {
        const float* x = xi ? x2 : x1;
        long long tot = MR * E_;
        build_ag_k<<<(unsigned)((tot + 255) / 256), 256>>>(x, emb1, gate_w, gate_b, Ag);
        tgemm_k<0,0,2,0,0,1><<<dim3(HEN / 128, 125, 1), 256, SMEM_BYTES>>>(
            16000, HEN, E_, 1.f, Ag, E_, 0, W1r, HEN, 0, Henc, HEN, 0,
            enc_b1, nullptr, 0, nullptr, 0, 0);
        tgemm_k<0,0,0,0,0,1><<<dim3(1, 125, 1), 256, SMEM_BYTES>>>(
            16000, D_, HEN, 1.f, Henc, HEN, 0, W2r, D_, 0, Hbuf[xi], D_, 0,
            enc_b2, nullptr, 0, nullptr, 0, 0);
    }

    // ---- per-view ----
    for (int xi = 0; xi < 2; xi++) {
        float* H = Hbuf[xi];
        // F = relu(H @ GLW), tf32-rounded
        tgemm_k<0,0,1,0,0,1><<<dim3(KF / 128, 125, 1), 256, SMEM_BYTES>>>(
            16000, KF, D_, 1.f, H, D_, 0, GLW, KF, 0, F, KF, 0,
            nullptr, nullptr, 0, nullptr, 0, 0);
        // att[b] = F_b @ F_b^T / 8 (symmetric)
        tgemm_k<0,1,0,0,1,0><<<dim3(16, 16, 8), 256, SMEM_BYTES>>>(
            2000, 2000, KF, 0.125f,
            F, KF, (long long)2000 * KF,
            F, KF, (long long)2000 * KF,
            att, 2000, (long long)2000 * 2000,
            nullptr, nullptr, 0, nullptr, 0, 0);
        topk_softmax_k<<<16000, 256>>>(att);
        colsum_k<<<dim3(8, 8), 256>>>(att, dinv);

        // GCN layer 1
        tgemm_k<0,0,0,1,0,1><<<dim3(HD / 128, 125, 1), 256, SMEM_BYTES>>>(
            16000, HD, D_, 1.f, H, D_, 0, GW1r, HD, 0, T, HD, 0,
            nullptr, dinv, 0, nullptr, 0, 0);
        tgemm_k<1,0,1,2,0,1><<<dim3(HD / 128, 16, 8), 256, SMEM_BYTES>>>(
            2000, HD, 2000, 1.f,
            att, 2000, (long long)2000 * 2000,
            T, HD, (long long)2000 * HD,
            O1, HD, (long long)2000 * HD,
            g_b1, dinv, 2000, T, HD, (long long)2000 * HD);
        // layer 2
        tgemm_k<0,0,0,1,0,1><<<dim3(HD / 128, 125, 1), 256, SMEM_BYTES>>>(
            16000, HD, HD, 1.f, O1, HD, 0, GW2r, HD, 0, T, HD, 0,
            nullptr, dinv, 0, nullptr, 0, 0);
        tgemm_k<1,0,1,2,0,1><<<dim3(HD / 128, 16, 8), 256, SMEM_BYTES>>>(
            2000, HD, 2000, 1.f,
            att, 2000, (long long)2000 * 2000,
            T, HD, (long long)2000 * HD,
            O2, HD, (long long)2000 * HD,
            g_b2, dinv, 2000, T, HD, (long long)2000 * HD);
        // layer 3 (no relu, O3 NOT rounded)
        tgemm_k<0,0,0,1,0,1><<<dim3(1, 125, 1), 256, SMEM_BYTES>>>(
            16000, D_, HD, 1.f, O2, HD, 0, GW3r, D_, 0, T, D_, 0,
            nullptr, dinv, 0, nullptr, 0, 0);
        tgemm_k<1,0,0,2,0,0><<<dim3(1, 16, 8), 256, SMEM_BYTES>>>(
            2000, D_, 2000, 1.f,
            att, 2000, (long long)2000 * 2000,
            T, D_, (long long)2000 * D_,
            O3, D_, (long long)2000 * D_,
            g_b3, dinv, 2000, T, D_, (long long)2000 * D_);

        meanz_k<<<8, 128>>>(O3, epsA[xi], muo[xi], stdo[xi], zb);
        decode_k<<<dim3(8, 8), 256>>>(zb, dW1[xi], dB1[xi], dG[xi], dBe[xi], dW2[xi], dB2[xi], xrec[xi]);
    }
}

// round 6
// speedup vs baseline: 2.2969x; 1.1440x over previous
#include <cuda_runtime.h>
#include <math.h>
#include <stdint.h>

// ---------------- problem constants ----------------
constexpr int B_  = 8;
constexpr int NN  = 2000;
constexpr int E_  = 512;
constexpr int HEN = 1024;
constexpr int D_  = 128;   // 2*IB
constexpr int HD  = 512;
constexpr int KF  = 4096;  // P*HD
constexpr int IB_ = 64;
constexpr long long MR = (long long)B_ * NN; // 16000 rows

constexpr int ROWCAP = 64;        // kept entries per row (50 + tie headroom)
constexpr int CAP    = 131072;    // CSC entries per batch (>= 2000*64)

// ---------------- scratch layout ----------------
constexpr long long SZ_AG   = MR * E_;
constexpr long long SZ_HENC = MR * HEN;
constexpr long long SZ_H    = MR * D_;
constexpr long long SZ_GLW  = (long long)D_ * KF;
constexpr long long SZ_F    = MR * KF;
constexpr long long SZ_ATT  = (long long)B_ * NN * NN;
constexpr long long SZ_DINV = MR;
constexpr long long SZ_T    = MR * HD;
constexpr long long SZ_O    = MR * HD;
constexpr long long SZ_O3   = MR * D_;
constexpr long long SZ_Z    = (long long)B_ * IB_;
constexpr long long SZ_W1   = (long long)E_ * HEN;
constexpr long long SZ_W2   = (long long)HEN * D_;
constexpr long long SZ_GW1  = (long long)D_ * HD;
constexpr long long SZ_GW2  = (long long)HD * HD;
constexpr long long SZ_GW3  = (long long)HD * D_;
constexpr long long SZ_ROWV = MR * ROWCAP;     // row-compressed weights
constexpr long long SZ_ROWC = MR * ROWCAP;     // row-compressed col indices (int)
constexpr long long SZ_RCNT = MR;              // per-row kept count (int)
constexpr long long SZ_CCNT = MR;              // per-col count (int)
constexpr long long SZ_COFF = MR;              // per-col offset (int)
constexpr long long SZ_CCUR = MR;              // per-col cursor (int)
constexpr long long SZ_CSUM = MR;              // per-col weight sum (float)
constexpr long long SZ_CSCV = (long long)B_ * CAP;  // CSC values
constexpr long long SZ_CSCR = (long long)B_ * CAP;  // CSC row ids (int)

constexpr long long OFF_AG   = 0;
constexpr long long OFF_HENC = OFF_AG + SZ_AG;
constexpr long long OFF_H1   = OFF_HENC + SZ_HENC;
constexpr long long OFF_H2   = OFF_H1 + SZ_H;
constexpr long long OFF_GLW  = OFF_H2 + SZ_H;
constexpr long long OFF_F    = OFF_GLW + SZ_GLW;
constexpr long long OFF_ATT  = OFF_F + SZ_F;
constexpr long long OFF_DINV = OFF_ATT + SZ_ATT;
constexpr long long OFF_T    = OFF_DINV + SZ_DINV;
constexpr long long OFF_O1   = OFF_T + SZ_T;
constexpr long long OFF_O2   = OFF_O1 + SZ_O;
constexpr long long OFF_O3   = OFF_O2 + SZ_O;
constexpr long long OFF_Z    = OFF_O3 + SZ_O3;
constexpr long long OFF_W1   = OFF_Z + SZ_Z;
constexpr long long OFF_W2   = OFF_W1 + SZ_W1;
constexpr long long OFF_GW1  = OFF_W2 + SZ_W2;
constexpr long long OFF_GW2  = OFF_GW1 + SZ_GW1;
constexpr long long OFF_GW3  = OFF_GW2 + SZ_GW2;
constexpr long long OFF_ROWV = OFF_GW3 + SZ_GW3;
constexpr long long OFF_ROWC = OFF_ROWV + SZ_ROWV;
constexpr long long OFF_RCNT = OFF_ROWC + SZ_ROWC;
constexpr long long OFF_CCNT = OFF_RCNT + SZ_RCNT;
constexpr long long OFF_COFF = OFF_CCNT + SZ_CCNT;
constexpr long long OFF_CCUR = OFF_COFF + SZ_COFF;
constexpr long long OFF_CSUM = OFF_CCUR + SZ_CCUR;
constexpr long long OFF_CSCV = OFF_CSUM + SZ_CSUM;
constexpr long long OFF_CSCR = OFF_CSCV + SZ_CSCV;
constexpr long long SCRATCH_TOTAL = OFF_CSCR + SZ_CSCR;

__device__ float g_scratch[SCRATCH_TOTAL];

// ---------------- tf32 helpers ----------------
__device__ __forceinline__ float rtf32(float v) {
    uint32_t r;
    asm("cvt.rna.tf32.f32 %0, %1;" : "=r"(r) : "f"(v));
    return __uint_as_float(r);
}

__device__ __forceinline__ void mma_tf32(float* c, const uint32_t* a, uint32_t b0, uint32_t b1) {
    asm volatile(
        "mma.sync.aligned.m16n8k8.row.col.f32.tf32.tf32.f32 "
        "{%0,%1,%2,%3}, {%4,%5,%6,%7}, {%8,%9}, {%0,%1,%2,%3};"
        : "+f"(c[0]), "+f"(c[1]), "+f"(c[2]), "+f"(c[3])
        : "r"(a[0]), "r"(a[1]), "r"(a[2]), "r"(a[3]), "r"(b0), "r"(b1));
}

__device__ __forceinline__ void cpa16(uint32_t dst, const float* src, bool pred) {
    int sz = pred ? 16 : 0;
    asm volatile("cp.async.cg.shared.global [%0], [%1], 16, %2;\n"
                 :: "r"(dst), "l"(src), "r"(sz));
}
__device__ __forceinline__ void cpa_commit() { asm volatile("cp.async.commit_group;\n"); }
__device__ __forceinline__ void cpa_wait1()  { asm volatile("cp.async.wait_group 1;\n"); }

// ---------------- tf32 tensor GEMM: 128x128 tile, cp.async 3-stage ----------------
// Inputs must be tf32-rounded fp32.  TA/TB transposes, ACT 0/1/2, EPI 0/1, SYM, RND.
constexpr int PK = 20;
constexpr int PM = 136;
constexpr int ASTG = 2560;
constexpr int BSTG = 2560;
constexpr int SMEM_BYTES = (3 * ASTG + 3 * BSTG) * 4;   // 61440

template<int TA, int TB, int ACT, int EPI, int SYM, int RND>
__global__ void __launch_bounds__(256, 2) tgemm_k(
    int M, int N, int K, float alpha,
    const float* __restrict__ A, int lda, long long sA,
    const float* __restrict__ B, int ldb, long long sB,
    float* __restrict__ C, int ldc, long long sC,
    const float* __restrict__ bias,
    const float* __restrict__ dinv, long long sD)
{
    extern __shared__ uint32_t sh[];

    const int bz = blockIdx.z;
    A += bz * sA; B += bz * sB; C += bz * sC;
    if (EPI) dinv += bz * sD;

    const int bn = blockIdx.x, bm = blockIdx.y;
    if (SYM && bm > bn) return;
    const int m0 = bm * 128, n0 = bn * 128;

    const int tid  = threadIdx.x;
    const int lane = tid & 31, warp = tid >> 5;
    const int g = lane >> 2, th = lane & 3;
    const int wm = (warp >> 1) * 32;
    const int wn = (warp & 1) * 64;

    uint32_t sbase;
    asm("{ .reg .u64 t; cvta.to.shared.u64 t, %1; cvt.u32.u64 %0, t; }"
        : "=r"(sbase) : "l"(sh));

    float acc[2][8][4];
#pragma unroll
    for (int i = 0; i < 2; i++)
#pragma unroll
        for (int j = 0; j < 8; j++)
#pragma unroll
            for (int l = 0; l < 4; l++) acc[i][j][l] = 0.f;

    const int KT = K >> 4;

    auto issue = [&](int kt, int stg) {
        uint32_t abase = sbase + (uint32_t)(stg * ASTG) * 4u;
#pragma unroll
        for (int it = 0; it < 2; it++) {
            int c = tid * 2 + it;
            if (TA == 0) {
                int row = c >> 2, kc = (c & 3) * 4;
                const float* src = A + (long long)(m0 + row) * lda + kt * 16 + kc;
                cpa16(abase + (uint32_t)(row * PK + kc) * 4u, src, (m0 + row) < M);
            } else {
                int kr = c >> 5, mc = (c & 31) * 4;
                const float* src = A + (long long)(kt * 16 + kr) * lda + m0 + mc;
                cpa16(abase + (uint32_t)(kr * PM + mc) * 4u, src, (m0 + mc) < M);
            }
        }
        uint32_t bbase = sbase + (uint32_t)(3 * ASTG + stg * BSTG) * 4u;
#pragma unroll
        for (int it = 0; it < 2; it++) {
            int c = tid * 2 + it;
            if (TB == 1) {
                int row = c >> 2, kc = (c & 3) * 4;
                const float* src = B + (long long)(n0 + row) * ldb + kt * 16 + kc;
                cpa16(bbase + (uint32_t)(row * PK + kc) * 4u, src, (n0 + row) < N);
            } else {
                int kr = c >> 5, nc = (c & 31) * 4;
                const float* src = B + (long long)(kt * 16 + kr) * ldb + n0 + nc;
                cpa16(bbase + (uint32_t)(kr * PM + nc) * 4u, src, (n0 + nc) < N);
            }
        }
    };

    auto mmaTile = [&](int stg) {
        const uint32_t* Ab = sh + stg * ASTG;
        const uint32_t* Bb = sh + 3 * ASTG + stg * BSTG;
#pragma unroll
        for (int s = 0; s < 2; s++) {
            const int k0 = s * 8;
            uint32_t a[2][4];
#pragma unroll
            for (int mt = 0; mt < 2; mt++) {
                int mrow = wm + mt * 16 + g;
                if (TA == 0) {
                    a[mt][0] = Ab[mrow * PK + k0 + th];
                    a[mt][1] = Ab[(mrow + 8) * PK + k0 + th];
                    a[mt][2] = Ab[mrow * PK + k0 + th + 4];
                    a[mt][3] = Ab[(mrow + 8) * PK + k0 + th + 4];
                } else {
                    a[mt][0] = Ab[(k0 + th) * PM + mrow];
                    a[mt][1] = Ab[(k0 + th) * PM + mrow + 8];
                    a[mt][2] = Ab[(k0 + th + 4) * PM + mrow];
                    a[mt][3] = Ab[(k0 + th + 4) * PM + mrow + 8];
                }
            }
#pragma unroll
            for (int nt = 0; nt < 8; nt++) {
                int nrow = wn + nt * 8 + g;
                uint32_t b0, b1;
                if (TB == 1) {
                    b0 = Bb[nrow * PK + k0 + th];
                    b1 = Bb[nrow * PK + k0 + th + 4];
                } else {
                    b0 = Bb[(k0 + th) * PM + nrow];
                    b1 = Bb[(k0 + th + 4) * PM + nrow];
                }
                mma_tf32(acc[0][nt], a[0], b0, b1);
                mma_tf32(acc[1][nt], a[1], b0, b1);
            }
        }
    };

    issue(0, 0); cpa_commit();
    if (KT > 1) issue(1, 1);
    cpa_commit();
    cpa_wait1();
    __syncthreads();

    for (int kt = 0; kt < KT; kt++) {
        int stg = kt % 3;
        if (kt + 2 < KT) issue(kt + 2, (kt + 2) % 3);
        cpa_commit();
        mmaTile(stg);
        cpa_wait1();
        __syncthreads();
    }

#pragma unroll
    for (int mt = 0; mt < 2; mt++) {
#pragma unroll
        for (int nt = 0; nt < 8; nt++) {
#pragma unroll
            for (int e = 0; e < 4; e++) {
                int gm = m0 + wm + mt * 16 + g + (e >= 2 ? 8 : 0);
                int gn = n0 + wn + nt * 8 + 2 * th + (e & 1);
                if (gm >= M || gn >= N) continue;
                float v = alpha * acc[mt][nt][e];
                if (EPI == 1) v = dinv[gm] * v;
                if (bias)     v += bias[gn];
                if (ACT == 1) v = fmaxf(v, 0.f);
                if (ACT == 2) v = 0.5f * v * (1.f + erff(v * 0.70710678118654752f));
                if (RND)      v = rtf32(v);
                C[(long long)gm * ldc + gn] = v;
                if (SYM && bm < bn) C[(long long)gn * ldc + gm] = v;
            }
        }
    }
}

// ---------------- tf32 round-copy ----------------
__global__ void round_copy_k(const float* __restrict__ src, float* __restrict__ dst, int n)
{
    int i = blockIdx.x * blockDim.x + threadIdx.x;
    if (i < n) dst[i] = rtf32(src[i]);
}

// ---------------- A-matrix builder ----------------
__global__ void build_ag_k(const float* __restrict__ x, const float* __restrict__ emb,
                           const float* __restrict__ gw, const float* __restrict__ gb,
                           float* __restrict__ Ag)
{
    long long idx = (long long)blockIdx.x * blockDim.x + threadIdx.x;
    if (idx >= MR * E_) return;
    int e = (int)(idx & (E_ - 1));
    long long rn = idx >> 9;
    int n = (int)(rn % NN);
    float t = fmaf(x[rn], gw[e], gb[e]);
    float sgm = 1.0f / (1.0f + expf(-t));
    Ag[idx] = rtf32(sgm * emb[(long long)n * E_ + e]);
}

// ---------------- concat gl_w ----------------
__global__ void build_glw_k(const float* __restrict__ glw, float* __restrict__ GLW)
{
    int idx = blockIdx.x * blockDim.x + threadIdx.x;
    if (idx >= D_ * KF) return;
    int k = idx / KF, c = idx % KF;
    int p = c >> 9, hh = c & 511;
    GLW[idx] = rtf32(glw[((long long)p * D_ + k) * HD + hh]);
}

// ---------------- top-k(50) -> row-compressed softmax output ----------------
__global__ void __launch_bounds__(256) topk_rows_k(
    const float* __restrict__ att,
    float* __restrict__ rowval, int* __restrict__ rowcol, int* __restrict__ rowcnt)
{
    __shared__ float s[2000];
    __shared__ int   hist[256];
    __shared__ float wredf[8];
    __shared__ float s_bcast;
    __shared__ int   s_selb, s_selk, s_pos;

    long long row = blockIdx.x;
    const float* r = att + row * 2000;
    int tid = threadIdx.x;
    int lane = tid & 31, wid = tid >> 5;

    for (int i = tid; i < 2000; i += 256) s[i] = r[i];
    if (tid == 0) s_pos = 0;
    __syncthreads();

    float mx = 0.f;
    for (int i = tid; i < 2000; i += 256) mx = fmaxf(mx, s[i]);
#pragma unroll
    for (int o = 16; o; o >>= 1) mx = fmaxf(mx, __shfl_xor_sync(0xffffffffu, mx, o));
    if (lane == 0) wredf[wid] = mx;
    __syncthreads();
    if (tid == 0) { float m = wredf[0]; for (int w = 1; w < 8; w++) m = fmaxf(m, wredf[w]); s_bcast = m; }
    __syncthreads();
    mx = s_bcast;

    unsigned prefix = 0u;
    int k = 50;
#pragma unroll
    for (int pass = 0; pass < 4; pass++) {
        const int shift = 24 - 8 * pass;
        const unsigned hmask = (pass == 0) ? 0u : (0xFFFFFFFFu << (shift + 8));
        if (tid < 256) hist[tid] = 0;
        __syncthreads();
        for (int i = tid; i < 2000; i += 256) {
            unsigned u = __float_as_uint(s[i]);
            if ((u & hmask) == prefix)
                atomicAdd(&hist[(u >> shift) & 255], 1);
        }
        __syncthreads();
        if (tid == 0) {
            int acc = 0, b = 255;
            for (; b > 0; b--) { acc += hist[b]; if (acc >= k) break; }
            if (acc < k) acc += hist[0];
            s_selb = b;
            s_selk = k - (acc - hist[b]);
        }
        __syncthreads();
        prefix |= ((unsigned)s_selb) << shift;
        k = s_selk;
        __syncthreads();
    }
    float thr = __uint_as_float(prefix);

    // sum of exp over kept set
    float sum = 0.f;
    for (int i = tid; i < 2000; i += 256) {
        float v = s[i];
        if (v >= thr) sum += expf(v - mx);
    }
#pragma unroll
    for (int o = 16; o; o >>= 1) sum += __shfl_xor_sync(0xffffffffu, sum, o);
    if (lane == 0) wredf[wid] = sum;
    __syncthreads();
    if (tid == 0) { float t = 0.f; for (int w = 0; w < 8; w++) t += wredf[w]; s_bcast = t; }
    __syncthreads();
    float inv = 1.0f / s_bcast;

    // emit row-compressed normalized weights
    for (int i = tid; i < 2000; i += 256) {
        float v = s[i];
        if (v >= thr) {
            int p = atomicAdd(&s_pos, 1);
            if (p < ROWCAP) {
                rowval[row * ROWCAP + p] = expf(v - mx) * inv;
                rowcol[row * ROWCAP + p] = i;
            }
        }
    }
    __syncthreads();
    if (tid == 0) rowcnt[row] = min(s_pos, ROWCAP);
}

// ---------------- zero int/float arrays ----------------
__global__ void zero_k(int* __restrict__ a, float* __restrict__ b, int n)
{
    int i = blockIdx.x * blockDim.x + threadIdx.x;
    if (i < n) { a[i] = 0; b[i] = 0.f; }
}

// ---------------- count column occupancy from rowbuf ----------------
__global__ void count_k(const int* __restrict__ rowcol, const int* __restrict__ rowcnt,
                        int* __restrict__ colcnt)
{
    int row = blockIdx.x;
    int b = row / NN;
    int cnt = rowcnt[row];
    if (threadIdx.x < cnt)
        atomicAdd(&colcnt[b * NN + rowcol[row * ROWCAP + threadIdx.x]], 1);
}

// ---------------- per-batch exclusive scan of colcnt (2000 entries) ----------------
__global__ void __launch_bounds__(256) scan_k(const int* __restrict__ colcnt,
                                              int* __restrict__ coloff, int* __restrict__ colcur)
{
    __shared__ int tsum[257];
    int b = blockIdx.x, tid = threadIdx.x;
    const int* cnt = colcnt + b * NN;
    int local[8];
    int tot = 0;
#pragma unroll
    for (int e = 0; e < 8; e++) {
        int i = tid * 8 + e;
        local[e] = tot;
        tot += (i < NN) ? cnt[i] : 0;
    }
    tsum[tid] = tot;
    __syncthreads();
    if (tid == 0) {
        int acc = 0;
        for (int t = 0; t < 256; t++) { int v = tsum[t]; tsum[t] = acc; acc += v; }
    }
    __syncthreads();
    int base = tsum[tid];
#pragma unroll
    for (int e = 0; e < 8; e++) {
        int i = tid * 8 + e;
        if (i < NN) {
            coloff[b * NN + i] = base + local[e];
            colcur[b * NN + i] = base + local[e];
        }
    }
}

// ---------------- place rowbuf entries into CSC; accumulate colsum ----------------
__global__ void place_k(const float* __restrict__ rowval, const int* __restrict__ rowcol,
                        const int* __restrict__ rowcnt,
                        int* __restrict__ colcur, float* __restrict__ colsum,
                        float* __restrict__ cscval, int* __restrict__ cscrow)
{
    int row = blockIdx.x;
    int b = row / NN, j = row % NN;
    int cnt = rowcnt[row];
    int e = threadIdx.x;
    if (e < cnt) {
        int   c = rowcol[row * ROWCAP + e];
        float w = rowval[row * ROWCAP + e];
        int pos = atomicAdd(&colcur[b * NN + c], 1);
        cscval[(long long)b * CAP + pos] = w;
        cscrow[(long long)b * CAP + pos] = j;
        atomicAdd(&colsum[b * NN + c], w);
    }
}

// ---------------- dinv = rsqrt(1 + colsum) ----------------
__global__ void dinv_k(const float* __restrict__ colsum, float* __restrict__ dinv)
{
    int i = blockIdx.x * blockDim.x + threadIdx.x;
    if (i < B_ * NN) dinv[i] = rsqrtf(1.0f + colsum[i]);
}

// ---------------- sparse GCN aggregation ----------------
// out[b,i,:] = ACT( dinv[b,i] * ( sum_e w_e * T[b,j_e,:] + T[b,i,:] ) + bias )
// block = DIM/2 threads (float2 per thread); grid = (NN, B_)
template<int DIM, int ACT, int RND>
__global__ void spagg_k(
    const float* __restrict__ cscval, const int* __restrict__ cscrow,
    const int* __restrict__ coloff, const int* __restrict__ colcnt,
    const float* __restrict__ T, const float* __restrict__ dinv,
    const float* __restrict__ bias, float* __restrict__ out)
{
    __shared__ float sw[256];
    __shared__ int   sj[256];
    int i = blockIdx.x, b = blockIdx.y, tid = threadIdx.x;
    const float* Tb = T + (long long)b * NN * DIM;
    int s0  = coloff[b * NN + i];
    int cnt = colcnt[b * NN + i];
    long long base = (long long)b * CAP + s0;

    float2 acc = *reinterpret_cast<const float2*>(&Tb[(long long)i * DIM + 2 * tid]);
    float2 acc2 = make_float2(0.f, 0.f);

    for (int e0 = 0; e0 < cnt; e0 += blockDim.x) {
        int chunk = min(cnt - e0, (int)blockDim.x);
        if (tid < chunk) {
            sw[tid] = cscval[base + e0 + tid];
            sj[tid] = cscrow[base + e0 + tid];
        }
        __syncthreads();
        int e = 0;
        for (; e + 1 < chunk; e += 2) {
            float2 t0 = *reinterpret_cast<const float2*>(&Tb[(long long)sj[e] * DIM + 2 * tid]);
            float2 t1 = *reinterpret_cast<const float2*>(&Tb[(long long)sj[e+1] * DIM + 2 * tid]);
            acc.x  = fmaf(sw[e],   t0.x, acc.x);
            acc.y  = fmaf(sw[e],   t0.y, acc.y);
            acc2.x = fmaf(sw[e+1], t1.x, acc2.x);
            acc2.y = fmaf(sw[e+1], t1.y, acc2.y);
        }
        if (e < chunk) {
            float2 t0 = *reinterpret_cast<const float2*>(&Tb[(long long)sj[e] * DIM + 2 * tid]);
            acc.x = fmaf(sw[e], t0.x, acc.x);
            acc.y = fmaf(sw[e], t0.y, acc.y);
        }
        __syncthreads();
    }
    float dv = dinv[b * NN + i];
    float vx = dv * (acc.x + acc2.x) + bias[2 * tid];
    float vy = dv * (acc.y + acc2.y) + bias[2 * tid + 1];
    if (ACT == 1) { vx = fmaxf(vx, 0.f); vy = fmaxf(vy, 0.f); }
    if (RND)      { vx = rtf32(vx);      vy = rtf32(vy); }
    *reinterpret_cast<float2*>(&out[((long long)b * NN + i) * DIM + 2 * tid]) = make_float2(vx, vy);
}

// ---------------- mean over nodes; mu/std/z ----------------
__global__ void meanz_k(const float* __restrict__ O3, const float* __restrict__ eps,
                        float* __restrict__ mu, float* __restrict__ stdv, float* __restrict__ z)
{
    int b = blockIdx.x, d = threadIdx.x;
    const float* p = O3 + ((long long)b * 2000) * 128 + d;
    float s0 = 0.f, s1 = 0.f, s2 = 0.f, s3 = 0.f;
    for (int i = 0; i < 2000; i += 4) {
        s0 += p[(long long)i * 128];
        s1 += p[(long long)(i + 1) * 128];
        s2 += p[(long long)(i + 2) * 128];
        s3 += p[(long long)(i + 3) * 128];
    }
    __shared__ float sg[128];
    sg[d] = ((s0 + s1) + (s2 + s3)) / 2000.0f;
    __syncthreads();
    if (d < 64) {
        float m = sg[d];
        float sp = log1pf(expf(sg[64 + d] - 64.0f));
        mu[b * 64 + d] = m;
        stdv[b * 64 + d] = sp;
        z[b * 64 + d] = fmaf(eps[b * 64 + d], sp, m);
    }
}

// ---------------- decoder ----------------
__global__ void __launch_bounds__(256) decode_k(
    const float* __restrict__ z, const float* __restrict__ w1, const float* __restrict__ b1,
    const float* __restrict__ gamma, const float* __restrict__ beta,
    const float* __restrict__ w2, const float* __restrict__ b2,
    float* __restrict__ xrec)
{
    __shared__ float h[1024];
    __shared__ float zs[64];
    int b = blockIdx.x, tid = threadIdx.x;
    if (tid < 64) zs[tid] = z[b * 64 + tid];
    __syncthreads();
    const float invc = 1.0f / sqrtf(1.0f + 1e-5f);
    for (int c = tid; c < 1024; c += 256) {
        float a = b1[c];
#pragma unroll 8
        for (int k = 0; k < 64; k++) a = fmaf(zs[k], w1[k * 1024 + c], a);
        a = a * (gamma[c] * invc) + beta[c];
        h[c] = fmaxf(a, 0.f);
    }
    __syncthreads();
    int c0 = blockIdx.y * 250;
    int c1 = min(c0 + 250, 2000);
    for (int c = c0 + tid; c < c1; c += 256) {
        float a = b2[c];
        for (int k = 0; k < 1024; k++) a = fmaf(h[k], w2[k * 2000 + c], a);
        xrec[b * 2000 + c] = fmaxf(a, 0.f);
    }
}

// ---------------- host orchestration ----------------
extern "C" void kernel_launch(void* const* d_in, const int* in_sizes, int n_in,
                              void* d_out, int out_size)
{
    const float* x1     = (const float*)d_in[0];
    const float* x2     = (const float*)d_in[1];
    const float* emb1   = (const float*)d_in[2];
    const float* gate_w = (const float*)d_in[3];
    const float* gate_b = (const float*)d_in[4];
    const float* enc_w1 = (const float*)d_in[5];
    const float* enc_b1 = (const float*)d_in[6];
    const float* enc_w2 = (const float*)d_in[7];
    const float* enc_b2 = (const float*)d_in[8];
    const float* gl_w   = (const float*)d_in[9];
    const float* g_w1   = (const float*)d_in[10];
    const float* g_b1   = (const float*)d_in[11];
    const float* g_w2   = (const float*)d_in[12];
    const float* g_b2   = (const float*)d_in[13];
    const float* g_w3   = (const float*)d_in[14];
    const float* g_b3   = (const float*)d_in[15];
    const float* dW1[2] = {(const float*)d_in[16], (const float*)d_in[22]};
    const float* dB1[2] = {(const float*)d_in[17], (const float*)d_in[23]};
    const float* dG [2] = {(const float*)d_in[18], (const float*)d_in[24]};
    const float* dBe[2] = {(const float*)d_in[19], (const float*)d_in[25]};
    const float* dW2[2] = {(const float*)d_in[20], (const float*)d_in[26]};
    const float* dB2[2] = {(const float*)d_in[21], (const float*)d_in[27]};
    const float* epsA[2]= {(const float*)d_in[28], (const float*)d_in[29]};

    static bool attr_done = false;
    if (!attr_done) {
        cudaFuncSetAttribute(tgemm_k<0,0,2,0,0,1>, cudaFuncAttributeMaxDynamicSharedMemorySize, SMEM_BYTES);
        cudaFuncSetAttribute(tgemm_k<0,0,0,0,0,1>, cudaFuncAttributeMaxDynamicSharedMemorySize, SMEM_BYTES);
        cudaFuncSetAttribute(tgemm_k<0,0,1,0,0,1>, cudaFuncAttributeMaxDynamicSharedMemorySize, SMEM_BYTES);
        cudaFuncSetAttribute(tgemm_k<0,1,0,0,1,0>, cudaFuncAttributeMaxDynamicSharedMemorySize, SMEM_BYTES);
        cudaFuncSetAttribute(tgemm_k<0,0,0,1,0,0>, cudaFuncAttributeMaxDynamicSharedMemorySize, SMEM_BYTES);
        attr_done = true;
    }

    float* sc = nullptr;
    cudaGetSymbolAddress((void**)&sc, g_scratch);
    float* Ag   = sc + OFF_AG;
    float* Henc = sc + OFF_HENC;
    float* Hbuf[2] = {sc + OFF_H1, sc + OFF_H2};
    float* GLW  = sc + OFF_GLW;
    float* F    = sc + OFF_F;
    float* att  = sc + OFF_ATT;
    float* dinv = sc + OFF_DINV;
    float* T    = sc + OFF_T;
    float* O1   = sc + OFF_O1;
    float* O2   = sc + OFF_O2;
    float* O3   = sc + OFF_O3;
    float* zb   = sc + OFF_Z;
    float* W1r  = sc + OFF_W1;
    float* W2r  = sc + OFF_W2;
    float* GW1r = sc + OFF_GW1;
    float* GW2r = sc + OFF_GW2;
    float* GW3r = sc + OFF_GW3;
    float* rowval = sc + OFF_ROWV;
    int*   rowcol = (int*)(sc + OFF_ROWC);
    int*   rowcnt = (int*)(sc + OFF_RCNT);
    int*   colcnt = (int*)(sc + OFF_CCNT);
    int*   coloff = (int*)(sc + OFF_COFF);
    int*   colcur = (int*)(sc + OFF_CCUR);
    float* colsum = sc + OFF_CSUM;
    float* cscval = sc + OFF_CSCV;
    int*   cscrow = (int*)(sc + OFF_CSCR);

    float* out = (float*)d_out;
    float* xrec[2] = {out,          out + 16000};
    float* muo [2] = {out + 32000,  out + 33024};
    float* stdo[2] = {out + 32512,  out + 33536};

    round_copy_k<<<(int)((SZ_W1  + 255) / 256), 256>>>(enc_w1, W1r,  (int)SZ_W1);
    round_copy_k<<<(int)((SZ_W2  + 255) / 256), 256>>>(enc_w2, W2r,  (int)SZ_W2);
    round_copy_k<<<(int)((SZ_GW1 + 255) / 256), 256>>>(g_w1,   GW1r, (int)SZ_GW1);
    round_copy_k<<<(int)((SZ_GW2 + 255) / 256), 256>>>(g_w2,   GW2r, (int)SZ_GW2);
    round_copy_k<<<(int)((SZ_GW3 + 255) / 256), 256>>>(g_w3,   GW3r, (int)SZ_GW3);
    build_glw_k<<<(D_ * KF + 255) / 256, 256>>>(gl_w, GLW);

    // ---- encoders ----
    for (int xi = 0; xi < 2; xi++) {
        const float* x = xi ? x2 : x1;
        long long tot = MR * E_;
        build_ag_k<<<(unsigned)((tot + 255) / 256), 256>>>(x, emb1, gate_w, gate_b, Ag);
        tgemm_k<0,0,2,0,0,1><<<dim3(HEN / 128, 125, 1), 256, SMEM_BYTES>>>(
            16000, HEN, E_, 1.f, Ag, E_, 0, W1r, HEN, 0, Henc, HEN, 0,
            enc_b1, nullptr, 0);
        tgemm_k<0,0,0,0,0,1><<<dim3(1, 125, 1), 256, SMEM_BYTES>>>(
            16000, D_, HEN, 1.f, Henc, HEN, 0, W2r, D_, 0, Hbuf[xi], D_, 0,
            enc_b2, nullptr, 0);
    }

    // ---- per-view ----
    for (int xi = 0; xi < 2; xi++) {
        float* H = Hbuf[xi];
        // F = relu(H @ GLW), tf32-rounded
        tgemm_k<0,0,1,0,0,1><<<dim3(KF / 128, 125, 1), 256, SMEM_BYTES>>>(
            16000, KF, D_, 1.f, H, D_, 0, GLW, KF, 0, F, KF, 0,
            nullptr, nullptr, 0);
        // att[b] = F_b @ F_b^T / 8 (dense logits; symmetric)
        tgemm_k<0,1,0,0,1,0><<<dim3(16, 16, 8), 256, SMEM_BYTES>>>(
            2000, 2000, KF, 0.125f,
            F, KF, (long long)2000 * KF,
            F, KF, (long long)2000 * KF,
            att, 2000, (long long)2000 * 2000,
            nullptr, nullptr, 0);

        // sparse adjacency pipeline
        zero_k<<<(B_ * NN + 255) / 256, 256>>>(colcnt, colsum, B_ * NN);
        topk_rows_k<<<16000, 256>>>(att, rowval, rowcol, rowcnt);
        count_k<<<16000, ROWCAP>>>(rowcol, rowcnt, colcnt);
        scan_k<<<B_, 256>>>(colcnt, coloff, colcur);
        place_k<<<16000, ROWCAP>>>(rowval, rowcol, rowcnt, colcur, colsum, cscval, cscrow);
        dinv_k<<<(B_ * NN + 255) / 256, 256>>>(colsum, dinv);

        // GCN layer 1: T = dinv ⊙ (H @ W1); O1 = relu(dinv(aggT + T) + b) [rounded]
        tgemm_k<0,0,0,1,0,0><<<dim3(HD / 128, 125, 1), 256, SMEM_BYTES>>>(
            16000, HD, D_, 1.f, H, D_, 0, GW1r, HD, 0, T, HD, 0,
            nullptr, dinv, NN);
        spagg_k<HD,1,1><<<dim3(NN, B_), HD/2>>>(cscval, cscrow, coloff, colcnt, T, dinv, g_b1, O1);
        // layer 2
        tgemm_k<0,0,0,1,0,0><<<dim3(HD / 128, 125, 1), 256, SMEM_BYTES>>>(
            16000, HD, HD, 1.f, O1, HD, 0, GW2r, HD, 0, T, HD, 0,
            nullptr, dinv, NN);
        spagg_k<HD,1,1><<<dim3(NN, B_), HD/2>>>(cscval, cscrow, coloff, colcnt, T, dinv, g_b2, O2);
        // layer 3 (no relu, O3 raw fp32)
        tgemm_k<0,0,0,1,0,0><<<dim3(1, 125, 1), 256, SMEM_BYTES>>>(
            16000, D_, HD, 1.f, O2, HD, 0, GW3r, D_, 0, T, D_, 0,
            nullptr, dinv, NN);
        spagg_k<D_,0,0><<<dim3(NN, B_), D_/2>>>(cscval, cscrow, coloff, colcnt, T, dinv, g_b3, O3);

        meanz_k<<<8, 128>>>(O3, epsA[xi], muo[xi], stdo[xi], zb);
        decode_k<<<dim3(8, 8), 256>>>(zb, dW1[xi], dB1[xi], dG[xi], dBe[xi], dW2[xi], dB2[xi], xrec[xi]);
    }
}

// round 8
// speedup vs baseline: 2.8483x; 1.2401x over previous
#include <cuda_runtime.h>
#include <cuda_fp16.h>
#include <math.h>
#include <stdint.h>

// ---------------- problem constants ----------------
constexpr int B_  = 8;
constexpr int NN  = 2000;
constexpr int E_  = 512;
constexpr int HEN = 1024;
constexpr int D_  = 128;   // 2*IB
constexpr int HD  = 512;
constexpr int KF  = 4096;  // P*HD
constexpr int IB_ = 64;
constexpr long long MR = (long long)B_ * NN; // 16000 rows

constexpr int ROWCAP = 64;
constexpr int CAP    = 131072;

// ---------------- scratch layout (floats; F region reused as half) ----------------
constexpr long long SZ_AG   = MR * E_;
constexpr long long SZ_HENC = MR * HEN;
constexpr long long SZ_H    = MR * D_;
constexpr long long SZ_GLW  = (long long)D_ * KF;
constexpr long long SZ_F    = MR * KF;          // allocated as floats; used as half (2x headroom)
constexpr long long SZ_ATT  = (long long)B_ * NN * NN;
constexpr long long SZ_DINV = MR;
constexpr long long SZ_T    = MR * HD;
constexpr long long SZ_O    = MR * HD;
constexpr long long SZ_O3   = MR * D_;
constexpr long long SZ_Z    = (long long)B_ * IB_;
constexpr long long SZ_W1   = (long long)E_ * HEN;
constexpr long long SZ_W2   = (long long)HEN * D_;
constexpr long long SZ_GW1  = (long long)D_ * HD;
constexpr long long SZ_GW2  = (long long)HD * HD;
constexpr long long SZ_GW3  = (long long)HD * D_;
constexpr long long SZ_ROWV = MR * ROWCAP;
constexpr long long SZ_ROWC = MR * ROWCAP;
constexpr long long SZ_RCNT = MR;
constexpr long long SZ_CCNT = MR;
constexpr long long SZ_COFF = MR;
constexpr long long SZ_CCUR = MR;
constexpr long long SZ_CSUM = MR;
constexpr long long SZ_CSCV = (long long)B_ * CAP;
constexpr long long SZ_CSCR = (long long)B_ * CAP;

constexpr long long OFF_AG   = 0;
constexpr long long OFF_HENC = OFF_AG + SZ_AG;
constexpr long long OFF_H1   = OFF_HENC + SZ_HENC;
constexpr long long OFF_H2   = OFF_H1 + SZ_H;
constexpr long long OFF_GLW  = OFF_H2 + SZ_H;
constexpr long long OFF_F    = OFF_GLW + SZ_GLW;
constexpr long long OFF_ATT  = OFF_F + SZ_F;
constexpr long long OFF_DINV = OFF_ATT + SZ_ATT;
constexpr long long OFF_T    = OFF_DINV + SZ_DINV;
constexpr long long OFF_O1   = OFF_T + SZ_T;
constexpr long long OFF_O2   = OFF_O1 + SZ_O;
constexpr long long OFF_O3   = OFF_O2 + SZ_O;
constexpr long long OFF_Z    = OFF_O3 + SZ_O3;
constexpr long long OFF_W1   = OFF_Z + SZ_Z;
constexpr long long OFF_W2   = OFF_W1 + SZ_W1;
constexpr long long OFF_GW1  = OFF_W2 + SZ_W2;
constexpr long long OFF_GW2  = OFF_GW1 + SZ_GW1;
constexpr long long OFF_GW3  = OFF_GW2 + SZ_GW2;
constexpr long long OFF_ROWV = OFF_GW3 + SZ_GW3;
constexpr long long OFF_ROWC = OFF_ROWV + SZ_ROWV;
constexpr long long OFF_RCNT = OFF_ROWC + SZ_ROWC;
constexpr long long OFF_CCNT = OFF_RCNT + SZ_RCNT;
constexpr long long OFF_COFF = OFF_CCNT + SZ_CCNT;
constexpr long long OFF_CCUR = OFF_COFF + SZ_COFF;
constexpr long long OFF_CSUM = OFF_CCUR + SZ_CCUR;
constexpr long long OFF_CSCV = OFF_CSUM + SZ_CSUM;
constexpr long long OFF_CSCR = OFF_CSCV + SZ_CSCV;
constexpr long long SCRATCH_TOTAL = OFF_CSCR + SZ_CSCR;

__device__ float g_scratch[SCRATCH_TOTAL];

// ---------------- precision helpers ----------------
__device__ __forceinline__ float rtf32(float v) {
    uint32_t r;
    asm("cvt.rna.tf32.f32 %0, %1;" : "=r"(r) : "f"(v));
    return __uint_as_float(r);
}

__device__ __forceinline__ void mma_tf32(float* c, const uint32_t* a, uint32_t b0, uint32_t b1) {
    asm volatile(
        "mma.sync.aligned.m16n8k8.row.col.f32.tf32.tf32.f32 "
        "{%0,%1,%2,%3}, {%4,%5,%6,%7}, {%8,%9}, {%0,%1,%2,%3};"
        : "+f"(c[0]), "+f"(c[1]), "+f"(c[2]), "+f"(c[3])
        : "r"(a[0]), "r"(a[1]), "r"(a[2]), "r"(a[3]), "r"(b0), "r"(b1));
}

__device__ __forceinline__ void mma_f16(float* c, const uint32_t* a, uint32_t b0, uint32_t b1) {
    asm volatile(
        "mma.sync.aligned.m16n8k16.row.col.f32.f16.f16.f32 "
        "{%0,%1,%2,%3}, {%4,%5,%6,%7}, {%8,%9}, {%0,%1,%2,%3};"
        : "+f"(c[0]), "+f"(c[1]), "+f"(c[2]), "+f"(c[3])
        : "r"(a[0]), "r"(a[1]), "r"(a[2]), "r"(a[3]), "r"(b0), "r"(b1));
}

__device__ __forceinline__ void cpa16(uint32_t dst, const void* src, bool pred) {
    int sz = pred ? 16 : 0;
    asm volatile("cp.async.cg.shared.global [%0], [%1], 16, %2;\n"
                 :: "r"(dst), "l"(src), "r"(sz));
}
__device__ __forceinline__ void cpa_commit() { asm volatile("cp.async.commit_group;\n"); }
__device__ __forceinline__ void cpa_wait1()  { asm volatile("cp.async.wait_group 1;\n"); }

__device__ __forceinline__ uint32_t smem_u32(const void* p) {
    uint32_t a;
    asm("{ .reg .u64 t; cvta.to.shared.u64 t, %1; cvt.u32.u64 %0, t; }" : "=r"(a) : "l"(p));
    return a;
}

// ---------------- tf32 tensor GEMM: 128x128 tile, cp.async 3-stage ----------------
// OUTH: store output as __half (for F).
constexpr int PK = 20;
constexpr int PM = 136;
constexpr int ASTG = 2560;
constexpr int BSTG = 2560;
constexpr int SMEM_BYTES = (3 * ASTG + 3 * BSTG) * 4;   // 61440

template<int TA, int TB, int ACT, int EPI, int RND, int OUTH>
__global__ void __launch_bounds__(256, 2) tgemm_k(
    int M, int N, int K, float alpha,
    const float* __restrict__ A, int lda, long long sA,
    const float* __restrict__ B, int ldb, long long sB,
    float* __restrict__ C, int ldc, long long sC,
    const float* __restrict__ bias,
    const float* __restrict__ dinv, long long sD)
{
    extern __shared__ uint32_t sh[];

    const int bz = blockIdx.z;
    A += bz * sA; B += bz * sB;
    if (EPI) dinv += bz * sD;

    const int bn = blockIdx.x, bm = blockIdx.y;
    const int m0 = bm * 128, n0 = bn * 128;

    const int tid  = threadIdx.x;
    const int lane = tid & 31, warp = tid >> 5;
    const int g = lane >> 2, th = lane & 3;
    const int wm = (warp >> 1) * 32;
    const int wn = (warp & 1) * 64;

    uint32_t sbase = smem_u32(sh);

    float acc[2][8][4];
#pragma unroll
    for (int i = 0; i < 2; i++)
#pragma unroll
        for (int j = 0; j < 8; j++)
#pragma unroll
            for (int l = 0; l < 4; l++) acc[i][j][l] = 0.f;

    const int KT = K >> 4;

    auto issue = [&](int kt, int stg) {
        uint32_t abase = sbase + (uint32_t)(stg * ASTG) * 4u;
#pragma unroll
        for (int it = 0; it < 2; it++) {
            int c = tid * 2 + it;
            if (TA == 0) {
                int row = c >> 2, kc = (c & 3) * 4;
                const float* src = A + (long long)(m0 + row) * lda + kt * 16 + kc;
                cpa16(abase + (uint32_t)(row * PK + kc) * 4u, src, (m0 + row) < M);
            } else {
                int kr = c >> 5, mc = (c & 31) * 4;
                const float* src = A + (long long)(kt * 16 + kr) * lda + m0 + mc;
                cpa16(abase + (uint32_t)(kr * PM + mc) * 4u, src, (m0 + mc) < M);
            }
        }
        uint32_t bbase = sbase + (uint32_t)(3 * ASTG + stg * BSTG) * 4u;
#pragma unroll
        for (int it = 0; it < 2; it++) {
            int c = tid * 2 + it;
            if (TB == 1) {
                int row = c >> 2, kc = (c & 3) * 4;
                const float* src = B + (long long)(n0 + row) * ldb + kt * 16 + kc;
                cpa16(bbase + (uint32_t)(row * PK + kc) * 4u, src, (n0 + row) < N);
            } else {
                int kr = c >> 5, nc = (c & 31) * 4;
                const float* src = B + (long long)(kt * 16 + kr) * ldb + n0 + nc;
                cpa16(bbase + (uint32_t)(kr * PM + nc) * 4u, src, (n0 + nc) < N);
            }
        }
    };

    auto mmaTile = [&](int stg) {
        const uint32_t* Ab = sh + stg * ASTG;
        const uint32_t* Bb = sh + 3 * ASTG + stg * BSTG;
#pragma unroll
        for (int s = 0; s < 2; s++) {
            const int k0 = s * 8;
            uint32_t a[2][4];
#pragma unroll
            for (int mt = 0; mt < 2; mt++) {
                int mrow = wm + mt * 16 + g;
                if (TA == 0) {
                    a[mt][0] = Ab[mrow * PK + k0 + th];
                    a[mt][1] = Ab[(mrow + 8) * PK + k0 + th];
                    a[mt][2] = Ab[mrow * PK + k0 + th + 4];
                    a[mt][3] = Ab[(mrow + 8) * PK + k0 + th + 4];
                } else {
                    a[mt][0] = Ab[(k0 + th) * PM + mrow];
                    a[mt][1] = Ab[(k0 + th) * PM + mrow + 8];
                    a[mt][2] = Ab[(k0 + th + 4) * PM + mrow];
                    a[mt][3] = Ab[(k0 + th + 4) * PM + mrow + 8];
                }
            }
#pragma unroll
            for (int nt = 0; nt < 8; nt++) {
                int nrow = wn + nt * 8 + g;
                uint32_t b0, b1;
                if (TB == 1) {
                    b0 = Bb[nrow * PK + k0 + th];
                    b1 = Bb[nrow * PK + k0 + th + 4];
                } else {
                    b0 = Bb[(k0 + th) * PM + nrow];
                    b1 = Bb[(k0 + th + 4) * PM + nrow];
                }
                mma_tf32(acc[0][nt], a[0], b0, b1);
                mma_tf32(acc[1][nt], a[1], b0, b1);
            }
        }
    };

    issue(0, 0); cpa_commit();
    if (KT > 1) issue(1, 1);
    cpa_commit();
    cpa_wait1();
    __syncthreads();

    for (int kt = 0; kt < KT; kt++) {
        int stg = kt % 3;
        if (kt + 2 < KT) issue(kt + 2, (kt + 2) % 3);
        cpa_commit();
        mmaTile(stg);
        cpa_wait1();
        __syncthreads();
    }

    __half* Ch = reinterpret_cast<__half*>(C) + (OUTH ? bz * sC : 0);
    float*  Cf = C + (OUTH ? 0 : bz * sC);
#pragma unroll
    for (int mt = 0; mt < 2; mt++) {
#pragma unroll
        for (int nt = 0; nt < 8; nt++) {
#pragma unroll
            for (int e = 0; e < 4; e++) {
                int gm = m0 + wm + mt * 16 + g + (e >= 2 ? 8 : 0);
                int gn = n0 + wn + nt * 8 + 2 * th + (e & 1);
                if (gm >= M || gn >= N) continue;
                float v = alpha * acc[mt][nt][e];
                if (EPI == 1) v = dinv[gm] * v;
                if (bias)     v += bias[gn];
                if (ACT == 1) v = fmaxf(v, 0.f);
                if (ACT == 2) v = 0.5f * v * (1.f + erff(v * 0.70710678118654752f));
                if (RND)      v = rtf32(v);
                if (OUTH) Ch[(long long)gm * ldc + gn] = __float2half_rn(v);
                else      Cf[(long long)gm * ldc + gn] = v;
            }
        }
    }
}

// ---------------- fp16 gram: att[b] = 0.125 * F_b @ F_b^T (symmetric) ----------------
// F is __half [NN, KF]. 128x128 tiles, k-tile 32 halves, 3-stage cp.async.
// Fragment u32 addressing identical to tf32 kernel (PK=20 u32 rows).
__global__ void __launch_bounds__(256, 2) hgram_k(const __half* __restrict__ F,
                                                  float* __restrict__ att)
{
    extern __shared__ uint32_t sh[];
    const int bn = blockIdx.x, bm = blockIdx.y, b = blockIdx.z;
    if (bm > bn) return;
    const int m0 = bm * 128, n0 = bn * 128;

    const int tid  = threadIdx.x;
    const int lane = tid & 31, warp = tid >> 5;
    const int g = lane >> 2, th = lane & 3;
    const int wm = (warp >> 1) * 32;
    const int wn = (warp & 1) * 64;

    uint32_t sbase = smem_u32(sh);
    const __half* Fb = F + (long long)b * NN * KF;
    float* attb = att + (long long)b * NN * NN;

    float acc[2][8][4];
#pragma unroll
    for (int i = 0; i < 2; i++)
#pragma unroll
        for (int j = 0; j < 8; j++)
#pragma unroll
            for (int l = 0; l < 4; l++) acc[i][j][l] = 0.f;

    const int KT = KF / 32;   // 128 k-tiles of 32 halves

    auto issue = [&](int kt, int stg) {
        uint32_t abase = sbase + (uint32_t)(stg * ASTG) * 4u;
        uint32_t bbase = sbase + (uint32_t)(3 * ASTG + stg * BSTG) * 4u;
#pragma unroll
        for (int it = 0; it < 2; it++) {
            int c = tid * 2 + it;            // 0..511
            int row = c >> 2, kc = c & 3;    // kc: which 16B chunk (8 halves)
            const __half* srcA = Fb + (long long)(m0 + row) * KF + kt * 32 + kc * 8;
            cpa16(abase + (uint32_t)(row * PK + kc * 4) * 4u, srcA, (m0 + row) < NN);
            const __half* srcB = Fb + (long long)(n0 + row) * KF + kt * 32 + kc * 8;
            cpa16(bbase + (uint32_t)(row * PK + kc * 4) * 4u, srcB, (n0 + row) < NN);
        }
    };

    auto mmaTile = [&](int stg) {
        const uint32_t* Ab = sh + stg * ASTG;
        const uint32_t* Bb = sh + 3 * ASTG + stg * BSTG;
#pragma unroll
        for (int s = 0; s < 2; s++) {
            const int k0 = s * 8;            // u32 offset: 8 u32 = 16 halves per k-step
            uint32_t a[2][4];
#pragma unroll
            for (int mt = 0; mt < 2; mt++) {
                int mrow = wm + mt * 16 + g;
                a[mt][0] = Ab[mrow * PK + k0 + th];
                a[mt][1] = Ab[(mrow + 8) * PK + k0 + th];
                a[mt][2] = Ab[mrow * PK + k0 + th + 4];
                a[mt][3] = Ab[(mrow + 8) * PK + k0 + th + 4];
            }
#pragma unroll
            for (int nt = 0; nt < 8; nt++) {
                int nrow = wn + nt * 8 + g;
                uint32_t b0 = Bb[nrow * PK + k0 + th];
                uint32_t b1 = Bb[nrow * PK + k0 + th + 4];
                mma_f16(acc[0][nt], a[0], b0, b1);
                mma_f16(acc[1][nt], a[1], b0, b1);
            }
        }
    };

    issue(0, 0); cpa_commit();
    if (KT > 1) issue(1, 1);
    cpa_commit();
    cpa_wait1();
    __syncthreads();

    for (int kt = 0; kt < KT; kt++) {
        int stg = kt % 3;
        if (kt + 2 < KT) issue(kt + 2, (kt + 2) % 3);
        cpa_commit();
        mmaTile(stg);
        cpa_wait1();
        __syncthreads();
    }

#pragma unroll
    for (int mt = 0; mt < 2; mt++) {
#pragma unroll
        for (int nt = 0; nt < 8; nt++) {
#pragma unroll
            for (int e = 0; e < 4; e++) {
                int gm = m0 + wm + mt * 16 + g + (e >= 2 ? 8 : 0);
                int gn = n0 + wn + nt * 8 + 2 * th + (e & 1);
                if (gm >= NN || gn >= NN) continue;
                float v = 0.125f * acc[mt][nt][e];
                attb[(long long)gm * NN + gn] = v;
                if (bm < bn) attb[(long long)gn * NN + gm] = v;
            }
        }
    }
}

// ---------------- tf32 round-copy ----------------
__global__ void round_copy_k(const float* __restrict__ src, float* __restrict__ dst, int n)
{
    int i = blockIdx.x * blockDim.x + threadIdx.x;
    if (i < n) dst[i] = rtf32(src[i]);
}

// ---------------- A-matrix builder ----------------
__global__ void build_ag_k(const float* __restrict__ x, const float* __restrict__ emb,
                           const float* __restrict__ gw, const float* __restrict__ gb,
                           float* __restrict__ Ag)
{
    long long idx = (long long)blockIdx.x * blockDim.x + threadIdx.x;
    if (idx >= MR * E_) return;
    int e = (int)(idx & (E_ - 1));
    long long rn = idx >> 9;
    int n = (int)(rn % NN);
    float t = fmaf(x[rn], gw[e], gb[e]);
    float sgm = 1.0f / (1.0f + expf(-t));
    Ag[idx] = rtf32(sgm * emb[(long long)n * E_ + e]);
}

// ---------------- concat gl_w ----------------
__global__ void build_glw_k(const float* __restrict__ glw, float* __restrict__ GLW)
{
    int idx = blockIdx.x * blockDim.x + threadIdx.x;
    if (idx >= D_ * KF) return;
    int k = idx / KF, c = idx % KF;
    int p = c >> 9, hh = c & 511;
    GLW[idx] = rtf32(glw[((long long)p * D_ + k) * HD + hh]);
}

// ---------------- top-k(50) -> row-compressed softmax output ----------------
__global__ void __launch_bounds__(256) topk_rows_k(
    const float* __restrict__ att,
    float* __restrict__ rowval, int* __restrict__ rowcol, int* __restrict__ rowcnt)
{
    __shared__ float s[2000];
    __shared__ int   hist[256];
    __shared__ float wredf[8];
    __shared__ float s_bcast;
    __shared__ int   s_selb, s_selk, s_pos;

    long long row = blockIdx.x;
    const float* r = att + row * 2000;
    int tid = threadIdx.x;
    int lane = tid & 31, wid = tid >> 5;

    for (int i = tid; i < 2000; i += 256) s[i] = r[i];
    if (tid == 0) s_pos = 0;
    __syncthreads();

    float mx = 0.f;
    for (int i = tid; i < 2000; i += 256) mx = fmaxf(mx, s[i]);
#pragma unroll
    for (int o = 16; o; o >>= 1) mx = fmaxf(mx, __shfl_xor_sync(0xffffffffu, mx, o));
    if (lane == 0) wredf[wid] = mx;
    __syncthreads();
    if (tid == 0) { float m = wredf[0]; for (int w = 1; w < 8; w++) m = fmaxf(m, wredf[w]); s_bcast = m; }
    __syncthreads();
    mx = s_bcast;

    unsigned prefix = 0u;
    int k = 50;
#pragma unroll
    for (int pass = 0; pass < 4; pass++) {
        const int shift = 24 - 8 * pass;
        const unsigned hmask = (pass == 0) ? 0u : (0xFFFFFFFFu << (shift + 8));
        if (tid < 256) hist[tid] = 0;
        __syncthreads();
        for (int i = tid; i < 2000; i += 256) {
            unsigned u = __float_as_uint(s[i]);
            if ((u & hmask) == prefix)
                atomicAdd(&hist[(u >> shift) & 255], 1);
        }
        __syncthreads();
        if (tid == 0) {
            int acc = 0, b = 255;
            for (; b > 0; b--) { acc += hist[b]; if (acc >= k) break; }
            if (acc < k) acc += hist[0];
            s_selb = b;
            s_selk = k - (acc - hist[b]);
        }
        __syncthreads();
        prefix |= ((unsigned)s_selb) << shift;
        k = s_selk;
        __syncthreads();
    }
    float thr = __uint_as_float(prefix);

    float sum = 0.f;
    for (int i = tid; i < 2000; i += 256) {
        float v = s[i];
        if (v >= thr) sum += expf(v - mx);
    }
#pragma unroll
    for (int o = 16; o; o >>= 1) sum += __shfl_xor_sync(0xffffffffu, sum, o);
    if (lane == 0) wredf[wid] = sum;
    __syncthreads();
    if (tid == 0) { float t = 0.f; for (int w = 0; w < 8; w++) t += wredf[w]; s_bcast = t; }
    __syncthreads();
    float inv = 1.0f / s_bcast;

    for (int i = tid; i < 2000; i += 256) {
        float v = s[i];
        if (v >= thr) {
            int p = atomicAdd(&s_pos, 1);
            if (p < ROWCAP) {
                rowval[row * ROWCAP + p] = expf(v - mx) * inv;
                rowcol[row * ROWCAP + p] = i;
            }
        }
    }
    __syncthreads();
    if (tid == 0) rowcnt[row] = min(s_pos, ROWCAP);
}

// ---------------- zero int/float arrays ----------------
__global__ void zero_k(int* __restrict__ a, float* __restrict__ b, int n)
{
    int i = blockIdx.x * blockDim.x + threadIdx.x;
    if (i < n) { a[i] = 0; b[i] = 0.f; }
}

// ---------------- count column occupancy ----------------
__global__ void count_k(const int* __restrict__ rowcol, const int* __restrict__ rowcnt,
                        int* __restrict__ colcnt)
{
    int row = blockIdx.x;
    int b = row / NN;
    int cnt = rowcnt[row];
    if (threadIdx.x < cnt)
        atomicAdd(&colcnt[b * NN + rowcol[row * ROWCAP + threadIdx.x]], 1);
}

// ---------------- per-batch exclusive scan ----------------
__global__ void __launch_bounds__(256) scan_k(const int* __restrict__ colcnt,
                                              int* __restrict__ coloff, int* __restrict__ colcur)
{
    __shared__ int tsum[257];
    int b = blockIdx.x, tid = threadIdx.x;
    const int* cnt = colcnt + b * NN;
    int local[8];
    int tot = 0;
#pragma unroll
    for (int e = 0; e < 8; e++) {
        int i = tid * 8 + e;
        local[e] = tot;
        tot += (i < NN) ? cnt[i] : 0;
    }
    tsum[tid] = tot;
    __syncthreads();
    if (tid == 0) {
        int acc = 0;
        for (int t = 0; t < 256; t++) { int v = tsum[t]; tsum[t] = acc; acc += v; }
    }
    __syncthreads();
    int base = tsum[tid];
#pragma unroll
    for (int e = 0; e < 8; e++) {
        int i = tid * 8 + e;
        if (i < NN) {
            coloff[b * NN + i] = base + local[e];
            colcur[b * NN + i] = base + local[e];
        }
    }
}

// ---------------- place into CSC ----------------
__global__ void place_k(const float* __restrict__ rowval, const int* __restrict__ rowcol,
                        const int* __restrict__ rowcnt,
                        int* __restrict__ colcur, float* __restrict__ colsum,
                        float* __restrict__ cscval, int* __restrict__ cscrow)
{
    int row = blockIdx.x;
    int b = row / NN, j = row % NN;
    int cnt = rowcnt[row];
    int e = threadIdx.x;
    if (e < cnt) {
        int   c = rowcol[row * ROWCAP + e];
        float w = rowval[row * ROWCAP + e];
        int pos = atomicAdd(&colcur[b * NN + c], 1);
        cscval[(long long)b * CAP + pos] = w;
        cscrow[(long long)b * CAP + pos] = j;
        atomicAdd(&colsum[b * NN + c], w);
    }
}

// ---------------- dinv ----------------
__global__ void dinv_k(const float* __restrict__ colsum, float* __restrict__ dinv)
{
    int i = blockIdx.x * blockDim.x + threadIdx.x;
    if (i < B_ * NN) dinv[i] = rsqrtf(1.0f + colsum[i]);
}

// ---------------- sparse GCN aggregation ----------------
template<int DIM, int ACT, int RND>
__global__ void spagg_k(
    const float* __restrict__ cscval, const int* __restrict__ cscrow,
    const int* __restrict__ coloff, const int* __restrict__ colcnt,
    const float* __restrict__ T, const float* __restrict__ dinv,
    const float* __restrict__ bias, float* __restrict__ out)
{
    __shared__ float sw[256];
    __shared__ int   sj[256];
    int i = blockIdx.x, b = blockIdx.y, tid = threadIdx.x;
    const float* Tb = T + (long long)b * NN * DIM;
    int s0  = coloff[b * NN + i];
    int cnt = colcnt[b * NN + i];
    long long base = (long long)b * CAP + s0;

    float2 acc = *reinterpret_cast<const float2*>(&Tb[(long long)i * DIM + 2 * tid]);
    float2 acc2 = make_float2(0.f, 0.f);

    for (int e0 = 0; e0 < cnt; e0 += blockDim.x) {
        int chunk = min(cnt - e0, (int)blockDim.x);
        if (tid < chunk) {
            sw[tid] = cscval[base + e0 + tid];
            sj[tid] = cscrow[base + e0 + tid];
        }
        __syncthreads();
        int e = 0;
        for (; e + 1 < chunk; e += 2) {
            float2 t0 = *reinterpret_cast<const float2*>(&Tb[(long long)sj[e] * DIM + 2 * tid]);
            float2 t1 = *reinterpret_cast<const float2*>(&Tb[(long long)sj[e+1] * DIM + 2 * tid]);
            acc.x  = fmaf(sw[e],   t0.x, acc.x);
            acc.y  = fmaf(sw[e],   t0.y, acc.y);
            acc2.x = fmaf(sw[e+1], t1.x, acc2.x);
            acc2.y = fmaf(sw[e+1], t1.y, acc2.y);
        }
        if (e < chunk) {
            float2 t0 = *reinterpret_cast<const float2*>(&Tb[(long long)sj[e] * DIM + 2 * tid]);
            acc.x = fmaf(sw[e], t0.x, acc.x);
            acc.y = fmaf(sw[e], t0.y, acc.y);
        }
        __syncthreads();
    }
    float dv = dinv[b * NN + i];
    float vx = dv * (acc.x + acc2.x) + bias[2 * tid];
    float vy = dv * (acc.y + acc2.y) + bias[2 * tid + 1];
    if (ACT == 1) { vx = fmaxf(vx, 0.f); vy = fmaxf(vy, 0.f); }
    if (RND)      { vx = rtf32(vx);      vy = rtf32(vy); }
    *reinterpret_cast<float2*>(&out[((long long)b * NN + i) * DIM + 2 * tid]) = make_float2(vx, vy);
}

// ---------------- mean over nodes; mu/std/z ----------------
__global__ void meanz_k(const float* __restrict__ O3, const float* __restrict__ eps,
                        float* __restrict__ mu, float* __restrict__ stdv, float* __restrict__ z)
{
    int b = blockIdx.x, d = threadIdx.x;
    const float* p = O3 + ((long long)b * 2000) * 128 + d;
    float s0 = 0.f, s1 = 0.f, s2 = 0.f, s3 = 0.f;
    for (int i = 0; i < 2000; i += 4) {
        s0 += p[(long long)i * 128];
        s1 += p[(long long)(i + 1) * 128];
        s2 += p[(long long)(i + 2) * 128];
        s3 += p[(long long)(i + 3) * 128];
    }
    __shared__ float sg[128];
    sg[d] = ((s0 + s1) + (s2 + s3)) / 2000.0f;
    __syncthreads();
    if (d < 64) {
        float m = sg[d];
        float sp = log1pf(expf(sg[64 + d] - 64.0f));
        mu[b * 64 + d] = m;
        stdv[b * 64 + d] = sp;
        z[b * 64 + d] = fmaf(eps[b * 64 + d], sp, m);
    }
}

// ---------------- decoder ----------------
__global__ void __launch_bounds__(256) decode_k(
    const float* __restrict__ z, const float* __restrict__ w1, const float* __restrict__ b1,
    const float* __restrict__ gamma, const float* __restrict__ beta,
    const float* __restrict__ w2, const float* __restrict__ b2,
    float* __restrict__ xrec)
{
    __shared__ float h[1024];
    __shared__ float zs[64];
    int b = blockIdx.x, tid = threadIdx.x;
    if (tid < 64) zs[tid] = z[b * 64 + tid];
    __syncthreads();
    const float invc = 1.0f / sqrtf(1.0f + 1e-5f);
    for (int c = tid; c < 1024; c += 256) {
        float a = b1[c];
#pragma unroll 8
        for (int k = 0; k < 64; k++) a = fmaf(zs[k], w1[k * 1024 + c], a);
        a = a * (gamma[c] * invc) + beta[c];
        h[c] = fmaxf(a, 0.f);
    }
    __syncthreads();
    int c0 = blockIdx.y * 250;
    int c1 = min(c0 + 250, 2000);
    for (int c = c0 + tid; c < c1; c += 256) {
        float a = b2[c];
        for (int k = 0; k < 1024; k++) a = fmaf(h[k], w2[k * 2000 + c], a);
        xrec[b * 2000 + c] = fmaxf(a, 0.f);
    }
}

// ---------------- host orchestration ----------------
extern "C" void kernel_launch(void* const* d_in, const int* in_sizes, int n_in,
                              void* d_out, int out_size)
{
    const float* x1     = (const float*)d_in[0];
    const float* x2     = (const float*)d_in[1];
    const float* emb1   = (const float*)d_in[2];
    const float* gate_w = (const float*)d_in[3];
    const float* gate_b = (const float*)d_in[4];
    const float* enc_w1 = (const float*)d_in[5];
    const float* enc_b1 = (const float*)d_in[6];
    const float* enc_w2 = (const float*)d_in[7];
    const float* enc_b2 = (const float*)d_in[8];
    const float* gl_w   = (const float*)d_in[9];
    const float* g_w1   = (const float*)d_in[10];
    const float* g_b1   = (const float*)d_in[11];
    const float* g_w2   = (const float*)d_in[12];
    const float* g_b2   = (const float*)d_in[13];
    const float* g_w3   = (const float*)d_in[14];
    const float* g_b3   = (const float*)d_in[15];
    const float* dW1[2] = {(const float*)d_in[16], (const float*)d_in[22]};
    const float* dB1[2] = {(const float*)d_in[17], (const float*)d_in[23]};
    const float* dG [2] = {(const float*)d_in[18], (const float*)d_in[24]};
    const float* dBe[2] = {(const float*)d_in[19], (const float*)d_in[25]};
    const float* dW2[2] = {(const float*)d_in[20], (const float*)d_in[26]};
    const float* dB2[2] = {(const float*)d_in[21], (const float*)d_in[27]};
    const float* epsA[2]= {(const float*)d_in[28], (const float*)d_in[29]};

    static bool attr_done = false;
    if (!attr_done) {
        cudaFuncSetAttribute(tgemm_k<0,0,2,0,1,0>, cudaFuncAttributeMaxDynamicSharedMemorySize, SMEM_BYTES);
        cudaFuncSetAttribute(tgemm_k<0,0,0,0,1,0>, cudaFuncAttributeMaxDynamicSharedMemorySize, SMEM_BYTES);
        cudaFuncSetAttribute(tgemm_k<0,0,1,0,0,1>, cudaFuncAttributeMaxDynamicSharedMemorySize, SMEM_BYTES);
        cudaFuncSetAttribute(tgemm_k<0,0,0,1,0,0>, cudaFuncAttributeMaxDynamicSharedMemorySize, SMEM_BYTES);
        cudaFuncSetAttribute(hgram_k, cudaFuncAttributeMaxDynamicSharedMemorySize, SMEM_BYTES);
        attr_done = true;
    }

    float* sc = nullptr;
    cudaGetSymbolAddress((void**)&sc, g_scratch);
    float* Ag   = sc + OFF_AG;
    float* Henc = sc + OFF_HENC;
    float* Hbuf[2] = {sc + OFF_H1, sc + OFF_H2};
    float* GLW  = sc + OFF_GLW;
    float* Fh_f = sc + OFF_F;                 // storage; used as half
    __half* Fh  = reinterpret_cast<__half*>(Fh_f);
    float* att  = sc + OFF_ATT;
    float* dinv = sc + OFF_DINV;
    float* T    = sc + OFF_T;
    float* O1   = sc + OFF_O1;
    float* O2   = sc + OFF_O2;
    float* O3   = sc + OFF_O3;
    float* zb   = sc + OFF_Z;
    float* W1r  = sc + OFF_W1;
    float* W2r  = sc + OFF_W2;
    float* GW1r = sc + OFF_GW1;
    float* GW2r = sc + OFF_GW2;
    float* GW3r = sc + OFF_GW3;
    float* rowval = sc + OFF_ROWV;
    int*   rowcol = (int*)(sc + OFF_ROWC);
    int*   rowcnt = (int*)(sc + OFF_RCNT);
    int*   colcnt = (int*)(sc + OFF_CCNT);
    int*   coloff = (int*)(sc + OFF_COFF);
    int*   colcur = (int*)(sc + OFF_CCUR);
    float* colsum = sc + OFF_CSUM;
    float* cscval = sc + OFF_CSCV;
    int*   cscrow = (int*)(sc + OFF_CSCR);

    float* out = (float*)d_out;
    float* xrec[2] = {out,          out + 16000};
    float* muo [2] = {out + 32000,  out + 33024};
    float* stdo[2] = {out + 32512,  out + 33536};

    round_copy_k<<<(int)((SZ_W1  + 255) / 256), 256>>>(enc_w1, W1r,  (int)SZ_W1);
    round_copy_k<<<(int)((SZ_W2  + 255) / 256), 256>>>(enc_w2, W2r,  (int)SZ_W2);
    round_copy_k<<<(int)((SZ_GW1 + 255) / 256), 256>>>(g_w1,   GW1r, (int)SZ_GW1);
    round_copy_k<<<(int)((SZ_GW2 + 255) / 256), 256>>>(g_w2,   GW2r, (int)SZ_GW2);
    round_copy_k<<<(int)((SZ_GW3 + 255) / 256), 256>>>(g_w3,   GW3r, (int)SZ_GW3);
    build_glw_k<<<(D_ * KF + 255) / 256, 256>>>(gl_w, GLW);

    // ---- encoders ----
    for (int xi = 0; xi < 2; xi++) {
        const float* x = xi ? x2 : x1;
        long long tot = MR * E_;
        build_ag_k<<<(unsigned)((tot + 255) / 256), 256>>>(x, emb1, gate_w, gate_b, Ag);
        tgemm_k<0,0,2,0,1,0><<<dim3(HEN / 128, 125, 1), 256, SMEM_BYTES>>>(
            16000, HEN, E_, 1.f, Ag, E_, 0, W1r, HEN, 0, Henc, HEN, 0,
            enc_b1, nullptr, 0);
        tgemm_k<0,0,0,0,1,0><<<dim3(1, 125, 1), 256, SMEM_BYTES>>>(
            16000, D_, HEN, 1.f, Henc, HEN, 0, W2r, D_, 0, Hbuf[xi], D_, 0,
            enc_b2, nullptr, 0);
    }

    // ---- per-view ----
    for (int xi = 0; xi < 2; xi++) {
        float* H = Hbuf[xi];
        // F = relu(H @ GLW) -> __half
        tgemm_k<0,0,1,0,0,1><<<dim3(KF / 128, 125, 1), 256, SMEM_BYTES>>>(
            16000, KF, D_, 1.f, H, D_, 0, GLW, KF, 0, Fh_f, KF, 0,
            nullptr, nullptr, 0);
        // att[b] = F_b @ F_b^T / 8 — fp16 mma, symmetric tiles
        hgram_k<<<dim3(16, 16, 8), 256, SMEM_BYTES>>>(Fh, att);

        // sparse adjacency pipeline
        zero_k<<<(B_ * NN + 255) / 256, 256>>>(colcnt, colsum, B_ * NN);
        topk_rows_k<<<16000, 256>>>(att, rowval, rowcol, rowcnt);
        count_k<<<16000, ROWCAP>>>(rowcol, rowcnt, colcnt);
        scan_k<<<B_, 256>>>(colcnt, coloff, colcur);
        place_k<<<16000, ROWCAP>>>(rowval, rowcol, rowcnt, colcur, colsum, cscval, cscrow);
        dinv_k<<<(B_ * NN + 255) / 256, 256>>>(colsum, dinv);

        // GCN layer 1
        tgemm_k<0,0,0,1,0,0><<<dim3(HD / 128, 125, 1), 256, SMEM_BYTES>>>(
            16000, HD, D_, 1.f, H, D_, 0, GW1r, HD, 0, T, HD, 0,
            nullptr, dinv, NN);
        spagg_k<HD,1,1><<<dim3(NN, B_), HD/2>>>(cscval, cscrow, coloff, colcnt, T, dinv, g_b1, O1);
        // layer 2
        tgemm_k<0,0,0,1,0,0><<<dim3(HD / 128, 125, 1), 256, SMEM_BYTES>>>(
            16000, HD, HD, 1.f, O1, HD, 0, GW2r, HD, 0, T, HD, 0,
            nullptr, dinv, NN);
        spagg_k<HD,1,1><<<dim3(NN, B_), HD/2>>>(cscval, cscrow, coloff, colcnt, T, dinv, g_b2, O2);
        // layer 3 (no relu)
        tgemm_k<0,0,0,1,0,0><<<dim3(1, 125, 1), 256, SMEM_BYTES>>>(
            16000, D_, HD, 1.f, O2, HD, 0, GW3r, D_, 0, T, D_, 0,
            nullptr, dinv, NN);
        spagg_k<D_,0,0><<<dim3(NN, B_), D_/2>>>(cscval, cscrow, coloff, colcnt, T, dinv, g_b3, O3);

        meanz_k<<<8, 128>>>(O3, epsA[xi], muo[xi], stdo[xi], zb);
        decode_k<<<dim3(8, 8), 256>>>(zb, dW1[xi], dB1[xi], dG[xi], dBe[xi], dW2[xi], dB2[xi], xrec[xi]);
    }
}

// round 9
// speedup vs baseline: 3.0494x; 1.0706x over previous
#include <cuda_runtime.h>
#include <cuda_fp16.h>
#include <math.h>
#include <stdint.h>

// ---------------- problem constants ----------------
constexpr int B_  = 8;
constexpr int B2  = 16;          // both views batched
constexpr int NN  = 2000;
constexpr int E_  = 512;
constexpr int HEN = 1024;
constexpr int D_  = 128;
constexpr int HD  = 512;
constexpr int KF  = 4096;
constexpr int IB_ = 64;
constexpr long long MR  = (long long)B_ * NN;   // 16000
constexpr long long MR2 = (long long)B2 * NN;   // 32000

constexpr int ROWCAP = 64;
constexpr int CAP    = 131072;

// ---------------- scratch layout (units: float slots) ----------------
constexpr long long SZ_AG   = MR2 * E_;
constexpr long long SZ_HENC = MR2 * HEN;
constexpr long long SZ_H    = MR2 * D_;
constexpr long long SZ_GLW  = (long long)D_ * KF;
constexpr long long SZ_FH   = MR2 * KF / 2;        // half storage
constexpr long long SZ_ATT  = (long long)B2 * NN * NN;
constexpr long long SZ_DINV = MR2;
constexpr long long SZ_TH   = MR2 * HD / 2;        // half storage
constexpr long long SZ_O    = MR2 * HD;
constexpr long long SZ_O3   = MR2 * D_;
constexpr long long SZ_Z    = (long long)B2 * IB_;
constexpr long long SZ_W1   = (long long)E_ * HEN;
constexpr long long SZ_W2   = (long long)HEN * D_;
constexpr long long SZ_GW1  = (long long)D_ * HD;
constexpr long long SZ_GW2  = (long long)HD * HD;
constexpr long long SZ_GW3  = (long long)HD * D_;
constexpr long long SZ_ROWV = MR2 * ROWCAP;
constexpr long long SZ_ROWC = MR2 * ROWCAP;
constexpr long long SZ_RCNT = MR2;
constexpr long long SZ_CCNT = MR2;
constexpr long long SZ_COFF = MR2;
constexpr long long SZ_CCUR = MR2;
constexpr long long SZ_CSUM = MR2;
constexpr long long SZ_CSCV = (long long)B2 * CAP;
constexpr long long SZ_CSCR = (long long)B2 * CAP;

constexpr long long OFF_AG   = 0;
constexpr long long OFF_HENC = OFF_AG + SZ_AG;
constexpr long long OFF_H    = OFF_HENC + SZ_HENC;
constexpr long long OFF_GLW  = OFF_H + SZ_H;
constexpr long long OFF_FH   = OFF_GLW + SZ_GLW;
constexpr long long OFF_ATT  = OFF_FH + SZ_FH;
constexpr long long OFF_DINV = OFF_ATT + SZ_ATT;
constexpr long long OFF_TH   = OFF_DINV + SZ_DINV;
constexpr long long OFF_O1   = OFF_TH + SZ_TH;
constexpr long long OFF_O2   = OFF_O1 + SZ_O;
constexpr long long OFF_O3   = OFF_O2 + SZ_O;
constexpr long long OFF_Z    = OFF_O3 + SZ_O3;
constexpr long long OFF_W1   = OFF_Z + SZ_Z;
constexpr long long OFF_W2   = OFF_W1 + SZ_W1;
constexpr long long OFF_GW1  = OFF_W2 + SZ_W2;
constexpr long long OFF_GW2  = OFF_GW1 + SZ_GW1;
constexpr long long OFF_GW3  = OFF_GW2 + SZ_GW2;
constexpr long long OFF_ROWV = OFF_GW3 + SZ_GW3;
constexpr long long OFF_ROWC = OFF_ROWV + SZ_ROWV;
constexpr long long OFF_RCNT = OFF_ROWC + SZ_ROWC;
constexpr long long OFF_CCNT = OFF_RCNT + SZ_RCNT;
constexpr long long OFF_COFF = OFF_CCNT + SZ_CCNT;
constexpr long long OFF_CCUR = OFF_COFF + SZ_COFF;
constexpr long long OFF_CSUM = OFF_CCUR + SZ_CCUR;
constexpr long long OFF_CSCV = OFF_CSUM + SZ_CSUM;
constexpr long long OFF_CSCR = OFF_CSCV + SZ_CSCV;
constexpr long long SCRATCH_TOTAL = OFF_CSCR + SZ_CSCR;

__device__ float g_scratch[SCRATCH_TOTAL];

// ---------------- precision helpers ----------------
__device__ __forceinline__ float rtf32(float v) {
    uint32_t r;
    asm("cvt.rna.tf32.f32 %0, %1;" : "=r"(r) : "f"(v));
    return __uint_as_float(r);
}

__device__ __forceinline__ void mma_tf32(float* c, const uint32_t* a, uint32_t b0, uint32_t b1) {
    asm volatile(
        "mma.sync.aligned.m16n8k8.row.col.f32.tf32.tf32.f32 "
        "{%0,%1,%2,%3}, {%4,%5,%6,%7}, {%8,%9}, {%0,%1,%2,%3};"
        : "+f"(c[0]), "+f"(c[1]), "+f"(c[2]), "+f"(c[3])
        : "r"(a[0]), "r"(a[1]), "r"(a[2]), "r"(a[3]), "r"(b0), "r"(b1));
}

__device__ __forceinline__ void mma_f16(float* c, const uint32_t* a, uint32_t b0, uint32_t b1) {
    asm volatile(
        "mma.sync.aligned.m16n8k16.row.col.f32.f16.f16.f32 "
        "{%0,%1,%2,%3}, {%4,%5,%6,%7}, {%8,%9}, {%0,%1,%2,%3};"
        : "+f"(c[0]), "+f"(c[1]), "+f"(c[2]), "+f"(c[3])
        : "r"(a[0]), "r"(a[1]), "r"(a[2]), "r"(a[3]), "r"(b0), "r"(b1));
}

__device__ __forceinline__ void cpa16(uint32_t dst, const void* src, bool pred) {
    int sz = pred ? 16 : 0;
    asm volatile("cp.async.cg.shared.global [%0], [%1], 16, %2;\n"
                 :: "r"(dst), "l"(src), "r"(sz));
}
__device__ __forceinline__ void cpa_commit() { asm volatile("cp.async.commit_group;\n"); }
__device__ __forceinline__ void cpa_wait1()  { asm volatile("cp.async.wait_group 1;\n"); }

__device__ __forceinline__ uint32_t smem_u32(const void* p) {
    uint32_t a;
    asm("{ .reg .u64 t; cvta.to.shared.u64 t, %1; cvt.u32.u64 %0, t; }" : "=r"(a) : "l"(p));
    return a;
}

// ---------------- tf32 tensor GEMM: 128x128 tile, cp.async 3-stage ----------------
// OUTH: store output as __half.
constexpr int PK = 20;
constexpr int PM = 136;
constexpr int ASTG = 2560;
constexpr int BSTG = 2560;
constexpr int SMEM_BYTES = (3 * ASTG + 3 * BSTG) * 4;   // 61440

template<int TA, int TB, int ACT, int EPI, int RND, int OUTH>
__global__ void __launch_bounds__(256, 2) tgemm_k(
    int M, int N, int K, float alpha,
    const float* __restrict__ A, int lda,
    const float* __restrict__ B, int ldb,
    float* __restrict__ C, int ldc,
    const float* __restrict__ bias,
    const float* __restrict__ dinv)
{
    extern __shared__ uint32_t sh[];

    const int bn = blockIdx.x, bm = blockIdx.y;
    const int m0 = bm * 128, n0 = bn * 128;

    const int tid  = threadIdx.x;
    const int lane = tid & 31, warp = tid >> 5;
    const int g = lane >> 2, th = lane & 3;
    const int wm = (warp >> 1) * 32;
    const int wn = (warp & 1) * 64;

    uint32_t sbase = smem_u32(sh);

    float acc[2][8][4];
#pragma unroll
    for (int i = 0; i < 2; i++)
#pragma unroll
        for (int j = 0; j < 8; j++)
#pragma unroll
            for (int l = 0; l < 4; l++) acc[i][j][l] = 0.f;

    const int KT = K >> 4;

    auto issue = [&](int kt, int stg) {
        uint32_t abase = sbase + (uint32_t)(stg * ASTG) * 4u;
#pragma unroll
        for (int it = 0; it < 2; it++) {
            int c = tid * 2 + it;
            if (TA == 0) {
                int row = c >> 2, kc = (c & 3) * 4;
                const float* src = A + (long long)(m0 + row) * lda + kt * 16 + kc;
                cpa16(abase + (uint32_t)(row * PK + kc) * 4u, src, (m0 + row) < M);
            } else {
                int kr = c >> 5, mc = (c & 31) * 4;
                const float* src = A + (long long)(kt * 16 + kr) * lda + m0 + mc;
                cpa16(abase + (uint32_t)(kr * PM + mc) * 4u, src, (m0 + mc) < M);
            }
        }
        uint32_t bbase = sbase + (uint32_t)(3 * ASTG + stg * BSTG) * 4u;
#pragma unroll
        for (int it = 0; it < 2; it++) {
            int c = tid * 2 + it;
            if (TB == 1) {
                int row = c >> 2, kc = (c & 3) * 4;
                const float* src = B + (long long)(n0 + row) * ldb + kt * 16 + kc;
                cpa16(bbase + (uint32_t)(row * PK + kc) * 4u, src, (n0 + row) < N);
            } else {
                int kr = c >> 5, nc = (c & 31) * 4;
                const float* src = B + (long long)(kt * 16 + kr) * ldb + n0 + nc;
                cpa16(bbase + (uint32_t)(kr * PM + nc) * 4u, src, (n0 + nc) < N);
            }
        }
    };

    auto mmaTile = [&](int stg) {
        const uint32_t* Ab = sh + stg * ASTG;
        const uint32_t* Bb = sh + 3 * ASTG + stg * BSTG;
#pragma unroll
        for (int s = 0; s < 2; s++) {
            const int k0 = s * 8;
            uint32_t a[2][4];
#pragma unroll
            for (int mt = 0; mt < 2; mt++) {
                int mrow = wm + mt * 16 + g;
                if (TA == 0) {
                    a[mt][0] = Ab[mrow * PK + k0 + th];
                    a[mt][1] = Ab[(mrow + 8) * PK + k0 + th];
                    a[mt][2] = Ab[mrow * PK + k0 + th + 4];
                    a[mt][3] = Ab[(mrow + 8) * PK + k0 + th + 4];
                } else {
                    a[mt][0] = Ab[(k0 + th) * PM + mrow];
                    a[mt][1] = Ab[(k0 + th) * PM + mrow + 8];
                    a[mt][2] = Ab[(k0 + th + 4) * PM + mrow];
                    a[mt][3] = Ab[(k0 + th + 4) * PM + mrow + 8];
                }
            }
#pragma unroll
            for (int nt = 0; nt < 8; nt++) {
                int nrow = wn + nt * 8 + g;
                uint32_t b0, b1;
                if (TB == 1) {
                    b0 = Bb[nrow * PK + k0 + th];
                    b1 = Bb[nrow * PK + k0 + th + 4];
                } else {
                    b0 = Bb[(k0 + th) * PM + nrow];
                    b1 = Bb[(k0 + th + 4) * PM + nrow];
                }
                mma_tf32(acc[0][nt], a[0], b0, b1);
                mma_tf32(acc[1][nt], a[1], b0, b1);
            }
        }
    };

    issue(0, 0); cpa_commit();
    if (KT > 1) issue(1, 1);
    cpa_commit();
    cpa_wait1();
    __syncthreads();

    for (int kt = 0; kt < KT; kt++) {
        int stg = kt % 3;
        if (kt + 2 < KT) issue(kt + 2, (kt + 2) % 3);
        cpa_commit();
        mmaTile(stg);
        cpa_wait1();
        __syncthreads();
    }

    __half* Ch = reinterpret_cast<__half*>(C);
#pragma unroll
    for (int mt = 0; mt < 2; mt++) {
#pragma unroll
        for (int nt = 0; nt < 8; nt++) {
#pragma unroll
            for (int e = 0; e < 4; e++) {
                int gm = m0 + wm + mt * 16 + g + (e >= 2 ? 8 : 0);
                int gn = n0 + wn + nt * 8 + 2 * th + (e & 1);
                if (gm >= M || gn >= N) continue;
                float v = alpha * acc[mt][nt][e];
                if (EPI == 1) v = dinv[gm] * v;
                if (bias)     v += bias[gn];
                if (ACT == 1) v = fmaxf(v, 0.f);
                if (ACT == 2) v = 0.5f * v * (1.f + erff(v * 0.70710678118654752f));
                if (RND)      v = rtf32(v);
                if (OUTH) Ch[(long long)gm * ldc + gn] = __float2half_rn(v);
                else      C[(long long)gm * ldc + gn] = v;
            }
        }
    }
}

// ---------------- fp16 gram: att[b] = 0.125 * F_b @ F_b^T (symmetric) ----------------
__global__ void __launch_bounds__(256, 2) hgram_k(const __half* __restrict__ F,
                                                  float* __restrict__ att)
{
    extern __shared__ uint32_t sh[];
    const int bn = blockIdx.x, bm = blockIdx.y, b = blockIdx.z;
    if (bm > bn) return;
    const int m0 = bm * 128, n0 = bn * 128;

    const int tid  = threadIdx.x;
    const int lane = tid & 31, warp = tid >> 5;
    const int g = lane >> 2, th = lane & 3;
    const int wm = (warp >> 1) * 32;
    const int wn = (warp & 1) * 64;

    uint32_t sbase = smem_u32(sh);
    const __half* Fb = F + (long long)b * NN * KF;
    float* attb = att + (long long)b * NN * NN;

    float acc[2][8][4];
#pragma unroll
    for (int i = 0; i < 2; i++)
#pragma unroll
        for (int j = 0; j < 8; j++)
#pragma unroll
            for (int l = 0; l < 4; l++) acc[i][j][l] = 0.f;

    const int KT = KF / 32;

    auto issue = [&](int kt, int stg) {
        uint32_t abase = sbase + (uint32_t)(stg * ASTG) * 4u;
        uint32_t bbase = sbase + (uint32_t)(3 * ASTG + stg * BSTG) * 4u;
#pragma unroll
        for (int it = 0; it < 2; it++) {
            int c = tid * 2 + it;
            int row = c >> 2, kc = c & 3;
            const __half* srcA = Fb + (long long)(m0 + row) * KF + kt * 32 + kc * 8;
            cpa16(abase + (uint32_t)(row * PK + kc * 4) * 4u, srcA, (m0 + row) < NN);
            const __half* srcB = Fb + (long long)(n0 + row) * KF + kt * 32 + kc * 8;
            cpa16(bbase + (uint32_t)(row * PK + kc * 4) * 4u, srcB, (n0 + row) < NN);
        }
    };

    auto mmaTile = [&](int stg) {
        const uint32_t* Ab = sh + stg * ASTG;
        const uint32_t* Bb = sh + 3 * ASTG + stg * BSTG;
#pragma unroll
        for (int s = 0; s < 2; s++) {
            const int k0 = s * 8;
            uint32_t a[2][4];
#pragma unroll
            for (int mt = 0; mt < 2; mt++) {
                int mrow = wm + mt * 16 + g;
                a[mt][0] = Ab[mrow * PK + k0 + th];
                a[mt][1] = Ab[(mrow + 8) * PK + k0 + th];
                a[mt][2] = Ab[mrow * PK + k0 + th + 4];
                a[mt][3] = Ab[(mrow + 8) * PK + k0 + th + 4];
            }
#pragma unroll
            for (int nt = 0; nt < 8; nt++) {
                int nrow = wn + nt * 8 + g;
                uint32_t b0 = Bb[nrow * PK + k0 + th];
                uint32_t b1 = Bb[nrow * PK + k0 + th + 4];
                mma_f16(acc[0][nt], a[0], b0, b1);
                mma_f16(acc[1][nt], a[1], b0, b1);
            }
        }
    };

    issue(0, 0); cpa_commit();
    if (KT > 1) issue(1, 1);
    cpa_commit();
    cpa_wait1();
    __syncthreads();

    for (int kt = 0; kt < KT; kt++) {
        int stg = kt % 3;
        if (kt + 2 < KT) issue(kt + 2, (kt + 2) % 3);
        cpa_commit();
        mmaTile(stg);
        cpa_wait1();
        __syncthreads();
    }

#pragma unroll
    for (int mt = 0; mt < 2; mt++) {
#pragma unroll
        for (int nt = 0; nt < 8; nt++) {
#pragma unroll
            for (int e = 0; e < 4; e++) {
                int gm = m0 + wm + mt * 16 + g + (e >= 2 ? 8 : 0);
                int gn = n0 + wn + nt * 8 + 2 * th + (e & 1);
                if (gm >= NN || gn >= NN) continue;
                float v = 0.125f * acc[mt][nt][e];
                attb[(long long)gm * NN + gn] = v;
                if (bm < bn) attb[(long long)gn * NN + gm] = v;
            }
        }
    }
}

// ---------------- tf32 round-copy ----------------
__global__ void round_copy_k(const float* __restrict__ src, float* __restrict__ dst, int n)
{
    int i = blockIdx.x * blockDim.x + threadIdx.x;
    if (i < n) dst[i] = rtf32(src[i]);
}

// ---------------- A-matrix builder, both views ----------------
__global__ void build_ag2_k(const float* __restrict__ x1, const float* __restrict__ x2,
                            const float* __restrict__ emb,
                            const float* __restrict__ gw, const float* __restrict__ gb,
                            float* __restrict__ Ag)
{
    long long idx = (long long)blockIdx.x * blockDim.x + threadIdx.x;
    if (idx >= MR2 * E_) return;
    int e = (int)(idx & (E_ - 1));
    long long r = idx >> 9;                 // 0..31999
    long long rv = (r < MR) ? r : r - MR;
    const float* x = (r < MR) ? x1 : x2;
    int n = (int)(rv % NN);
    float t = fmaf(x[rv], gw[e], gb[e]);
    float sgm = 1.0f / (1.0f + expf(-t));
    Ag[idx] = rtf32(sgm * emb[(long long)n * E_ + e]);
}

// ---------------- concat gl_w ----------------
__global__ void build_glw_k(const float* __restrict__ glw, float* __restrict__ GLW)
{
    int idx = blockIdx.x * blockDim.x + threadIdx.x;
    if (idx >= D_ * KF) return;
    int k = idx / KF, c = idx % KF;
    int p = c >> 9, hh = c & 511;
    GLW[idx] = rtf32(glw[((long long)p * D_ + k) * HD + hh]);
}

// ---------------- top-k(50) -> row-compressed softmax output ----------------
__global__ void __launch_bounds__(256) topk_rows_k(
    const float* __restrict__ att,
    float* __restrict__ rowval, int* __restrict__ rowcol, int* __restrict__ rowcnt)
{
    __shared__ float s[2000];
    __shared__ int   hist[256];
    __shared__ float wredf[8];
    __shared__ float s_bcast;
    __shared__ int   s_selb, s_selk, s_pos;

    long long row = blockIdx.x;
    const float* r = att + row * 2000;
    int tid = threadIdx.x;
    int lane = tid & 31, wid = tid >> 5;

    for (int i = tid; i < 2000; i += 256) s[i] = r[i];
    if (tid == 0) s_pos = 0;
    __syncthreads();

    float mx = 0.f;
    for (int i = tid; i < 2000; i += 256) mx = fmaxf(mx, s[i]);
#pragma unroll
    for (int o = 16; o; o >>= 1) mx = fmaxf(mx, __shfl_xor_sync(0xffffffffu, mx, o));
    if (lane == 0) wredf[wid] = mx;
    __syncthreads();
    if (tid == 0) { float m = wredf[0]; for (int w = 1; w < 8; w++) m = fmaxf(m, wredf[w]); s_bcast = m; }
    __syncthreads();
    mx = s_bcast;

    unsigned prefix = 0u;
    int k = 50;
#pragma unroll
    for (int pass = 0; pass < 4; pass++) {
        const int shift = 24 - 8 * pass;
        const unsigned hmask = (pass == 0) ? 0u : (0xFFFFFFFFu << (shift + 8));
        if (tid < 256) hist[tid] = 0;
        __syncthreads();
        for (int i = tid; i < 2000; i += 256) {
            unsigned u = __float_as_uint(s[i]);
            if ((u & hmask) == prefix)
                atomicAdd(&hist[(u >> shift) & 255], 1);
        }
        __syncthreads();
        if (tid == 0) {
            int acc = 0, b = 255;
            for (; b > 0; b--) { acc += hist[b]; if (acc >= k) break; }
            if (acc < k) acc += hist[0];
            s_selb = b;
            s_selk = k - (acc - hist[b]);
        }
        __syncthreads();
        prefix |= ((unsigned)s_selb) << shift;
        k = s_selk;
        __syncthreads();
    }
    float thr = __uint_as_float(prefix);

    float sum = 0.f;
    for (int i = tid; i < 2000; i += 256) {
        float v = s[i];
        if (v >= thr) sum += expf(v - mx);
    }
#pragma unroll
    for (int o = 16; o; o >>= 1) sum += __shfl_xor_sync(0xffffffffu, sum, o);
    if (lane == 0) wredf[wid] = sum;
    __syncthreads();
    if (tid == 0) { float t = 0.f; for (int w = 0; w < 8; w++) t += wredf[w]; s_bcast = t; }
    __syncthreads();
    float inv = 1.0f / s_bcast;

    for (int i = tid; i < 2000; i += 256) {
        float v = s[i];
        if (v >= thr) {
            int p = atomicAdd(&s_pos, 1);
            if (p < ROWCAP) {
                rowval[row * ROWCAP + p] = expf(v - mx) * inv;
                rowcol[row * ROWCAP + p] = i;
            }
        }
    }
    __syncthreads();
    if (tid == 0) rowcnt[row] = min(s_pos, ROWCAP);
}

// ---------------- zero int/float arrays ----------------
__global__ void zero_k(int* __restrict__ a, float* __restrict__ b, int n)
{
    int i = blockIdx.x * blockDim.x + threadIdx.x;
    if (i < n) { a[i] = 0; b[i] = 0.f; }
}

// ---------------- count column occupancy ----------------
__global__ void count_k(const int* __restrict__ rowcol, const int* __restrict__ rowcnt,
                        int* __restrict__ colcnt)
{
    int row = blockIdx.x;
    int b = row / NN;
    int cnt = rowcnt[row];
    if (threadIdx.x < cnt)
        atomicAdd(&colcnt[b * NN + rowcol[row * ROWCAP + threadIdx.x]], 1);
}

// ---------------- per-batch exclusive scan ----------------
__global__ void __launch_bounds__(256) scan_k(const int* __restrict__ colcnt,
                                              int* __restrict__ coloff, int* __restrict__ colcur)
{
    __shared__ int tsum[257];
    int b = blockIdx.x, tid = threadIdx.x;
    const int* cnt = colcnt + b * NN;
    int local[8];
    int tot = 0;
#pragma unroll
    for (int e = 0; e < 8; e++) {
        int i = tid * 8 + e;
        local[e] = tot;
        tot += (i < NN) ? cnt[i] : 0;
    }
    tsum[tid] = tot;
    __syncthreads();
    if (tid == 0) {
        int acc = 0;
        for (int t = 0; t < 256; t++) { int v = tsum[t]; tsum[t] = acc; acc += v; }
    }
    __syncthreads();
    int base = tsum[tid];
#pragma unroll
    for (int e = 0; e < 8; e++) {
        int i = tid * 8 + e;
        if (i < NN) {
            coloff[b * NN + i] = base + local[e];
            colcur[b * NN + i] = base + local[e];
        }
    }
}

// ---------------- place into CSC ----------------
__global__ void place_k(const float* __restrict__ rowval, const int* __restrict__ rowcol,
                        const int* __restrict__ rowcnt,
                        int* __restrict__ colcur, float* __restrict__ colsum,
                        float* __restrict__ cscval, int* __restrict__ cscrow)
{
    int row = blockIdx.x;
    int b = row / NN, j = row % NN;
    int cnt = rowcnt[row];
    int e = threadIdx.x;
    if (e < cnt) {
        int   c = rowcol[row * ROWCAP + e];
        float w = rowval[row * ROWCAP + e];
        int pos = atomicAdd(&colcur[b * NN + c], 1);
        cscval[(long long)b * CAP + pos] = w;
        cscrow[(long long)b * CAP + pos] = j;
        atomicAdd(&colsum[b * NN + c], w);
    }
}

// ---------------- dinv ----------------
__global__ void dinv_k(const float* __restrict__ colsum, float* __restrict__ dinv, int n)
{
    int i = blockIdx.x * blockDim.x + threadIdx.x;
    if (i < n) dinv[i] = rsqrtf(1.0f + colsum[i]);
}

// ---------------- sparse GCN aggregation, T in fp16 ----------------
template<int DIM, int ACT, int RND>
__global__ void spagg_k(
    const float* __restrict__ cscval, const int* __restrict__ cscrow,
    const int* __restrict__ coloff, const int* __restrict__ colcnt,
    const __half* __restrict__ T, const float* __restrict__ dinv,
    const float* __restrict__ bias, float* __restrict__ out)
{
    __shared__ float sw[256];
    __shared__ int   sj[256];
    int i = blockIdx.x, b = blockIdx.y, tid = threadIdx.x;
    const __half* Tb = T + (long long)b * NN * DIM;
    int s0  = coloff[b * NN + i];
    int cnt = colcnt[b * NN + i];
    long long base = (long long)b * CAP + s0;

    float2 acc = __half22float2(*reinterpret_cast<const __half2*>(&Tb[(long long)i * DIM + 2 * tid]));
    float2 acc2 = make_float2(0.f, 0.f);

    for (int e0 = 0; e0 < cnt; e0 += blockDim.x) {
        int chunk = min(cnt - e0, (int)blockDim.x);
        if (tid < chunk) {
            sw[tid] = cscval[base + e0 + tid];
            sj[tid] = cscrow[base + e0 + tid];
        }
        __syncthreads();
        int e = 0;
        for (; e + 1 < chunk; e += 2) {
            float2 t0 = __half22float2(*reinterpret_cast<const __half2*>(&Tb[(long long)sj[e]   * DIM + 2 * tid]));
            float2 t1 = __half22float2(*reinterpret_cast<const __half2*>(&Tb[(long long)sj[e+1] * DIM + 2 * tid]));
            acc.x  = fmaf(sw[e],   t0.x, acc.x);
            acc.y  = fmaf(sw[e],   t0.y, acc.y);
            acc2.x = fmaf(sw[e+1], t1.x, acc2.x);
            acc2.y = fmaf(sw[e+1], t1.y, acc2.y);
        }
        if (e < chunk) {
            float2 t0 = __half22float2(*reinterpret_cast<const __half2*>(&Tb[(long long)sj[e] * DIM + 2 * tid]));
            acc.x = fmaf(sw[e], t0.x, acc.x);
            acc.y = fmaf(sw[e], t0.y, acc.y);
        }
        __syncthreads();
    }
    float dv = dinv[b * NN + i];
    float vx = dv * (acc.x + acc2.x) + bias[2 * tid];
    float vy = dv * (acc.y + acc2.y) + bias[2 * tid + 1];
    if (ACT == 1) { vx = fmaxf(vx, 0.f); vy = fmaxf(vy, 0.f); }
    if (RND)      { vx = rtf32(vx);      vy = rtf32(vy); }
    *reinterpret_cast<float2*>(&out[((long long)b * NN + i) * DIM + 2 * tid]) = make_float2(vx, vy);
}

// ---------------- mean over nodes; mu/std/z, all 16 batches ----------------
__global__ void meanz2_k(const float* __restrict__ O3,
                         const float* __restrict__ eps1, const float* __restrict__ eps2,
                         float* __restrict__ mu1, float* __restrict__ std1,
                         float* __restrict__ mu2, float* __restrict__ std2,
                         float* __restrict__ z)
{
    int b = blockIdx.x, d = threadIdx.x;    // b 0..15
    const float* p = O3 + ((long long)b * 2000) * 128 + d;
    float s0 = 0.f, s1 = 0.f, s2 = 0.f, s3 = 0.f;
    for (int i = 0; i < 2000; i += 4) {
        s0 += p[(long long)i * 128];
        s1 += p[(long long)(i + 1) * 128];
        s2 += p[(long long)(i + 2) * 128];
        s3 += p[(long long)(i + 3) * 128];
    }
    __shared__ float sg[128];
    sg[d] = ((s0 + s1) + (s2 + s3)) / 2000.0f;
    __syncthreads();
    if (d < 64) {
        int view = b >> 3, bb = b & 7;
        const float* eps = view ? eps2 : eps1;
        float* mu = view ? mu2 : mu1;
        float* sd = view ? std2 : std1;
        float m = sg[d];
        float sp = log1pf(expf(sg[64 + d] - 64.0f));
        mu[bb * 64 + d] = m;
        sd[bb * 64 + d] = sp;
        z[b * 64 + d] = fmaf(eps[bb * 64 + d], sp, m);
    }
}

// ---------------- decoder ----------------
__global__ void __launch_bounds__(256) decode_k(
    const float* __restrict__ z, const float* __restrict__ w1, const float* __restrict__ b1,
    const float* __restrict__ gamma, const float* __restrict__ beta,
    const float* __restrict__ w2, const float* __restrict__ b2,
    float* __restrict__ xrec)
{
    __shared__ float h[1024];
    __shared__ float zs[64];
    int b = blockIdx.x, tid = threadIdx.x;
    if (tid < 64) zs[tid] = z[b * 64 + tid];
    __syncthreads();
    const float invc = 1.0f / sqrtf(1.0f + 1e-5f);
    for (int c = tid; c < 1024; c += 256) {
        float a = b1[c];
#pragma unroll 8
        for (int k = 0; k < 64; k++) a = fmaf(zs[k], w1[k * 1024 + c], a);
        a = a * (gamma[c] * invc) + beta[c];
        h[c] = fmaxf(a, 0.f);
    }
    __syncthreads();
    int c0 = blockIdx.y * 250;
    int c1 = min(c0 + 250, 2000);
    for (int c = c0 + tid; c < c1; c += 256) {
        float a = b2[c];
        for (int k = 0; k < 1024; k++) a = fmaf(h[k], w2[k * 2000 + c], a);
        xrec[b * 2000 + c] = fmaxf(a, 0.f);
    }
}

// ---------------- host orchestration ----------------
extern "C" void kernel_launch(void* const* d_in, const int* in_sizes, int n_in,
                              void* d_out, int out_size)
{
    const float* x1     = (const float*)d_in[0];
    const float* x2     = (const float*)d_in[1];
    const float* emb1   = (const float*)d_in[2];
    const float* gate_w = (const float*)d_in[3];
    const float* gate_b = (const float*)d_in[4];
    const float* enc_w1 = (const float*)d_in[5];
    const float* enc_b1 = (const float*)d_in[6];
    const float* enc_w2 = (const float*)d_in[7];
    const float* enc_b2 = (const float*)d_in[8];
    const float* gl_w   = (const float*)d_in[9];
    const float* g_w1   = (const float*)d_in[10];
    const float* g_b1   = (const float*)d_in[11];
    const float* g_w2   = (const float*)d_in[12];
    const float* g_b2   = (const float*)d_in[13];
    const float* g_w3   = (const float*)d_in[14];
    const float* g_b3   = (const float*)d_in[15];
    const float* dW1[2] = {(const float*)d_in[16], (const float*)d_in[22]};
    const float* dB1[2] = {(const float*)d_in[17], (const float*)d_in[23]};
    const float* dG [2] = {(const float*)d_in[18], (const float*)d_in[24]};
    const float* dBe[2] = {(const float*)d_in[19], (const float*)d_in[25]};
    const float* dW2[2] = {(const float*)d_in[20], (const float*)d_in[26]};
    const float* dB2[2] = {(const float*)d_in[21], (const float*)d_in[27]};
    const float* epsA[2]= {(const float*)d_in[28], (const float*)d_in[29]};

    static bool attr_done = false;
    if (!attr_done) {
        cudaFuncSetAttribute(tgemm_k<0,0,2,0,1,0>, cudaFuncAttributeMaxDynamicSharedMemorySize, SMEM_BYTES);
        cudaFuncSetAttribute(tgemm_k<0,0,0,0,1,0>, cudaFuncAttributeMaxDynamicSharedMemorySize, SMEM_BYTES);
        cudaFuncSetAttribute(tgemm_k<0,0,1,0,0,1>, cudaFuncAttributeMaxDynamicSharedMemorySize, SMEM_BYTES);
        cudaFuncSetAttribute(tgemm_k<0,0,0,1,0,1>, cudaFuncAttributeMaxDynamicSharedMemorySize, SMEM_BYTES);
        cudaFuncSetAttribute(hgram_k, cudaFuncAttributeMaxDynamicSharedMemorySize, SMEM_BYTES);
        attr_done = true;
    }

    float* sc = nullptr;
    cudaGetSymbolAddress((void**)&sc, g_scratch);
    float* Ag   = sc + OFF_AG;
    float* Henc = sc + OFF_HENC;
    float* H    = sc + OFF_H;
    float* GLW  = sc + OFF_GLW;
    float* Fh_f = sc + OFF_FH;
    __half* Fh  = reinterpret_cast<__half*>(Fh_f);
    float* att  = sc + OFF_ATT;
    float* dinv = sc + OFF_DINV;
    float* Th_f = sc + OFF_TH;
    __half* Th  = reinterpret_cast<__half*>(Th_f);
    float* O1   = sc + OFF_O1;
    float* O2   = sc + OFF_O2;
    float* O3   = sc + OFF_O3;
    float* zb   = sc + OFF_Z;
    float* W1r  = sc + OFF_W1;
    float* W2r  = sc + OFF_W2;
    float* GW1r = sc + OFF_GW1;
    float* GW2r = sc + OFF_GW2;
    float* GW3r = sc + OFF_GW3;
    float* rowval = sc + OFF_ROWV;
    int*   rowcol = (int*)(sc + OFF_ROWC);
    int*   rowcnt = (int*)(sc + OFF_RCNT);
    int*   colcnt = (int*)(sc + OFF_CCNT);
    int*   coloff = (int*)(sc + OFF_COFF);
    int*   colcur = (int*)(sc + OFF_CCUR);
    float* colsum = sc + OFF_CSUM;
    float* cscval = sc + OFF_CSCV;
    int*   cscrow = (int*)(sc + OFF_CSCR);

    float* out = (float*)d_out;
    float* xrec[2] = {out,          out + 16000};
    float* muo [2] = {out + 32000,  out + 33024};
    float* stdo[2] = {out + 32512,  out + 33536};

    round_copy_k<<<(int)((SZ_W1  + 255) / 256), 256>>>(enc_w1, W1r,  (int)SZ_W1);
    round_copy_k<<<(int)((SZ_W2  + 255) / 256), 256>>>(enc_w2, W2r,  (int)SZ_W2);
    round_copy_k<<<(int)((SZ_GW1 + 255) / 256), 256>>>(g_w1,   GW1r, (int)SZ_GW1);
    round_copy_k<<<(int)((SZ_GW2 + 255) / 256), 256>>>(g_w2,   GW2r, (int)SZ_GW2);
    round_copy_k<<<(int)((SZ_GW3 + 255) / 256), 256>>>(g_w3,   GW3r, (int)SZ_GW3);
    build_glw_k<<<(D_ * KF + 255) / 256, 256>>>(gl_w, GLW);

    // ---- encoders, both views batched (M = 32000) ----
    build_ag2_k<<<(unsigned)((MR2 * E_ + 255) / 256), 256>>>(x1, x2, emb1, gate_w, gate_b, Ag);
    tgemm_k<0,0,2,0,1,0><<<dim3(HEN / 128, 250), 256, SMEM_BYTES>>>(
        (int)MR2, HEN, E_, 1.f, Ag, E_, W1r, HEN, Henc, HEN, enc_b1, nullptr);
    tgemm_k<0,0,0,0,1,0><<<dim3(1, 250), 256, SMEM_BYTES>>>(
        (int)MR2, D_, HEN, 1.f, Henc, HEN, W2r, D_, H, D_, enc_b2, nullptr);

    // ---- F = relu(H @ GLW) -> half, both views ----
    tgemm_k<0,0,1,0,0,1><<<dim3(KF / 128, 250), 256, SMEM_BYTES>>>(
        (int)MR2, KF, D_, 1.f, H, D_, GLW, KF, Fh_f, KF, nullptr, nullptr);

    // ---- gram for all 16 batches ----
    hgram_k<<<dim3(16, 16, B2), 256, SMEM_BYTES>>>(Fh, att);

    // ---- sparse adjacency pipeline, 16 batches ----
    zero_k<<<(int)((MR2 + 255) / 256), 256>>>(colcnt, colsum, (int)MR2);
    topk_rows_k<<<(unsigned)MR2, 256>>>(att, rowval, rowcol, rowcnt);
    count_k<<<(unsigned)MR2, ROWCAP>>>(rowcol, rowcnt, colcnt);
    scan_k<<<B2, 256>>>(colcnt, coloff, colcur);
    place_k<<<(unsigned)MR2, ROWCAP>>>(rowval, rowcol, rowcnt, colcur, colsum, cscval, cscrow);
    dinv_k<<<(int)((MR2 + 255) / 256), 256>>>(colsum, dinv, (int)MR2);

    // ---- GCN layers, 16 batches ----
    tgemm_k<0,0,0,1,0,1><<<dim3(HD / 128, 250), 256, SMEM_BYTES>>>(
        (int)MR2, HD, D_, 1.f, H, D_, GW1r, HD, Th_f, HD, nullptr, dinv);
    spagg_k<HD,1,1><<<dim3(NN, B2), HD/2>>>(cscval, cscrow, coloff, colcnt, Th, dinv, g_b1, O1);
    tgemm_k<0,0,0,1,0,1><<<dim3(HD / 128, 250), 256, SMEM_BYTES>>>(
        (int)MR2, HD, HD, 1.f, O1, HD, GW2r, HD, Th_f, HD, nullptr, dinv);
    spagg_k<HD,1,1><<<dim3(NN, B2), HD/2>>>(cscval, cscrow, coloff, colcnt, Th, dinv, g_b2, O2);
    tgemm_k<0,0,0,1,0,1><<<dim3(1, 250), 256, SMEM_BYTES>>>(
        (int)MR2, D_, HD, 1.f, O2, HD, GW3r, D_, Th_f, D_, nullptr, dinv);
    spagg_k<D_,0,0><<<dim3(NN, B2), D_/2>>>(cscval, cscrow, coloff, colcnt, Th, dinv, g_b3, O3);

    // ---- VIB head + decoders ----
    meanz2_k<<<B2, 128>>>(O3, epsA[0], epsA[1], muo[0], stdo[0], muo[1], stdo[1], zb);
    decode_k<<<dim3(8, 8), 256>>>(zb,       dW1[0], dB1[0], dG[0], dBe[0], dW2[0], dB2[0], xrec[0]);
    decode_k<<<dim3(8, 8), 256>>>(zb + 512, dW1[1], dB1[1], dG[1], dBe[1], dW2[1], dB2[1], xrec[1]);
}

// round 10
// speedup vs baseline: 3.0748x; 1.0083x over previous
#include <cuda_runtime.h>
#include <cuda_fp16.h>
#include <math.h>
#include <stdint.h>

// ---------------- problem constants ----------------
constexpr int B_  = 8;
constexpr int B2  = 16;          // both views batched
constexpr int NN  = 2000;
constexpr int E_  = 512;
constexpr int HEN = 1024;
constexpr int D_  = 128;
constexpr int HD  = 512;
constexpr int KF  = 4096;
constexpr int IB_ = 64;
constexpr long long MR  = (long long)B_ * NN;   // 16000
constexpr long long MR2 = (long long)B2 * NN;   // 32000

constexpr int ROWCAP = 64;
constexpr int CAP    = 131072;

// ---------------- scratch layout (units: float slots) ----------------
constexpr long long SZ_AG   = MR2 * E_;
constexpr long long SZ_HENC = MR2 * HEN;
constexpr long long SZ_H    = MR2 * D_;
constexpr long long SZ_GLW  = (long long)D_ * KF;
constexpr long long SZ_FH   = MR2 * KF / 2;        // half storage
constexpr long long SZ_ATT  = (long long)B2 * NN * NN;
constexpr long long SZ_DINV = MR2;
constexpr long long SZ_TH   = MR2 * HD / 2;        // half storage
constexpr long long SZ_O    = MR2 * HD;
constexpr long long SZ_O3   = MR2 * D_;
constexpr long long SZ_Z    = (long long)B2 * IB_;
constexpr long long SZ_W1   = (long long)E_ * HEN;
constexpr long long SZ_W2   = (long long)HEN * D_;
constexpr long long SZ_GW1  = (long long)D_ * HD;
constexpr long long SZ_GW2  = (long long)HD * HD;
constexpr long long SZ_GW3  = (long long)HD * D_;
constexpr long long SZ_ROWV = MR2 * ROWCAP;
constexpr long long SZ_ROWC = MR2 * ROWCAP;
constexpr long long SZ_RCNT = MR2;
constexpr long long SZ_CCNT = MR2;
constexpr long long SZ_COFF = MR2;
constexpr long long SZ_CCUR = MR2;
constexpr long long SZ_CSUM = MR2;
constexpr long long SZ_CSCV = (long long)B2 * CAP;
constexpr long long SZ_CSCR = (long long)B2 * CAP;

constexpr long long OFF_AG   = 0;
constexpr long long OFF_HENC = OFF_AG + SZ_AG;
constexpr long long OFF_H    = OFF_HENC + SZ_HENC;
constexpr long long OFF_GLW  = OFF_H + SZ_H;
constexpr long long OFF_FH   = OFF_GLW + SZ_GLW;
constexpr long long OFF_ATT  = OFF_FH + SZ_FH;
constexpr long long OFF_DINV = OFF_ATT + SZ_ATT;
constexpr long long OFF_TH   = OFF_DINV + SZ_DINV;
constexpr long long OFF_O1   = OFF_TH + SZ_TH;
constexpr long long OFF_O2   = OFF_O1 + SZ_O;
constexpr long long OFF_O3   = OFF_O2 + SZ_O;
constexpr long long OFF_Z    = OFF_O3 + SZ_O3;
constexpr long long OFF_W1   = OFF_Z + SZ_Z;
constexpr long long OFF_W2   = OFF_W1 + SZ_W1;
constexpr long long OFF_GW1  = OFF_W2 + SZ_W2;
constexpr long long OFF_GW2  = OFF_GW1 + SZ_GW1;
constexpr long long OFF_GW3  = OFF_GW2 + SZ_GW2;
constexpr long long OFF_ROWV = OFF_GW3 + SZ_GW3;
constexpr long long OFF_ROWC = OFF_ROWV + SZ_ROWV;
constexpr long long OFF_RCNT = OFF_ROWC + SZ_ROWC;
constexpr long long OFF_CCNT = OFF_RCNT + SZ_RCNT;
constexpr long long OFF_COFF = OFF_CCNT + SZ_CCNT;
constexpr long long OFF_CCUR = OFF_COFF + SZ_COFF;
constexpr long long OFF_CSUM = OFF_CCUR + SZ_CCUR;
constexpr long long OFF_CSCV = OFF_CSUM + SZ_CSUM;
constexpr long long OFF_CSCR = OFF_CSCV + SZ_CSCV;
constexpr long long SCRATCH_TOTAL = OFF_CSCR + SZ_CSCR;

__device__ float g_scratch[SCRATCH_TOTAL];

// ---------------- precision helpers ----------------
__device__ __forceinline__ float rtf32(float v) {
    uint32_t r;
    asm("cvt.rna.tf32.f32 %0, %1;" : "=r"(r) : "f"(v));
    return __uint_as_float(r);
}

__device__ __forceinline__ void mma_tf32(float* c, const uint32_t* a, uint32_t b0, uint32_t b1) {
    asm volatile(
        "mma.sync.aligned.m16n8k8.row.col.f32.tf32.tf32.f32 "
        "{%0,%1,%2,%3}, {%4,%5,%6,%7}, {%8,%9}, {%0,%1,%2,%3};"
        : "+f"(c[0]), "+f"(c[1]), "+f"(c[2]), "+f"(c[3])
        : "r"(a[0]), "r"(a[1]), "r"(a[2]), "r"(a[3]), "r"(b0), "r"(b1));
}

__device__ __forceinline__ void mma_f16(float* c, const uint32_t* a, uint32_t b0, uint32_t b1) {
    asm volatile(
        "mma.sync.aligned.m16n8k16.row.col.f32.f16.f16.f32 "
        "{%0,%1,%2,%3}, {%4,%5,%6,%7}, {%8,%9}, {%0,%1,%2,%3};"
        : "+f"(c[0]), "+f"(c[1]), "+f"(c[2]), "+f"(c[3])
        : "r"(a[0]), "r"(a[1]), "r"(a[2]), "r"(a[3]), "r"(b0), "r"(b1));
}

__device__ __forceinline__ void ldsm4(uint32_t* r, uint32_t addr) {
    asm volatile("ldmatrix.sync.aligned.m8n8.x4.shared.b16 {%0,%1,%2,%3}, [%4];"
                 : "=r"(r[0]), "=r"(r[1]), "=r"(r[2]), "=r"(r[3]) : "r"(addr));
}

__device__ __forceinline__ void cpa16(uint32_t dst, const void* src, bool pred) {
    int sz = pred ? 16 : 0;
    asm volatile("cp.async.cg.shared.global [%0], [%1], 16, %2;\n"
                 :: "r"(dst), "l"(src), "r"(sz));
}
__device__ __forceinline__ void cpa_commit() { asm volatile("cp.async.commit_group;\n"); }
__device__ __forceinline__ void cpa_wait1()  { asm volatile("cp.async.wait_group 1;\n"); }

__device__ __forceinline__ uint32_t smem_u32(const void* p) {
    uint32_t a;
    asm("{ .reg .u64 t; cvta.to.shared.u64 t, %1; cvt.u32.u64 %0, t; }" : "=r"(a) : "l"(p));
    return a;
}

// ---------------- tf32 tensor GEMM: 128x128 tile, cp.async 3-stage ----------------
// OUTH: store output as __half.
constexpr int PK = 20;
constexpr int PM = 136;
constexpr int ASTG = 2560;
constexpr int BSTG = 2560;
constexpr int SMEM_BYTES = (3 * ASTG + 3 * BSTG) * 4;   // 61440

template<int TA, int TB, int ACT, int EPI, int RND, int OUTH>
__global__ void __launch_bounds__(256, 2) tgemm_k(
    int M, int N, int K, float alpha,
    const float* __restrict__ A, int lda,
    const float* __restrict__ B, int ldb,
    float* __restrict__ C, int ldc,
    const float* __restrict__ bias,
    const float* __restrict__ dinv)
{
    extern __shared__ uint32_t sh[];

    const int bn = blockIdx.x, bm = blockIdx.y;
    const int m0 = bm * 128, n0 = bn * 128;

    const int tid  = threadIdx.x;
    const int lane = tid & 31, warp = tid >> 5;
    const int g = lane >> 2, th = lane & 3;
    const int wm = (warp >> 1) * 32;
    const int wn = (warp & 1) * 64;

    uint32_t sbase = smem_u32(sh);

    float acc[2][8][4];
#pragma unroll
    for (int i = 0; i < 2; i++)
#pragma unroll
        for (int j = 0; j < 8; j++)
#pragma unroll
            for (int l = 0; l < 4; l++) acc[i][j][l] = 0.f;

    const int KT = K >> 4;

    auto issue = [&](int kt, int stg) {
        uint32_t abase = sbase + (uint32_t)(stg * ASTG) * 4u;
#pragma unroll
        for (int it = 0; it < 2; it++) {
            int c = tid * 2 + it;
            if (TA == 0) {
                int row = c >> 2, kc = (c & 3) * 4;
                const float* src = A + (long long)(m0 + row) * lda + kt * 16 + kc;
                cpa16(abase + (uint32_t)(row * PK + kc) * 4u, src, (m0 + row) < M);
            } else {
                int kr = c >> 5, mc = (c & 31) * 4;
                const float* src = A + (long long)(kt * 16 + kr) * lda + m0 + mc;
                cpa16(abase + (uint32_t)(kr * PM + mc) * 4u, src, (m0 + mc) < M);
            }
        }
        uint32_t bbase = sbase + (uint32_t)(3 * ASTG + stg * BSTG) * 4u;
#pragma unroll
        for (int it = 0; it < 2; it++) {
            int c = tid * 2 + it;
            if (TB == 1) {
                int row = c >> 2, kc = (c & 3) * 4;
                const float* src = B + (long long)(n0 + row) * ldb + kt * 16 + kc;
                cpa16(bbase + (uint32_t)(row * PK + kc) * 4u, src, (n0 + row) < N);
            } else {
                int kr = c >> 5, nc = (c & 31) * 4;
                const float* src = B + (long long)(kt * 16 + kr) * ldb + n0 + nc;
                cpa16(bbase + (uint32_t)(kr * PM + nc) * 4u, src, (n0 + nc) < N);
            }
        }
    };

    auto mmaTile = [&](int stg) {
        const uint32_t* Ab = sh + stg * ASTG;
        const uint32_t* Bb = sh + 3 * ASTG + stg * BSTG;
#pragma unroll
        for (int s = 0; s < 2; s++) {
            const int k0 = s * 8;
            uint32_t a[2][4];
#pragma unroll
            for (int mt = 0; mt < 2; mt++) {
                int mrow = wm + mt * 16 + g;
                if (TA == 0) {
                    a[mt][0] = Ab[mrow * PK + k0 + th];
                    a[mt][1] = Ab[(mrow + 8) * PK + k0 + th];
                    a[mt][2] = Ab[mrow * PK + k0 + th + 4];
                    a[mt][3] = Ab[(mrow + 8) * PK + k0 + th + 4];
                } else {
                    a[mt][0] = Ab[(k0 + th) * PM + mrow];
                    a[mt][1] = Ab[(k0 + th) * PM + mrow + 8];
                    a[mt][2] = Ab[(k0 + th + 4) * PM + mrow];
                    a[mt][3] = Ab[(k0 + th + 4) * PM + mrow + 8];
                }
            }
#pragma unroll
            for (int nt = 0; nt < 8; nt++) {
                int nrow = wn + nt * 8 + g;
                uint32_t b0, b1;
                if (TB == 1) {
                    b0 = Bb[nrow * PK + k0 + th];
                    b1 = Bb[nrow * PK + k0 + th + 4];
                } else {
                    b0 = Bb[(k0 + th) * PM + nrow];
                    b1 = Bb[(k0 + th + 4) * PM + nrow];
                }
                mma_tf32(acc[0][nt], a[0], b0, b1);
                mma_tf32(acc[1][nt], a[1], b0, b1);
            }
        }
    };

    issue(0, 0); cpa_commit();
    if (KT > 1) issue(1, 1);
    cpa_commit();
    cpa_wait1();
    __syncthreads();

    for (int kt = 0; kt < KT; kt++) {
        int stg = kt % 3;
        if (kt + 2 < KT) issue(kt + 2, (kt + 2) % 3);
        cpa_commit();
        mmaTile(stg);
        cpa_wait1();
        __syncthreads();
    }

    __half* Ch = reinterpret_cast<__half*>(C);
#pragma unroll
    for (int mt = 0; mt < 2; mt++) {
#pragma unroll
        for (int nt = 0; nt < 8; nt++) {
#pragma unroll
            for (int e = 0; e < 4; e++) {
                int gm = m0 + wm + mt * 16 + g + (e >= 2 ? 8 : 0);
                int gn = n0 + wn + nt * 8 + 2 * th + (e & 1);
                if (gm >= M || gn >= N) continue;
                float v = alpha * acc[mt][nt][e];
                if (EPI == 1) v = dinv[gm] * v;
                if (bias)     v += bias[gn];
                if (ACT == 1) v = fmaxf(v, 0.f);
                if (ACT == 2) v = 0.5f * v * (1.f + erff(v * 0.70710678118654752f));
                if (RND)      v = rtf32(v);
                if (OUTH) Ch[(long long)gm * ldc + gn] = __float2half_rn(v);
                else      C[(long long)gm * ldc + gn] = v;
            }
        }
    }
}

// ---------------- fp16 gram: att[b] = 0.125 * F_b @ F_b^T (symmetric), ldmatrix frags ----------------
__global__ void __launch_bounds__(256, 2) hgram_k(const __half* __restrict__ F,
                                                  float* __restrict__ att)
{
    extern __shared__ uint32_t sh[];
    const int bn = blockIdx.x, bm = blockIdx.y, b = blockIdx.z;
    if (bm > bn) return;
    const int m0 = bm * 128, n0 = bn * 128;

    const int tid  = threadIdx.x;
    const int lane = tid & 31, warp = tid >> 5;
    const int g = lane >> 2, th = lane & 3;
    const int wm = (warp >> 1) * 32;
    const int wn = (warp & 1) * 64;
    const int r8 = lane & 7, sel = lane >> 3;   // ldmatrix addressing

    uint32_t sbase = smem_u32(sh);
    const __half* Fb = F + (long long)b * NN * KF;
    float* attb = att + (long long)b * NN * NN;

    float acc[2][8][4];
#pragma unroll
    for (int i = 0; i < 2; i++)
#pragma unroll
        for (int j = 0; j < 8; j++)
#pragma unroll
            for (int l = 0; l < 4; l++) acc[i][j][l] = 0.f;

    const int KT = KF / 32;

    auto issue = [&](int kt, int stg) {
        uint32_t abase = sbase + (uint32_t)(stg * ASTG) * 4u;
        uint32_t bbase = sbase + (uint32_t)(3 * ASTG + stg * BSTG) * 4u;
#pragma unroll
        for (int it = 0; it < 2; it++) {
            int c = tid * 2 + it;
            int row = c >> 2, kc = c & 3;
            const __half* srcA = Fb + (long long)(m0 + row) * KF + kt * 32 + kc * 8;
            cpa16(abase + (uint32_t)(row * PK + kc * 4) * 4u, srcA, (m0 + row) < NN);
            const __half* srcB = Fb + (long long)(n0 + row) * KF + kt * 32 + kc * 8;
            cpa16(bbase + (uint32_t)(row * PK + kc * 4) * 4u, srcB, (n0 + row) < NN);
        }
    };

    auto mmaTile = [&](int stg) {
        uint32_t abase = sbase + (uint32_t)(stg * ASTG) * 4u;
        uint32_t bbase = sbase + (uint32_t)(3 * ASTG + stg * BSTG) * 4u;
#pragma unroll
        for (int s = 0; s < 2; s++) {
            const int k0 = s * 8;                    // u32 offset of this k-step
            // A fragments: per mt one ldmatrix.x4 covers (m16 x k16)
            uint32_t a[2][4];
#pragma unroll
            for (int mt = 0; mt < 2; mt++) {
                int row = wm + mt * 16 + ((sel & 1) << 3) + r8;
                int ku  = k0 + ((sel & 2) << 1);     // mats 2,3 -> k+4 u32
                ldsm4(a[mt], abase + (uint32_t)(row * PK + ku) * 4u);
            }
            // B fragments: per 32-n group, one x4 for b0 (k0..7) and one for b1 (k8..15)
            uint32_t b0v[8], b1v[8];
#pragma unroll
            for (int g4 = 0; g4 < 2; g4++) {
                int row = wn + g4 * 32 + sel * 8 + r8;
                ldsm4(&b0v[g4 * 4], bbase + (uint32_t)(row * PK + k0) * 4u);
                ldsm4(&b1v[g4 * 4], bbase + (uint32_t)(row * PK + k0 + 4) * 4u);
            }
#pragma unroll
            for (int nt = 0; nt < 8; nt++) {
                mma_f16(acc[0][nt], a[0], b0v[nt], b1v[nt]);
                mma_f16(acc[1][nt], a[1], b0v[nt], b1v[nt]);
            }
        }
    };

    issue(0, 0); cpa_commit();
    if (KT > 1) issue(1, 1);
    cpa_commit();
    cpa_wait1();
    __syncthreads();

    for (int kt = 0; kt < KT; kt++) {
        int stg = kt % 3;
        if (kt + 2 < KT) issue(kt + 2, (kt + 2) % 3);
        cpa_commit();
        mmaTile(stg);
        cpa_wait1();
        __syncthreads();
    }

#pragma unroll
    for (int mt = 0; mt < 2; mt++) {
#pragma unroll
        for (int nt = 0; nt < 8; nt++) {
#pragma unroll
            for (int e = 0; e < 4; e++) {
                int gm = m0 + wm + mt * 16 + g + (e >= 2 ? 8 : 0);
                int gn = n0 + wn + nt * 8 + 2 * th + (e & 1);
                if (gm >= NN || gn >= NN) continue;
                float v = 0.125f * acc[mt][nt][e];
                attb[(long long)gm * NN + gn] = v;
                if (bm < bn) attb[(long long)gn * NN + gm] = v;
            }
        }
    }
}

// ---------------- tf32 round-copy ----------------
__global__ void round_copy_k(const float* __restrict__ src, float* __restrict__ dst, int n)
{
    int i = blockIdx.x * blockDim.x + threadIdx.x;
    if (i < n) dst[i] = rtf32(src[i]);
}

// ---------------- A-matrix builder, both views ----------------
__global__ void build_ag2_k(const float* __restrict__ x1, const float* __restrict__ x2,
                            const float* __restrict__ emb,
                            const float* __restrict__ gw, const float* __restrict__ gb,
                            float* __restrict__ Ag)
{
    long long idx = (long long)blockIdx.x * blockDim.x + threadIdx.x;
    if (idx >= MR2 * E_) return;
    int e = (int)(idx & (E_ - 1));
    long long r = idx >> 9;
    long long rv = (r < MR) ? r : r - MR;
    const float* x = (r < MR) ? x1 : x2;
    int n = (int)(rv % NN);
    float t = fmaf(x[rv], gw[e], gb[e]);
    float sgm = 1.0f / (1.0f + expf(-t));
    Ag[idx] = rtf32(sgm * emb[(long long)n * E_ + e]);
}

// ---------------- concat gl_w ----------------
__global__ void build_glw_k(const float* __restrict__ glw, float* __restrict__ GLW)
{
    int idx = blockIdx.x * blockDim.x + threadIdx.x;
    if (idx >= D_ * KF) return;
    int k = idx / KF, c = idx % KF;
    int p = c >> 9, hh = c & 511;
    GLW[idx] = rtf32(glw[((long long)p * D_ + k) * HD + hh]);
}

// ---------------- top-k(50) -> row-compressed softmax output ----------------
__global__ void __launch_bounds__(256) topk_rows_k(
    const float* __restrict__ att,
    float* __restrict__ rowval, int* __restrict__ rowcol, int* __restrict__ rowcnt)
{
    __shared__ float s[2000];
    __shared__ int   hist[256];
    __shared__ float wredf[8];
    __shared__ float s_bcast;
    __shared__ int   s_selb, s_selk, s_pos;

    long long row = blockIdx.x;
    const float* r = att + row * 2000;
    int tid = threadIdx.x;
    int lane = tid & 31, wid = tid >> 5;

    for (int i = tid; i < 2000; i += 256) s[i] = r[i];
    if (tid == 0) s_pos = 0;
    __syncthreads();

    float mx = 0.f;
    for (int i = tid; i < 2000; i += 256) mx = fmaxf(mx, s[i]);
#pragma unroll
    for (int o = 16; o; o >>= 1) mx = fmaxf(mx, __shfl_xor_sync(0xffffffffu, mx, o));
    if (lane == 0) wredf[wid] = mx;
    __syncthreads();
    if (tid == 0) { float m = wredf[0]; for (int w = 1; w < 8; w++) m = fmaxf(m, wredf[w]); s_bcast = m; }
    __syncthreads();
    mx = s_bcast;

    unsigned prefix = 0u;
    int k = 50;
#pragma unroll
    for (int pass = 0; pass < 4; pass++) {
        const int shift = 24 - 8 * pass;
        const unsigned hmask = (pass == 0) ? 0u : (0xFFFFFFFFu << (shift + 8));
        if (tid < 256) hist[tid] = 0;
        __syncthreads();
        for (int i = tid; i < 2000; i += 256) {
            unsigned u = __float_as_uint(s[i]);
            if ((u & hmask) == prefix)
                atomicAdd(&hist[(u >> shift) & 255], 1);
        }
        __syncthreads();
        if (tid == 0) {
            int acc = 0, b = 255;
            for (; b > 0; b--) { acc += hist[b]; if (acc >= k) break; }
            if (acc < k) acc += hist[0];
            s_selb = b;
            s_selk = k - (acc - hist[b]);
        }
        __syncthreads();
        prefix |= ((unsigned)s_selb) << shift;
        k = s_selk;
        __syncthreads();
    }
    float thr = __uint_as_float(prefix);

    float sum = 0.f;
    for (int i = tid; i < 2000; i += 256) {
        float v = s[i];
        if (v >= thr) sum += expf(v - mx);
    }
#pragma unroll
    for (int o = 16; o; o >>= 1) sum += __shfl_xor_sync(0xffffffffu, sum, o);
    if (lane == 0) wredf[wid] = sum;
    __syncthreads();
    if (tid == 0) { float t = 0.f; for (int w = 0; w < 8; w++) t += wredf[w]; s_bcast = t; }
    __syncthreads();
    float inv = 1.0f / s_bcast;

    for (int i = tid; i < 2000; i += 256) {
        float v = s[i];
        if (v >= thr) {
            int p = atomicAdd(&s_pos, 1);
            if (p < ROWCAP) {
                rowval[row * ROWCAP + p] = expf(v - mx) * inv;
                rowcol[row * ROWCAP + p] = i;
            }
        }
    }
    __syncthreads();
    if (tid == 0) rowcnt[row] = min(s_pos, ROWCAP);
}

// ---------------- zero int/float arrays ----------------
__global__ void zero_k(int* __restrict__ a, float* __restrict__ b, int n)
{
    int i = blockIdx.x * blockDim.x + threadIdx.x;
    if (i < n) { a[i] = 0; b[i] = 0.f; }
}

// ---------------- count column occupancy ----------------
__global__ void count_k(const int* __restrict__ rowcol, const int* __restrict__ rowcnt,
                        int* __restrict__ colcnt)
{
    int row = blockIdx.x;
    int b = row / NN;
    int cnt = rowcnt[row];
    if (threadIdx.x < cnt)
        atomicAdd(&colcnt[b * NN + rowcol[row * ROWCAP + threadIdx.x]], 1);
}

// ---------------- per-batch exclusive scan ----------------
__global__ void __launch_bounds__(256) scan_k(const int* __restrict__ colcnt,
                                              int* __restrict__ coloff, int* __restrict__ colcur)
{
    __shared__ int tsum[257];
    int b = blockIdx.x, tid = threadIdx.x;
    const int* cnt = colcnt + b * NN;
    int local[8];
    int tot = 0;
#pragma unroll
    for (int e = 0; e < 8; e++) {
        int i = tid * 8 + e;
        local[e] = tot;
        tot += (i < NN) ? cnt[i] : 0;
    }
    tsum[tid] = tot;
    __syncthreads();
    if (tid == 0) {
        int acc = 0;
        for (int t = 0; t < 256; t++) { int v = tsum[t]; tsum[t] = acc; acc += v; }
    }
    __syncthreads();
    int base = tsum[tid];
#pragma unroll
    for (int e = 0; e < 8; e++) {
        int i = tid * 8 + e;
        if (i < NN) {
            coloff[b * NN + i] = base + local[e];
            colcur[b * NN + i] = base + local[e];
        }
    }
}

// ---------------- place into CSC ----------------
__global__ void place_k(const float* __restrict__ rowval, const int* __restrict__ rowcol,
                        const int* __restrict__ rowcnt,
                        int* __restrict__ colcur, float* __restrict__ colsum,
                        float* __restrict__ cscval, int* __restrict__ cscrow)
{
    int row = blockIdx.x;
    int b = row / NN, j = row % NN;
    int cnt = rowcnt[row];
    int e = threadIdx.x;
    if (e < cnt) {
        int   c = rowcol[row * ROWCAP + e];
        float w = rowval[row * ROWCAP + e];
        int pos = atomicAdd(&colcur[b * NN + c], 1);
        cscval[(long long)b * CAP + pos] = w;
        cscrow[(long long)b * CAP + pos] = j;
        atomicAdd(&colsum[b * NN + c], w);
    }
}

// ---------------- dinv ----------------
__global__ void dinv_k(const float* __restrict__ colsum, float* __restrict__ dinv, int n)
{
    int i = blockIdx.x * blockDim.x + threadIdx.x;
    if (i < n) dinv[i] = rsqrtf(1.0f + colsum[i]);
}

// ---------------- sparse GCN aggregation, T in fp16 ----------------
template<int DIM, int ACT, int RND>
__global__ void spagg_k(
    const float* __restrict__ cscval, const int* __restrict__ cscrow,
    const int* __restrict__ coloff, const int* __restrict__ colcnt,
    const __half* __restrict__ T, const float* __restrict__ dinv,
    const float* __restrict__ bias, float* __restrict__ out)
{
    __shared__ float sw[256];
    __shared__ int   sj[256];
    int i = blockIdx.x, b = blockIdx.y, tid = threadIdx.x;
    const __half* Tb = T + (long long)b * NN * DIM;
    int s0  = coloff[b * NN + i];
    int cnt = colcnt[b * NN + i];
    long long base = (long long)b * CAP + s0;

    float2 acc = __half22float2(*reinterpret_cast<const __half2*>(&Tb[(long long)i * DIM + 2 * tid]));
    float2 acc2 = make_float2(0.f, 0.f);

    for (int e0 = 0; e0 < cnt; e0 += blockDim.x) {
        int chunk = min(cnt - e0, (int)blockDim.x);
        if (tid < chunk) {
            sw[tid] = cscval[base + e0 + tid];
            sj[tid] = cscrow[base + e0 + tid];
        }
        __syncthreads();
        int e = 0;
        for (; e + 1 < chunk; e += 2) {
            float2 t0 = __half22float2(*reinterpret_cast<const __half2*>(&Tb[(long long)sj[e]   * DIM + 2 * tid]));
            float2 t1 = __half22float2(*reinterpret_cast<const __half2*>(&Tb[(long long)sj[e+1] * DIM + 2 * tid]));
            acc.x  = fmaf(sw[e],   t0.x, acc.x);
            acc.y  = fmaf(sw[e],   t0.y, acc.y);
            acc2.x = fmaf(sw[e+1], t1.x, acc2.x);
            acc2.y = fmaf(sw[e+1], t1.y, acc2.y);
        }
        if (e < chunk) {
            float2 t0 = __half22float2(*reinterpret_cast<const __half2*>(&Tb[(long long)sj[e] * DIM + 2 * tid]));
            acc.x = fmaf(sw[e], t0.x, acc.x);
            acc.y = fmaf(sw[e], t0.y, acc.y);
        }
        __syncthreads();
    }
    float dv = dinv[b * NN + i];
    float vx = dv * (acc.x + acc2.x) + bias[2 * tid];
    float vy = dv * (acc.y + acc2.y) + bias[2 * tid + 1];
    if (ACT == 1) { vx = fmaxf(vx, 0.f); vy = fmaxf(vy, 0.f); }
    if (RND)      { vx = rtf32(vx);      vy = rtf32(vy); }
    *reinterpret_cast<float2*>(&out[((long long)b * NN + i) * DIM + 2 * tid]) = make_float2(vx, vy);
}

// ---------------- mean over nodes; mu/std/z, all 16 batches ----------------
__global__ void meanz2_k(const float* __restrict__ O3,
                         const float* __restrict__ eps1, const float* __restrict__ eps2,
                         float* __restrict__ mu1, float* __restrict__ std1,
                         float* __restrict__ mu2, float* __restrict__ std2,
                         float* __restrict__ z)
{
    int b = blockIdx.x, d = threadIdx.x;
    const float* p = O3 + ((long long)b * 2000) * 128 + d;
    float s0 = 0.f, s1 = 0.f, s2 = 0.f, s3 = 0.f;
    for (int i = 0; i < 2000; i += 4) {
        s0 += p[(long long)i * 128];
        s1 += p[(long long)(i + 1) * 128];
        s2 += p[(long long)(i + 2) * 128];
        s3 += p[(long long)(i + 3) * 128];
    }
    __shared__ float sg[128];
    sg[d] = ((s0 + s1) + (s2 + s3)) / 2000.0f;
    __syncthreads();
    if (d < 64) {
        int view = b >> 3, bb = b & 7;
        const float* eps = view ? eps2 : eps1;
        float* mu = view ? mu2 : mu1;
        float* sd = view ? std2 : std1;
        float m = sg[d];
        float sp = log1pf(expf(sg[64 + d] - 64.0f));
        mu[bb * 64 + d] = m;
        sd[bb * 64 + d] = sp;
        z[b * 64 + d] = fmaf(eps[bb * 64 + d], sp, m);
    }
}

// ---------------- decoder ----------------
__global__ void __launch_bounds__(256) decode_k(
    const float* __restrict__ z, const float* __restrict__ w1, const float* __restrict__ b1,
    const float* __restrict__ gamma, const float* __restrict__ beta,
    const float* __restrict__ w2, const float* __restrict__ b2,
    float* __restrict__ xrec)
{
    __shared__ float h[1024];
    __shared__ float zs[64];
    int b = blockIdx.x, tid = threadIdx.x;
    if (tid < 64) zs[tid] = z[b * 64 + tid];
    __syncthreads();
    const float invc = 1.0f / sqrtf(1.0f + 1e-5f);
    for (int c = tid; c < 1024; c += 256) {
        float a = b1[c];
#pragma unroll 8
        for (int k = 0; k < 64; k++) a = fmaf(zs[k], w1[k * 1024 + c], a);
        a = a * (gamma[c] * invc) + beta[c];
        h[c] = fmaxf(a, 0.f);
    }
    __syncthreads();
    int c0 = blockIdx.y * 250;
    int c1 = min(c0 + 250, 2000);
    for (int c = c0 + tid; c < c1; c += 256) {
        float a = b2[c];
        for (int k = 0; k < 1024; k++) a = fmaf(h[k], w2[k * 2000 + c], a);
        xrec[b * 2000 + c] = fmaxf(a, 0.f);
    }
}

// ---------------- host orchestration ----------------
extern "C" void kernel_launch(void* const* d_in, const int* in_sizes, int n_in,
                              void* d_out, int out_size)
{
    const float* x1     = (const float*)d_in[0];
    const float* x2     = (const float*)d_in[1];
    const float* emb1   = (const float*)d_in[2];
    const float* gate_w = (const float*)d_in[3];
    const float* gate_b = (const float*)d_in[4];
    const float* enc_w1 = (const float*)d_in[5];
    const float* enc_b1 = (const float*)d_in[6];
    const float* enc_w2 = (const float*)d_in[7];
    const float* enc_b2 = (const float*)d_in[8];
    const float* gl_w   = (const float*)d_in[9];
    const float* g_w1   = (const float*)d_in[10];
    const float* g_b1   = (const float*)d_in[11];
    const float* g_w2   = (const float*)d_in[12];
    const float* g_b2   = (const float*)d_in[13];
    const float* g_w3   = (const float*)d_in[14];
    const float* g_b3   = (const float*)d_in[15];
    const float* dW1[2] = {(const float*)d_in[16], (const float*)d_in[22]};
    const float* dB1[2] = {(const float*)d_in[17], (const float*)d_in[23]};
    const float* dG [2] = {(const float*)d_in[18], (const float*)d_in[24]};
    const float* dBe[2] = {(const float*)d_in[19], (const float*)d_in[25]};
    const float* dW2[2] = {(const float*)d_in[20], (const float*)d_in[26]};
    const float* dB2[2] = {(const float*)d_in[21], (const float*)d_in[27]};
    const float* epsA[2]= {(const float*)d_in[28], (const float*)d_in[29]};

    static bool attr_done = false;
    if (!attr_done) {
        cudaFuncSetAttribute(tgemm_k<0,0,2,0,1,0>, cudaFuncAttributeMaxDynamicSharedMemorySize, SMEM_BYTES);
        cudaFuncSetAttribute(tgemm_k<0,0,0,0,1,0>, cudaFuncAttributeMaxDynamicSharedMemorySize, SMEM_BYTES);
        cudaFuncSetAttribute(tgemm_k<0,0,1,0,0,1>, cudaFuncAttributeMaxDynamicSharedMemorySize, SMEM_BYTES);
        cudaFuncSetAttribute(tgemm_k<0,0,0,1,0,1>, cudaFuncAttributeMaxDynamicSharedMemorySize, SMEM_BYTES);
        cudaFuncSetAttribute(hgram_k, cudaFuncAttributeMaxDynamicSharedMemorySize, SMEM_BYTES);
        attr_done = true;
    }

    float* sc = nullptr;
    cudaGetSymbolAddress((void**)&sc, g_scratch);
    float* Ag   = sc + OFF_AG;
    float* Henc = sc + OFF_HENC;
    float* H    = sc + OFF_H;
    float* GLW  = sc + OFF_GLW;
    float* Fh_f = sc + OFF_FH;
    __half* Fh  = reinterpret_cast<__half*>(Fh_f);
    float* att  = sc + OFF_ATT;
    float* dinv = sc + OFF_DINV;
    float* Th_f = sc + OFF_TH;
    __half* Th  = reinterpret_cast<__half*>(Th_f);
    float* O1   = sc + OFF_O1;
    float* O2   = sc + OFF_O2;
    float* O3   = sc + OFF_O3;
    float* zb   = sc + OFF_Z;
    float* W1r  = sc + OFF_W1;
    float* W2r  = sc + OFF_W2;
    float* GW1r = sc + OFF_GW1;
    float* GW2r = sc + OFF_GW2;
    float* GW3r = sc + OFF_GW3;
    float* rowval = sc + OFF_ROWV;
    int*   rowcol = (int*)(sc + OFF_ROWC);
    int*   rowcnt = (int*)(sc + OFF_RCNT);
    int*   colcnt = (int*)(sc + OFF_CCNT);
    int*   coloff = (int*)(sc + OFF_COFF);
    int*   colcur = (int*)(sc + OFF_CCUR);
    float* colsum = sc + OFF_CSUM;
    float* cscval = sc + OFF_CSCV;
    int*   cscrow = (int*)(sc + OFF_CSCR);

    float* out = (float*)d_out;
    float* xrec[2] = {out,          out + 16000};
    float* muo [2] = {out + 32000,  out + 33024};
    float* stdo[2] = {out + 32512,  out + 33536};

    round_copy_k<<<(int)((SZ_W1  + 255) / 256), 256>>>(enc_w1, W1r,  (int)SZ_W1);
    round_copy_k<<<(int)((SZ_W2  + 255) / 256), 256>>>(enc_w2, W2r,  (int)SZ_W2);
    round_copy_k<<<(int)((SZ_GW1 + 255) / 256), 256>>>(g_w1,   GW1r, (int)SZ_GW1);
    round_copy_k<<<(int)((SZ_GW2 + 255) / 256), 256>>>(g_w2,   GW2r, (int)SZ_GW2);
    round_copy_k<<<(int)((SZ_GW3 + 255) / 256), 256>>>(g_w3,   GW3r, (int)SZ_GW3);
    build_glw_k<<<(D_ * KF + 255) / 256, 256>>>(gl_w, GLW);

    // ---- encoders, both views batched (M = 32000) ----
    build_ag2_k<<<(unsigned)((MR2 * E_ + 255) / 256), 256>>>(x1, x2, emb1, gate_w, gate_b, Ag);
    tgemm_k<0,0,2,0,1,0><<<dim3(HEN / 128, 250), 256, SMEM_BYTES>>>(
        (int)MR2, HEN, E_, 1.f, Ag, E_, W1r, HEN, Henc, HEN, enc_b1, nullptr);
    tgemm_k<0,0,0,0,1,0><<<dim3(1, 250), 256, SMEM_BYTES>>>(
        (int)MR2, D_, HEN, 1.f, Henc, HEN, W2r, D_, H, D_, enc_b2, nullptr);

    // ---- F = relu(H @ GLW) -> half, both views ----
    tgemm_k<0,0,1,0,0,1><<<dim3(KF / 128, 250), 256, SMEM_BYTES>>>(
        (int)MR2, KF, D_, 1.f, H, D_, GLW, KF, Fh_f, KF, nullptr, nullptr);

    // ---- gram for all 16 batches (fp16 mma + ldmatrix) ----
    hgram_k<<<dim3(16, 16, B2), 256, SMEM_BYTES>>>(Fh, att);

    // ---- sparse adjacency pipeline, 16 batches ----
    zero_k<<<(int)((MR2 + 255) / 256), 256>>>(colcnt, colsum, (int)MR2);
    topk_rows_k<<<(unsigned)MR2, 256>>>(att, rowval, rowcol, rowcnt);
    count_k<<<(unsigned)MR2, ROWCAP>>>(rowcol, rowcnt, colcnt);
    scan_k<<<B2, 256>>>(colcnt, coloff, colcur);
    place_k<<<(unsigned)MR2, ROWCAP>>>(rowval, rowcol, rowcnt, colcur, colsum, cscval, cscrow);
    dinv_k<<<(int)((MR2 + 255) / 256), 256>>>(colsum, dinv, (int)MR2);

    // ---- GCN layers, 16 batches ----
    tgemm_k<0,0,0,1,0,1><<<dim3(HD / 128, 250), 256, SMEM_BYTES>>>(
        (int)MR2, HD, D_, 1.f, H, D_, GW1r, HD, Th_f, HD, nullptr, dinv);
    spagg_k<HD,1,1><<<dim3(NN, B2), HD/2>>>(cscval, cscrow, coloff, colcnt, Th, dinv, g_b1, O1);
    tgemm_k<0,0,0,1,0,1><<<dim3(HD / 128, 250), 256, SMEM_BYTES>>>(
        (int)MR2, HD, HD, 1.f, O1, HD, GW2r, HD, Th_f, HD, nullptr, dinv);
    spagg_k<HD,1,1><<<dim3(NN, B2), HD/2>>>(cscval, cscrow, coloff, colcnt, Th, dinv, g_b2, O2);
    tgemm_k<0,0,0,1,0,1><<<dim3(1, 250), 256, SMEM_BYTES>>>(
        (int)MR2, D_, HD, 1.f, O2, HD, GW3r, D_, Th_f, D_, nullptr, dinv);
    spagg_k<D_,0,0><<<dim3(NN, B2), D_/2>>>(cscval, cscrow, coloff, colcnt, Th, dinv, g_b3, O3);

    // ---- VIB head + decoders ----
    meanz2_k<<<B2, 128>>>(O3, epsA[0], epsA[1], muo[0], stdo[0], muo[1], stdo[1], zb);
    decode_k<<<dim3(8, 8), 256>>>(zb,       dW1[0], dB1[0], dG[0], dBe[0], dW2[0], dB2[0], xrec[0]);
    decode_k<<<dim3(8, 8), 256>>>(zb + 512, dW1[1], dB1[1], dG[1], dBe[1], dW2[1], dB2[1], xrec[1]);
}

// round 11
// speedup vs baseline: 3.6063x; 1.1729x over previous
#include <cuda_runtime.h>
#include <cuda_fp16.h>
#include <math.h>
#include <stdint.h>

// ---------------- problem constants ----------------
constexpr int B_  = 8;
constexpr int B2  = 16;
constexpr int NN  = 2000;
constexpr int E_  = 512;
constexpr int HEN = 1024;
constexpr int D_  = 128;
constexpr int HD  = 512;
constexpr int KF  = 4096;
constexpr int IB_ = 64;
constexpr long long MR  = (long long)B_ * NN;
constexpr long long MR2 = (long long)B2 * NN;   // 32000

constexpr int ROWCAP = 64;
constexpr int CAP    = 131072;

// ---------------- scratch layout (units: float slots; halves use /2) ----------------
constexpr long long SZ_AGH  = MR2 * E_ / 2;
constexpr long long SZ_HENH = MR2 * HEN / 2;
constexpr long long SZ_HH   = MR2 * D_ / 2;
constexpr long long SZ_GLWT = (long long)KF * D_ / 2;     // half [KF, D]
constexpr long long SZ_FH   = MR2 * KF / 2;
constexpr long long SZ_ATT  = (long long)B2 * NN * NN;
constexpr long long SZ_DINV = MR2;
constexpr long long SZ_TH   = MR2 * HD / 2;
constexpr long long SZ_OH   = MR2 * HD / 2;               // O1/O2 half
constexpr long long SZ_O3   = MR2 * D_;
constexpr long long SZ_Z    = (long long)B2 * IB_;
constexpr long long SZ_W1T  = (long long)HEN * E_ / 2;    // half [HEN, E]
constexpr long long SZ_W2T  = (long long)D_ * HEN / 2;    // half [D, HEN]
constexpr long long SZ_GW1T = (long long)HD * D_ / 2;
constexpr long long SZ_GW2T = (long long)HD * HD / 2;
constexpr long long SZ_GW3T = (long long)D_ * HD / 2;
constexpr long long SZ_ROWV = MR2 * ROWCAP;
constexpr long long SZ_ROWC = MR2 * ROWCAP;
constexpr long long SZ_RCNT = MR2;
constexpr long long SZ_CCNT = MR2;
constexpr long long SZ_COFF = MR2;
constexpr long long SZ_CCUR = MR2;
constexpr long long SZ_CSUM = MR2;
constexpr long long SZ_CSCV = (long long)B2 * CAP;
constexpr long long SZ_CSCR = (long long)B2 * CAP;

constexpr long long OFF_AGH  = 0;
constexpr long long OFF_HENH = OFF_AGH + SZ_AGH;
constexpr long long OFF_HH   = OFF_HENH + SZ_HENH;
constexpr long long OFF_GLWT = OFF_HH + SZ_HH;
constexpr long long OFF_FH   = OFF_GLWT + SZ_GLWT;
constexpr long long OFF_ATT  = OFF_FH + SZ_FH;
constexpr long long OFF_DINV = OFF_ATT + SZ_ATT;
constexpr long long OFF_TH   = OFF_DINV + SZ_DINV;
constexpr long long OFF_O1H  = OFF_TH + SZ_TH;
constexpr long long OFF_O2H  = OFF_O1H + SZ_OH;
constexpr long long OFF_O3   = OFF_O2H + SZ_OH;
constexpr long long OFF_Z    = OFF_O3 + SZ_O3;
constexpr long long OFF_W1T  = OFF_Z + SZ_Z;
constexpr long long OFF_W2T  = OFF_W1T + SZ_W1T;
constexpr long long OFF_GW1T = OFF_W2T + SZ_W2T;
constexpr long long OFF_GW2T = OFF_GW1T + SZ_GW1T;
constexpr long long OFF_GW3T = OFF_GW2T + SZ_GW2T;
constexpr long long OFF_ROWV = OFF_GW3T + SZ_GW3T;
constexpr long long OFF_ROWC = OFF_ROWV + SZ_ROWV;
constexpr long long OFF_RCNT = OFF_ROWC + SZ_ROWC;
constexpr long long OFF_CCNT = OFF_RCNT + SZ_RCNT;
constexpr long long OFF_COFF = OFF_CCNT + SZ_CCNT;
constexpr long long OFF_CCUR = OFF_COFF + SZ_COFF;
constexpr long long OFF_CSUM = OFF_CCUR + SZ_CCUR;
constexpr long long OFF_CSCV = OFF_CSUM + SZ_CSUM;
constexpr long long OFF_CSCR = OFF_CSCV + SZ_CSCV;
constexpr long long SCRATCH_TOTAL = OFF_CSCR + SZ_CSCR;

__device__ float g_scratch[SCRATCH_TOTAL];

// ---------------- helpers ----------------
__device__ __forceinline__ void mma_f16(float* c, const uint32_t* a, uint32_t b0, uint32_t b1) {
    asm volatile(
        "mma.sync.aligned.m16n8k16.row.col.f32.f16.f16.f32 "
        "{%0,%1,%2,%3}, {%4,%5,%6,%7}, {%8,%9}, {%0,%1,%2,%3};"
        : "+f"(c[0]), "+f"(c[1]), "+f"(c[2]), "+f"(c[3])
        : "r"(a[0]), "r"(a[1]), "r"(a[2]), "r"(a[3]), "r"(b0), "r"(b1));
}

__device__ __forceinline__ void ldsm4(uint32_t* r, uint32_t addr) {
    asm volatile("ldmatrix.sync.aligned.m8n8.x4.shared.b16 {%0,%1,%2,%3}, [%4];"
                 : "=r"(r[0]), "=r"(r[1]), "=r"(r[2]), "=r"(r[3]) : "r"(addr));
}

__device__ __forceinline__ void cpa16(uint32_t dst, const void* src, bool pred) {
    int sz = pred ? 16 : 0;
    asm volatile("cp.async.cg.shared.global [%0], [%1], 16, %2;\n"
                 :: "r"(dst), "l"(src), "r"(sz));
}
__device__ __forceinline__ void cpa_commit() { asm volatile("cp.async.commit_group;\n"); }
__device__ __forceinline__ void cpa_wait1()  { asm volatile("cp.async.wait_group 1;\n"); }

__device__ __forceinline__ uint32_t smem_u32(const void* p) {
    uint32_t a;
    asm("{ .reg .u64 t; cvta.to.shared.u64 t, %1; cvt.u32.u64 %0, t; }" : "=r"(a) : "l"(p));
    return a;
}

constexpr int PK = 20;          // u32 row stride in smem (conflict-free, 16B aligned)
constexpr int ASTG = 2560;
constexpr int BSTG = 2560;
constexpr int SMEM_BYTES = (3 * ASTG + 3 * BSTG) * 4;   // 61440

// ================= unified fp16 GEMM: C = act(epi(A @ Bt^T) + bias) =================
// A: half [M, K] row-major. Bt: half [N, K] row-major. k-tile 32 halves.
// ACT: 0 none, 1 relu, 2 gelu. EPI: 0 none, 1 dinv[m] scale. OUTH: 1 -> half C.
template<int ACT, int EPI, int OUTH>
__global__ void __launch_bounds__(256, 2) hgemm_k(
    int M, int N, int K,
    const __half* __restrict__ A,
    const __half* __restrict__ Bt,
    void* __restrict__ C, int ldc,
    const float* __restrict__ bias,
    const float* __restrict__ dinv)
{
    extern __shared__ uint32_t sh[];
    const int bn = blockIdx.x, bm = blockIdx.y;
    const int m0 = bm * 128, n0 = bn * 128;

    const int tid  = threadIdx.x;
    const int lane = tid & 31, warp = tid >> 5;
    const int g = lane >> 2, th = lane & 3;
    const int wm = (warp >> 1) * 32;
    const int wn = (warp & 1) * 64;
    const int r8 = lane & 7, sel = lane >> 3;

    uint32_t sbase = smem_u32(sh);

    float acc[2][8][4];
#pragma unroll
    for (int i = 0; i < 2; i++)
#pragma unroll
        for (int j = 0; j < 8; j++)
#pragma unroll
            for (int l = 0; l < 4; l++) acc[i][j][l] = 0.f;

    const int KT = K / 32;

    auto issue = [&](int kt, int stg) {
        uint32_t abase = sbase + (uint32_t)(stg * ASTG) * 4u;
        uint32_t bbase = sbase + (uint32_t)(3 * ASTG + stg * BSTG) * 4u;
#pragma unroll
        for (int it = 0; it < 2; it++) {
            int c = tid * 2 + it;
            int row = c >> 2, kc = c & 3;
            const __half* srcA = A + (long long)(m0 + row) * K + kt * 32 + kc * 8;
            cpa16(abase + (uint32_t)(row * PK + kc * 4) * 4u, srcA, (m0 + row) < M);
            const __half* srcB = Bt + (long long)(n0 + row) * K + kt * 32 + kc * 8;
            cpa16(bbase + (uint32_t)(row * PK + kc * 4) * 4u, srcB, (n0 + row) < N);
        }
    };

    auto mmaTile = [&](int stg) {
        uint32_t abase = sbase + (uint32_t)(stg * ASTG) * 4u;
        uint32_t bbase = sbase + (uint32_t)(3 * ASTG + stg * BSTG) * 4u;
#pragma unroll
        for (int s = 0; s < 2; s++) {
            const int k0 = s * 8;
            uint32_t a[2][4];
#pragma unroll
            for (int mt = 0; mt < 2; mt++) {
                int row = wm + mt * 16 + ((sel & 1) << 3) + r8;
                int ku  = k0 + ((sel & 2) << 1);
                ldsm4(a[mt], abase + (uint32_t)(row * PK + ku) * 4u);
            }
            uint32_t b0v[8], b1v[8];
#pragma unroll
            for (int g4 = 0; g4 < 2; g4++) {
                int row = wn + g4 * 32 + sel * 8 + r8;
                ldsm4(&b0v[g4 * 4], bbase + (uint32_t)(row * PK + k0) * 4u);
                ldsm4(&b1v[g4 * 4], bbase + (uint32_t)(row * PK + k0 + 4) * 4u);
            }
#pragma unroll
            for (int nt = 0; nt < 8; nt++) {
                mma_f16(acc[0][nt], a[0], b0v[nt], b1v[nt]);
                mma_f16(acc[1][nt], a[1], b0v[nt], b1v[nt]);
            }
        }
    };

    issue(0, 0); cpa_commit();
    if (KT > 1) issue(1, 1);
    cpa_commit();
    cpa_wait1();
    __syncthreads();

    for (int kt = 0; kt < KT; kt++) {
        int stg = kt % 3;
        if (kt + 2 < KT) issue(kt + 2, (kt + 2) % 3);
        cpa_commit();
        mmaTile(stg);
        cpa_wait1();
        __syncthreads();
    }

    __half* Ch = (__half*)C;
    float*  Cf = (float*)C;
#pragma unroll
    for (int mt = 0; mt < 2; mt++) {
#pragma unroll
        for (int nt = 0; nt < 8; nt++) {
#pragma unroll
            for (int eh = 0; eh < 2; eh++) {        // eh: 0 -> (e0,e1), 1 -> (e2,e3)
                int gm = m0 + wm + mt * 16 + g + (eh ? 8 : 0);
                int gn = n0 + wn + nt * 8 + 2 * th;
                if (gm >= M || gn >= N) continue;
                float v0 = acc[mt][nt][eh * 2 + 0];
                float v1 = acc[mt][nt][eh * 2 + 1];
                if (EPI == 1) { float dv = dinv[gm]; v0 *= dv; v1 *= dv; }
                if (bias)     { v0 += bias[gn]; v1 += bias[gn + 1]; }
                if (ACT == 1) { v0 = fmaxf(v0, 0.f); v1 = fmaxf(v1, 0.f); }
                if (ACT == 2) {
                    v0 = 0.5f * v0 * (1.f + erff(v0 * 0.70710678118654752f));
                    v1 = 0.5f * v1 * (1.f + erff(v1 * 0.70710678118654752f));
                }
                if (OUTH) {
                    *reinterpret_cast<__half2*>(&Ch[(long long)gm * ldc + gn]) =
                        __floats2half2_rn(v0, v1);
                } else {
                    Cf[(long long)gm * ldc + gn]     = v0;
                    Cf[(long long)gm * ldc + gn + 1] = v1;
                }
            }
        }
    }
}

// ---------------- fp16 gram: att[b] = 0.125 * F_b @ F_b^T (symmetric), ldmatrix ----------------
__global__ void __launch_bounds__(256, 2) hgram_k(const __half* __restrict__ F,
                                                  float* __restrict__ att)
{
    extern __shared__ uint32_t sh[];
    const int bn = blockIdx.x, bm = blockIdx.y, b = blockIdx.z;
    if (bm > bn) return;
    const int m0 = bm * 128, n0 = bn * 128;

    const int tid  = threadIdx.x;
    const int lane = tid & 31, warp = tid >> 5;
    const int g = lane >> 2, th = lane & 3;
    const int wm = (warp >> 1) * 32;
    const int wn = (warp & 1) * 64;
    const int r8 = lane & 7, sel = lane >> 3;

    uint32_t sbase = smem_u32(sh);
    const __half* Fb = F + (long long)b * NN * KF;
    float* attb = att + (long long)b * NN * NN;

    float acc[2][8][4];
#pragma unroll
    for (int i = 0; i < 2; i++)
#pragma unroll
        for (int j = 0; j < 8; j++)
#pragma unroll
            for (int l = 0; l < 4; l++) acc[i][j][l] = 0.f;

    const int KT = KF / 32;

    auto issue = [&](int kt, int stg) {
        uint32_t abase = sbase + (uint32_t)(stg * ASTG) * 4u;
        uint32_t bbase = sbase + (uint32_t)(3 * ASTG + stg * BSTG) * 4u;
#pragma unroll
        for (int it = 0; it < 2; it++) {
            int c = tid * 2 + it;
            int row = c >> 2, kc = c & 3;
            const __half* srcA = Fb + (long long)(m0 + row) * KF + kt * 32 + kc * 8;
            cpa16(abase + (uint32_t)(row * PK + kc * 4) * 4u, srcA, (m0 + row) < NN);
            const __half* srcB = Fb + (long long)(n0 + row) * KF + kt * 32 + kc * 8;
            cpa16(bbase + (uint32_t)(row * PK + kc * 4) * 4u, srcB, (n0 + row) < NN);
        }
    };

    auto mmaTile = [&](int stg) {
        uint32_t abase = sbase + (uint32_t)(stg * ASTG) * 4u;
        uint32_t bbase = sbase + (uint32_t)(3 * ASTG + stg * BSTG) * 4u;
#pragma unroll
        for (int s = 0; s < 2; s++) {
            const int k0 = s * 8;
            uint32_t a[2][4];
#pragma unroll
            for (int mt = 0; mt < 2; mt++) {
                int row = wm + mt * 16 + ((sel & 1) << 3) + r8;
                int ku  = k0 + ((sel & 2) << 1);
                ldsm4(a[mt], abase + (uint32_t)(row * PK + ku) * 4u);
            }
            uint32_t b0v[8], b1v[8];
#pragma unroll
            for (int g4 = 0; g4 < 2; g4++) {
                int row = wn + g4 * 32 + sel * 8 + r8;
                ldsm4(&b0v[g4 * 4], bbase + (uint32_t)(row * PK + k0) * 4u);
                ldsm4(&b1v[g4 * 4], bbase + (uint32_t)(row * PK + k0 + 4) * 4u);
            }
#pragma unroll
            for (int nt = 0; nt < 8; nt++) {
                mma_f16(acc[0][nt], a[0], b0v[nt], b1v[nt]);
                mma_f16(acc[1][nt], a[1], b0v[nt], b1v[nt]);
            }
        }
    };

    issue(0, 0); cpa_commit();
    if (KT > 1) issue(1, 1);
    cpa_commit();
    cpa_wait1();
    __syncthreads();

    for (int kt = 0; kt < KT; kt++) {
        int stg = kt % 3;
        if (kt + 2 < KT) issue(kt + 2, (kt + 2) % 3);
        cpa_commit();
        mmaTile(stg);
        cpa_wait1();
        __syncthreads();
    }

#pragma unroll
    for (int mt = 0; mt < 2; mt++) {
#pragma unroll
        for (int nt = 0; nt < 8; nt++) {
#pragma unroll
            for (int e = 0; e < 4; e++) {
                int gm = m0 + wm + mt * 16 + g + (e >= 2 ? 8 : 0);
                int gn = n0 + wn + nt * 8 + 2 * th + (e & 1);
                if (gm >= NN || gn >= NN) continue;
                float v = 0.125f * acc[mt][nt][e];
                attb[(long long)gm * NN + gn] = v;
                if (bm < bn) attb[(long long)gn * NN + gm] = v;
            }
        }
    }
}

// ---------------- weight transpose to half: dst[n,k] = src[k,n] ----------------
__global__ void trhalf_k(const float* __restrict__ src, __half* __restrict__ dst, int K, int N)
{
    int idx = blockIdx.x * blockDim.x + threadIdx.x;
    if (idx >= K * N) return;
    int n = idx / K, k = idx % K;
    dst[(long long)n * K + k] = __float2half_rn(src[(long long)k * N + n]);
}

// ---------------- gl_w [P,D,HD] -> GLWt half [KF, D] ----------------
__global__ void glwt_k(const float* __restrict__ glw, __half* __restrict__ GLWt)
{
    int idx = blockIdx.x * blockDim.x + threadIdx.x;
    if (idx >= KF * D_) return;
    int c = idx / D_, k = idx % D_;
    int p = c >> 9, hh = c & 511;
    GLWt[idx] = __float2half_rn(glw[((long long)p * D_ + k) * HD + hh]);
}

// ---------------- A-matrix builder, both views, half output ----------------
__global__ void build_ag2_k(const float* __restrict__ x1, const float* __restrict__ x2,
                            const float* __restrict__ emb,
                            const float* __restrict__ gw, const float* __restrict__ gb,
                            __half* __restrict__ Ag)
{
    long long idx = (long long)blockIdx.x * blockDim.x + threadIdx.x;
    if (idx >= MR2 * E_) return;
    int e = (int)(idx & (E_ - 1));
    long long r = idx >> 9;
    long long rv = (r < MR) ? r : r - MR;
    const float* x = (r < MR) ? x1 : x2;
    int n = (int)(rv % NN);
    float t = fmaf(x[rv], gw[e], gb[e]);
    float sgm = 1.0f / (1.0f + expf(-t));
    Ag[idx] = __float2half_rn(sgm * emb[(long long)n * E_ + e]);
}

// ---------------- top-k(50) -> row-compressed softmax output ----------------
__global__ void __launch_bounds__(256) topk_rows_k(
    const float* __restrict__ att,
    float* __restrict__ rowval, int* __restrict__ rowcol, int* __restrict__ rowcnt)
{
    __shared__ float s[2000];
    __shared__ int   hist[256];
    __shared__ float wredf[8];
    __shared__ float s_bcast;
    __shared__ int   s_selb, s_selk, s_pos;

    long long row = blockIdx.x;
    const float* r = att + row * 2000;
    int tid = threadIdx.x;
    int lane = tid & 31, wid = tid >> 5;

    for (int i = tid; i < 2000; i += 256) s[i] = r[i];
    if (tid == 0) s_pos = 0;
    __syncthreads();

    float mx = 0.f;
    for (int i = tid; i < 2000; i += 256) mx = fmaxf(mx, s[i]);
#pragma unroll
    for (int o = 16; o; o >>= 1) mx = fmaxf(mx, __shfl_xor_sync(0xffffffffu, mx, o));
    if (lane == 0) wredf[wid] = mx;
    __syncthreads();
    if (tid == 0) { float m = wredf[0]; for (int w = 1; w < 8; w++) m = fmaxf(m, wredf[w]); s_bcast = m; }
    __syncthreads();
    mx = s_bcast;

    unsigned prefix = 0u;
    int k = 50;
#pragma unroll
    for (int pass = 0; pass < 4; pass++) {
        const int shift = 24 - 8 * pass;
        const unsigned hmask = (pass == 0) ? 0u : (0xFFFFFFFFu << (shift + 8));
        if (tid < 256) hist[tid] = 0;
        __syncthreads();
        for (int i = tid; i < 2000; i += 256) {
            unsigned u = __float_as_uint(s[i]);
            if ((u & hmask) == prefix)
                atomicAdd(&hist[(u >> shift) & 255], 1);
        }
        __syncthreads();
        if (tid == 0) {
            int acc = 0, b = 255;
            for (; b > 0; b--) { acc += hist[b]; if (acc >= k) break; }
            if (acc < k) acc += hist[0];
            s_selb = b;
            s_selk = k - (acc - hist[b]);
        }
        __syncthreads();
        prefix |= ((unsigned)s_selb) << shift;
        k = s_selk;
        __syncthreads();
    }
    float thr = __uint_as_float(prefix);

    float sum = 0.f;
    for (int i = tid; i < 2000; i += 256) {
        float v = s[i];
        if (v >= thr) sum += expf(v - mx);
    }
#pragma unroll
    for (int o = 16; o; o >>= 1) sum += __shfl_xor_sync(0xffffffffu, sum, o);
    if (lane == 0) wredf[wid] = sum;
    __syncthreads();
    if (tid == 0) { float t = 0.f; for (int w = 0; w < 8; w++) t += wredf[w]; s_bcast = t; }
    __syncthreads();
    float inv = 1.0f / s_bcast;

    for (int i = tid; i < 2000; i += 256) {
        float v = s[i];
        if (v >= thr) {
            int p = atomicAdd(&s_pos, 1);
            if (p < ROWCAP) {
                rowval[row * ROWCAP + p] = expf(v - mx) * inv;
                rowcol[row * ROWCAP + p] = i;
            }
        }
    }
    __syncthreads();
    if (tid == 0) rowcnt[row] = min(s_pos, ROWCAP);
}

// ---------------- zero ----------------
__global__ void zero_k(int* __restrict__ a, float* __restrict__ b, int n)
{
    int i = blockIdx.x * blockDim.x + threadIdx.x;
    if (i < n) { a[i] = 0; b[i] = 0.f; }
}

// ---------------- count column occupancy ----------------
__global__ void count_k(const int* __restrict__ rowcol, const int* __restrict__ rowcnt,
                        int* __restrict__ colcnt)
{
    int row = blockIdx.x;
    int b = row / NN;
    int cnt = rowcnt[row];
    if (threadIdx.x < cnt)
        atomicAdd(&colcnt[b * NN + rowcol[row * ROWCAP + threadIdx.x]], 1);
}

// ---------------- per-batch exclusive scan ----------------
__global__ void __launch_bounds__(256) scan_k(const int* __restrict__ colcnt,
                                              int* __restrict__ coloff, int* __restrict__ colcur)
{
    __shared__ int tsum[257];
    int b = blockIdx.x, tid = threadIdx.x;
    const int* cnt = colcnt + b * NN;
    int local[8];
    int tot = 0;
#pragma unroll
    for (int e = 0; e < 8; e++) {
        int i = tid * 8 + e;
        local[e] = tot;
        tot += (i < NN) ? cnt[i] : 0;
    }
    tsum[tid] = tot;
    __syncthreads();
    if (tid == 0) {
        int acc = 0;
        for (int t = 0; t < 256; t++) { int v = tsum[t]; tsum[t] = acc; acc += v; }
    }
    __syncthreads();
    int base = tsum[tid];
#pragma unroll
    for (int e = 0; e < 8; e++) {
        int i = tid * 8 + e;
        if (i < NN) {
            coloff[b * NN + i] = base + local[e];
            colcur[b * NN + i] = base + local[e];
        }
    }
}

// ---------------- place into CSC ----------------
__global__ void place_k(const float* __restrict__ rowval, const int* __restrict__ rowcol,
                        const int* __restrict__ rowcnt,
                        int* __restrict__ colcur, float* __restrict__ colsum,
                        float* __restrict__ cscval, int* __restrict__ cscrow)
{
    int row = blockIdx.x;
    int b = row / NN, j = row % NN;
    int cnt = rowcnt[row];
    int e = threadIdx.x;
    if (e < cnt) {
        int   c = rowcol[row * ROWCAP + e];
        float w = rowval[row * ROWCAP + e];
        int pos = atomicAdd(&colcur[b * NN + c], 1);
        cscval[(long long)b * CAP + pos] = w;
        cscrow[(long long)b * CAP + pos] = j;
        atomicAdd(&colsum[b * NN + c], w);
    }
}

// ---------------- dinv ----------------
__global__ void dinv_k(const float* __restrict__ colsum, float* __restrict__ dinv, int n)
{
    int i = blockIdx.x * blockDim.x + threadIdx.x;
    if (i < n) dinv[i] = rsqrtf(1.0f + colsum[i]);
}

// ---------------- sparse GCN aggregation, T fp16 in; OUTH: half out ----------------
template<int DIM, int ACT, int OUTH>
__global__ void spagg_k(
    const float* __restrict__ cscval, const int* __restrict__ cscrow,
    const int* __restrict__ coloff, const int* __restrict__ colcnt,
    const __half* __restrict__ T, const float* __restrict__ dinv,
    const float* __restrict__ bias, void* __restrict__ out)
{
    __shared__ float sw[256];
    __shared__ int   sj[256];
    int i = blockIdx.x, b = blockIdx.y, tid = threadIdx.x;
    const __half* Tb = T + (long long)b * NN * DIM;
    int s0  = coloff[b * NN + i];
    int cnt = colcnt[b * NN + i];
    long long base = (long long)b * CAP + s0;

    float2 acc = __half22float2(*reinterpret_cast<const __half2*>(&Tb[(long long)i * DIM + 2 * tid]));
    float2 acc2 = make_float2(0.f, 0.f);

    for (int e0 = 0; e0 < cnt; e0 += blockDim.x) {
        int chunk = min(cnt - e0, (int)blockDim.x);
        if (tid < chunk) {
            sw[tid] = cscval[base + e0 + tid];
            sj[tid] = cscrow[base + e0 + tid];
        }
        __syncthreads();
        int e = 0;
        for (; e + 1 < chunk; e += 2) {
            float2 t0 = __half22float2(*reinterpret_cast<const __half2*>(&Tb[(long long)sj[e]   * DIM + 2 * tid]));
            float2 t1 = __half22float2(*reinterpret_cast<const __half2*>(&Tb[(long long)sj[e+1] * DIM + 2 * tid]));
            acc.x  = fmaf(sw[e],   t0.x, acc.x);
            acc.y  = fmaf(sw[e],   t0.y, acc.y);
            acc2.x = fmaf(sw[e+1], t1.x, acc2.x);
            acc2.y = fmaf(sw[e+1], t1.y, acc2.y);
        }
        if (e < chunk) {
            float2 t0 = __half22float2(*reinterpret_cast<const __half2*>(&Tb[(long long)sj[e] * DIM + 2 * tid]));
            acc.x = fmaf(sw[e], t0.x, acc.x);
            acc.y = fmaf(sw[e], t0.y, acc.y);
        }
        __syncthreads();
    }
    float dv = dinv[b * NN + i];
    float vx = dv * (acc.x + acc2.x) + bias[2 * tid];
    float vy = dv * (acc.y + acc2.y) + bias[2 * tid + 1];
    if (ACT == 1) { vx = fmaxf(vx, 0.f); vy = fmaxf(vy, 0.f); }
    if (OUTH) {
        __half* oh = (__half*)out;
        *reinterpret_cast<__half2*>(&oh[((long long)b * NN + i) * DIM + 2 * tid]) =
            __floats2half2_rn(vx, vy);
    } else {
        float* of = (float*)out;
        *reinterpret_cast<float2*>(&of[((long long)b * NN + i) * DIM + 2 * tid]) = make_float2(vx, vy);
    }
}

// ---------------- mean over nodes; mu/std/z ----------------
__global__ void meanz2_k(const float* __restrict__ O3,
                         const float* __restrict__ eps1, const float* __restrict__ eps2,
                         float* __restrict__ mu1, float* __restrict__ std1,
                         float* __restrict__ mu2, float* __restrict__ std2,
                         float* __restrict__ z)
{
    int b = blockIdx.x, d = threadIdx.x;
    const float* p = O3 + ((long long)b * 2000) * 128 + d;
    float s0 = 0.f, s1 = 0.f, s2 = 0.f, s3 = 0.f;
    for (int i = 0; i < 2000; i += 4) {
        s0 += p[(long long)i * 128];
        s1 += p[(long long)(i + 1) * 128];
        s2 += p[(long long)(i + 2) * 128];
        s3 += p[(long long)(i + 3) * 128];
    }
    __shared__ float sg[128];
    sg[d] = ((s0 + s1) + (s2 + s3)) / 2000.0f;
    __syncthreads();
    if (d < 64) {
        int view = b >> 3, bb = b & 7;
        const float* eps = view ? eps2 : eps1;
        float* mu = view ? mu2 : mu1;
        float* sd = view ? std2 : std1;
        float m = sg[d];
        float sp = log1pf(expf(sg[64 + d] - 64.0f));
        mu[bb * 64 + d] = m;
        sd[bb * 64 + d] = sp;
        z[b * 64 + d] = fmaf(eps[bb * 64 + d], sp, m);
    }
}

// ---------------- decoder ----------------
__global__ void __launch_bounds__(256) decode_k(
    const float* __restrict__ z, const float* __restrict__ w1, const float* __restrict__ b1,
    const float* __restrict__ gamma, const float* __restrict__ beta,
    const float* __restrict__ w2, const float* __restrict__ b2,
    float* __restrict__ xrec)
{
    __shared__ float h[1024];
    __shared__ float zs[64];
    int b = blockIdx.x, tid = threadIdx.x;
    if (tid < 64) zs[tid] = z[b * 64 + tid];
    __syncthreads();
    const float invc = 1.0f / sqrtf(1.0f + 1e-5f);
    for (int c = tid; c < 1024; c += 256) {
        float a = b1[c];
#pragma unroll 8
        for (int k = 0; k < 64; k++) a = fmaf(zs[k], w1[k * 1024 + c], a);
        a = a * (gamma[c] * invc) + beta[c];
        h[c] = fmaxf(a, 0.f);
    }
    __syncthreads();
    int c0 = blockIdx.y * 250;
    int c1 = min(c0 + 250, 2000);
    for (int c = c0 + tid; c < c1; c += 256) {
        float a = b2[c];
        for (int k = 0; k < 1024; k++) a = fmaf(h[k], w2[k * 2000 + c], a);
        xrec[b * 2000 + c] = fmaxf(a, 0.f);
    }
}

// ---------------- host orchestration ----------------
extern "C" void kernel_launch(void* const* d_in, const int* in_sizes, int n_in,
                              void* d_out, int out_size)
{
    const float* x1     = (const float*)d_in[0];
    const float* x2     = (const float*)d_in[1];
    const float* emb1   = (const float*)d_in[2];
    const float* gate_w = (const float*)d_in[3];
    const float* gate_b = (const float*)d_in[4];
    const float* enc_w1 = (const float*)d_in[5];
    const float* enc_b1 = (const float*)d_in[6];
    const float* enc_w2 = (const float*)d_in[7];
    const float* enc_b2 = (const float*)d_in[8];
    const float* gl_w   = (const float*)d_in[9];
    const float* g_w1   = (const float*)d_in[10];
    const float* g_b1   = (const float*)d_in[11];
    const float* g_w2   = (const float*)d_in[12];
    const float* g_b2   = (const float*)d_in[13];
    const float* g_w3   = (const float*)d_in[14];
    const float* g_b3   = (const float*)d_in[15];
    const float* dW1[2] = {(const float*)d_in[16], (const float*)d_in[22]};
    const float* dB1[2] = {(const float*)d_in[17], (const float*)d_in[23]};
    const float* dG [2] = {(const float*)d_in[18], (const float*)d_in[24]};
    const float* dBe[2] = {(const float*)d_in[19], (const float*)d_in[25]};
    const float* dW2[2] = {(const float*)d_in[20], (const float*)d_in[26]};
    const float* dB2[2] = {(const float*)d_in[21], (const float*)d_in[27]};
    const float* epsA[2]= {(const float*)d_in[28], (const float*)d_in[29]};

    static bool attr_done = false;
    if (!attr_done) {
        cudaFuncSetAttribute(hgemm_k<2,0,1>, cudaFuncAttributeMaxDynamicSharedMemorySize, SMEM_BYTES);
        cudaFuncSetAttribute(hgemm_k<0,0,1>, cudaFuncAttributeMaxDynamicSharedMemorySize, SMEM_BYTES);
        cudaFuncSetAttribute(hgemm_k<1,0,1>, cudaFuncAttributeMaxDynamicSharedMemorySize, SMEM_BYTES);
        cudaFuncSetAttribute(hgemm_k<0,1,1>, cudaFuncAttributeMaxDynamicSharedMemorySize, SMEM_BYTES);
        cudaFuncSetAttribute(hgram_k, cudaFuncAttributeMaxDynamicSharedMemorySize, SMEM_BYTES);
        attr_done = true;
    }

    float* sc = nullptr;
    cudaGetSymbolAddress((void**)&sc, g_scratch);
    __half* Agh  = (__half*)(sc + OFF_AGH);
    __half* Henh = (__half*)(sc + OFF_HENH);
    __half* Hh   = (__half*)(sc + OFF_HH);
    __half* GLWt = (__half*)(sc + OFF_GLWT);
    __half* Fh   = (__half*)(sc + OFF_FH);
    float*  att  = sc + OFF_ATT;
    float*  dinv = sc + OFF_DINV;
    __half* Th   = (__half*)(sc + OFF_TH);
    __half* O1h  = (__half*)(sc + OFF_O1H);
    __half* O2h  = (__half*)(sc + OFF_O2H);
    float*  O3   = sc + OFF_O3;
    float*  zb   = sc + OFF_Z;
    __half* W1t  = (__half*)(sc + OFF_W1T);
    __half* W2t  = (__half*)(sc + OFF_W2T);
    __half* GW1t = (__half*)(sc + OFF_GW1T);
    __half* GW2t = (__half*)(sc + OFF_GW2T);
    __half* GW3t = (__half*)(sc + OFF_GW3T);
    float* rowval = sc + OFF_ROWV;
    int*   rowcol = (int*)(sc + OFF_ROWC);
    int*   rowcnt = (int*)(sc + OFF_RCNT);
    int*   colcnt = (int*)(sc + OFF_CCNT);
    int*   coloff = (int*)(sc + OFF_COFF);
    int*   colcur = (int*)(sc + OFF_CCUR);
    float* colsum = sc + OFF_CSUM;
    float* cscval = sc + OFF_CSCV;
    int*   cscrow = (int*)(sc + OFF_CSCR);

    float* out = (float*)d_out;
    float* xrec[2] = {out,          out + 16000};
    float* muo [2] = {out + 32000,  out + 33024};
    float* stdo[2] = {out + 32512,  out + 33536};

    // weight prep: transpose to half [N,K]
    trhalf_k<<<(E_ * HEN + 255) / 256, 256>>>(enc_w1, W1t, E_, HEN);
    trhalf_k<<<(HEN * D_ + 255) / 256, 256>>>(enc_w2, W2t, HEN, D_);
    trhalf_k<<<(D_ * HD + 255) / 256, 256>>>(g_w1, GW1t, D_, HD);
    trhalf_k<<<(HD * HD + 255) / 256, 256>>>(g_w2, GW2t, HD, HD);
    trhalf_k<<<(HD * D_ + 255) / 256, 256>>>(g_w3, GW3t, HD, D_);
    glwt_k<<<(KF * D_ + 255) / 256, 256>>>(gl_w, GLWt);

    // ---- encoders, both views batched (M = 32000) ----
    build_ag2_k<<<(unsigned)((MR2 * E_ + 255) / 256), 256>>>(x1, x2, emb1, gate_w, gate_b, Agh);
    hgemm_k<2,0,1><<<dim3(HEN / 128, 250), 256, SMEM_BYTES>>>(
        (int)MR2, HEN, E_, Agh, W1t, Henh, HEN, enc_b1, nullptr);
    hgemm_k<0,0,1><<<dim3(1, 250), 256, SMEM_BYTES>>>(
        (int)MR2, D_, HEN, Henh, W2t, Hh, D_, enc_b2, nullptr);

    // ---- F = relu(H @ GLW) -> half ----
    hgemm_k<1,0,1><<<dim3(KF / 128, 250), 256, SMEM_BYTES>>>(
        (int)MR2, KF, D_, Hh, GLWt, Fh, KF, nullptr, nullptr);

    // ---- gram for all 16 batches ----
    hgram_k<<<dim3(16, 16, B2), 256, SMEM_BYTES>>>(Fh, att);

    // ---- sparse adjacency pipeline ----
    zero_k<<<(int)((MR2 + 255) / 256), 256>>>(colcnt, colsum, (int)MR2);
    topk_rows_k<<<(unsigned)MR2, 256>>>(att, rowval, rowcol, rowcnt);
    count_k<<<(unsigned)MR2, ROWCAP>>>(rowcol, rowcnt, colcnt);
    scan_k<<<B2, 256>>>(colcnt, coloff, colcur);
    place_k<<<(unsigned)MR2, ROWCAP>>>(rowval, rowcol, rowcnt, colcur, colsum, cscval, cscrow);
    dinv_k<<<(int)((MR2 + 255) / 256), 256>>>(colsum, dinv, (int)MR2);

    // ---- GCN layers ----
    hgemm_k<0,1,1><<<dim3(HD / 128, 250), 256, SMEM_BYTES>>>(
        (int)MR2, HD, D_, Hh, GW1t, Th, HD, nullptr, dinv);
    spagg_k<HD,1,1><<<dim3(NN, B2), HD/2>>>(cscval, cscrow, coloff, colcnt, Th, dinv, g_b1, O1h);
    hgemm_k<0,1,1><<<dim3(HD / 128, 250), 256, SMEM_BYTES>>>(
        (int)MR2, HD, HD, O1h, GW2t, Th, HD, nullptr, dinv);
    spagg_k<HD,1,1><<<dim3(NN, B2), HD/2>>>(cscval, cscrow, coloff, colcnt, Th, dinv, g_b2, O2h);
    hgemm_k<0,1,1><<<dim3(1, 250), 256, SMEM_BYTES>>>(
        (int)MR2, D_, HD, O2h, GW3t, Th, D_, nullptr, dinv);
    spagg_k<D_,0,0><<<dim3(NN, B2), D_/2>>>(cscval, cscrow, coloff, colcnt, Th, dinv, g_b3, O3);

    // ---- VIB head + decoders ----
    meanz2_k<<<B2, 128>>>(O3, epsA[0], epsA[1], muo[0], stdo[0], muo[1], stdo[1], zb);
    decode_k<<<dim3(8, 8), 256>>>(zb,       dW1[0], dB1[0], dG[0], dBe[0], dW2[0], dB2[0], xrec[0]);
    decode_k<<<dim3(8, 8), 256>>>(zb + 512, dW1[1], dB1[1], dG[1], dBe[1], dW2[1], dB2[1], xrec[1]);
}

// round 13
// speedup vs baseline: 3.7455x; 1.0386x over previous
#include <cuda_runtime.h>
#include <cuda_fp16.h>
#include <math.h>
#include <stdint.h>

// ---------------- problem constants ----------------
constexpr int B_  = 8;
constexpr int B2  = 16;
constexpr int NN  = 2000;
constexpr int E_  = 512;
constexpr int HEN = 1024;
constexpr int D_  = 128;
constexpr int HD  = 512;
constexpr int KF  = 4096;
constexpr int IB_ = 64;
constexpr long long MR  = (long long)B_ * NN;
constexpr long long MR2 = (long long)B2 * NN;   // 32000

constexpr int ROWCAP = 64;
constexpr int CAP    = 131072;

// ---------------- scratch layout (units: float slots; halves use /2) ----------------
constexpr long long SZ_AGH  = MR2 * E_ / 2;
constexpr long long SZ_HENH = MR2 * HEN / 2;
constexpr long long SZ_HH   = MR2 * D_ / 2;
constexpr long long SZ_GLWT = (long long)KF * D_ / 2;
constexpr long long SZ_FH   = MR2 * KF / 2;
constexpr long long SZ_ATT  = (long long)B2 * NN * NN;     // fp32 att (exact top-k)
constexpr long long SZ_DINV = MR2;
constexpr long long SZ_TH   = MR2 * HD / 2;
constexpr long long SZ_OH   = MR2 * HD / 2;
constexpr long long SZ_O3   = MR2 * D_;
constexpr long long SZ_Z    = (long long)B2 * IB_;
constexpr long long SZ_W1T  = (long long)HEN * E_ / 2;
constexpr long long SZ_W2T  = (long long)D_ * HEN / 2;
constexpr long long SZ_GW1T = (long long)HD * D_ / 2;
constexpr long long SZ_GW2T = (long long)HD * HD / 2;
constexpr long long SZ_GW3T = (long long)D_ * HD / 2;
constexpr long long SZ_ROWV = MR2 * ROWCAP;
constexpr long long SZ_ROWC = MR2 * ROWCAP;
constexpr long long SZ_RCNT = MR2;
constexpr long long SZ_CCNT = MR2;
constexpr long long SZ_COFF = MR2;
constexpr long long SZ_CCUR = MR2;
constexpr long long SZ_CSUM = MR2;
constexpr long long SZ_CSCV = (long long)B2 * CAP;
constexpr long long SZ_CSCR = (long long)B2 * CAP;

constexpr long long OFF_AGH  = 0;
constexpr long long OFF_HENH = OFF_AGH + SZ_AGH;
constexpr long long OFF_HH   = OFF_HENH + SZ_HENH;
constexpr long long OFF_GLWT = OFF_HH + SZ_HH;
constexpr long long OFF_FH   = OFF_GLWT + SZ_GLWT;
constexpr long long OFF_ATT  = OFF_FH + SZ_FH;
constexpr long long OFF_DINV = OFF_ATT + SZ_ATT;
constexpr long long OFF_TH   = OFF_DINV + SZ_DINV;
constexpr long long OFF_O1H  = OFF_TH + SZ_TH;
constexpr long long OFF_O2H  = OFF_O1H + SZ_OH;
constexpr long long OFF_O3   = OFF_O2H + SZ_OH;
constexpr long long OFF_Z    = OFF_O3 + SZ_O3;
constexpr long long OFF_W1T  = OFF_Z + SZ_Z;
constexpr long long OFF_W2T  = OFF_W1T + SZ_W1T;
constexpr long long OFF_GW1T = OFF_W2T + SZ_W2T;
constexpr long long OFF_GW2T = OFF_GW1T + SZ_GW1T;
constexpr long long OFF_GW3T = OFF_GW2T + SZ_GW2T;
constexpr long long OFF_ROWV = OFF_GW3T + SZ_GW3T;
constexpr long long OFF_ROWC = OFF_ROWV + SZ_ROWV;
constexpr long long OFF_RCNT = OFF_ROWC + SZ_ROWC;
constexpr long long OFF_CCNT = OFF_RCNT + SZ_RCNT;
constexpr long long OFF_COFF = OFF_CCNT + SZ_CCNT;
constexpr long long OFF_CCUR = OFF_COFF + SZ_COFF;
constexpr long long OFF_CSUM = OFF_CCUR + SZ_CCUR;
constexpr long long OFF_CSCV = OFF_CSUM + SZ_CSUM;
constexpr long long OFF_CSCR = OFF_CSCV + SZ_CSCV;
constexpr long long SCRATCH_TOTAL = OFF_CSCR + SZ_CSCR;

__device__ float g_scratch[SCRATCH_TOTAL];

// ---------------- helpers ----------------
__device__ __forceinline__ void mma_f16(float* c, const uint32_t* a, uint32_t b0, uint32_t b1) {
    asm volatile(
        "mma.sync.aligned.m16n8k16.row.col.f32.f16.f16.f32 "
        "{%0,%1,%2,%3}, {%4,%5,%6,%7}, {%8,%9}, {%0,%1,%2,%3};"
        : "+f"(c[0]), "+f"(c[1]), "+f"(c[2]), "+f"(c[3])
        : "r"(a[0]), "r"(a[1]), "r"(a[2]), "r"(a[3]), "r"(b0), "r"(b1));
}

__device__ __forceinline__ void ldsm4(uint32_t* r, uint32_t addr) {
    asm volatile("ldmatrix.sync.aligned.m8n8.x4.shared.b16 {%0,%1,%2,%3}, [%4];"
                 : "=r"(r[0]), "=r"(r[1]), "=r"(r[2]), "=r"(r[3]) : "r"(addr));
}

__device__ __forceinline__ void cpa16(uint32_t dst, const void* src, bool pred) {
    int sz = pred ? 16 : 0;
    asm volatile("cp.async.cg.shared.global [%0], [%1], 16, %2;\n"
                 :: "r"(dst), "l"(src), "r"(sz));
}
__device__ __forceinline__ void cpa_commit() { asm volatile("cp.async.commit_group;\n"); }
__device__ __forceinline__ void cpa_wait1()  { asm volatile("cp.async.wait_group 1;\n"); }

__device__ __forceinline__ uint32_t smem_u32(const void* p) {
    uint32_t a;
    asm("{ .reg .u64 t; cvta.to.shared.u64 t, %1; cvt.u32.u64 %0, t; }" : "=r"(a) : "l"(p));
    return a;
}

constexpr int PK = 20;
constexpr int ASTG = 2560;
constexpr int BSTG = 2560;
constexpr int SMEM_BYTES = (3 * ASTG + 3 * BSTG) * 4;   // 61440

// ================= unified fp16 GEMM =================
template<int ACT, int EPI, int OUTH>
__global__ void __launch_bounds__(256, 2) hgemm_k(
    int M, int N, int K,
    const __half* __restrict__ A,
    const __half* __restrict__ Bt,
    void* __restrict__ C, int ldc,
    const float* __restrict__ bias,
    const float* __restrict__ dinv)
{
    extern __shared__ uint32_t sh[];
    const int bn = blockIdx.x, bm = blockIdx.y;
    const int m0 = bm * 128, n0 = bn * 128;

    const int tid  = threadIdx.x;
    const int lane = tid & 31, warp = tid >> 5;
    const int g = lane >> 2, th = lane & 3;
    const int wm = (warp >> 1) * 32;
    const int wn = (warp & 1) * 64;
    const int r8 = lane & 7, sel = lane >> 3;

    uint32_t sbase = smem_u32(sh);

    float acc[2][8][4];
#pragma unroll
    for (int i = 0; i < 2; i++)
#pragma unroll
        for (int j = 0; j < 8; j++)
#pragma unroll
            for (int l = 0; l < 4; l++) acc[i][j][l] = 0.f;

    const int KT = K / 32;

    auto issue = [&](int kt, int stg) {
        uint32_t abase = sbase + (uint32_t)(stg * ASTG) * 4u;
        uint32_t bbase = sbase + (uint32_t)(3 * ASTG + stg * BSTG) * 4u;
#pragma unroll
        for (int it = 0; it < 2; it++) {
            int c = tid * 2 + it;
            int row = c >> 2, kc = c & 3;
            const __half* srcA = A + (long long)(m0 + row) * K + kt * 32 + kc * 8;
            cpa16(abase + (uint32_t)(row * PK + kc * 4) * 4u, srcA, (m0 + row) < M);
            const __half* srcB = Bt + (long long)(n0 + row) * K + kt * 32 + kc * 8;
            cpa16(bbase + (uint32_t)(row * PK + kc * 4) * 4u, srcB, (n0 + row) < N);
        }
    };

    auto mmaTile = [&](int stg) {
        uint32_t abase = sbase + (uint32_t)(stg * ASTG) * 4u;
        uint32_t bbase = sbase + (uint32_t)(3 * ASTG + stg * BSTG) * 4u;
#pragma unroll
        for (int s = 0; s < 2; s++) {
            const int k0 = s * 8;
            uint32_t a[2][4];
#pragma unroll
            for (int mt = 0; mt < 2; mt++) {
                int row = wm + mt * 16 + ((sel & 1) << 3) + r8;
                int ku  = k0 + ((sel & 2) << 1);
                ldsm4(a[mt], abase + (uint32_t)(row * PK + ku) * 4u);
            }
            uint32_t b0v[8], b1v[8];
#pragma unroll
            for (int g4 = 0; g4 < 2; g4++) {
                int row = wn + g4 * 32 + sel * 8 + r8;
                ldsm4(&b0v[g4 * 4], bbase + (uint32_t)(row * PK + k0) * 4u);
                ldsm4(&b1v[g4 * 4], bbase + (uint32_t)(row * PK + k0 + 4) * 4u);
            }
#pragma unroll
            for (int nt = 0; nt < 8; nt++) {
                mma_f16(acc[0][nt], a[0], b0v[nt], b1v[nt]);
                mma_f16(acc[1][nt], a[1], b0v[nt], b1v[nt]);
            }
        }
    };

    issue(0, 0); cpa_commit();
    if (KT > 1) issue(1, 1);
    cpa_commit();
    cpa_wait1();
    __syncthreads();

    for (int kt = 0; kt < KT; kt++) {
        int stg = kt % 3;
        if (kt + 2 < KT) issue(kt + 2, (kt + 2) % 3);
        cpa_commit();
        mmaTile(stg);
        cpa_wait1();
        __syncthreads();
    }

    __half* Ch = (__half*)C;
    float*  Cf = (float*)C;
#pragma unroll
    for (int mt = 0; mt < 2; mt++) {
#pragma unroll
        for (int nt = 0; nt < 8; nt++) {
#pragma unroll
            for (int eh = 0; eh < 2; eh++) {
                int gm = m0 + wm + mt * 16 + g + (eh ? 8 : 0);
                int gn = n0 + wn + nt * 8 + 2 * th;
                if (gm >= M || gn >= N) continue;
                float v0 = acc[mt][nt][eh * 2 + 0];
                float v1 = acc[mt][nt][eh * 2 + 1];
                if (EPI == 1) { float dv = dinv[gm]; v0 *= dv; v1 *= dv; }
                if (bias)     { v0 += bias[gn]; v1 += bias[gn + 1]; }
                if (ACT == 1) { v0 = fmaxf(v0, 0.f); v1 = fmaxf(v1, 0.f); }
                if (ACT == 2) {
                    v0 = 0.5f * v0 * (1.f + erff(v0 * 0.70710678118654752f));
                    v1 = 0.5f * v1 * (1.f + erff(v1 * 0.70710678118654752f));
                }
                if (OUTH) {
                    *reinterpret_cast<__half2*>(&Ch[(long long)gm * ldc + gn]) =
                        __floats2half2_rn(v0, v1);
                } else {
                    Cf[(long long)gm * ldc + gn]     = v0;
                    Cf[(long long)gm * ldc + gn + 1] = v1;
                }
            }
        }
    }
}

// ---------------- fp16 gram, fp32 att output (exact top-k downstream) ----------------
__global__ void __launch_bounds__(256, 2) hgram_k(const __half* __restrict__ F,
                                                  float* __restrict__ att)
{
    extern __shared__ uint32_t sh[];
    const int bn = blockIdx.x, bm = blockIdx.y, b = blockIdx.z;
    if (bm > bn) return;
    const int m0 = bm * 128, n0 = bn * 128;

    const int tid  = threadIdx.x;
    const int lane = tid & 31, warp = tid >> 5;
    const int g = lane >> 2, th = lane & 3;
    const int wm = (warp >> 1) * 32;
    const int wn = (warp & 1) * 64;
    const int r8 = lane & 7, sel = lane >> 3;

    uint32_t sbase = smem_u32(sh);
    const __half* Fb = F + (long long)b * NN * KF;
    float* attb = att + (long long)b * NN * NN;

    float acc[2][8][4];
#pragma unroll
    for (int i = 0; i < 2; i++)
#pragma unroll
        for (int j = 0; j < 8; j++)
#pragma unroll
            for (int l = 0; l < 4; l++) acc[i][j][l] = 0.f;

    const int KT = KF / 32;

    auto issue = [&](int kt, int stg) {
        uint32_t abase = sbase + (uint32_t)(stg * ASTG) * 4u;
        uint32_t bbase = sbase + (uint32_t)(3 * ASTG + stg * BSTG) * 4u;
#pragma unroll
        for (int it = 0; it < 2; it++) {
            int c = tid * 2 + it;
            int row = c >> 2, kc = c & 3;
            const __half* srcA = Fb + (long long)(m0 + row) * KF + kt * 32 + kc * 8;
            cpa16(abase + (uint32_t)(row * PK + kc * 4) * 4u, srcA, (m0 + row) < NN);
            const __half* srcB = Fb + (long long)(n0 + row) * KF + kt * 32 + kc * 8;
            cpa16(bbase + (uint32_t)(row * PK + kc * 4) * 4u, srcB, (n0 + row) < NN);
        }
    };

    auto mmaTile = [&](int stg) {
        uint32_t abase = sbase + (uint32_t)(stg * ASTG) * 4u;
        uint32_t bbase = sbase + (uint32_t)(3 * ASTG + stg * BSTG) * 4u;
#pragma unroll
        for (int s = 0; s < 2; s++) {
            const int k0 = s * 8;
            uint32_t a[2][4];
#pragma unroll
            for (int mt = 0; mt < 2; mt++) {
                int row = wm + mt * 16 + ((sel & 1) << 3) + r8;
                int ku  = k0 + ((sel & 2) << 1);
                ldsm4(a[mt], abase + (uint32_t)(row * PK + ku) * 4u);
            }
            uint32_t b0v[8], b1v[8];
#pragma unroll
            for (int g4 = 0; g4 < 2; g4++) {
                int row = wn + g4 * 32 + sel * 8 + r8;
                ldsm4(&b0v[g4 * 4], bbase + (uint32_t)(row * PK + k0) * 4u);
                ldsm4(&b1v[g4 * 4], bbase + (uint32_t)(row * PK + k0 + 4) * 4u);
            }
#pragma unroll
            for (int nt = 0; nt < 8; nt++) {
                mma_f16(acc[0][nt], a[0], b0v[nt], b1v[nt]);
                mma_f16(acc[1][nt], a[1], b0v[nt], b1v[nt]);
            }
        }
    };

    issue(0, 0); cpa_commit();
    if (KT > 1) issue(1, 1);
    cpa_commit();
    cpa_wait1();
    __syncthreads();

    for (int kt = 0; kt < KT; kt++) {
        int stg = kt % 3;
        if (kt + 2 < KT) issue(kt + 2, (kt + 2) % 3);
        cpa_commit();
        mmaTile(stg);
        cpa_wait1();
        __syncthreads();
    }

#pragma unroll
    for (int mt = 0; mt < 2; mt++) {
#pragma unroll
        for (int nt = 0; nt < 8; nt++) {
#pragma unroll
            for (int e = 0; e < 4; e++) {
                int gm = m0 + wm + mt * 16 + g + (e >= 2 ? 8 : 0);
                int gn = n0 + wn + nt * 8 + 2 * th + (e & 1);
                if (gm >= NN || gn >= NN) continue;
                float v = 0.125f * acc[mt][nt][e];
                attb[(long long)gm * NN + gn] = v;
                if (bm < bn) attb[(long long)gn * NN + gm] = v;
            }
        }
    }
}

// ---------------- weight transpose to half ----------------
__global__ void trhalf_k(const float* __restrict__ src, __half* __restrict__ dst, int K, int N)
{
    int idx = blockIdx.x * blockDim.x + threadIdx.x;
    if (idx >= K * N) return;
    int n = idx / K, k = idx % K;
    dst[(long long)n * K + k] = __float2half_rn(src[(long long)k * N + n]);
}

// ---------------- gl_w -> GLWt half [KF, D] ----------------
__global__ void glwt_k(const float* __restrict__ glw, __half* __restrict__ GLWt)
{
    int idx = blockIdx.x * blockDim.x + threadIdx.x;
    if (idx >= KF * D_) return;
    int c = idx / D_, k = idx % D_;
    int p = c >> 9, hh = c & 511;
    GLWt[idx] = __float2half_rn(glw[((long long)p * D_ + k) * HD + hh]);
}

// ---------------- A-matrix builder ----------------
__global__ void build_ag2_k(const float* __restrict__ x1, const float* __restrict__ x2,
                            const float* __restrict__ emb,
                            const float* __restrict__ gw, const float* __restrict__ gb,
                            __half* __restrict__ Ag)
{
    long long idx = (long long)blockIdx.x * blockDim.x + threadIdx.x;
    if (idx >= MR2 * E_) return;
    int e = (int)(idx & (E_ - 1));
    long long r = idx >> 9;
    long long rv = (r < MR) ? r : r - MR;
    const float* x = (r < MR) ? x1 : x2;
    int n = (int)(rv % NN);
    float t = fmaf(x[rv], gw[e], gb[e]);
    float sgm = 1.0f / (1.0f + expf(-t));
    Ag[idx] = __float2half_rn(sgm * emb[(long long)n * E_ + e]);
}

// ---------------- top-k(50): register-resident, fp32 att ----------------
__global__ void __launch_bounds__(256) topk_rows_k(
    const float* __restrict__ att,
    float* __restrict__ rowval, int* __restrict__ rowcol, int* __restrict__ rowcnt)
{
    __shared__ int   hist[256];
    __shared__ float wredf[8];
    __shared__ float s_bcast;
    __shared__ int   s_selb, s_selk, s_pos;

    long long row = blockIdx.x;
    const float* r = att + row * 2000;
    int tid = threadIdx.x;
    int lane = tid & 31, wid = tid >> 5;

    float v[8];
#pragma unroll
    for (int p = 0; p < 8; p++) {
        int i = tid + p * 256;
        v[p] = (i < 2000) ? r[i] : 0.f;
    }
    if (tid == 0) s_pos = 0;

    float mx = 0.f;
#pragma unroll
    for (int p = 0; p < 8; p++) mx = fmaxf(mx, v[p]);
#pragma unroll
    for (int o = 16; o; o >>= 1) mx = fmaxf(mx, __shfl_xor_sync(0xffffffffu, mx, o));
    if (lane == 0) wredf[wid] = mx;
    __syncthreads();
    if (tid == 0) { float m = wredf[0]; for (int w = 1; w < 8; w++) m = fmaxf(m, wredf[w]); s_bcast = m; }
    __syncthreads();
    mx = s_bcast;

    unsigned prefix = 0u;
    int k = 50;
#pragma unroll
    for (int pass = 0; pass < 4; pass++) {
        const int shift = 24 - 8 * pass;
        const unsigned hmask = (pass == 0) ? 0u : (0xFFFFFFFFu << (shift + 8));
        if (tid < 256) hist[tid] = 0;
        __syncthreads();
#pragma unroll
        for (int p = 0; p < 8; p++) {
            int i = tid + p * 256;
            if (i < 2000) {
                unsigned u = __float_as_uint(v[p]);
                if ((u & hmask) == prefix)
                    atomicAdd(&hist[(u >> shift) & 255], 1);
            }
        }
        __syncthreads();
        if (tid == 0) {
            int acc = 0, b = 255;
            for (; b > 0; b--) { acc += hist[b]; if (acc >= k) break; }
            if (acc < k) acc += hist[0];
            s_selb = b;
            s_selk = k - (acc - hist[b]);
        }
        __syncthreads();
        prefix |= ((unsigned)s_selb) << shift;
        k = s_selk;
        __syncthreads();
    }
    float thr = __uint_as_float(prefix);

    float sum = 0.f;
#pragma unroll
    for (int p = 0; p < 8; p++) {
        int i = tid + p * 256;
        if (i < 2000 && v[p] >= thr) sum += expf(v[p] - mx);
    }
#pragma unroll
    for (int o = 16; o; o >>= 1) sum += __shfl_xor_sync(0xffffffffu, sum, o);
    if (lane == 0) wredf[wid] = sum;
    __syncthreads();
    if (tid == 0) { float t = 0.f; for (int w = 0; w < 8; w++) t += wredf[w]; s_bcast = t; }
    __syncthreads();
    float inv = 1.0f / s_bcast;

#pragma unroll
    for (int p = 0; p < 8; p++) {
        int i = tid + p * 256;
        if (i < 2000 && v[p] >= thr) {
            int pos = atomicAdd(&s_pos, 1);
            if (pos < ROWCAP) {
                rowval[row * ROWCAP + pos] = expf(v[p] - mx) * inv;
                rowcol[row * ROWCAP + pos] = i;
            }
        }
    }
    __syncthreads();
    if (tid == 0) rowcnt[row] = min(s_pos, ROWCAP);
}

// ---------------- zero ----------------
__global__ void zero_k(int* __restrict__ a, float* __restrict__ b, int n)
{
    int i = blockIdx.x * blockDim.x + threadIdx.x;
    if (i < n) { a[i] = 0; b[i] = 0.f; }
}

// ---------------- count column occupancy ----------------
__global__ void count_k(const int* __restrict__ rowcol, const int* __restrict__ rowcnt,
                        int* __restrict__ colcnt)
{
    int row = blockIdx.x;
    int b = row / NN;
    int cnt = rowcnt[row];
    if (threadIdx.x < cnt)
        atomicAdd(&colcnt[b * NN + rowcol[row * ROWCAP + threadIdx.x]], 1);
}

// ---------------- per-batch exclusive scan ----------------
__global__ void __launch_bounds__(256) scan_k(const int* __restrict__ colcnt,
                                              int* __restrict__ coloff, int* __restrict__ colcur)
{
    __shared__ int tsum[257];
    int b = blockIdx.x, tid = threadIdx.x;
    const int* cnt = colcnt + b * NN;
    int local[8];
    int tot = 0;
#pragma unroll
    for (int e = 0; e < 8; e++) {
        int i = tid * 8 + e;
        local[e] = tot;
        tot += (i < NN) ? cnt[i] : 0;
    }
    tsum[tid] = tot;
    __syncthreads();
    if (tid == 0) {
        int acc = 0;
        for (int t = 0; t < 256; t++) { int v = tsum[t]; tsum[t] = acc; acc += v; }
    }
    __syncthreads();
    int base = tsum[tid];
#pragma unroll
    for (int e = 0; e < 8; e++) {
        int i = tid * 8 + e;
        if (i < NN) {
            coloff[b * NN + i] = base + local[e];
            colcur[b * NN + i] = base + local[e];
        }
    }
}

// ---------------- place into CSC ----------------
__global__ void place_k(const float* __restrict__ rowval, const int* __restrict__ rowcol,
                        const int* __restrict__ rowcnt,
                        int* __restrict__ colcur, float* __restrict__ colsum,
                        float* __restrict__ cscval, int* __restrict__ cscrow)
{
    int row = blockIdx.x;
    int b = row / NN, j = row % NN;
    int cnt = rowcnt[row];
    int e = threadIdx.x;
    if (e < cnt) {
        int   c = rowcol[row * ROWCAP + e];
        float w = rowval[row * ROWCAP + e];
        int pos = atomicAdd(&colcur[b * NN + c], 1);
        cscval[(long long)b * CAP + pos] = w;
        cscrow[(long long)b * CAP + pos] = j;
        atomicAdd(&colsum[b * NN + c], w);
    }
}

// ---------------- dinv ----------------
__global__ void dinv_k(const float* __restrict__ colsum, float* __restrict__ dinv, int n)
{
    int i = blockIdx.x * blockDim.x + threadIdx.x;
    if (i < n) dinv[i] = rsqrtf(1.0f + colsum[i]);
}

// ---------------- sparse GCN aggregation, ILP-4 gather ----------------
template<int DIM, int ACT, int OUTH>
__global__ void spagg_k(
    const float* __restrict__ cscval, const int* __restrict__ cscrow,
    const int* __restrict__ coloff, const int* __restrict__ colcnt,
    const __half* __restrict__ T, const float* __restrict__ dinv,
    const float* __restrict__ bias, void* __restrict__ out)
{
    __shared__ float sw[256];
    __shared__ int   sj[256];
    int i = blockIdx.x, b = blockIdx.y, tid = threadIdx.x;
    const __half* Tb = T + (long long)b * NN * DIM;
    int s0  = coloff[b * NN + i];
    int cnt = colcnt[b * NN + i];
    long long base = (long long)b * CAP + s0;

    float2 a0 = __half22float2(*reinterpret_cast<const __half2*>(&Tb[(long long)i * DIM + 2 * tid]));
    float2 a1 = make_float2(0.f, 0.f);
    float2 a2 = make_float2(0.f, 0.f);
    float2 a3 = make_float2(0.f, 0.f);

    for (int e0 = 0; e0 < cnt; e0 += blockDim.x) {
        int chunk = min(cnt - e0, (int)blockDim.x);
        if (tid < chunk) {
            sw[tid] = cscval[base + e0 + tid];
            sj[tid] = cscrow[base + e0 + tid];
        }
        __syncthreads();
        int e = 0;
        for (; e + 3 < chunk; e += 4) {
            float2 t0 = __half22float2(*reinterpret_cast<const __half2*>(&Tb[(long long)sj[e]   * DIM + 2 * tid]));
            float2 t1 = __half22float2(*reinterpret_cast<const __half2*>(&Tb[(long long)sj[e+1] * DIM + 2 * tid]));
            float2 t2 = __half22float2(*reinterpret_cast<const __half2*>(&Tb[(long long)sj[e+2] * DIM + 2 * tid]));
            float2 t3 = __half22float2(*reinterpret_cast<const __half2*>(&Tb[(long long)sj[e+3] * DIM + 2 * tid]));
            a0.x = fmaf(sw[e],   t0.x, a0.x); a0.y = fmaf(sw[e],   t0.y, a0.y);
            a1.x = fmaf(sw[e+1], t1.x, a1.x); a1.y = fmaf(sw[e+1], t1.y, a1.y);
            a2.x = fmaf(sw[e+2], t2.x, a2.x); a2.y = fmaf(sw[e+2], t2.y, a2.y);
            a3.x = fmaf(sw[e+3], t3.x, a3.x); a3.y = fmaf(sw[e+3], t3.y, a3.y);
        }
        for (; e < chunk; e++) {
            float2 t0 = __half22float2(*reinterpret_cast<const __half2*>(&Tb[(long long)sj[e] * DIM + 2 * tid]));
            a0.x = fmaf(sw[e], t0.x, a0.x);
            a0.y = fmaf(sw[e], t0.y, a0.y);
        }
        __syncthreads();
    }
    float dv = dinv[b * NN + i];
    float vx = dv * ((a0.x + a1.x) + (a2.x + a3.x)) + bias[2 * tid];
    float vy = dv * ((a0.y + a1.y) + (a2.y + a3.y)) + bias[2 * tid + 1];
    if (ACT == 1) { vx = fmaxf(vx, 0.f); vy = fmaxf(vy, 0.f); }
    if (OUTH) {
        __half* oh = (__half*)out;
        *reinterpret_cast<__half2*>(&oh[((long long)b * NN + i) * DIM + 2 * tid]) =
            __floats2half2_rn(vx, vy);
    } else {
        float* of = (float*)out;
        *reinterpret_cast<float2*>(&of[((long long)b * NN + i) * DIM + 2 * tid]) = make_float2(vx, vy);
    }
}

// ---------------- mean over nodes; mu/std/z ----------------
__global__ void meanz2_k(const float* __restrict__ O3,
                         const float* __restrict__ eps1, const float* __restrict__ eps2,
                         float* __restrict__ mu1, float* __restrict__ std1,
                         float* __restrict__ mu2, float* __restrict__ std2,
                         float* __restrict__ z)
{
    int b = blockIdx.x, d = threadIdx.x;
    const float* p = O3 + ((long long)b * 2000) * 128 + d;
    float s0 = 0.f, s1 = 0.f, s2 = 0.f, s3 = 0.f;
    for (int i = 0; i < 2000; i += 4) {
        s0 += p[(long long)i * 128];
        s1 += p[(long long)(i + 1) * 128];
        s2 += p[(long long)(i + 2) * 128];
        s3 += p[(long long)(i + 3) * 128];
    }
    __shared__ float sg[128];
    sg[d] = ((s0 + s1) + (s2 + s3)) / 2000.0f;
    __syncthreads();
    if (d < 64) {
        int view = b >> 3, bb = b & 7;
        const float* eps = view ? eps2 : eps1;
        float* mu = view ? mu2 : mu1;
        float* sd = view ? std2 : std1;
        float m = sg[d];
        float sp = log1pf(expf(sg[64 + d] - 64.0f));
        mu[bb * 64 + d] = m;
        sd[bb * 64 + d] = sp;
        z[b * 64 + d] = fmaf(eps[bb * 64 + d], sp, m);
    }
}

// ---------------- decoder ----------------
__global__ void __launch_bounds__(256) decode_k(
    const float* __restrict__ z, const float* __restrict__ w1, const float* __restrict__ b1,
    const float* __restrict__ gamma, const float* __restrict__ beta,
    const float* __restrict__ w2, const float* __restrict__ b2,
    float* __restrict__ xrec)
{
    __shared__ float h[1024];
    __shared__ float zs[64];
    int b = blockIdx.x, tid = threadIdx.x;
    if (tid < 64) zs[tid] = z[b * 64 + tid];
    __syncthreads();
    const float invc = 1.0f / sqrtf(1.0f + 1e-5f);
    for (int c = tid; c < 1024; c += 256) {
        float a = b1[c];
#pragma unroll 8
        for (int k = 0; k < 64; k++) a = fmaf(zs[k], w1[k * 1024 + c], a);
        a = a * (gamma[c] * invc) + beta[c];
        h[c] = fmaxf(a, 0.f);
    }
    __syncthreads();
    int c0 = blockIdx.y * 250;
    int c1 = min(c0 + 250, 2000);
    for (int c = c0 + tid; c < c1; c += 256) {
        float a = b2[c];
        for (int k = 0; k < 1024; k++) a = fmaf(h[k], w2[k * 2000 + c], a);
        xrec[b * 2000 + c] = fmaxf(a, 0.f);
    }
}

// ---------------- host orchestration ----------------
extern "C" void kernel_launch(void* const* d_in, const int* in_sizes, int n_in,
                              void* d_out, int out_size)
{
    const float* x1     = (const float*)d_in[0];
    const float* x2     = (const float*)d_in[1];
    const float* emb1   = (const float*)d_in[2];
    const float* gate_w = (const float*)d_in[3];
    const float* gate_b = (const float*)d_in[4];
    const float* enc_w1 = (const float*)d_in[5];
    const float* enc_b1 = (const float*)d_in[6];
    const float* enc_w2 = (const float*)d_in[7];
    const float* enc_b2 = (const float*)d_in[8];
    const float* gl_w   = (const float*)d_in[9];
    const float* g_w1   = (const float*)d_in[10];
    const float* g_b1   = (const float*)d_in[11];
    const float* g_w2   = (const float*)d_in[12];
    const float* g_b2   = (const float*)d_in[13];
    const float* g_w3   = (const float*)d_in[14];
    const float* g_b3   = (const float*)d_in[15];
    const float* dW1[2] = {(const float*)d_in[16], (const float*)d_in[22]};
    const float* dB1[2] = {(const float*)d_in[17], (const float*)d_in[23]};
    const float* dG [2] = {(const float*)d_in[18], (const float*)d_in[24]};
    const float* dBe[2] = {(const float*)d_in[19], (const float*)d_in[25]};
    const float* dW2[2] = {(const float*)d_in[20], (const float*)d_in[26]};
    const float* dB2[2] = {(const float*)d_in[21], (const float*)d_in[27]};
    const float* epsA[2]= {(const float*)d_in[28], (const float*)d_in[29]};

    static bool attr_done = false;
    if (!attr_done) {
        cudaFuncSetAttribute(hgemm_k<2,0,1>, cudaFuncAttributeMaxDynamicSharedMemorySize, SMEM_BYTES);
        cudaFuncSetAttribute(hgemm_k<0,0,1>, cudaFuncAttributeMaxDynamicSharedMemorySize, SMEM_BYTES);
        cudaFuncSetAttribute(hgemm_k<1,0,1>, cudaFuncAttributeMaxDynamicSharedMemorySize, SMEM_BYTES);
        cudaFuncSetAttribute(hgemm_k<0,1,1>, cudaFuncAttributeMaxDynamicSharedMemorySize, SMEM_BYTES);
        cudaFuncSetAttribute(hgram_k, cudaFuncAttributeMaxDynamicSharedMemorySize, SMEM_BYTES);
        attr_done = true;
    }

    float* sc = nullptr;
    cudaGetSymbolAddress((void**)&sc, g_scratch);
    __half* Agh  = (__half*)(sc + OFF_AGH);
    __half* Henh = (__half*)(sc + OFF_HENH);
    __half* Hh   = (__half*)(sc + OFF_HH);
    __half* GLWt = (__half*)(sc + OFF_GLWT);
    __half* Fh   = (__half*)(sc + OFF_FH);
    float*  att  = sc + OFF_ATT;
    float*  dinv = sc + OFF_DINV;
    __half* Th   = (__half*)(sc + OFF_TH);
    __half* O1h  = (__half*)(sc + OFF_O1H);
    __half* O2h  = (__half*)(sc + OFF_O2H);
    float*  O3   = sc + OFF_O3;
    float*  zb   = sc + OFF_Z;
    __half* W1t  = (__half*)(sc + OFF_W1T);
    __half* W2t  = (__half*)(sc + OFF_W2T);
    __half* GW1t = (__half*)(sc + OFF_GW1T);
    __half* GW2t = (__half*)(sc + OFF_GW2T);
    __half* GW3t = (__half*)(sc + OFF_GW3T);
    float* rowval = sc + OFF_ROWV;
    int*   rowcol = (int*)(sc + OFF_ROWC);
    int*   rowcnt = (int*)(sc + OFF_RCNT);
    int*   colcnt = (int*)(sc + OFF_CCNT);
    int*   coloff = (int*)(sc + OFF_COFF);
    int*   colcur = (int*)(sc + OFF_CCUR);
    float* colsum = sc + OFF_CSUM;
    float* cscval = sc + OFF_CSCV;
    int*   cscrow = (int*)(sc + OFF_CSCR);

    float* out = (float*)d_out;
    float* xrec[2] = {out,          out + 16000};
    float* muo [2] = {out + 32000,  out + 33024};
    float* stdo[2] = {out + 32512,  out + 33536};

    trhalf_k<<<(E_ * HEN + 255) / 256, 256>>>(enc_w1, W1t, E_, HEN);
    trhalf_k<<<(HEN * D_ + 255) / 256, 256>>>(enc_w2, W2t, HEN, D_);
    trhalf_k<<<(D_ * HD + 255) / 256, 256>>>(g_w1, GW1t, D_, HD);
    trhalf_k<<<(HD * HD + 255) / 256, 256>>>(g_w2, GW2t, HD, HD);
    trhalf_k<<<(HD * D_ + 255) / 256, 256>>>(g_w3, GW3t, HD, D_);
    glwt_k<<<(KF * D_ + 255) / 256, 256>>>(gl_w, GLWt);

    // ---- encoders, both views batched (M = 32000) ----
    build_ag2_k<<<(unsigned)((MR2 * E_ + 255) / 256), 256>>>(x1, x2, emb1, gate_w, gate_b, Agh);
    hgemm_k<2,0,1><<<dim3(HEN / 128, 250), 256, SMEM_BYTES>>>(
        (int)MR2, HEN, E_, Agh, W1t, Henh, HEN, enc_b1, nullptr);
    hgemm_k<0,0,1><<<dim3(1, 250), 256, SMEM_BYTES>>>(
        (int)MR2, D_, HEN, Henh, W2t, Hh, D_, enc_b2, nullptr);

    // ---- F = relu(H @ GLW) -> half ----
    hgemm_k<1,0,1><<<dim3(KF / 128, 250), 256, SMEM_BYTES>>>(
        (int)MR2, KF, D_, Hh, GLWt, Fh, KF, nullptr, nullptr);

    // ---- gram (fp32 att output) ----
    hgram_k<<<dim3(16, 16, B2), 256, SMEM_BYTES>>>(Fh, att);

    // ---- sparse adjacency pipeline ----
    zero_k<<<(int)((MR2 + 255) / 256), 256>>>(colcnt, colsum, (int)MR2);
    topk_rows_k<<<(unsigned)MR2, 256>>>(att, rowval, rowcol, rowcnt);
    count_k<<<(unsigned)MR2, ROWCAP>>>(rowcol, rowcnt, colcnt);
    scan_k<<<B2, 256>>>(colcnt, coloff, colcur);
    place_k<<<(unsigned)MR2, ROWCAP>>>(rowval, rowcol, rowcnt, colcur, colsum, cscval, cscrow);
    dinv_k<<<(int)((MR2 + 255) / 256), 256>>>(colsum, dinv, (int)MR2);

    // ---- GCN layers ----
    hgemm_k<0,1,1><<<dim3(HD / 128, 250), 256, SMEM_BYTES>>>(
        (int)MR2, HD, D_, Hh, GW1t, Th, HD, nullptr, dinv);
    spagg_k<HD,1,1><<<dim3(NN, B2), HD/2>>>(cscval, cscrow, coloff, colcnt, Th, dinv, g_b1, O1h);
    hgemm_k<0,1,1><<<dim3(HD / 128, 250), 256, SMEM_BYTES>>>(
        (int)MR2, HD, HD, O1h, GW2t, Th, HD, nullptr, dinv);
    spagg_k<HD,1,1><<<dim3(NN, B2), HD/2>>>(cscval, cscrow, coloff, colcnt, Th, dinv, g_b2, O2h);
    hgemm_k<0,1,1><<<dim3(1, 250), 256, SMEM_BYTES>>>(
        (int)MR2, D_, HD, O2h, GW3t, Th, D_, nullptr, dinv);
    spagg_k<D_,0,0><<<dim3(NN, B2), D_/2>>>(cscval, cscrow, coloff, colcnt, Th, dinv, g_b3, O3);

    // ---- VIB head + decoders ----
    meanz2_k<<<B2, 128>>>(O3, epsA[0], epsA[1], muo[0], stdo[0], muo[1], stdo[1], zb);
    decode_k<<<dim3(8, 8), 256>>>(zb,       dW1[0], dB1[0], dG[0], dBe[0], dW2[0], dB2[0], xrec[0]);
    decode_k<<<dim3(8, 8), 256>>>(zb + 512, dW1[1], dB1[1], dG[1], dBe[1], dW2[1], dB2[1], xrec[1]);
}

// round 14
// speedup vs baseline: 3.7552x; 1.0026x over previous
#include <cuda_runtime.h>
#include <cuda_fp16.h>
#include <math.h>
#include <stdint.h>

// ---------------- problem constants ----------------
constexpr int B_  = 8;
constexpr int B2  = 16;
constexpr int NN  = 2000;
constexpr int E_  = 512;
constexpr int HEN = 1024;
constexpr int D_  = 128;
constexpr int HD  = 512;
constexpr int KF  = 4096;
constexpr int IB_ = 64;
constexpr long long MR  = (long long)B_ * NN;
constexpr long long MR2 = (long long)B2 * NN;   // 32000

constexpr int ROWCAP = 64;
constexpr int CAP    = 131072;

// ---------------- scratch layout ----------------
constexpr long long SZ_AGH  = MR2 * E_ / 2;
constexpr long long SZ_HENH = MR2 * HEN / 2;
constexpr long long SZ_HH   = MR2 * D_ / 2;
constexpr long long SZ_GLWT = (long long)KF * D_ / 2;
constexpr long long SZ_FH   = MR2 * KF / 2;
constexpr long long SZ_ATT  = (long long)B2 * NN * NN;     // fp32 att (exact top-k)
constexpr long long SZ_DINV = MR2;
constexpr long long SZ_TH   = MR2 * HD / 2;
constexpr long long SZ_OH   = MR2 * HD / 2;
constexpr long long SZ_O3   = MR2 * D_;
constexpr long long SZ_Z    = (long long)B2 * IB_;
constexpr long long SZ_W1T  = (long long)HEN * E_ / 2;
constexpr long long SZ_W2T  = (long long)D_ * HEN / 2;
constexpr long long SZ_GW1T = (long long)HD * D_ / 2;
constexpr long long SZ_GW2T = (long long)HD * HD / 2;
constexpr long long SZ_GW3T = (long long)D_ * HD / 2;
constexpr long long SZ_ROWV = MR2 * ROWCAP;
constexpr long long SZ_ROWC = MR2 * ROWCAP;
constexpr long long SZ_RCNT = MR2;
constexpr long long SZ_CCNT = MR2;
constexpr long long SZ_COFF = MR2;
constexpr long long SZ_CCUR = MR2;
constexpr long long SZ_CSUM = MR2;
constexpr long long SZ_CSCV = (long long)B2 * CAP;
constexpr long long SZ_CSCR = (long long)B2 * CAP;

constexpr long long OFF_AGH  = 0;
constexpr long long OFF_HENH = OFF_AGH + SZ_AGH;
constexpr long long OFF_HH   = OFF_HENH + SZ_HENH;
constexpr long long OFF_GLWT = OFF_HH + SZ_HH;
constexpr long long OFF_FH   = OFF_GLWT + SZ_GLWT;
constexpr long long OFF_ATT  = OFF_FH + SZ_FH;
constexpr long long OFF_DINV = OFF_ATT + SZ_ATT;
constexpr long long OFF_TH   = OFF_DINV + SZ_DINV;
constexpr long long OFF_O1H  = OFF_TH + SZ_TH;
constexpr long long OFF_O2H  = OFF_O1H + SZ_OH;
constexpr long long OFF_O3   = OFF_O2H + SZ_OH;
constexpr long long OFF_Z    = OFF_O3 + SZ_O3;
constexpr long long OFF_W1T  = OFF_Z + SZ_Z;
constexpr long long OFF_W2T  = OFF_W1T + SZ_W1T;
constexpr long long OFF_GW1T = OFF_W2T + SZ_W2T;
constexpr long long OFF_GW2T = OFF_GW1T + SZ_GW1T;
constexpr long long OFF_GW3T = OFF_GW2T + SZ_GW2T;
constexpr long long OFF_ROWV = OFF_GW3T + SZ_GW3T;
constexpr long long OFF_ROWC = OFF_ROWV + SZ_ROWV;
constexpr long long OFF_RCNT = OFF_ROWC + SZ_ROWC;
constexpr long long OFF_CCNT = OFF_RCNT + SZ_RCNT;
constexpr long long OFF_COFF = OFF_CCNT + SZ_CCNT;
constexpr long long OFF_CCUR = OFF_COFF + SZ_COFF;
constexpr long long OFF_CSUM = OFF_CCUR + SZ_CCUR;
constexpr long long OFF_CSCV = OFF_CSUM + SZ_CSUM;
constexpr long long OFF_CSCR = OFF_CSCV + SZ_CSCV;
constexpr long long SCRATCH_TOTAL = OFF_CSCR + SZ_CSCR;

__device__ float g_scratch[SCRATCH_TOTAL];

// ---------------- helpers ----------------
__device__ __forceinline__ void mma_f16(float* c, const uint32_t* a, uint32_t b0, uint32_t b1) {
    asm volatile(
        "mma.sync.aligned.m16n8k16.row.col.f32.f16.f16.f32 "
        "{%0,%1,%2,%3}, {%4,%5,%6,%7}, {%8,%9}, {%0,%1,%2,%3};"
        : "+f"(c[0]), "+f"(c[1]), "+f"(c[2]), "+f"(c[3])
        : "r"(a[0]), "r"(a[1]), "r"(a[2]), "r"(a[3]), "r"(b0), "r"(b1));
}

__device__ __forceinline__ void ldsm4(uint32_t* r, uint32_t addr) {
    asm volatile("ldmatrix.sync.aligned.m8n8.x4.shared.b16 {%0,%1,%2,%3}, [%4];"
                 : "=r"(r[0]), "=r"(r[1]), "=r"(r[2]), "=r"(r[3]) : "r"(addr));
}

__device__ __forceinline__ void cpa16(uint32_t dst, const void* src, bool pred) {
    int sz = pred ? 16 : 0;
    asm volatile("cp.async.cg.shared.global [%0], [%1], 16, %2;\n"
                 :: "r"(dst), "l"(src), "r"(sz));
}
__device__ __forceinline__ void cpa_commit() { asm volatile("cp.async.commit_group;\n"); }
__device__ __forceinline__ void cpa_wait1()  { asm volatile("cp.async.wait_group 1;\n"); }

__device__ __forceinline__ uint32_t smem_u32(const void* p) {
    uint32_t a;
    asm("{ .reg .u64 t; cvta.to.shared.u64 t, %1; cvt.u32.u64 %0, t; }" : "=r"(a) : "l"(p));
    return a;
}

constexpr int PK = 20;
constexpr int ASTG = 2560;
constexpr int BSTG = 2560;
constexpr int SMEM_BYTES = (3 * ASTG + 3 * BSTG) * 4;   // 61440

// ================= unified fp16 GEMM =================
template<int ACT, int EPI, int OUTH>
__global__ void __launch_bounds__(256, 2) hgemm_k(
    int M, int N, int K,
    const __half* __restrict__ A,
    const __half* __restrict__ Bt,
    void* __restrict__ C, int ldc,
    const float* __restrict__ bias,
    const float* __restrict__ dinv)
{
    extern __shared__ uint32_t sh[];
    const int bn = blockIdx.x, bm = blockIdx.y;
    const int m0 = bm * 128, n0 = bn * 128;

    const int tid  = threadIdx.x;
    const int lane = tid & 31, warp = tid >> 5;
    const int g = lane >> 2, th = lane & 3;
    const int wm = (warp >> 1) * 32;
    const int wn = (warp & 1) * 64;
    const int r8 = lane & 7, sel = lane >> 3;

    uint32_t sbase = smem_u32(sh);

    float acc[2][8][4];
#pragma unroll
    for (int i = 0; i < 2; i++)
#pragma unroll
        for (int j = 0; j < 8; j++)
#pragma unroll
            for (int l = 0; l < 4; l++) acc[i][j][l] = 0.f;

    const int KT = K / 32;

    auto issue = [&](int kt, int stg) {
        uint32_t abase = sbase + (uint32_t)(stg * ASTG) * 4u;
        uint32_t bbase = sbase + (uint32_t)(3 * ASTG + stg * BSTG) * 4u;
#pragma unroll
        for (int it = 0; it < 2; it++) {
            int c = tid * 2 + it;
            int row = c >> 2, kc = c & 3;
            const __half* srcA = A + (long long)(m0 + row) * K + kt * 32 + kc * 8;
            cpa16(abase + (uint32_t)(row * PK + kc * 4) * 4u, srcA, (m0 + row) < M);
            const __half* srcB = Bt + (long long)(n0 + row) * K + kt * 32 + kc * 8;
            cpa16(bbase + (uint32_t)(row * PK + kc * 4) * 4u, srcB, (n0 + row) < N);
        }
    };

    auto mmaTile = [&](int stg) {
        uint32_t abase = sbase + (uint32_t)(stg * ASTG) * 4u;
        uint32_t bbase = sbase + (uint32_t)(3 * ASTG + stg * BSTG) * 4u;
#pragma unroll
        for (int s = 0; s < 2; s++) {
            const int k0 = s * 8;
            uint32_t a[2][4];
#pragma unroll
            for (int mt = 0; mt < 2; mt++) {
                int row = wm + mt * 16 + ((sel & 1) << 3) + r8;
                int ku  = k0 + ((sel & 2) << 1);
                ldsm4(a[mt], abase + (uint32_t)(row * PK + ku) * 4u);
            }
            uint32_t b0v[8], b1v[8];
#pragma unroll
            for (int g4 = 0; g4 < 2; g4++) {
                int row = wn + g4 * 32 + sel * 8 + r8;
                ldsm4(&b0v[g4 * 4], bbase + (uint32_t)(row * PK + k0) * 4u);
                ldsm4(&b1v[g4 * 4], bbase + (uint32_t)(row * PK + k0 + 4) * 4u);
            }
#pragma unroll
            for (int nt = 0; nt < 8; nt++) {
                mma_f16(acc[0][nt], a[0], b0v[nt], b1v[nt]);
                mma_f16(acc[1][nt], a[1], b0v[nt], b1v[nt]);
            }
        }
    };

    issue(0, 0); cpa_commit();
    if (KT > 1) issue(1, 1);
    cpa_commit();
    cpa_wait1();
    __syncthreads();

    for (int kt = 0; kt < KT; kt++) {
        int stg = kt % 3;
        if (kt + 2 < KT) issue(kt + 2, (kt + 2) % 3);
        cpa_commit();
        mmaTile(stg);
        cpa_wait1();
        __syncthreads();
    }

    __half* Ch = (__half*)C;
    float*  Cf = (float*)C;
#pragma unroll
    for (int mt = 0; mt < 2; mt++) {
#pragma unroll
        for (int nt = 0; nt < 8; nt++) {
#pragma unroll
            for (int eh = 0; eh < 2; eh++) {
                int gm = m0 + wm + mt * 16 + g + (eh ? 8 : 0);
                int gn = n0 + wn + nt * 8 + 2 * th;
                if (gm >= M || gn >= N) continue;
                float v0 = acc[mt][nt][eh * 2 + 0];
                float v1 = acc[mt][nt][eh * 2 + 1];
                if (EPI == 1) { float dv = dinv[gm]; v0 *= dv; v1 *= dv; }
                if (bias)     { v0 += bias[gn]; v1 += bias[gn + 1]; }
                if (ACT == 1) { v0 = fmaxf(v0, 0.f); v1 = fmaxf(v1, 0.f); }
                if (ACT == 2) {
                    v0 = 0.5f * v0 * (1.f + erff(v0 * 0.70710678118654752f));
                    v1 = 0.5f * v1 * (1.f + erff(v1 * 0.70710678118654752f));
                }
                if (OUTH) {
                    *reinterpret_cast<__half2*>(&Ch[(long long)gm * ldc + gn]) =
                        __floats2half2_rn(v0, v1);
                } else {
                    Cf[(long long)gm * ldc + gn]     = v0;
                    Cf[(long long)gm * ldc + gn + 1] = v1;
                }
            }
        }
    }
}

// ---------------- fp16 gram, fp32 att; coalesced mirror via smem transpose ----------------
__global__ void __launch_bounds__(256, 2) hgram_k(const __half* __restrict__ F,
                                                  float* __restrict__ att)
{
    extern __shared__ uint32_t sh[];
    const int bn = blockIdx.x, bm = blockIdx.y, b = blockIdx.z;
    if (bm > bn) return;
    const int m0 = bm * 128, n0 = bn * 128;

    const int tid  = threadIdx.x;
    const int lane = tid & 31, warp = tid >> 5;
    const int g = lane >> 2, th = lane & 3;
    const int wm = (warp >> 1) * 32;
    const int wn = (warp & 1) * 64;
    const int r8 = lane & 7, sel = lane >> 3;

    uint32_t sbase = smem_u32(sh);
    const __half* Fb = F + (long long)b * NN * KF;
    float* attb = att + (long long)b * NN * NN;

    float acc[2][8][4];
#pragma unroll
    for (int i = 0; i < 2; i++)
#pragma unroll
        for (int j = 0; j < 8; j++)
#pragma unroll
            for (int l = 0; l < 4; l++) acc[i][j][l] = 0.f;

    const int KT = KF / 32;

    auto issue = [&](int kt, int stg) {
        uint32_t abase = sbase + (uint32_t)(stg * ASTG) * 4u;
        uint32_t bbase = sbase + (uint32_t)(3 * ASTG + stg * BSTG) * 4u;
#pragma unroll
        for (int it = 0; it < 2; it++) {
            int c = tid * 2 + it;
            int row = c >> 2, kc = c & 3;
            const __half* srcA = Fb + (long long)(m0 + row) * KF + kt * 32 + kc * 8;
            cpa16(abase + (uint32_t)(row * PK + kc * 4) * 4u, srcA, (m0 + row) < NN);
            const __half* srcB = Fb + (long long)(n0 + row) * KF + kt * 32 + kc * 8;
            cpa16(bbase + (uint32_t)(row * PK + kc * 4) * 4u, srcB, (n0 + row) < NN);
        }
    };

    auto mmaTile = [&](int stg) {
        uint32_t abase = sbase + (uint32_t)(stg * ASTG) * 4u;
        uint32_t bbase = sbase + (uint32_t)(3 * ASTG + stg * BSTG) * 4u;
#pragma unroll
        for (int s = 0; s < 2; s++) {
            const int k0 = s * 8;
            uint32_t a[2][4];
#pragma unroll
            for (int mt = 0; mt < 2; mt++) {
                int row = wm + mt * 16 + ((sel & 1) << 3) + r8;
                int ku  = k0 + ((sel & 2) << 1);
                ldsm4(a[mt], abase + (uint32_t)(row * PK + ku) * 4u);
            }
            uint32_t b0v[8], b1v[8];
#pragma unroll
            for (int g4 = 0; g4 < 2; g4++) {
                int row = wn + g4 * 32 + sel * 8 + r8;
                ldsm4(&b0v[g4 * 4], bbase + (uint32_t)(row * PK + k0) * 4u);
                ldsm4(&b1v[g4 * 4], bbase + (uint32_t)(row * PK + k0 + 4) * 4u);
            }
#pragma unroll
            for (int nt = 0; nt < 8; nt++) {
                mma_f16(acc[0][nt], a[0], b0v[nt], b1v[nt]);
                mma_f16(acc[1][nt], a[1], b0v[nt], b1v[nt]);
            }
        }
    };

    issue(0, 0); cpa_commit();
    if (KT > 1) issue(1, 1);
    cpa_commit();
    cpa_wait1();
    __syncthreads();

    for (int kt = 0; kt < KT; kt++) {
        int stg = kt % 3;
        if (kt + 2 < KT) issue(kt + 2, (kt + 2) % 3);
        cpa_commit();
        mmaTile(stg);
        cpa_wait1();
        __syncthreads();
    }

    // ---- direct stores: float2 (adjacent columns) ----
#pragma unroll
    for (int mt = 0; mt < 2; mt++) {
#pragma unroll
        for (int nt = 0; nt < 8; nt++) {
#pragma unroll
            for (int eh = 0; eh < 2; eh++) {
                int gm = m0 + wm + mt * 16 + g + (eh ? 8 : 0);
                int gn = n0 + wn + nt * 8 + 2 * th;
                if (gm >= NN || gn + 1 >= NN) continue;
                float2 v = make_float2(0.125f * acc[mt][nt][eh * 2 + 0],
                                       0.125f * acc[mt][nt][eh * 2 + 1]);
                *reinterpret_cast<float2*>(&attb[(long long)gm * NN + gn]) = v;
            }
        }
    }

    // ---- mirror stores: transpose through smem, write coalesced rows ----
    if (bm < bn) {
        float* smf = reinterpret_cast<float*>(sh);   // 64 x 132 floats = 33 KB
#pragma unroll
        for (int p = 0; p < 2; p++) {
            if ((warp & 1) == p) {
#pragma unroll
                for (int mt = 0; mt < 2; mt++) {
#pragma unroll
                    for (int nt = 0; nt < 8; nt++) {
#pragma unroll
                        for (int eh = 0; eh < 2; eh++) {
                            int gml  = wm + mt * 16 + g + (eh ? 8 : 0);
                            int rowl = nt * 8 + 2 * th;       // gn local within 64-row pass
                            smf[rowl * 132 + gml]       = 0.125f * acc[mt][nt][eh * 2 + 0];
                            smf[(rowl + 1) * 132 + gml] = 0.125f * acc[mt][nt][eh * 2 + 1];
                        }
                    }
                }
            }
            __syncthreads();
            for (int idx = tid; idx < 2048; idx += 256) {
                int rowl = idx >> 5, c4 = (idx & 31) << 2;
                int gn = n0 + p * 64 + rowl;
                if (gn < NN && m0 + c4 + 3 < NN) {
                    float4 v = *reinterpret_cast<float4*>(&smf[rowl * 132 + c4]);
                    *reinterpret_cast<float4*>(&attb[(long long)gn * NN + m0 + c4]) = v;
                }
            }
            __syncthreads();
        }
    }
}

// ---------------- weight transpose to half ----------------
__global__ void trhalf_k(const float* __restrict__ src, __half* __restrict__ dst, int K, int N)
{
    int idx = blockIdx.x * blockDim.x + threadIdx.x;
    if (idx >= K * N) return;
    int n = idx / K, k = idx % K;
    dst[(long long)n * K + k] = __float2half_rn(src[(long long)k * N + n]);
}

// ---------------- gl_w -> GLWt half [KF, D] ----------------
__global__ void glwt_k(const float* __restrict__ glw, __half* __restrict__ GLWt)
{
    int idx = blockIdx.x * blockDim.x + threadIdx.x;
    if (idx >= KF * D_) return;
    int c = idx / D_, k = idx % D_;
    int p = c >> 9, hh = c & 511;
    GLWt[idx] = __float2half_rn(glw[((long long)p * D_ + k) * HD + hh]);
}

// ---------------- A-matrix builder ----------------
__global__ void build_ag2_k(const float* __restrict__ x1, const float* __restrict__ x2,
                            const float* __restrict__ emb,
                            const float* __restrict__ gw, const float* __restrict__ gb,
                            __half* __restrict__ Ag)
{
    long long idx = (long long)blockIdx.x * blockDim.x + threadIdx.x;
    if (idx >= MR2 * E_) return;
    int e = (int)(idx & (E_ - 1));
    long long r = idx >> 9;
    long long rv = (r < MR) ? r : r - MR;
    const float* x = (r < MR) ? x1 : x2;
    int n = (int)(rv % NN);
    float t = fmaf(x[rv], gw[e], gb[e]);
    float sgm = 1.0f / (1.0f + expf(-t));
    Ag[idx] = __float2half_rn(sgm * emb[(long long)n * E_ + e]);
}

// ---------------- top-k(50): register-resident, fp32 att ----------------
__global__ void __launch_bounds__(256) topk_rows_k(
    const float* __restrict__ att,
    float* __restrict__ rowval, int* __restrict__ rowcol, int* __restrict__ rowcnt)
{
    __shared__ int   hist[256];
    __shared__ float wredf[8];
    __shared__ float s_bcast;
    __shared__ int   s_selb, s_selk, s_pos;

    long long row = blockIdx.x;
    const float* r = att + row * 2000;
    int tid = threadIdx.x;
    int lane = tid & 31, wid = tid >> 5;

    float v[8];
#pragma unroll
    for (int p = 0; p < 8; p++) {
        int i = tid + p * 256;
        v[p] = (i < 2000) ? r[i] : 0.f;
    }
    if (tid == 0) s_pos = 0;

    float mx = 0.f;
#pragma unroll
    for (int p = 0; p < 8; p++) mx = fmaxf(mx, v[p]);
#pragma unroll
    for (int o = 16; o; o >>= 1) mx = fmaxf(mx, __shfl_xor_sync(0xffffffffu, mx, o));
    if (lane == 0) wredf[wid] = mx;
    __syncthreads();
    if (tid == 0) { float m = wredf[0]; for (int w = 1; w < 8; w++) m = fmaxf(m, wredf[w]); s_bcast = m; }
    __syncthreads();
    mx = s_bcast;

    unsigned prefix = 0u;
    int k = 50;
#pragma unroll
    for (int pass = 0; pass < 4; pass++) {
        const int shift = 24 - 8 * pass;
        const unsigned hmask = (pass == 0) ? 0u : (0xFFFFFFFFu << (shift + 8));
        if (tid < 256) hist[tid] = 0;
        __syncthreads();
#pragma unroll
        for (int p = 0; p < 8; p++) {
            int i = tid + p * 256;
            if (i < 2000) {
                unsigned u = __float_as_uint(v[p]);
                if ((u & hmask) == prefix)
                    atomicAdd(&hist[(u >> shift) & 255], 1);
            }
        }
        __syncthreads();
        if (tid == 0) {
            int acc = 0, b = 255;
            for (; b > 0; b--) { acc += hist[b]; if (acc >= k) break; }
            if (acc < k) acc += hist[0];
            s_selb = b;
            s_selk = k - (acc - hist[b]);
        }
        __syncthreads();
        prefix |= ((unsigned)s_selb) << shift;
        k = s_selk;
        __syncthreads();
    }
    float thr = __uint_as_float(prefix);

    float sum = 0.f;
#pragma unroll
    for (int p = 0; p < 8; p++) {
        int i = tid + p * 256;
        if (i < 2000 && v[p] >= thr) sum += expf(v[p] - mx);
    }
#pragma unroll
    for (int o = 16; o; o >>= 1) sum += __shfl_xor_sync(0xffffffffu, sum, o);
    if (lane == 0) wredf[wid] = sum;
    __syncthreads();
    if (tid == 0) { float t = 0.f; for (int w = 0; w < 8; w++) t += wredf[w]; s_bcast = t; }
    __syncthreads();
    float inv = 1.0f / s_bcast;

#pragma unroll
    for (int p = 0; p < 8; p++) {
        int i = tid + p * 256;
        if (i < 2000 && v[p] >= thr) {
            int pos = atomicAdd(&s_pos, 1);
            if (pos < ROWCAP) {
                rowval[row * ROWCAP + pos] = expf(v[p] - mx) * inv;
                rowcol[row * ROWCAP + pos] = i;
            }
        }
    }
    __syncthreads();
    if (tid == 0) rowcnt[row] = min(s_pos, ROWCAP);
}

// ---------------- zero ----------------
__global__ void zero_k(int* __restrict__ a, float* __restrict__ b, int n)
{
    int i = blockIdx.x * blockDim.x + threadIdx.x;
    if (i < n) { a[i] = 0; b[i] = 0.f; }
}

// ---------------- count column occupancy ----------------
__global__ void count_k(const int* __restrict__ rowcol, const int* __restrict__ rowcnt,
                        int* __restrict__ colcnt)
{
    int row = blockIdx.x;
    int b = row / NN;
    int cnt = rowcnt[row];
    if (threadIdx.x < cnt)
        atomicAdd(&colcnt[b * NN + rowcol[row * ROWCAP + threadIdx.x]], 1);
}

// ---------------- per-batch exclusive scan ----------------
__global__ void __launch_bounds__(256) scan_k(const int* __restrict__ colcnt,
                                              int* __restrict__ coloff, int* __restrict__ colcur)
{
    __shared__ int tsum[257];
    int b = blockIdx.x, tid = threadIdx.x;
    const int* cnt = colcnt + b * NN;
    int local[8];
    int tot = 0;
#pragma unroll
    for (int e = 0; e < 8; e++) {
        int i = tid * 8 + e;
        local[e] = tot;
        tot += (i < NN) ? cnt[i] : 0;
    }
    tsum[tid] = tot;
    __syncthreads();
    if (tid == 0) {
        int acc = 0;
        for (int t = 0; t < 256; t++) { int v = tsum[t]; tsum[t] = acc; acc += v; }
    }
    __syncthreads();
    int base = tsum[tid];
#pragma unroll
    for (int e = 0; e < 8; e++) {
        int i = tid * 8 + e;
        if (i < NN) {
            coloff[b * NN + i] = base + local[e];
            colcur[b * NN + i] = base + local[e];
        }
    }
}

// ---------------- place into CSC ----------------
__global__ void place_k(const float* __restrict__ rowval, const int* __restrict__ rowcol,
                        const int* __restrict__ rowcnt,
                        int* __restrict__ colcur, float* __restrict__ colsum,
                        float* __restrict__ cscval, int* __restrict__ cscrow)
{
    int row = blockIdx.x;
    int b = row / NN, j = row % NN;
    int cnt = rowcnt[row];
    int e = threadIdx.x;
    if (e < cnt) {
        int   c = rowcol[row * ROWCAP + e];
        float w = rowval[row * ROWCAP + e];
        int pos = atomicAdd(&colcur[b * NN + c], 1);
        cscval[(long long)b * CAP + pos] = w;
        cscrow[(long long)b * CAP + pos] = j;
        atomicAdd(&colsum[b * NN + c], w);
    }
}

// ---------------- dinv ----------------
__global__ void dinv_k(const float* __restrict__ colsum, float* __restrict__ dinv, int n)
{
    int i = blockIdx.x * blockDim.x + threadIdx.x;
    if (i < n) dinv[i] = rsqrtf(1.0f + colsum[i]);
}

// ---------------- sparse GCN aggregation, ILP-4 gather ----------------
template<int DIM, int ACT, int OUTH>
__global__ void spagg_k(
    const float* __restrict__ cscval, const int* __restrict__ cscrow,
    const int* __restrict__ coloff, const int* __restrict__ colcnt,
    const __half* __restrict__ T, const float* __restrict__ dinv,
    const float* __restrict__ bias, void* __restrict__ out)
{
    __shared__ float sw[256];
    __shared__ int   sj[256];
    int i = blockIdx.x, b = blockIdx.y, tid = threadIdx.x;
    const __half* Tb = T + (long long)b * NN * DIM;
    int s0  = coloff[b * NN + i];
    int cnt = colcnt[b * NN + i];
    long long base = (long long)b * CAP + s0;

    float2 a0 = __half22float2(*reinterpret_cast<const __half2*>(&Tb[(long long)i * DIM + 2 * tid]));
    float2 a1 = make_float2(0.f, 0.f);
    float2 a2 = make_float2(0.f, 0.f);
    float2 a3 = make_float2(0.f, 0.f);

    for (int e0 = 0; e0 < cnt; e0 += blockDim.x) {
        int chunk = min(cnt - e0, (int)blockDim.x);
        if (tid < chunk) {
            sw[tid] = cscval[base + e0 + tid];
            sj[tid] = cscrow[base + e0 + tid];
        }
        __syncthreads();
        int e = 0;
        for (; e + 3 < chunk; e += 4) {
            float2 t0 = __half22float2(*reinterpret_cast<const __half2*>(&Tb[(long long)sj[e]   * DIM + 2 * tid]));
            float2 t1 = __half22float2(*reinterpret_cast<const __half2*>(&Tb[(long long)sj[e+1] * DIM + 2 * tid]));
            float2 t2 = __half22float2(*reinterpret_cast<const __half2*>(&Tb[(long long)sj[e+2] * DIM + 2 * tid]));
            float2 t3 = __half22float2(*reinterpret_cast<const __half2*>(&Tb[(long long)sj[e+3] * DIM + 2 * tid]));
            a0.x = fmaf(sw[e],   t0.x, a0.x); a0.y = fmaf(sw[e],   t0.y, a0.y);
            a1.x = fmaf(sw[e+1], t1.x, a1.x); a1.y = fmaf(sw[e+1], t1.y, a1.y);
            a2.x = fmaf(sw[e+2], t2.x, a2.x); a2.y = fmaf(sw[e+2], t2.y, a2.y);
            a3.x = fmaf(sw[e+3], t3.x, a3.x); a3.y = fmaf(sw[e+3], t3.y, a3.y);
        }
        for (; e < chunk; e++) {
            float2 t0 = __half22float2(*reinterpret_cast<const __half2*>(&Tb[(long long)sj[e] * DIM + 2 * tid]));
            a0.x = fmaf(sw[e], t0.x, a0.x);
            a0.y = fmaf(sw[e], t0.y, a0.y);
        }
        __syncthreads();
    }
    float dv = dinv[b * NN + i];
    float vx = dv * ((a0.x + a1.x) + (a2.x + a3.x)) + bias[2 * tid];
    float vy = dv * ((a0.y + a1.y) + (a2.y + a3.y)) + bias[2 * tid + 1];
    if (ACT == 1) { vx = fmaxf(vx, 0.f); vy = fmaxf(vy, 0.f); }
    if (OUTH) {
        __half* oh = (__half*)out;
        *reinterpret_cast<__half2*>(&oh[((long long)b * NN + i) * DIM + 2 * tid]) =
            __floats2half2_rn(vx, vy);
    } else {
        float* of = (float*)out;
        *reinterpret_cast<float2*>(&of[((long long)b * NN + i) * DIM + 2 * tid]) = make_float2(vx, vy);
    }
}

// ---------------- mean over nodes; mu/std/z ----------------
__global__ void meanz2_k(const float* __restrict__ O3,
                         const float* __restrict__ eps1, const float* __restrict__ eps2,
                         float* __restrict__ mu1, float* __restrict__ std1,
                         float* __restrict__ mu2, float* __restrict__ std2,
                         float* __restrict__ z)
{
    int b = blockIdx.x, d = threadIdx.x;
    const float* p = O3 + ((long long)b * 2000) * 128 + d;
    float s0 = 0.f, s1 = 0.f, s2 = 0.f, s3 = 0.f;
    for (int i = 0; i < 2000; i += 4) {
        s0 += p[(long long)i * 128];
        s1 += p[(long long)(i + 1) * 128];
        s2 += p[(long long)(i + 2) * 128];
        s3 += p[(long long)(i + 3) * 128];
    }
    __shared__ float sg[128];
    sg[d] = ((s0 + s1) + (s2 + s3)) / 2000.0f;
    __syncthreads();
    if (d < 64) {
        int view = b >> 3, bb = b & 7;
        const float* eps = view ? eps2 : eps1;
        float* mu = view ? mu2 : mu1;
        float* sd = view ? std2 : std1;
        float m = sg[d];
        float sp = log1pf(expf(sg[64 + d] - 64.0f));
        mu[bb * 64 + d] = m;
        sd[bb * 64 + d] = sp;
        z[b * 64 + d] = fmaf(eps[bb * 64 + d], sp, m);
    }
}

// ---------------- decoder ----------------
__global__ void __launch_bounds__(256) decode_k(
    const float* __restrict__ z, const float* __restrict__ w1, const float* __restrict__ b1,
    const float* __restrict__ gamma, const float* __restrict__ beta,
    const float* __restrict__ w2, const float* __restrict__ b2,
    float* __restrict__ xrec)
{
    __shared__ float h[1024];
    __shared__ float zs[64];
    int b = blockIdx.x, tid = threadIdx.x;
    if (tid < 64) zs[tid] = z[b * 64 + tid];
    __syncthreads();
    const float invc = 1.0f / sqrtf(1.0f + 1e-5f);
    for (int c = tid; c < 1024; c += 256) {
        float a = b1[c];
#pragma unroll 8
        for (int k = 0; k < 64; k++) a = fmaf(zs[k], w1[k * 1024 + c], a);
        a = a * (gamma[c] * invc) + beta[c];
        h[c] = fmaxf(a, 0.f);
    }
    __syncthreads();
    int c0 = blockIdx.y * 250;
    int c1 = min(c0 + 250, 2000);
    for (int c = c0 + tid; c < c1; c += 256) {
        float a = b2[c];
        for (int k = 0; k < 1024; k++) a = fmaf(h[k], w2[k * 2000 + c], a);
        xrec[b * 2000 + c] = fmaxf(a, 0.f);
    }
}

// ---------------- host orchestration ----------------
extern "C" void kernel_launch(void* const* d_in, const int* in_sizes, int n_in,
                              void* d_out, int out_size)
{
    const float* x1     = (const float*)d_in[0];
    const float* x2     = (const float*)d_in[1];
    const float* emb1   = (const float*)d_in[2];
    const float* gate_w = (const float*)d_in[3];
    const float* gate_b = (const float*)d_in[4];
    const float* enc_w1 = (const float*)d_in[5];
    const float* enc_b1 = (const float*)d_in[6];
    const float* enc_w2 = (const float*)d_in[7];
    const float* enc_b2 = (const float*)d_in[8];
    const float* gl_w   = (const float*)d_in[9];
    const float* g_w1   = (const float*)d_in[10];
    const float* g_b1   = (const float*)d_in[11];
    const float* g_w2   = (const float*)d_in[12];
    const float* g_b2   = (const float*)d_in[13];
    const float* g_w3   = (const float*)d_in[14];
    const float* g_b3   = (const float*)d_in[15];
    const float* dW1[2] = {(const float*)d_in[16], (const float*)d_in[22]};
    const float* dB1[2] = {(const float*)d_in[17], (const float*)d_in[23]};
    const float* dG [2] = {(const float*)d_in[18], (const float*)d_in[24]};
    const float* dBe[2] = {(const float*)d_in[19], (const float*)d_in[25]};
    const float* dW2[2] = {(const float*)d_in[20], (const float*)d_in[26]};
    const float* dB2[2] = {(const float*)d_in[21], (const float*)d_in[27]};
    const float* epsA[2]= {(const float*)d_in[28], (const float*)d_in[29]};

    static bool attr_done = false;
    if (!attr_done) {
        cudaFuncSetAttribute(hgemm_k<2,0,1>, cudaFuncAttributeMaxDynamicSharedMemorySize, SMEM_BYTES);
        cudaFuncSetAttribute(hgemm_k<0,0,1>, cudaFuncAttributeMaxDynamicSharedMemorySize, SMEM_BYTES);
        cudaFuncSetAttribute(hgemm_k<1,0,1>, cudaFuncAttributeMaxDynamicSharedMemorySize, SMEM_BYTES);
        cudaFuncSetAttribute(hgemm_k<0,1,1>, cudaFuncAttributeMaxDynamicSharedMemorySize, SMEM_BYTES);
        cudaFuncSetAttribute(hgram_k, cudaFuncAttributeMaxDynamicSharedMemorySize, SMEM_BYTES);
        attr_done = true;
    }

    float* sc = nullptr;
    cudaGetSymbolAddress((void**)&sc, g_scratch);
    __half* Agh  = (__half*)(sc + OFF_AGH);
    __half* Henh = (__half*)(sc + OFF_HENH);
    __half* Hh   = (__half*)(sc + OFF_HH);
    __half* GLWt = (__half*)(sc + OFF_GLWT);
    __half* Fh   = (__half*)(sc + OFF_FH);
    float*  att  = sc + OFF_ATT;
    float*  dinv = sc + OFF_DINV;
    __half* Th   = (__half*)(sc + OFF_TH);
    __half* O1h  = (__half*)(sc + OFF_O1H);
    __half* O2h  = (__half*)(sc + OFF_O2H);
    float*  O3   = sc + OFF_O3;
    float*  zb   = sc + OFF_Z;
    __half* W1t  = (__half*)(sc + OFF_W1T);
    __half* W2t  = (__half*)(sc + OFF_W2T);
    __half* GW1t = (__half*)(sc + OFF_GW1T);
    __half* GW2t = (__half*)(sc + OFF_GW2T);
    __half* GW3t = (__half*)(sc + OFF_GW3T);
    float* rowval = sc + OFF_ROWV;
    int*   rowcol = (int*)(sc + OFF_ROWC);
    int*   rowcnt = (int*)(sc + OFF_RCNT);
    int*   colcnt = (int*)(sc + OFF_CCNT);
    int*   coloff = (int*)(sc + OFF_COFF);
    int*   colcur = (int*)(sc + OFF_CCUR);
    float* colsum = sc + OFF_CSUM;
    float* cscval = sc + OFF_CSCV;
    int*   cscrow = (int*)(sc + OFF_CSCR);

    float* out = (float*)d_out;
    float* xrec[2] = {out,          out + 16000};
    float* muo [2] = {out + 32000,  out + 33024};
    float* stdo[2] = {out + 32512,  out + 33536};

    trhalf_k<<<(E_ * HEN + 255) / 256, 256>>>(enc_w1, W1t, E_, HEN);
    trhalf_k<<<(HEN * D_ + 255) / 256, 256>>>(enc_w2, W2t, HEN, D_);
    trhalf_k<<<(D_ * HD + 255) / 256, 256>>>(g_w1, GW1t, D_, HD);
    trhalf_k<<<(HD * HD + 255) / 256, 256>>>(g_w2, GW2t, HD, HD);
    trhalf_k<<<(HD * D_ + 255) / 256, 256>>>(g_w3, GW3t, HD, D_);
    glwt_k<<<(KF * D_ + 255) / 256, 256>>>(gl_w, GLWt);

    // ---- encoders, both views batched (M = 32000) ----
    build_ag2_k<<<(unsigned)((MR2 * E_ + 255) / 256), 256>>>(x1, x2, emb1, gate_w, gate_b, Agh);
    hgemm_k<2,0,1><<<dim3(HEN / 128, 250), 256, SMEM_BYTES>>>(
        (int)MR2, HEN, E_, Agh, W1t, Henh, HEN, enc_b1, nullptr);
    hgemm_k<0,0,1><<<dim3(1, 250), 256, SMEM_BYTES>>>(
        (int)MR2, D_, HEN, Henh, W2t, Hh, D_, enc_b2, nullptr);

    // ---- F = relu(H @ GLW) -> half ----
    hgemm_k<1,0,1><<<dim3(KF / 128, 250), 256, SMEM_BYTES>>>(
        (int)MR2, KF, D_, Hh, GLWt, Fh, KF, nullptr, nullptr);

    // ---- gram (fp32 att, coalesced mirror) ----
    hgram_k<<<dim3(16, 16, B2), 256, SMEM_BYTES>>>(Fh, att);

    // ---- sparse adjacency pipeline ----
    zero_k<<<(int)((MR2 + 255) / 256), 256>>>(colcnt, colsum, (int)MR2);
    topk_rows_k<<<(unsigned)MR2, 256>>>(att, rowval, rowcol, rowcnt);
    count_k<<<(unsigned)MR2, ROWCAP>>>(rowcol, rowcnt, colcnt);
    scan_k<<<B2, 256>>>(colcnt, coloff, colcur);
    place_k<<<(unsigned)MR2, ROWCAP>>>(rowval, rowcol, rowcnt, colcur, colsum, cscval, cscrow);
    dinv_k<<<(int)((MR2 + 255) / 256), 256>>>(colsum, dinv, (int)MR2);

    // ---- GCN layers ----
    hgemm_k<0,1,1><<<dim3(HD / 128, 250), 256, SMEM_BYTES>>>(
        (int)MR2, HD, D_, Hh, GW1t, Th, HD, nullptr, dinv);
    spagg_k<HD,1,1><<<dim3(NN, B2), HD/2>>>(cscval, cscrow, coloff, colcnt, Th, dinv, g_b1, O1h);
    hgemm_k<0,1,1><<<dim3(HD / 128, 250), 256, SMEM_BYTES>>>(
        (int)MR2, HD, HD, O1h, GW2t, Th, HD, nullptr, dinv);
    spagg_k<HD,1,1><<<dim3(NN, B2), HD/2>>>(cscval, cscrow, coloff, colcnt, Th, dinv, g_b2, O2h);
    hgemm_k<0,1,1><<<dim3(1, 250), 256, SMEM_BYTES>>>(
        (int)MR2, D_, HD, O2h, GW3t, Th, D_, nullptr, dinv);
    spagg_k<D_,0,0><<<dim3(NN, B2), D_/2>>>(cscval, cscrow, coloff, colcnt, Th, dinv, g_b3, O3);

    // ---- VIB head + decoders ----
    meanz2_k<<<B2, 128>>>(O3, epsA[0], epsA[1], muo[0], stdo[0], muo[1], stdo[1], zb);
    decode_k<<<dim3(8, 8), 256>>>(zb,       dW1[0], dB1[0], dG[0], dBe[0], dW2[0], dB2[0], xrec[0]);
    decode_k<<<dim3(8, 8), 256>>>(zb + 512, dW1[1], dB1[1], dG[1], dBe[1], dW2[1], dB2[1], xrec[1]);
}

// round 15
// speedup vs baseline: 3.9565x; 1.0536x over previous
#include <cuda_runtime.h>
#include <cuda_fp16.h>
#include <math.h>
#include <stdint.h>

// ---------------- problem constants ----------------
constexpr int B_  = 8;
constexpr int B2  = 16;
constexpr int NN  = 2000;
constexpr int E_  = 512;
constexpr int HEN = 1024;
constexpr int D_  = 128;
constexpr int HD  = 512;
constexpr int KF  = 4096;
constexpr int IB_ = 64;
constexpr long long MR  = (long long)B_ * NN;
constexpr long long MR2 = (long long)B2 * NN;   // 32000

constexpr int ROWCAP = 64;
constexpr int CAP    = 131072;

// ---------------- scratch layout ----------------
constexpr long long SZ_AGH  = MR2 * E_ / 2;
constexpr long long SZ_HENH = MR2 * HEN / 2;
constexpr long long SZ_HH   = MR2 * D_ / 2;
constexpr long long SZ_GLWT = (long long)KF * D_ / 2;
constexpr long long SZ_FH   = MR2 * KF / 2;
constexpr long long SZ_ATT  = (long long)B2 * NN * NN;
constexpr long long SZ_DINV = MR2;
constexpr long long SZ_TH   = MR2 * HD / 2;
constexpr long long SZ_OH   = MR2 * HD / 2;
constexpr long long SZ_O3   = MR2 * D_;
constexpr long long SZ_Z    = (long long)B2 * IB_;
constexpr long long SZ_W1T  = (long long)HEN * E_ / 2;
constexpr long long SZ_W2T  = (long long)D_ * HEN / 2;
constexpr long long SZ_GW1T = (long long)HD * D_ / 2;
constexpr long long SZ_GW2T = (long long)HD * HD / 2;
constexpr long long SZ_GW3T = (long long)D_ * HD / 2;
constexpr long long SZ_ROWV = MR2 * ROWCAP;
constexpr long long SZ_ROWC = MR2 * ROWCAP;
constexpr long long SZ_RCNT = MR2;
constexpr long long SZ_CCNT = MR2;
constexpr long long SZ_COFF = MR2;
constexpr long long SZ_CCUR = MR2;
constexpr long long SZ_CSUM = MR2;
constexpr long long SZ_CSCV = (long long)B2 * CAP;
constexpr long long SZ_CSCR = (long long)B2 * CAP;

constexpr long long OFF_AGH  = 0;
constexpr long long OFF_HENH = OFF_AGH + SZ_AGH;
constexpr long long OFF_HH   = OFF_HENH + SZ_HENH;
constexpr long long OFF_GLWT = OFF_HH + SZ_HH;
constexpr long long OFF_FH   = OFF_GLWT + SZ_GLWT;
constexpr long long OFF_ATT  = OFF_FH + SZ_FH;
constexpr long long OFF_DINV = OFF_ATT + SZ_ATT;
constexpr long long OFF_TH   = OFF_DINV + SZ_DINV;
constexpr long long OFF_O1H  = OFF_TH + SZ_TH;
constexpr long long OFF_O2H  = OFF_O1H + SZ_OH;
constexpr long long OFF_O3   = OFF_O2H + SZ_OH;
constexpr long long OFF_Z    = OFF_O3 + SZ_O3;
constexpr long long OFF_W1T  = OFF_Z + SZ_Z;
constexpr long long OFF_W2T  = OFF_W1T + SZ_W1T;
constexpr long long OFF_GW1T = OFF_W2T + SZ_W2T;
constexpr long long OFF_GW2T = OFF_GW1T + SZ_GW1T;
constexpr long long OFF_GW3T = OFF_GW2T + SZ_GW2T;
constexpr long long OFF_ROWV = OFF_GW3T + SZ_GW3T;
constexpr long long OFF_ROWC = OFF_ROWV + SZ_ROWV;
constexpr long long OFF_RCNT = OFF_ROWC + SZ_ROWC;
constexpr long long OFF_CCNT = OFF_RCNT + SZ_RCNT;
constexpr long long OFF_COFF = OFF_CCNT + SZ_CCNT;
constexpr long long OFF_CCUR = OFF_COFF + SZ_COFF;
constexpr long long OFF_CSUM = OFF_CCUR + SZ_CCUR;
constexpr long long OFF_CSCV = OFF_CSUM + SZ_CSUM;
constexpr long long OFF_CSCR = OFF_CSCV + SZ_CSCV;
constexpr long long SCRATCH_TOTAL = OFF_CSCR + SZ_CSCR;

__device__ float g_scratch[SCRATCH_TOTAL];

// ---------------- helpers ----------------
__device__ __forceinline__ void mma_f16(float* c, const uint32_t* a, uint32_t b0, uint32_t b1) {
    asm volatile(
        "mma.sync.aligned.m16n8k16.row.col.f32.f16.f16.f32 "
        "{%0,%1,%2,%3}, {%4,%5,%6,%7}, {%8,%9}, {%0,%1,%2,%3};"
        : "+f"(c[0]), "+f"(c[1]), "+f"(c[2]), "+f"(c[3])
        : "r"(a[0]), "r"(a[1]), "r"(a[2]), "r"(a[3]), "r"(b0), "r"(b1));
}

__device__ __forceinline__ void ldsm4(uint32_t* r, uint32_t addr) {
    asm volatile("ldmatrix.sync.aligned.m8n8.x4.shared.b16 {%0,%1,%2,%3}, [%4];"
                 : "=r"(r[0]), "=r"(r[1]), "=r"(r[2]), "=r"(r[3]) : "r"(addr));
}

__device__ __forceinline__ void cpa16(uint32_t dst, const void* src, bool pred) {
    int sz = pred ? 16 : 0;
    asm volatile("cp.async.cg.shared.global [%0], [%1], 16, %2;\n"
                 :: "r"(dst), "l"(src), "r"(sz));
}
__device__ __forceinline__ void cpa_commit() { asm volatile("cp.async.commit_group;\n"); }
__device__ __forceinline__ void cpa_wait1()  { asm volatile("cp.async.wait_group 1;\n"); }

__device__ __forceinline__ uint32_t smem_u32(const void* p) {
    uint32_t a;
    asm("{ .reg .u64 t; cvta.to.shared.u64 t, %1; cvt.u32.u64 %0, t; }" : "=r"(a) : "l"(p));
    return a;
}

constexpr int PK = 20;
constexpr int ASTG = 2560;
constexpr int BSTG = 2560;
constexpr int SMEM_BYTES = (3 * ASTG + 3 * BSTG) * 4;   // 61440

// ================= unified fp16 GEMM =================
template<int ACT, int EPI, int OUTH>
__global__ void __launch_bounds__(256, 2) hgemm_k(
    int M, int N, int K,
    const __half* __restrict__ A,
    const __half* __restrict__ Bt,
    void* __restrict__ C, int ldc,
    const float* __restrict__ bias,
    const float* __restrict__ dinv)
{
    extern __shared__ uint32_t sh[];
    const int bn = blockIdx.x, bm = blockIdx.y;
    const int m0 = bm * 128, n0 = bn * 128;

    const int tid  = threadIdx.x;
    const int lane = tid & 31, warp = tid >> 5;
    const int g = lane >> 2, th = lane & 3;
    const int wm = (warp >> 1) * 32;
    const int wn = (warp & 1) * 64;
    const int r8 = lane & 7, sel = lane >> 3;

    uint32_t sbase = smem_u32(sh);

    float acc[2][8][4];
#pragma unroll
    for (int i = 0; i < 2; i++)
#pragma unroll
        for (int j = 0; j < 8; j++)
#pragma unroll
            for (int l = 0; l < 4; l++) acc[i][j][l] = 0.f;

    const int KT = K / 32;

    auto issue = [&](int kt, int stg) {
        uint32_t abase = sbase + (uint32_t)(stg * ASTG) * 4u;
        uint32_t bbase = sbase + (uint32_t)(3 * ASTG + stg * BSTG) * 4u;
#pragma unroll
        for (int it = 0; it < 2; it++) {
            int c = tid * 2 + it;
            int row = c >> 2, kc = c & 3;
            const __half* srcA = A + (long long)(m0 + row) * K + kt * 32 + kc * 8;
            cpa16(abase + (uint32_t)(row * PK + kc * 4) * 4u, srcA, (m0 + row) < M);
            const __half* srcB = Bt + (long long)(n0 + row) * K + kt * 32 + kc * 8;
            cpa16(bbase + (uint32_t)(row * PK + kc * 4) * 4u, srcB, (n0 + row) < N);
        }
    };

    auto mmaTile = [&](int stg) {
        uint32_t abase = sbase + (uint32_t)(stg * ASTG) * 4u;
        uint32_t bbase = sbase + (uint32_t)(3 * ASTG + stg * BSTG) * 4u;
#pragma unroll
        for (int s = 0; s < 2; s++) {
            const int k0 = s * 8;
            uint32_t a[2][4];
#pragma unroll
            for (int mt = 0; mt < 2; mt++) {
                int row = wm + mt * 16 + ((sel & 1) << 3) + r8;
                int ku  = k0 + ((sel & 2) << 1);
                ldsm4(a[mt], abase + (uint32_t)(row * PK + ku) * 4u);
            }
            uint32_t b0v[8], b1v[8];
#pragma unroll
            for (int g4 = 0; g4 < 2; g4++) {
                int row = wn + g4 * 32 + sel * 8 + r8;
                ldsm4(&b0v[g4 * 4], bbase + (uint32_t)(row * PK + k0) * 4u);
                ldsm4(&b1v[g4 * 4], bbase + (uint32_t)(row * PK + k0 + 4) * 4u);
            }
#pragma unroll
            for (int nt = 0; nt < 8; nt++) {
                mma_f16(acc[0][nt], a[0], b0v[nt], b1v[nt]);
                mma_f16(acc[1][nt], a[1], b0v[nt], b1v[nt]);
            }
        }
    };

    issue(0, 0); cpa_commit();
    if (KT > 1) issue(1, 1);
    cpa_commit();
    cpa_wait1();
    __syncthreads();

    for (int kt = 0; kt < KT; kt++) {
        int stg = kt % 3;
        if (kt + 2 < KT) issue(kt + 2, (kt + 2) % 3);
        cpa_commit();
        mmaTile(stg);
        cpa_wait1();
        __syncthreads();
    }

    __half* Ch = (__half*)C;
    float*  Cf = (float*)C;
#pragma unroll
    for (int mt = 0; mt < 2; mt++) {
#pragma unroll
        for (int nt = 0; nt < 8; nt++) {
#pragma unroll
            for (int eh = 0; eh < 2; eh++) {
                int gm = m0 + wm + mt * 16 + g + (eh ? 8 : 0);
                int gn = n0 + wn + nt * 8 + 2 * th;
                if (gm >= M || gn >= N) continue;
                float v0 = acc[mt][nt][eh * 2 + 0];
                float v1 = acc[mt][nt][eh * 2 + 1];
                if (EPI == 1) { float dv = dinv[gm]; v0 *= dv; v1 *= dv; }
                if (bias)     { v0 += bias[gn]; v1 += bias[gn + 1]; }
                if (ACT == 1) { v0 = fmaxf(v0, 0.f); v1 = fmaxf(v1, 0.f); }
                if (ACT == 2) {
                    v0 = 0.5f * v0 * (1.f + erff(v0 * 0.70710678118654752f));
                    v1 = 0.5f * v1 * (1.f + erff(v1 * 0.70710678118654752f));
                }
                if (OUTH) {
                    *reinterpret_cast<__half2*>(&Ch[(long long)gm * ldc + gn]) =
                        __floats2half2_rn(v0, v1);
                } else {
                    Cf[(long long)gm * ldc + gn]     = v0;
                    Cf[(long long)gm * ldc + gn + 1] = v1;
                }
            }
        }
    }
}

// ---------------- fp16 gram, fp32 att; coalesced mirror via smem transpose ----------------
__global__ void __launch_bounds__(256, 2) hgram_k(const __half* __restrict__ F,
                                                  float* __restrict__ att)
{
    extern __shared__ uint32_t sh[];
    const int bn = blockIdx.x, bm = blockIdx.y, b = blockIdx.z;
    if (bm > bn) return;
    const int m0 = bm * 128, n0 = bn * 128;

    const int tid  = threadIdx.x;
    const int lane = tid & 31, warp = tid >> 5;
    const int g = lane >> 2, th = lane & 3;
    const int wm = (warp >> 1) * 32;
    const int wn = (warp & 1) * 64;
    const int r8 = lane & 7, sel = lane >> 3;

    uint32_t sbase = smem_u32(sh);
    const __half* Fb = F + (long long)b * NN * KF;
    float* attb = att + (long long)b * NN * NN;

    float acc[2][8][4];
#pragma unroll
    for (int i = 0; i < 2; i++)
#pragma unroll
        for (int j = 0; j < 8; j++)
#pragma unroll
            for (int l = 0; l < 4; l++) acc[i][j][l] = 0.f;

    const int KT = KF / 32;

    auto issue = [&](int kt, int stg) {
        uint32_t abase = sbase + (uint32_t)(stg * ASTG) * 4u;
        uint32_t bbase = sbase + (uint32_t)(3 * ASTG + stg * BSTG) * 4u;
#pragma unroll
        for (int it = 0; it < 2; it++) {
            int c = tid * 2 + it;
            int row = c >> 2, kc = c & 3;
            const __half* srcA = Fb + (long long)(m0 + row) * KF + kt * 32 + kc * 8;
            cpa16(abase + (uint32_t)(row * PK + kc * 4) * 4u, srcA, (m0 + row) < NN);
            const __half* srcB = Fb + (long long)(n0 + row) * KF + kt * 32 + kc * 8;
            cpa16(bbase + (uint32_t)(row * PK + kc * 4) * 4u, srcB, (n0 + row) < NN);
        }
    };

    auto mmaTile = [&](int stg) {
        uint32_t abase = sbase + (uint32_t)(stg * ASTG) * 4u;
        uint32_t bbase = sbase + (uint32_t)(3 * ASTG + stg * BSTG) * 4u;
#pragma unroll
        for (int s = 0; s < 2; s++) {
            const int k0 = s * 8;
            uint32_t a[2][4];
#pragma unroll
            for (int mt = 0; mt < 2; mt++) {
                int row = wm + mt * 16 + ((sel & 1) << 3) + r8;
                int ku  = k0 + ((sel & 2) << 1);
                ldsm4(a[mt], abase + (uint32_t)(row * PK + ku) * 4u);
            }
            uint32_t b0v[8], b1v[8];
#pragma unroll
            for (int g4 = 0; g4 < 2; g4++) {
                int row = wn + g4 * 32 + sel * 8 + r8;
                ldsm4(&b0v[g4 * 4], bbase + (uint32_t)(row * PK + k0) * 4u);
                ldsm4(&b1v[g4 * 4], bbase + (uint32_t)(row * PK + k0 + 4) * 4u);
            }
#pragma unroll
            for (int nt = 0; nt < 8; nt++) {
                mma_f16(acc[0][nt], a[0], b0v[nt], b1v[nt]);
                mma_f16(acc[1][nt], a[1], b0v[nt], b1v[nt]);
            }
        }
    };

    issue(0, 0); cpa_commit();
    if (KT > 1) issue(1, 1);
    cpa_commit();
    cpa_wait1();
    __syncthreads();

    for (int kt = 0; kt < KT; kt++) {
        int stg = kt % 3;
        if (kt + 2 < KT) issue(kt + 2, (kt + 2) % 3);
        cpa_commit();
        mmaTile(stg);
        cpa_wait1();
        __syncthreads();
    }

    // direct stores (float2)
#pragma unroll
    for (int mt = 0; mt < 2; mt++) {
#pragma unroll
        for (int nt = 0; nt < 8; nt++) {
#pragma unroll
            for (int eh = 0; eh < 2; eh++) {
                int gm = m0 + wm + mt * 16 + g + (eh ? 8 : 0);
                int gn = n0 + wn + nt * 8 + 2 * th;
                if (gm >= NN || gn + 1 >= NN) continue;
                float2 v = make_float2(0.125f * acc[mt][nt][eh * 2 + 0],
                                       0.125f * acc[mt][nt][eh * 2 + 1]);
                *reinterpret_cast<float2*>(&attb[(long long)gm * NN + gn]) = v;
            }
        }
    }

    // mirror via smem transpose (coalesced)
    if (bm < bn) {
        float* smf = reinterpret_cast<float*>(sh);
#pragma unroll
        for (int p = 0; p < 2; p++) {
            if ((warp & 1) == p) {
#pragma unroll
                for (int mt = 0; mt < 2; mt++) {
#pragma unroll
                    for (int nt = 0; nt < 8; nt++) {
#pragma unroll
                        for (int eh = 0; eh < 2; eh++) {
                            int gml  = wm + mt * 16 + g + (eh ? 8 : 0);
                            int rowl = nt * 8 + 2 * th;
                            smf[rowl * 132 + gml]       = 0.125f * acc[mt][nt][eh * 2 + 0];
                            smf[(rowl + 1) * 132 + gml] = 0.125f * acc[mt][nt][eh * 2 + 1];
                        }
                    }
                }
            }
            __syncthreads();
            for (int idx = tid; idx < 2048; idx += 256) {
                int rowl = idx >> 5, c4 = (idx & 31) << 2;
                int gn = n0 + p * 64 + rowl;
                if (gn < NN && m0 + c4 + 3 < NN) {
                    float4 v = *reinterpret_cast<float4*>(&smf[rowl * 132 + c4]);
                    *reinterpret_cast<float4*>(&attb[(long long)gn * NN + m0 + c4]) = v;
                }
            }
            __syncthreads();
        }
    }
}

// ---------------- weight transpose to half ----------------
__global__ void trhalf_k(const float* __restrict__ src, __half* __restrict__ dst, int K, int N)
{
    int idx = blockIdx.x * blockDim.x + threadIdx.x;
    if (idx >= K * N) return;
    int n = idx / K, k = idx % K;
    dst[(long long)n * K + k] = __float2half_rn(src[(long long)k * N + n]);
}

// ---------------- gl_w -> GLWt half [KF, D] ----------------
__global__ void glwt_k(const float* __restrict__ glw, __half* __restrict__ GLWt)
{
    int idx = blockIdx.x * blockDim.x + threadIdx.x;
    if (idx >= KF * D_) return;
    int c = idx / D_, k = idx % D_;
    int p = c >> 9, hh = c & 511;
    GLWt[idx] = __float2half_rn(glw[((long long)p * D_ + k) * HD + hh]);
}

// ---------------- A-matrix builder ----------------
__global__ void build_ag2_k(const float* __restrict__ x1, const float* __restrict__ x2,
                            const float* __restrict__ emb,
                            const float* __restrict__ gw, const float* __restrict__ gb,
                            __half* __restrict__ Ag)
{
    long long idx = (long long)blockIdx.x * blockDim.x + threadIdx.x;
    if (idx >= MR2 * E_) return;
    int e = (int)(idx & (E_ - 1));
    long long r = idx >> 9;
    long long rv = (r < MR) ? r : r - MR;
    const float* x = (r < MR) ? x1 : x2;
    int n = (int)(rv % NN);
    float t = fmaf(x[rv], gw[e], gb[e]);
    float sgm = 1.0f / (1.0f + expf(-t));
    Ag[idx] = __float2half_rn(sgm * emb[(long long)n * E_ + e]);
}

// ---------------- top-k(50): register-resident, fp32 att ----------------
__global__ void __launch_bounds__(256) topk_rows_k(
    const float* __restrict__ att,
    float* __restrict__ rowval, int* __restrict__ rowcol, int* __restrict__ rowcnt)
{
    __shared__ int   hist[256];
    __shared__ float wredf[8];
    __shared__ float s_bcast;
    __shared__ int   s_selb, s_selk, s_pos;

    long long row = blockIdx.x;
    const float* r = att + row * 2000;
    int tid = threadIdx.x;
    int lane = tid & 31, wid = tid >> 5;

    float v[8];
#pragma unroll
    for (int p = 0; p < 8; p++) {
        int i = tid + p * 256;
        v[p] = (i < 2000) ? r[i] : 0.f;
    }
    if (tid == 0) s_pos = 0;

    float mx = 0.f;
#pragma unroll
    for (int p = 0; p < 8; p++) mx = fmaxf(mx, v[p]);
#pragma unroll
    for (int o = 16; o; o >>= 1) mx = fmaxf(mx, __shfl_xor_sync(0xffffffffu, mx, o));
    if (lane == 0) wredf[wid] = mx;
    __syncthreads();
    if (tid == 0) { float m = wredf[0]; for (int w = 1; w < 8; w++) m = fmaxf(m, wredf[w]); s_bcast = m; }
    __syncthreads();
    mx = s_bcast;

    unsigned prefix = 0u;
    int k = 50;
#pragma unroll
    for (int pass = 0; pass < 4; pass++) {
        const int shift = 24 - 8 * pass;
        const unsigned hmask = (pass == 0) ? 0u : (0xFFFFFFFFu << (shift + 8));
        if (tid < 256) hist[tid] = 0;
        __syncthreads();
#pragma unroll
        for (int p = 0; p < 8; p++) {
            int i = tid + p * 256;
            if (i < 2000) {
                unsigned u = __float_as_uint(v[p]);
                if ((u & hmask) == prefix)
                    atomicAdd(&hist[(u >> shift) & 255], 1);
            }
        }
        __syncthreads();
        if (tid == 0) {
            int acc = 0, b = 255;
            for (; b > 0; b--) { acc += hist[b]; if (acc >= k) break; }
            if (acc < k) acc += hist[0];
            s_selb = b;
            s_selk = k - (acc - hist[b]);
        }
        __syncthreads();
        prefix |= ((unsigned)s_selb) << shift;
        k = s_selk;
        __syncthreads();
    }
    float thr = __uint_as_float(prefix);

    float sum = 0.f;
#pragma unroll
    for (int p = 0; p < 8; p++) {
        int i = tid + p * 256;
        if (i < 2000 && v[p] >= thr) sum += expf(v[p] - mx);
    }
#pragma unroll
    for (int o = 16; o; o >>= 1) sum += __shfl_xor_sync(0xffffffffu, sum, o);
    if (lane == 0) wredf[wid] = sum;
    __syncthreads();
    if (tid == 0) { float t = 0.f; for (int w = 0; w < 8; w++) t += wredf[w]; s_bcast = t; }
    __syncthreads();
    float inv = 1.0f / s_bcast;

#pragma unroll
    for (int p = 0; p < 8; p++) {
        int i = tid + p * 256;
        if (i < 2000 && v[p] >= thr) {
            int pos = atomicAdd(&s_pos, 1);
            if (pos < ROWCAP) {
                rowval[row * ROWCAP + pos] = expf(v[p] - mx) * inv;
                rowcol[row * ROWCAP + pos] = i;
            }
        }
    }
    __syncthreads();
    if (tid == 0) rowcnt[row] = min(s_pos, ROWCAP);
}

// ---------------- zero ----------------
__global__ void zero_k(int* __restrict__ a, float* __restrict__ b, int n)
{
    int i = blockIdx.x * blockDim.x + threadIdx.x;
    if (i < n) { a[i] = 0; b[i] = 0.f; }
}

// ---------------- count column occupancy ----------------
__global__ void count_k(const int* __restrict__ rowcol, const int* __restrict__ rowcnt,
                        int* __restrict__ colcnt)
{
    int row = blockIdx.x;
    int b = row / NN;
    int cnt = rowcnt[row];
    if (threadIdx.x < cnt)
        atomicAdd(&colcnt[b * NN + rowcol[row * ROWCAP + threadIdx.x]], 1);
}

// ---------------- per-batch exclusive scan ----------------
__global__ void __launch_bounds__(256) scan_k(const int* __restrict__ colcnt,
                                              int* __restrict__ coloff, int* __restrict__ colcur)
{
    __shared__ int tsum[257];
    int b = blockIdx.x, tid = threadIdx.x;
    const int* cnt = colcnt + b * NN;
    int local[8];
    int tot = 0;
#pragma unroll
    for (int e = 0; e < 8; e++) {
        int i = tid * 8 + e;
        local[e] = tot;
        tot += (i < NN) ? cnt[i] : 0;
    }
    tsum[tid] = tot;
    __syncthreads();
    if (tid == 0) {
        int acc = 0;
        for (int t = 0; t < 256; t++) { int v = tsum[t]; tsum[t] = acc; acc += v; }
    }
    __syncthreads();
    int base = tsum[tid];
#pragma unroll
    for (int e = 0; e < 8; e++) {
        int i = tid * 8 + e;
        if (i < NN) {
            coloff[b * NN + i] = base + local[e];
            colcur[b * NN + i] = base + local[e];
        }
    }
}

// ---------------- place into CSC ----------------
__global__ void place_k(const float* __restrict__ rowval, const int* __restrict__ rowcol,
                        const int* __restrict__ rowcnt,
                        int* __restrict__ colcur, float* __restrict__ colsum,
                        float* __restrict__ cscval, int* __restrict__ cscrow)
{
    int row = blockIdx.x;
    int b = row / NN, j = row % NN;
    int cnt = rowcnt[row];
    int e = threadIdx.x;
    if (e < cnt) {
        int   c = rowcol[row * ROWCAP + e];
        float w = rowval[row * ROWCAP + e];
        int pos = atomicAdd(&colcur[b * NN + c], 1);
        cscval[(long long)b * CAP + pos] = w;
        cscrow[(long long)b * CAP + pos] = j;
        atomicAdd(&colsum[b * NN + c], w);
    }
}

// ---------------- dinv ----------------
__global__ void dinv_k(const float* __restrict__ colsum, float* __restrict__ dinv, int n)
{
    int i = blockIdx.x * blockDim.x + threadIdx.x;
    if (i < n) dinv[i] = rsqrtf(1.0f + colsum[i]);
}

// ---------------- sparse GCN aggregation, ILP-4 gather ----------------
template<int DIM, int ACT, int OUTH>
__global__ void spagg_k(
    const float* __restrict__ cscval, const int* __restrict__ cscrow,
    const int* __restrict__ coloff, const int* __restrict__ colcnt,
    const __half* __restrict__ T, const float* __restrict__ dinv,
    const float* __restrict__ bias, void* __restrict__ out)
{
    __shared__ float sw[256];
    __shared__ int   sj[256];
    int i = blockIdx.x, b = blockIdx.y, tid = threadIdx.x;
    const __half* Tb = T + (long long)b * NN * DIM;
    int s0  = coloff[b * NN + i];
    int cnt = colcnt[b * NN + i];
    long long base = (long long)b * CAP + s0;

    float2 a0 = __half22float2(*reinterpret_cast<const __half2*>(&Tb[(long long)i * DIM + 2 * tid]));
    float2 a1 = make_float2(0.f, 0.f);
    float2 a2 = make_float2(0.f, 0.f);
    float2 a3 = make_float2(0.f, 0.f);

    for (int e0 = 0; e0 < cnt; e0 += blockDim.x) {
        int chunk = min(cnt - e0, (int)blockDim.x);
        if (tid < chunk) {
            sw[tid] = cscval[base + e0 + tid];
            sj[tid] = cscrow[base + e0 + tid];
        }
        __syncthreads();
        int e = 0;
        for (; e + 3 < chunk; e += 4) {
            float2 t0 = __half22float2(*reinterpret_cast<const __half2*>(&Tb[(long long)sj[e]   * DIM + 2 * tid]));
            float2 t1 = __half22float2(*reinterpret_cast<const __half2*>(&Tb[(long long)sj[e+1] * DIM + 2 * tid]));
            float2 t2 = __half22float2(*reinterpret_cast<const __half2*>(&Tb[(long long)sj[e+2] * DIM + 2 * tid]));
            float2 t3 = __half22float2(*reinterpret_cast<const __half2*>(&Tb[(long long)sj[e+3] * DIM + 2 * tid]));
            a0.x = fmaf(sw[e],   t0.x, a0.x); a0.y = fmaf(sw[e],   t0.y, a0.y);
            a1.x = fmaf(sw[e+1], t1.x, a1.x); a1.y = fmaf(sw[e+1], t1.y, a1.y);
            a2.x = fmaf(sw[e+2], t2.x, a2.x); a2.y = fmaf(sw[e+2], t2.y, a2.y);
            a3.x = fmaf(sw[e+3], t3.x, a3.x); a3.y = fmaf(sw[e+3], t3.y, a3.y);
        }
        for (; e < chunk; e++) {
            float2 t0 = __half22float2(*reinterpret_cast<const __half2*>(&Tb[(long long)sj[e] * DIM + 2 * tid]));
            a0.x = fmaf(sw[e], t0.x, a0.x);
            a0.y = fmaf(sw[e], t0.y, a0.y);
        }
        __syncthreads();
    }
    float dv = dinv[b * NN + i];
    float vx = dv * ((a0.x + a1.x) + (a2.x + a3.x)) + bias[2 * tid];
    float vy = dv * ((a0.y + a1.y) + (a2.y + a3.y)) + bias[2 * tid + 1];
    if (ACT == 1) { vx = fmaxf(vx, 0.f); vy = fmaxf(vy, 0.f); }
    if (OUTH) {
        __half* oh = (__half*)out;
        *reinterpret_cast<__half2*>(&oh[((long long)b * NN + i) * DIM + 2 * tid]) =
            __floats2half2_rn(vx, vy);
    } else {
        float* of = (float*)out;
        *reinterpret_cast<float2*>(&of[((long long)b * NN + i) * DIM + 2 * tid]) = make_float2(vx, vy);
    }
}

// ---------------- per-view mean over nodes; mu/std/z ----------------
__global__ void meanz1_k(const float* __restrict__ O3, const float* __restrict__ eps,
                         float* __restrict__ mu, float* __restrict__ stdv,
                         float* __restrict__ z)
{
    int b = blockIdx.x, d = threadIdx.x;    // b 0..7 (view-local)
    const float* p = O3 + ((long long)b * 2000) * 128 + d;
    float s0 = 0.f, s1 = 0.f, s2 = 0.f, s3 = 0.f;
    for (int i = 0; i < 2000; i += 4) {
        s0 += p[(long long)i * 128];
        s1 += p[(long long)(i + 1) * 128];
        s2 += p[(long long)(i + 2) * 128];
        s3 += p[(long long)(i + 3) * 128];
    }
    __shared__ float sg[128];
    sg[d] = ((s0 + s1) + (s2 + s3)) / 2000.0f;
    __syncthreads();
    if (d < 64) {
        float m = sg[d];
        float sp = log1pf(expf(sg[64 + d] - 64.0f));
        mu[b * 64 + d] = m;
        stdv[b * 64 + d] = sp;
        z[b * 64 + d] = fmaf(eps[b * 64 + d], sp, m);
    }
}

// ---------------- decoder ----------------
__global__ void __launch_bounds__(256) decode_k(
    const float* __restrict__ z, const float* __restrict__ w1, const float* __restrict__ b1,
    const float* __restrict__ gamma, const float* __restrict__ beta,
    const float* __restrict__ w2, const float* __restrict__ b2,
    float* __restrict__ xrec)
{
    __shared__ float h[1024];
    __shared__ float zs[64];
    int b = blockIdx.x, tid = threadIdx.x;
    if (tid < 64) zs[tid] = z[b * 64 + tid];
    __syncthreads();
    const float invc = 1.0f / sqrtf(1.0f + 1e-5f);
    for (int c = tid; c < 1024; c += 256) {
        float a = b1[c];
#pragma unroll 8
        for (int k = 0; k < 64; k++) a = fmaf(zs[k], w1[k * 1024 + c], a);
        a = a * (gamma[c] * invc) + beta[c];
        h[c] = fmaxf(a, 0.f);
    }
    __syncthreads();
    int c0 = blockIdx.y * 250;
    int c1 = min(c0 + 250, 2000);
    for (int c = c0 + tid; c < c1; c += 256) {
        float a = b2[c];
        for (int k = 0; k < 1024; k++) a = fmaf(h[k], w2[k * 2000 + c], a);
        xrec[b * 2000 + c] = fmaxf(a, 0.f);
    }
}

// ---------------- host orchestration ----------------
extern "C" void kernel_launch(void* const* d_in, const int* in_sizes, int n_in,
                              void* d_out, int out_size)
{
    const float* x1     = (const float*)d_in[0];
    const float* x2     = (const float*)d_in[1];
    const float* emb1   = (const float*)d_in[2];
    const float* gate_w = (const float*)d_in[3];
    const float* gate_b = (const float*)d_in[4];
    const float* enc_w1 = (const float*)d_in[5];
    const float* enc_b1 = (const float*)d_in[6];
    const float* enc_w2 = (const float*)d_in[7];
    const float* enc_b2 = (const float*)d_in[8];
    const float* gl_w   = (const float*)d_in[9];
    const float* g_w1   = (const float*)d_in[10];
    const float* g_b1   = (const float*)d_in[11];
    const float* g_w2   = (const float*)d_in[12];
    const float* g_b2   = (const float*)d_in[13];
    const float* g_w3   = (const float*)d_in[14];
    const float* g_b3   = (const float*)d_in[15];
    const float* dW1[2] = {(const float*)d_in[16], (const float*)d_in[22]};
    const float* dB1[2] = {(const float*)d_in[17], (const float*)d_in[23]};
    const float* dG [2] = {(const float*)d_in[18], (const float*)d_in[24]};
    const float* dBe[2] = {(const float*)d_in[19], (const float*)d_in[25]};
    const float* dW2[2] = {(const float*)d_in[20], (const float*)d_in[26]};
    const float* dB2[2] = {(const float*)d_in[21], (const float*)d_in[27]};
    const float* epsA[2]= {(const float*)d_in[28], (const float*)d_in[29]};

    static cudaStream_t s1 = nullptr;
    static cudaEvent_t evF = nullptr, evJ = nullptr;
    static bool attr_done = false;
    if (!attr_done) {
        cudaFuncSetAttribute(hgemm_k<2,0,1>, cudaFuncAttributeMaxDynamicSharedMemorySize, SMEM_BYTES);
        cudaFuncSetAttribute(hgemm_k<0,0,1>, cudaFuncAttributeMaxDynamicSharedMemorySize, SMEM_BYTES);
        cudaFuncSetAttribute(hgemm_k<1,0,1>, cudaFuncAttributeMaxDynamicSharedMemorySize, SMEM_BYTES);
        cudaFuncSetAttribute(hgemm_k<0,1,1>, cudaFuncAttributeMaxDynamicSharedMemorySize, SMEM_BYTES);
        cudaFuncSetAttribute(hgram_k, cudaFuncAttributeMaxDynamicSharedMemorySize, SMEM_BYTES);
        cudaStreamCreateWithFlags(&s1, cudaStreamNonBlocking);
        cudaEventCreateWithFlags(&evF, cudaEventDisableTiming);
        cudaEventCreateWithFlags(&evJ, cudaEventDisableTiming);
        attr_done = true;
    }

    float* sc = nullptr;
    cudaGetSymbolAddress((void**)&sc, g_scratch);
    __half* Agh  = (__half*)(sc + OFF_AGH);
    __half* Henh = (__half*)(sc + OFF_HENH);
    __half* Hh   = (__half*)(sc + OFF_HH);
    __half* GLWt = (__half*)(sc + OFF_GLWT);
    __half* Fh   = (__half*)(sc + OFF_FH);
    float*  att  = sc + OFF_ATT;
    float*  dinv = sc + OFF_DINV;
    __half* Th   = (__half*)(sc + OFF_TH);
    __half* O1h  = (__half*)(sc + OFF_O1H);
    __half* O2h  = (__half*)(sc + OFF_O2H);
    float*  O3   = sc + OFF_O3;
    float*  zb   = sc + OFF_Z;
    __half* W1t  = (__half*)(sc + OFF_W1T);
    __half* W2t  = (__half*)(sc + OFF_W2T);
    __half* GW1t = (__half*)(sc + OFF_GW1T);
    __half* GW2t = (__half*)(sc + OFF_GW2T);
    __half* GW3t = (__half*)(sc + OFF_GW3T);
    float* rowval = sc + OFF_ROWV;
    int*   rowcol = (int*)(sc + OFF_ROWC);
    int*   rowcnt = (int*)(sc + OFF_RCNT);
    int*   colcnt = (int*)(sc + OFF_CCNT);
    int*   coloff = (int*)(sc + OFF_COFF);
    int*   colcur = (int*)(sc + OFF_CCUR);
    float* colsum = sc + OFF_CSUM;
    float* cscval = sc + OFF_CSCV;
    int*   cscrow = (int*)(sc + OFF_CSCR);

    float* out = (float*)d_out;
    float* xrec[2] = {out,          out + 16000};
    float* muo [2] = {out + 32000,  out + 33024};
    float* stdo[2] = {out + 32512,  out + 33536};

    trhalf_k<<<(E_ * HEN + 255) / 256, 256>>>(enc_w1, W1t, E_, HEN);
    trhalf_k<<<(HEN * D_ + 255) / 256, 256>>>(enc_w2, W2t, HEN, D_);
    trhalf_k<<<(D_ * HD + 255) / 256, 256>>>(g_w1, GW1t, D_, HD);
    trhalf_k<<<(HD * HD + 255) / 256, 256>>>(g_w2, GW2t, HD, HD);
    trhalf_k<<<(HD * D_ + 255) / 256, 256>>>(g_w3, GW3t, HD, D_);
    glwt_k<<<(KF * D_ + 255) / 256, 256>>>(gl_w, GLWt);

    // ---- encoders + F, both views batched (default stream) ----
    build_ag2_k<<<(unsigned)((MR2 * E_ + 255) / 256), 256>>>(x1, x2, emb1, gate_w, gate_b, Agh);
    hgemm_k<2,0,1><<<dim3(HEN / 128, 250), 256, SMEM_BYTES>>>(
        (int)MR2, HEN, E_, Agh, W1t, Henh, HEN, enc_b1, nullptr);
    hgemm_k<0,0,1><<<dim3(1, 250), 256, SMEM_BYTES>>>(
        (int)MR2, D_, HEN, Henh, W2t, Hh, D_, enc_b2, nullptr);
    hgemm_k<1,0,1><<<dim3(KF / 128, 250), 256, SMEM_BYTES>>>(
        (int)MR2, KF, D_, Hh, GLWt, Fh, KF, nullptr, nullptr);

    // ---- fork: view 0 on default stream, view 1 on s1 ----
    cudaEventRecord(evF, 0);
    cudaStreamWaitEvent(s1, evF, 0);

    for (int v = 0; v < 2; v++) {
        cudaStream_t st = v ? s1 : 0;
        long long bo = (long long)v * 8 * NN;               // row offset
        __half* Fv  = Fh + bo * KF;
        float*  av  = att + bo * NN;
        float*  rvv = rowval + bo * ROWCAP;
        int*    rcv = rowcol + bo * ROWCAP;
        int*    rnv = rowcnt + bo;
        int*    ccv = colcnt + bo;
        int*    cov = coloff + bo;
        int*    cuv = colcur + bo;
        float*  csv = colsum + bo;
        float*  dvv = dinv + bo;
        float*  vv  = cscval + (long long)v * 8 * CAP;
        int*    rv2 = cscrow + (long long)v * 8 * CAP;
        __half* Hv  = Hh + bo * D_;
        __half* Tv  = Th + bo * HD;
        __half* O1v = O1h + bo * HD;
        __half* O2v = O2h + bo * HD;
        float*  O3v = O3 + bo * D_;

        hgram_k<<<dim3(16, 16, 8), 256, SMEM_BYTES, st>>>(Fv, av);
        zero_k<<<(8 * NN + 255) / 256, 256, 0, st>>>(ccv, csv, 8 * NN);
        topk_rows_k<<<16000, 256, 0, st>>>(av, rvv, rcv, rnv);
        count_k<<<16000, ROWCAP, 0, st>>>(rcv, rnv, ccv);
        scan_k<<<8, 256, 0, st>>>(ccv, cov, cuv);
        place_k<<<16000, ROWCAP, 0, st>>>(rvv, rcv, rnv, cuv, csv, vv, rv2);
        dinv_k<<<(8 * NN + 255) / 256, 256, 0, st>>>(csv, dvv, 8 * NN);

        hgemm_k<0,1,1><<<dim3(HD / 128, 125), 256, SMEM_BYTES, st>>>(
            16000, HD, D_, Hv, GW1t, Tv, HD, nullptr, dvv);
        spagg_k<HD,1,1><<<dim3(NN, 8), HD/2, 0, st>>>(vv, rv2, cov, ccv, Tv, dvv, g_b1, O1v);
        hgemm_k<0,1,1><<<dim3(HD / 128, 125), 256, SMEM_BYTES, st>>>(
            16000, HD, HD, O1v, GW2t, Tv, HD, nullptr, dvv);
        spagg_k<HD,1,1><<<dim3(NN, 8), HD/2, 0, st>>>(vv, rv2, cov, ccv, Tv, dvv, g_b2, O2v);
        hgemm_k<0,1,1><<<dim3(1, 125), 256, SMEM_BYTES, st>>>(
            16000, D_, HD, O2v, GW3t, Tv, D_, nullptr, dvv);
        spagg_k<D_,0,0><<<dim3(NN, 8), D_/2, 0, st>>>(vv, rv2, cov, ccv, Tv, dvv, g_b3, O3v);

        meanz1_k<<<8, 128, 0, st>>>(O3v, epsA[v], muo[v], stdo[v], zb + v * 512);
        decode_k<<<dim3(8, 8), 256, 0, st>>>(zb + v * 512, dW1[v], dB1[v], dG[v], dBe[v],
                                             dW2[v], dB2[v], xrec[v]);
    }

    // ---- join s1 back to the default (capture-origin) stream ----
    cudaEventRecord(evJ, s1);
    cudaStreamWaitEvent(0, evJ, 0);
}

// round 16
// speedup vs baseline: 3.9887x; 1.0081x over previous
#include <cuda_runtime.h>
#include <cuda_fp16.h>
#include <math.h>
#include <stdint.h>

// ---------------- problem constants ----------------
constexpr int B_  = 8;
constexpr int B2  = 16;
constexpr int NN  = 2000;
constexpr int E_  = 512;
constexpr int HEN = 1024;
constexpr int D_  = 128;
constexpr int HD  = 512;
constexpr int KF  = 4096;
constexpr int IB_ = 64;
constexpr long long MR  = (long long)B_ * NN;   // 16000
constexpr long long MR2 = (long long)B2 * NN;   // 32000

constexpr int ROWCAP = 64;
constexpr int CAP    = 131072;

// ---------------- scratch layout ----------------
constexpr long long SZ_AGH  = MR2 * E_ / 2;
constexpr long long SZ_HENH = MR2 * HEN / 2;
constexpr long long SZ_HH   = MR2 * D_ / 2;
constexpr long long SZ_GLWT = (long long)KF * D_ / 2;
constexpr long long SZ_FH   = MR2 * KF / 2;
constexpr long long SZ_ATT  = (long long)B2 * NN * NN;
constexpr long long SZ_DINV = MR2;
constexpr long long SZ_TH   = MR2 * HD / 2;
constexpr long long SZ_OH   = MR2 * HD / 2;
constexpr long long SZ_O3   = MR2 * D_;
constexpr long long SZ_Z    = (long long)B2 * IB_;
constexpr long long SZ_W1T  = (long long)HEN * E_ / 2;
constexpr long long SZ_W2T  = (long long)D_ * HEN / 2;
constexpr long long SZ_GW1T = (long long)HD * D_ / 2;
constexpr long long SZ_GW2T = (long long)HD * HD / 2;
constexpr long long SZ_GW3T = (long long)D_ * HD / 2;
constexpr long long SZ_ROWV = MR2 * ROWCAP;
constexpr long long SZ_ROWC = MR2 * ROWCAP;
constexpr long long SZ_RCNT = MR2;
constexpr long long SZ_CCNT = MR2;
constexpr long long SZ_COFF = MR2;
constexpr long long SZ_CCUR = MR2;
constexpr long long SZ_CSUM = MR2;
constexpr long long SZ_CSCV = (long long)B2 * CAP;
constexpr long long SZ_CSCR = (long long)B2 * CAP;

constexpr long long OFF_AGH  = 0;
constexpr long long OFF_HENH = OFF_AGH + SZ_AGH;
constexpr long long OFF_HH   = OFF_HENH + SZ_HENH;
constexpr long long OFF_GLWT = OFF_HH + SZ_HH;
constexpr long long OFF_FH   = OFF_GLWT + SZ_GLWT;
constexpr long long OFF_ATT  = OFF_FH + SZ_FH;
constexpr long long OFF_DINV = OFF_ATT + SZ_ATT;
constexpr long long OFF_TH   = OFF_DINV + SZ_DINV;
constexpr long long OFF_O1H  = OFF_TH + SZ_TH;
constexpr long long OFF_O2H  = OFF_O1H + SZ_OH;
constexpr long long OFF_O3   = OFF_O2H + SZ_OH;
constexpr long long OFF_Z    = OFF_O3 + SZ_O3;
constexpr long long OFF_W1T  = OFF_Z + SZ_Z;
constexpr long long OFF_W2T  = OFF_W1T + SZ_W1T;
constexpr long long OFF_GW1T = OFF_W2T + SZ_W2T;
constexpr long long OFF_GW2T = OFF_GW1T + SZ_GW1T;
constexpr long long OFF_GW3T = OFF_GW2T + SZ_GW2T;
constexpr long long OFF_ROWV = OFF_GW3T + SZ_GW3T;
constexpr long long OFF_ROWC = OFF_ROWV + SZ_ROWV;
constexpr long long OFF_RCNT = OFF_ROWC + SZ_ROWC;
constexpr long long OFF_CCNT = OFF_RCNT + SZ_RCNT;
constexpr long long OFF_COFF = OFF_CCNT + SZ_CCNT;
constexpr long long OFF_CCUR = OFF_COFF + SZ_COFF;
constexpr long long OFF_CSUM = OFF_CCUR + SZ_CCUR;
constexpr long long OFF_CSCV = OFF_CSUM + SZ_CSUM;
constexpr long long OFF_CSCR = OFF_CSCV + SZ_CSCV;
constexpr long long SCRATCH_TOTAL = OFF_CSCR + SZ_CSCR;

__device__ float g_scratch[SCRATCH_TOTAL];

// ---------------- helpers ----------------
__device__ __forceinline__ void mma_f16(float* c, const uint32_t* a, uint32_t b0, uint32_t b1) {
    asm volatile(
        "mma.sync.aligned.m16n8k16.row.col.f32.f16.f16.f32 "
        "{%0,%1,%2,%3}, {%4,%5,%6,%7}, {%8,%9}, {%0,%1,%2,%3};"
        : "+f"(c[0]), "+f"(c[1]), "+f"(c[2]), "+f"(c[3])
        : "r"(a[0]), "r"(a[1]), "r"(a[2]), "r"(a[3]), "r"(b0), "r"(b1));
}

__device__ __forceinline__ void ldsm4(uint32_t* r, uint32_t addr) {
    asm volatile("ldmatrix.sync.aligned.m8n8.x4.shared.b16 {%0,%1,%2,%3}, [%4];"
                 : "=r"(r[0]), "=r"(r[1]), "=r"(r[2]), "=r"(r[3]) : "r"(addr));
}

__device__ __forceinline__ void cpa16(uint32_t dst, const void* src, bool pred) {
    int sz = pred ? 16 : 0;
    asm volatile("cp.async.cg.shared.global [%0], [%1], 16, %2;\n"
                 :: "r"(dst), "l"(src), "r"(sz));
}
__device__ __forceinline__ void cpa_commit() { asm volatile("cp.async.commit_group;\n"); }
__device__ __forceinline__ void cpa_wait1()  { asm volatile("cp.async.wait_group 1;\n"); }

__device__ __forceinline__ uint32_t smem_u32(const void* p) {
    uint32_t a;
    asm("{ .reg .u64 t; cvta.to.shared.u64 t, %1; cvt.u32.u64 %0, t; }" : "=r"(a) : "l"(p));
    return a;
}

constexpr int PK = 20;
constexpr int ASTG = 2560;
constexpr int BSTG = 2560;
constexpr int SMEM_BYTES = (3 * ASTG + 3 * BSTG) * 4;   // 61440

// ================= unified fp16 GEMM =================
template<int ACT, int EPI, int OUTH>
__global__ void __launch_bounds__(256, 2) hgemm_k(
    int M, int N, int K,
    const __half* __restrict__ A,
    const __half* __restrict__ Bt,
    void* __restrict__ C, int ldc,
    const float* __restrict__ bias,
    const float* __restrict__ dinv)
{
    extern __shared__ uint32_t sh[];
    const int bn = blockIdx.x, bm = blockIdx.y;
    const int m0 = bm * 128, n0 = bn * 128;

    const int tid  = threadIdx.x;
    const int lane = tid & 31, warp = tid >> 5;
    const int g = lane >> 2, th = lane & 3;
    const int wm = (warp >> 1) * 32;
    const int wn = (warp & 1) * 64;
    const int r8 = lane & 7, sel = lane >> 3;

    uint32_t sbase = smem_u32(sh);

    float acc[2][8][4];
#pragma unroll
    for (int i = 0; i < 2; i++)
#pragma unroll
        for (int j = 0; j < 8; j++)
#pragma unroll
            for (int l = 0; l < 4; l++) acc[i][j][l] = 0.f;

    const int KT = K / 32;

    auto issue = [&](int kt, int stg) {
        uint32_t abase = sbase + (uint32_t)(stg * ASTG) * 4u;
        uint32_t bbase = sbase + (uint32_t)(3 * ASTG + stg * BSTG) * 4u;
#pragma unroll
        for (int it = 0; it < 2; it++) {
            int c = tid * 2 + it;
            int row = c >> 2, kc = c & 3;
            const __half* srcA = A + (long long)(m0 + row) * K + kt * 32 + kc * 8;
            cpa16(abase + (uint32_t)(row * PK + kc * 4) * 4u, srcA, (m0 + row) < M);
            const __half* srcB = Bt + (long long)(n0 + row) * K + kt * 32 + kc * 8;
            cpa16(bbase + (uint32_t)(row * PK + kc * 4) * 4u, srcB, (n0 + row) < N);
        }
    };

    auto mmaTile = [&](int stg) {
        uint32_t abase = sbase + (uint32_t)(stg * ASTG) * 4u;
        uint32_t bbase = sbase + (uint32_t)(3 * ASTG + stg * BSTG) * 4u;
#pragma unroll
        for (int s = 0; s < 2; s++) {
            const int k0 = s * 8;
            uint32_t a[2][4];
#pragma unroll
            for (int mt = 0; mt < 2; mt++) {
                int row = wm + mt * 16 + ((sel & 1) << 3) + r8;
                int ku  = k0 + ((sel & 2) << 1);
                ldsm4(a[mt], abase + (uint32_t)(row * PK + ku) * 4u);
            }
            uint32_t b0v[8], b1v[8];
#pragma unroll
            for (int g4 = 0; g4 < 2; g4++) {
                int row = wn + g4 * 32 + sel * 8 + r8;
                ldsm4(&b0v[g4 * 4], bbase + (uint32_t)(row * PK + k0) * 4u);
                ldsm4(&b1v[g4 * 4], bbase + (uint32_t)(row * PK + k0 + 4) * 4u);
            }
#pragma unroll
            for (int nt = 0; nt < 8; nt++) {
                mma_f16(acc[0][nt], a[0], b0v[nt], b1v[nt]);
                mma_f16(acc[1][nt], a[1], b0v[nt], b1v[nt]);
            }
        }
    };

    issue(0, 0); cpa_commit();
    if (KT > 1) issue(1, 1);
    cpa_commit();
    cpa_wait1();
    __syncthreads();

    for (int kt = 0; kt < KT; kt++) {
        int stg = kt % 3;
        if (kt + 2 < KT) issue(kt + 2, (kt + 2) % 3);
        cpa_commit();
        mmaTile(stg);
        cpa_wait1();
        __syncthreads();
    }

    __half* Ch = (__half*)C;
    float*  Cf = (float*)C;
#pragma unroll
    for (int mt = 0; mt < 2; mt++) {
#pragma unroll
        for (int nt = 0; nt < 8; nt++) {
#pragma unroll
            for (int eh = 0; eh < 2; eh++) {
                int gm = m0 + wm + mt * 16 + g + (eh ? 8 : 0);
                int gn = n0 + wn + nt * 8 + 2 * th;
                if (gm >= M || gn >= N) continue;
                float v0 = acc[mt][nt][eh * 2 + 0];
                float v1 = acc[mt][nt][eh * 2 + 1];
                if (EPI == 1) { float dv = dinv[gm]; v0 *= dv; v1 *= dv; }
                if (bias)     { v0 += bias[gn]; v1 += bias[gn + 1]; }
                if (ACT == 1) { v0 = fmaxf(v0, 0.f); v1 = fmaxf(v1, 0.f); }
                if (ACT == 2) {
                    v0 = 0.5f * v0 * (1.f + erff(v0 * 0.70710678118654752f));
                    v1 = 0.5f * v1 * (1.f + erff(v1 * 0.70710678118654752f));
                }
                if (OUTH) {
                    *reinterpret_cast<__half2*>(&Ch[(long long)gm * ldc + gn]) =
                        __floats2half2_rn(v0, v1);
                } else {
                    Cf[(long long)gm * ldc + gn]     = v0;
                    Cf[(long long)gm * ldc + gn + 1] = v1;
                }
            }
        }
    }
}

// ---------------- fp16 gram, fp32 att; coalesced mirror via smem transpose ----------------
__global__ void __launch_bounds__(256, 2) hgram_k(const __half* __restrict__ F,
                                                  float* __restrict__ att)
{
    extern __shared__ uint32_t sh[];
    const int bn = blockIdx.x, bm = blockIdx.y, b = blockIdx.z;
    if (bm > bn) return;
    const int m0 = bm * 128, n0 = bn * 128;

    const int tid  = threadIdx.x;
    const int lane = tid & 31, warp = tid >> 5;
    const int g = lane >> 2, th = lane & 3;
    const int wm = (warp >> 1) * 32;
    const int wn = (warp & 1) * 64;
    const int r8 = lane & 7, sel = lane >> 3;

    uint32_t sbase = smem_u32(sh);
    const __half* Fb = F + (long long)b * NN * KF;
    float* attb = att + (long long)b * NN * NN;

    float acc[2][8][4];
#pragma unroll
    for (int i = 0; i < 2; i++)
#pragma unroll
        for (int j = 0; j < 8; j++)
#pragma unroll
            for (int l = 0; l < 4; l++) acc[i][j][l] = 0.f;

    const int KT = KF / 32;

    auto issue = [&](int kt, int stg) {
        uint32_t abase = sbase + (uint32_t)(stg * ASTG) * 4u;
        uint32_t bbase = sbase + (uint32_t)(3 * ASTG + stg * BSTG) * 4u;
#pragma unroll
        for (int it = 0; it < 2; it++) {
            int c = tid * 2 + it;
            int row = c >> 2, kc = c & 3;
            const __half* srcA = Fb + (long long)(m0 + row) * KF + kt * 32 + kc * 8;
            cpa16(abase + (uint32_t)(row * PK + kc * 4) * 4u, srcA, (m0 + row) < NN);
            const __half* srcB = Fb + (long long)(n0 + row) * KF + kt * 32 + kc * 8;
            cpa16(bbase + (uint32_t)(row * PK + kc * 4) * 4u, srcB, (n0 + row) < NN);
        }
    };

    auto mmaTile = [&](int stg) {
        uint32_t abase = sbase + (uint32_t)(stg * ASTG) * 4u;
        uint32_t bbase = sbase + (uint32_t)(3 * ASTG + stg * BSTG) * 4u;
#pragma unroll
        for (int s = 0; s < 2; s++) {
            const int k0 = s * 8;
            uint32_t a[2][4];
#pragma unroll
            for (int mt = 0; mt < 2; mt++) {
                int row = wm + mt * 16 + ((sel & 1) << 3) + r8;
                int ku  = k0 + ((sel & 2) << 1);
                ldsm4(a[mt], abase + (uint32_t)(row * PK + ku) * 4u);
            }
            uint32_t b0v[8], b1v[8];
#pragma unroll
            for (int g4 = 0; g4 < 2; g4++) {
                int row = wn + g4 * 32 + sel * 8 + r8;
                ldsm4(&b0v[g4 * 4], bbase + (uint32_t)(row * PK + k0) * 4u);
                ldsm4(&b1v[g4 * 4], bbase + (uint32_t)(row * PK + k0 + 4) * 4u);
            }
#pragma unroll
            for (int nt = 0; nt < 8; nt++) {
                mma_f16(acc[0][nt], a[0], b0v[nt], b1v[nt]);
                mma_f16(acc[1][nt], a[1], b0v[nt], b1v[nt]);
            }
        }
    };

    issue(0, 0); cpa_commit();
    if (KT > 1) issue(1, 1);
    cpa_commit();
    cpa_wait1();
    __syncthreads();

    for (int kt = 0; kt < KT; kt++) {
        int stg = kt % 3;
        if (kt + 2 < KT) issue(kt + 2, (kt + 2) % 3);
        cpa_commit();
        mmaTile(stg);
        cpa_wait1();
        __syncthreads();
    }

    // direct stores (float2)
#pragma unroll
    for (int mt = 0; mt < 2; mt++) {
#pragma unroll
        for (int nt = 0; nt < 8; nt++) {
#pragma unroll
            for (int eh = 0; eh < 2; eh++) {
                int gm = m0 + wm + mt * 16 + g + (eh ? 8 : 0);
                int gn = n0 + wn + nt * 8 + 2 * th;
                if (gm >= NN || gn + 1 >= NN) continue;
                float2 v = make_float2(0.125f * acc[mt][nt][eh * 2 + 0],
                                       0.125f * acc[mt][nt][eh * 2 + 1]);
                *reinterpret_cast<float2*>(&attb[(long long)gm * NN + gn]) = v;
            }
        }
    }

    // mirror via smem transpose (coalesced)
    if (bm < bn) {
        float* smf = reinterpret_cast<float*>(sh);
#pragma unroll
        for (int p = 0; p < 2; p++) {
            if ((warp & 1) == p) {
#pragma unroll
                for (int mt = 0; mt < 2; mt++) {
#pragma unroll
                    for (int nt = 0; nt < 8; nt++) {
#pragma unroll
                        for (int eh = 0; eh < 2; eh++) {
                            int gml  = wm + mt * 16 + g + (eh ? 8 : 0);
                            int rowl = nt * 8 + 2 * th;
                            smf[rowl * 132 + gml]       = 0.125f * acc[mt][nt][eh * 2 + 0];
                            smf[(rowl + 1) * 132 + gml] = 0.125f * acc[mt][nt][eh * 2 + 1];
                        }
                    }
                }
            }
            __syncthreads();
            for (int idx = tid; idx < 2048; idx += 256) {
                int rowl = idx >> 5, c4 = (idx & 31) << 2;
                int gn = n0 + p * 64 + rowl;
                if (gn < NN && m0 + c4 + 3 < NN) {
                    float4 v = *reinterpret_cast<float4*>(&smf[rowl * 132 + c4]);
                    *reinterpret_cast<float4*>(&attb[(long long)gn * NN + m0 + c4]) = v;
                }
            }
            __syncthreads();
        }
    }
}

// ---------------- weight transpose to half ----------------
__global__ void trhalf_k(const float* __restrict__ src, __half* __restrict__ dst, int K, int N)
{
    int idx = blockIdx.x * blockDim.x + threadIdx.x;
    if (idx >= K * N) return;
    int n = idx / K, k = idx % K;
    dst[(long long)n * K + k] = __float2half_rn(src[(long long)k * N + n]);
}

// ---------------- gl_w -> GLWt half [KF, D] ----------------
__global__ void glwt_k(const float* __restrict__ glw, __half* __restrict__ GLWt)
{
    int idx = blockIdx.x * blockDim.x + threadIdx.x;
    if (idx >= KF * D_) return;
    int c = idx / D_, k = idx % D_;
    int p = c >> 9, hh = c & 511;
    GLWt[idx] = __float2half_rn(glw[((long long)p * D_ + k) * HD + hh]);
}

// ---------------- A-matrix builder (single view, 8 batches) ----------------
__global__ void build_ag1_k(const float* __restrict__ x,
                            const float* __restrict__ emb,
                            const float* __restrict__ gw, const float* __restrict__ gb,
                            __half* __restrict__ Ag)
{
    long long idx = (long long)blockIdx.x * blockDim.x + threadIdx.x;
    if (idx >= MR * E_) return;
    int e = (int)(idx & (E_ - 1));
    long long r = idx >> 9;
    int n = (int)(r % NN);
    float t = fmaf(x[r], gw[e], gb[e]);
    float sgm = 1.0f / (1.0f + expf(-t));
    Ag[idx] = __float2half_rn(sgm * emb[(long long)n * E_ + e]);
}

// ---------------- top-k(50): register-resident, fp32 att ----------------
__global__ void __launch_bounds__(256) topk_rows_k(
    const float* __restrict__ att,
    float* __restrict__ rowval, int* __restrict__ rowcol, int* __restrict__ rowcnt)
{
    __shared__ int   hist[256];
    __shared__ float wredf[8];
    __shared__ float s_bcast;
    __shared__ int   s_selb, s_selk, s_pos;

    long long row = blockIdx.x;
    const float* r = att + row * 2000;
    int tid = threadIdx.x;
    int lane = tid & 31, wid = tid >> 5;

    float v[8];
#pragma unroll
    for (int p = 0; p < 8; p++) {
        int i = tid + p * 256;
        v[p] = (i < 2000) ? r[i] : 0.f;
    }
    if (tid == 0) s_pos = 0;

    float mx = 0.f;
#pragma unroll
    for (int p = 0; p < 8; p++) mx = fmaxf(mx, v[p]);
#pragma unroll
    for (int o = 16; o; o >>= 1) mx = fmaxf(mx, __shfl_xor_sync(0xffffffffu, mx, o));
    if (lane == 0) wredf[wid] = mx;
    __syncthreads();
    if (tid == 0) { float m = wredf[0]; for (int w = 1; w < 8; w++) m = fmaxf(m, wredf[w]); s_bcast = m; }
    __syncthreads();
    mx = s_bcast;

    unsigned prefix = 0u;
    int k = 50;
#pragma unroll
    for (int pass = 0; pass < 4; pass++) {
        const int shift = 24 - 8 * pass;
        const unsigned hmask = (pass == 0) ? 0u : (0xFFFFFFFFu << (shift + 8));
        if (tid < 256) hist[tid] = 0;
        __syncthreads();
#pragma unroll
        for (int p = 0; p < 8; p++) {
            int i = tid + p * 256;
            if (i < 2000) {
                unsigned u = __float_as_uint(v[p]);
                if ((u & hmask) == prefix)
                    atomicAdd(&hist[(u >> shift) & 255], 1);
            }
        }
        __syncthreads();
        if (tid == 0) {
            int acc = 0, b = 255;
            for (; b > 0; b--) { acc += hist[b]; if (acc >= k) break; }
            if (acc < k) acc += hist[0];
            s_selb = b;
            s_selk = k - (acc - hist[b]);
        }
        __syncthreads();
        prefix |= ((unsigned)s_selb) << shift;
        k = s_selk;
        __syncthreads();
    }
    float thr = __uint_as_float(prefix);

    float sum = 0.f;
#pragma unroll
    for (int p = 0; p < 8; p++) {
        int i = tid + p * 256;
        if (i < 2000 && v[p] >= thr) sum += expf(v[p] - mx);
    }
#pragma unroll
    for (int o = 16; o; o >>= 1) sum += __shfl_xor_sync(0xffffffffu, sum, o);
    if (lane == 0) wredf[wid] = sum;
    __syncthreads();
    if (tid == 0) { float t = 0.f; for (int w = 0; w < 8; w++) t += wredf[w]; s_bcast = t; }
    __syncthreads();
    float inv = 1.0f / s_bcast;

#pragma unroll
    for (int p = 0; p < 8; p++) {
        int i = tid + p * 256;
        if (i < 2000 && v[p] >= thr) {
            int pos = atomicAdd(&s_pos, 1);
            if (pos < ROWCAP) {
                rowval[row * ROWCAP + pos] = expf(v[p] - mx) * inv;
                rowcol[row * ROWCAP + pos] = i;
            }
        }
    }
    __syncthreads();
    if (tid == 0) rowcnt[row] = min(s_pos, ROWCAP);
}

// ---------------- zero ----------------
__global__ void zero_k(int* __restrict__ a, float* __restrict__ b, int n)
{
    int i = blockIdx.x * blockDim.x + threadIdx.x;
    if (i < n) { a[i] = 0; b[i] = 0.f; }
}

// ---------------- count column occupancy ----------------
__global__ void count_k(const int* __restrict__ rowcol, const int* __restrict__ rowcnt,
                        int* __restrict__ colcnt)
{
    int row = blockIdx.x;
    int b = row / NN;
    int cnt = rowcnt[row];
    if (threadIdx.x < cnt)
        atomicAdd(&colcnt[b * NN + rowcol[row * ROWCAP + threadIdx.x]], 1);
}

// ---------------- per-batch exclusive scan ----------------
__global__ void __launch_bounds__(256) scan_k(const int* __restrict__ colcnt,
                                              int* __restrict__ coloff, int* __restrict__ colcur)
{
    __shared__ int tsum[257];
    int b = blockIdx.x, tid = threadIdx.x;
    const int* cnt = colcnt + b * NN;
    int local[8];
    int tot = 0;
#pragma unroll
    for (int e = 0; e < 8; e++) {
        int i = tid * 8 + e;
        local[e] = tot;
        tot += (i < NN) ? cnt[i] : 0;
    }
    tsum[tid] = tot;
    __syncthreads();
    if (tid == 0) {
        int acc = 0;
        for (int t = 0; t < 256; t++) { int v = tsum[t]; tsum[t] = acc; acc += v; }
    }
    __syncthreads();
    int base = tsum[tid];
#pragma unroll
    for (int e = 0; e < 8; e++) {
        int i = tid * 8 + e;
        if (i < NN) {
            coloff[b * NN + i] = base + local[e];
            colcur[b * NN + i] = base + local[e];
        }
    }
}

// ---------------- place into CSC ----------------
__global__ void place_k(const float* __restrict__ rowval, const int* __restrict__ rowcol,
                        const int* __restrict__ rowcnt,
                        int* __restrict__ colcur, float* __restrict__ colsum,
                        float* __restrict__ cscval, int* __restrict__ cscrow)
{
    int row = blockIdx.x;
    int b = row / NN, j = row % NN;
    int cnt = rowcnt[row];
    int e = threadIdx.x;
    if (e < cnt) {
        int   c = rowcol[row * ROWCAP + e];
        float w = rowval[row * ROWCAP + e];
        int pos = atomicAdd(&colcur[b * NN + c], 1);
        cscval[(long long)b * CAP + pos] = w;
        cscrow[(long long)b * CAP + pos] = j;
        atomicAdd(&colsum[b * NN + c], w);
    }
}

// ---------------- dinv ----------------
__global__ void dinv_k(const float* __restrict__ colsum, float* __restrict__ dinv, int n)
{
    int i = blockIdx.x * blockDim.x + threadIdx.x;
    if (i < n) dinv[i] = rsqrtf(1.0f + colsum[i]);
}

// ---------------- sparse GCN aggregation, ILP-4 gather ----------------
template<int DIM, int ACT, int OUTH>
__global__ void spagg_k(
    const float* __restrict__ cscval, const int* __restrict__ cscrow,
    const int* __restrict__ coloff, const int* __restrict__ colcnt,
    const __half* __restrict__ T, const float* __restrict__ dinv,
    const float* __restrict__ bias, void* __restrict__ out)
{
    __shared__ float sw[256];
    __shared__ int   sj[256];
    int i = blockIdx.x, b = blockIdx.y, tid = threadIdx.x;
    const __half* Tb = T + (long long)b * NN * DIM;
    int s0  = coloff[b * NN + i];
    int cnt = colcnt[b * NN + i];
    long long base = (long long)b * CAP + s0;

    float2 a0 = __half22float2(*reinterpret_cast<const __half2*>(&Tb[(long long)i * DIM + 2 * tid]));
    float2 a1 = make_float2(0.f, 0.f);
    float2 a2 = make_float2(0.f, 0.f);
    float2 a3 = make_float2(0.f, 0.f);

    for (int e0 = 0; e0 < cnt; e0 += blockDim.x) {
        int chunk = min(cnt - e0, (int)blockDim.x);
        if (tid < chunk) {
            sw[tid] = cscval[base + e0 + tid];
            sj[tid] = cscrow[base + e0 + tid];
        }
        __syncthreads();
        int e = 0;
        for (; e + 3 < chunk; e += 4) {
            float2 t0 = __half22float2(*reinterpret_cast<const __half2*>(&Tb[(long long)sj[e]   * DIM + 2 * tid]));
            float2 t1 = __half22float2(*reinterpret_cast<const __half2*>(&Tb[(long long)sj[e+1] * DIM + 2 * tid]));
            float2 t2 = __half22float2(*reinterpret_cast<const __half2*>(&Tb[(long long)sj[e+2] * DIM + 2 * tid]));
            float2 t3 = __half22float2(*reinterpret_cast<const __half2*>(&Tb[(long long)sj[e+3] * DIM + 2 * tid]));
            a0.x = fmaf(sw[e],   t0.x, a0.x); a0.y = fmaf(sw[e],   t0.y, a0.y);
            a1.x = fmaf(sw[e+1], t1.x, a1.x); a1.y = fmaf(sw[e+1], t1.y, a1.y);
            a2.x = fmaf(sw[e+2], t2.x, a2.x); a2.y = fmaf(sw[e+2], t2.y, a2.y);
            a3.x = fmaf(sw[e+3], t3.x, a3.x); a3.y = fmaf(sw[e+3], t3.y, a3.y);
        }
        for (; e < chunk; e++) {
            float2 t0 = __half22float2(*reinterpret_cast<const __half2*>(&Tb[(long long)sj[e] * DIM + 2 * tid]));
            a0.x = fmaf(sw[e], t0.x, a0.x);
            a0.y = fmaf(sw[e], t0.y, a0.y);
        }
        __syncthreads();
    }
    float dv = dinv[b * NN + i];
    float vx = dv * ((a0.x + a1.x) + (a2.x + a3.x)) + bias[2 * tid];
    float vy = dv * ((a0.y + a1.y) + (a2.y + a3.y)) + bias[2 * tid + 1];
    if (ACT == 1) { vx = fmaxf(vx, 0.f); vy = fmaxf(vy, 0.f); }
    if (OUTH) {
        __half* oh = (__half*)out;
        *reinterpret_cast<__half2*>(&oh[((long long)b * NN + i) * DIM + 2 * tid]) =
            __floats2half2_rn(vx, vy);
    } else {
        float* of = (float*)out;
        *reinterpret_cast<float2*>(&of[((long long)b * NN + i) * DIM + 2 * tid]) = make_float2(vx, vy);
    }
}

// ---------------- per-view mean over nodes; mu/std/z ----------------
__global__ void meanz1_k(const float* __restrict__ O3, const float* __restrict__ eps,
                         float* __restrict__ mu, float* __restrict__ stdv,
                         float* __restrict__ z)
{
    int b = blockIdx.x, d = threadIdx.x;
    const float* p = O3 + ((long long)b * 2000) * 128 + d;
    float s0 = 0.f, s1 = 0.f, s2 = 0.f, s3 = 0.f;
    for (int i = 0; i < 2000; i += 4) {
        s0 += p[(long long)i * 128];
        s1 += p[(long long)(i + 1) * 128];
        s2 += p[(long long)(i + 2) * 128];
        s3 += p[(long long)(i + 3) * 128];
    }
    __shared__ float sg[128];
    sg[d] = ((s0 + s1) + (s2 + s3)) / 2000.0f;
    __syncthreads();
    if (d < 64) {
        float m = sg[d];
        float sp = log1pf(expf(sg[64 + d] - 64.0f));
        mu[b * 64 + d] = m;
        stdv[b * 64 + d] = sp;
        z[b * 64 + d] = fmaf(eps[b * 64 + d], sp, m);
    }
}

// ---------------- decoder ----------------
__global__ void __launch_bounds__(256) decode_k(
    const float* __restrict__ z, const float* __restrict__ w1, const float* __restrict__ b1,
    const float* __restrict__ gamma, const float* __restrict__ beta,
    const float* __restrict__ w2, const float* __restrict__ b2,
    float* __restrict__ xrec)
{
    __shared__ float h[1024];
    __shared__ float zs[64];
    int b = blockIdx.x, tid = threadIdx.x;
    if (tid < 64) zs[tid] = z[b * 64 + tid];
    __syncthreads();
    const float invc = 1.0f / sqrtf(1.0f + 1e-5f);
    for (int c = tid; c < 1024; c += 256) {
        float a = b1[c];
#pragma unroll 8
        for (int k = 0; k < 64; k++) a = fmaf(zs[k], w1[k * 1024 + c], a);
        a = a * (gamma[c] * invc) + beta[c];
        h[c] = fmaxf(a, 0.f);
    }
    __syncthreads();
    int c0 = blockIdx.y * 250;
    int c1 = min(c0 + 250, 2000);
    for (int c = c0 + tid; c < c1; c += 256) {
        float a = b2[c];
        for (int k = 0; k < 1024; k++) a = fmaf(h[k], w2[k * 2000 + c], a);
        xrec[b * 2000 + c] = fmaxf(a, 0.f);
    }
}

// ---------------- host orchestration ----------------
extern "C" void kernel_launch(void* const* d_in, const int* in_sizes, int n_in,
                              void* d_out, int out_size)
{
    const float* x1     = (const float*)d_in[0];
    const float* x2     = (const float*)d_in[1];
    const float* emb1   = (const float*)d_in[2];
    const float* gate_w = (const float*)d_in[3];
    const float* gate_b = (const float*)d_in[4];
    const float* enc_w1 = (const float*)d_in[5];
    const float* enc_b1 = (const float*)d_in[6];
    const float* enc_w2 = (const float*)d_in[7];
    const float* enc_b2 = (const float*)d_in[8];
    const float* gl_w   = (const float*)d_in[9];
    const float* g_w1   = (const float*)d_in[10];
    const float* g_b1   = (const float*)d_in[11];
    const float* g_w2   = (const float*)d_in[12];
    const float* g_b2   = (const float*)d_in[13];
    const float* g_w3   = (const float*)d_in[14];
    const float* g_b3   = (const float*)d_in[15];
    const float* dW1[2] = {(const float*)d_in[16], (const float*)d_in[22]};
    const float* dB1[2] = {(const float*)d_in[17], (const float*)d_in[23]};
    const float* dG [2] = {(const float*)d_in[18], (const float*)d_in[24]};
    const float* dBe[2] = {(const float*)d_in[19], (const float*)d_in[25]};
    const float* dW2[2] = {(const float*)d_in[20], (const float*)d_in[26]};
    const float* dB2[2] = {(const float*)d_in[21], (const float*)d_in[27]};
    const float* epsA[2]= {(const float*)d_in[28], (const float*)d_in[29]};
    const float* xin[2] = {x1, x2};

    static cudaStream_t s1 = nullptr;
    static cudaEvent_t evF = nullptr, evJ = nullptr;
    static bool attr_done = false;
    if (!attr_done) {
        cudaFuncSetAttribute(hgemm_k<2,0,1>, cudaFuncAttributeMaxDynamicSharedMemorySize, SMEM_BYTES);
        cudaFuncSetAttribute(hgemm_k<0,0,1>, cudaFuncAttributeMaxDynamicSharedMemorySize, SMEM_BYTES);
        cudaFuncSetAttribute(hgemm_k<1,0,1>, cudaFuncAttributeMaxDynamicSharedMemorySize, SMEM_BYTES);
        cudaFuncSetAttribute(hgemm_k<0,1,1>, cudaFuncAttributeMaxDynamicSharedMemorySize, SMEM_BYTES);
        cudaFuncSetAttribute(hgram_k, cudaFuncAttributeMaxDynamicSharedMemorySize, SMEM_BYTES);
        cudaStreamCreateWithFlags(&s1, cudaStreamNonBlocking);
        cudaEventCreateWithFlags(&evF, cudaEventDisableTiming);
        cudaEventCreateWithFlags(&evJ, cudaEventDisableTiming);
        attr_done = true;
    }

    float* sc = nullptr;
    cudaGetSymbolAddress((void**)&sc, g_scratch);
    __half* Agh  = (__half*)(sc + OFF_AGH);
    __half* Henh = (__half*)(sc + OFF_HENH);
    __half* Hh   = (__half*)(sc + OFF_HH);
    __half* GLWt = (__half*)(sc + OFF_GLWT);
    __half* Fh   = (__half*)(sc + OFF_FH);
    float*  att  = sc + OFF_ATT;
    float*  dinv = sc + OFF_DINV;
    __half* Th   = (__half*)(sc + OFF_TH);
    __half* O1h  = (__half*)(sc + OFF_O1H);
    __half* O2h  = (__half*)(sc + OFF_O2H);
    float*  O3   = sc + OFF_O3;
    float*  zb   = sc + OFF_Z;
    __half* W1t  = (__half*)(sc + OFF_W1T);
    __half* W2t  = (__half*)(sc + OFF_W2T);
    __half* GW1t = (__half*)(sc + OFF_GW1T);
    __half* GW2t = (__half*)(sc + OFF_GW2T);
    __half* GW3t = (__half*)(sc + OFF_GW3T);
    float* rowval = sc + OFF_ROWV;
    int*   rowcol = (int*)(sc + OFF_ROWC);
    int*   rowcnt = (int*)(sc + OFF_RCNT);
    int*   colcnt = (int*)(sc + OFF_CCNT);
    int*   coloff = (int*)(sc + OFF_COFF);
    int*   colcur = (int*)(sc + OFF_CCUR);
    float* colsum = sc + OFF_CSUM;
    float* cscval = sc + OFF_CSCV;
    int*   cscrow = (int*)(sc + OFF_CSCR);

    float* out = (float*)d_out;
    float* xrec[2] = {out,          out + 16000};
    float* muo [2] = {out + 32000,  out + 33024};
    float* stdo[2] = {out + 32512,  out + 33536};

    // ---- shared weight prep (default stream), then fork ----
    trhalf_k<<<(E_ * HEN + 255) / 256, 256>>>(enc_w1, W1t, E_, HEN);
    trhalf_k<<<(HEN * D_ + 255) / 256, 256>>>(enc_w2, W2t, HEN, D_);
    trhalf_k<<<(D_ * HD + 255) / 256, 256>>>(g_w1, GW1t, D_, HD);
    trhalf_k<<<(HD * HD + 255) / 256, 256>>>(g_w2, GW2t, HD, HD);
    trhalf_k<<<(HD * D_ + 255) / 256, 256>>>(g_w3, GW3t, HD, D_);
    glwt_k<<<(KF * D_ + 255) / 256, 256>>>(gl_w, GLWt);

    cudaEventRecord(evF, 0);
    cudaStreamWaitEvent(s1, evF, 0);

    // ---- full per-view pipelines on two streams ----
    for (int v = 0; v < 2; v++) {
        cudaStream_t st = v ? s1 : 0;
        long long bo = (long long)v * 8 * NN;
        __half* Agv = Agh + bo * E_;
        __half* Hev = Henh + bo * HEN;
        __half* Hv  = Hh + bo * D_;
        __half* Fv  = Fh + bo * KF;
        float*  av  = att + bo * NN;
        float*  rvv = rowval + bo * ROWCAP;
        int*    rcv = rowcol + bo * ROWCAP;
        int*    rnv = rowcnt + bo;
        int*    ccv = colcnt + bo;
        int*    cov = coloff + bo;
        int*    cuv = colcur + bo;
        float*  csv = colsum + bo;
        float*  dvv = dinv + bo;
        float*  vv  = cscval + (long long)v * 8 * CAP;
        int*    rv2 = cscrow + (long long)v * 8 * CAP;
        __half* Tv  = Th + bo * HD;
        __half* O1v = O1h + bo * HD;
        __half* O2v = O2h + bo * HD;
        float*  O3v = O3 + bo * D_;

        // encoder chain (per view, M = 16000)
        build_ag1_k<<<(unsigned)((MR * E_ + 255) / 256), 256, 0, st>>>(
            xin[v], emb1, gate_w, gate_b, Agv);
        hgemm_k<2,0,1><<<dim3(HEN / 128, 125), 256, SMEM_BYTES, st>>>(
            (int)MR, HEN, E_, Agv, W1t, Hev, HEN, enc_b1, nullptr);
        hgemm_k<0,0,1><<<dim3(1, 125), 256, SMEM_BYTES, st>>>(
            (int)MR, D_, HEN, Hev, W2t, Hv, D_, enc_b2, nullptr);
        hgemm_k<1,0,1><<<dim3(KF / 128, 125), 256, SMEM_BYTES, st>>>(
            (int)MR, KF, D_, Hv, GLWt, Fv, KF, nullptr, nullptr);

        // gram + sparse adjacency
        hgram_k<<<dim3(16, 16, 8), 256, SMEM_BYTES, st>>>(Fv, av);
        zero_k<<<(8 * NN + 255) / 256, 256, 0, st>>>(ccv, csv, 8 * NN);
        topk_rows_k<<<16000, 256, 0, st>>>(av, rvv, rcv, rnv);
        count_k<<<16000, ROWCAP, 0, st>>>(rcv, rnv, ccv);
        scan_k<<<8, 256, 0, st>>>(ccv, cov, cuv);
        place_k<<<16000, ROWCAP, 0, st>>>(rvv, rcv, rnv, cuv, csv, vv, rv2);
        dinv_k<<<(8 * NN + 255) / 256, 256, 0, st>>>(csv, dvv, 8 * NN);

        // GCN
        hgemm_k<0,1,1><<<dim3(HD / 128, 125), 256, SMEM_BYTES, st>>>(
            16000, HD, D_, Hv, GW1t, Tv, HD, nullptr, dvv);
        spagg_k<HD,1,1><<<dim3(NN, 8), HD/2, 0, st>>>(vv, rv2, cov, ccv, Tv, dvv, g_b1, O1v);
        hgemm_k<0,1,1><<<dim3(HD / 128, 125), 256, SMEM_BYTES, st>>>(
            16000, HD, HD, O1v, GW2t, Tv, HD, nullptr, dvv);
        spagg_k<HD,1,1><<<dim3(NN, 8), HD/2, 0, st>>>(vv, rv2, cov, ccv, Tv, dvv, g_b2, O2v);
        hgemm_k<0,1,1><<<dim3(1, 125), 256, SMEM_BYTES, st>>>(
            16000, D_, HD, O2v, GW3t, Tv, D_, nullptr, dvv);
        spagg_k<D_,0,0><<<dim3(NN, 8), D_/2, 0, st>>>(vv, rv2, cov, ccv, Tv, dvv, g_b3, O3v);

        // VIB head + decoder
        meanz1_k<<<8, 128, 0, st>>>(O3v, epsA[v], muo[v], stdo[v], zb + v * 512);
        decode_k<<<dim3(8, 8), 256, 0, st>>>(zb + v * 512, dW1[v], dB1[v], dG[v], dBe[v],
                                             dW2[v], dB2[v], xrec[v]);
    }

    // ---- join ----
    cudaEventRecord(evJ, s1);
    cudaStreamWaitEvent(0, evJ, 0);
}